// round 4
// baseline (speedup 1.0000x reference)
#include <cuda_runtime.h>
#include <cuda_bf16.h>
#include <math.h>
#include <stdint.h>

// Problem constants
#define S_STEPS 24
#define BATCH   128
#define SEQT    24
#define DIN     512
#define D       128
#define DFF     2048
#define NH      4
#define DH      32
#define NC      64
#define NT      38400  // BATCH * S*(S+1)/2
#define NBT     3072   // BATCH*SEQT

// fp32 scratch
__device__ float g_h0[NBT * D];
__device__ float g_Y[NT * D];

// bf16 buffers
__device__ __nv_bfloat16 g_xbf[NBT * DIN];
__device__ __nv_bfloat16 g_wfc_bf[D * DIN];
__device__ __nv_bfloat16 g_qkvw_bf[2 * 3 * D * D];
__device__ __nv_bfloat16 g_outw_bf[2 * D * D];
__device__ __nv_bfloat16 g_ff1w_bf[2 * DFF * D];
__device__ __nv_bfloat16 g_ff2w_bf[2 * D * DFF];
__device__ __nv_bfloat16 g_Ybf[NT * D];
__device__ __nv_bfloat16 g_qkvbf[NT * 3 * D];
__device__ __nv_bfloat16 g_ctxbf[NT * D];
__device__ __nv_bfloat16 g_Hbf[(size_t)NT * DFF];

__device__ __forceinline__ uint32_t smem_u32(const void* p) {
    return (uint32_t)__cvta_generic_to_shared(p);
}

// ---------------------------------------------------------------------------
// bf16 GEMM core: 128x128 block tile, BK=32, 256 threads (8 warps 4x2),
// 3-stage cp.async pipeline, ldmatrix fragments, m16n8k16 bf16 mma.
// A[M,K] row-major, W[N,K] row-major (so C = A @ W^T). K % 32 == 0, K >= 64.
// ---------------------------------------------------------------------------
#define SSTR 40                 // smem row stride in bf16 (32 + 8 pad)
#define TILE (128 * SSTR)       // elems per stage per operand
#define GEMM_SMEM  (3 * TILE * 2 * 2)            // 61440 B
#define GEMM_SMEM_LN (GEMM_SMEM + 512 * 4)       // + reduction arrays

__device__ __forceinline__ void gemm_core(
    const __nv_bfloat16* __restrict__ A, const __nv_bfloat16* __restrict__ W,
    int K, int m0, int n0, __nv_bfloat16* As, __nv_bfloat16* Bs,
    float (&acc)[2][8][4])
{
    const int t = threadIdx.x, warp = t >> 5, lane = t & 31;
    const int wm = (warp >> 1) * 32, wn = (warp & 1) * 64;
    const int ldrow = t >> 2, ldch = (t & 3) * 8;
    const int xr = lane & 15, xc = (lane >> 4) * 8;

#pragma unroll
    for (int i = 0; i < 2; ++i)
#pragma unroll
        for (int j = 0; j < 8; ++j)
#pragma unroll
            for (int k = 0; k < 4; ++k) acc[i][j][k] = 0.f;

    auto issue = [&](int k0, int st) {
        __nv_bfloat16* as = As + st * TILE;
        __nv_bfloat16* bs = Bs + st * TILE;
#pragma unroll
        for (int r = 0; r < 2; ++r) {
            int row = ldrow + 64 * r;
            const __nv_bfloat16* ga = A + (size_t)(m0 + row) * K + k0 + ldch;
            asm volatile("cp.async.cg.shared.global [%0], [%1], 16;"
                :: "r"(smem_u32(&as[row * SSTR + ldch])), "l"(ga));
            const __nv_bfloat16* gb = W + (size_t)(n0 + row) * K + k0 + ldch;
            asm volatile("cp.async.cg.shared.global [%0], [%1], 16;"
                :: "r"(smem_u32(&bs[row * SSTR + ldch])), "l"(gb));
        }
        asm volatile("cp.async.commit_group;");
    };

    const int KT = K >> 5;
    issue(0, 0);
    issue(32, 1);
    for (int kt = 0; kt < KT; ++kt) {
        if (kt + 1 < KT) { asm volatile("cp.async.wait_group 1;"); }
        else             { asm volatile("cp.async.wait_group 0;"); }
        __syncthreads();
        if (kt + 2 < KT) issue((kt + 2) << 5, (kt + 2) % 3);

        const __nv_bfloat16* as = As + (kt % 3) * TILE;
        const __nv_bfloat16* bs = Bs + (kt % 3) * TILE;
#pragma unroll
        for (int ks = 0; ks < 32; ks += 16) {
            uint32_t af[2][4];
#pragma unroll
            for (int mt = 0; mt < 2; ++mt) {
                uint32_t ad = smem_u32(&as[(wm + mt * 16 + xr) * SSTR + ks + xc]);
                asm volatile("ldmatrix.sync.aligned.m8n8.x4.shared.b16 {%0,%1,%2,%3},[%4];"
                    : "=r"(af[mt][0]), "=r"(af[mt][1]), "=r"(af[mt][2]), "=r"(af[mt][3])
                    : "r"(ad));
            }
            uint32_t bfr[8][2];
#pragma unroll
            for (int np = 0; np < 4; ++np) {
                uint32_t bd = smem_u32(&bs[(wn + np * 16 + xr) * SSTR + ks + xc]);
                uint32_t r0, r1, r2, r3;
                asm volatile("ldmatrix.sync.aligned.m8n8.x4.shared.b16 {%0,%1,%2,%3},[%4];"
                    : "=r"(r0), "=r"(r1), "=r"(r2), "=r"(r3) : "r"(bd));
                bfr[2 * np][0] = r0; bfr[2 * np + 1][0] = r1;
                bfr[2 * np][1] = r2; bfr[2 * np + 1][1] = r3;
            }
#pragma unroll
            for (int mt = 0; mt < 2; ++mt)
#pragma unroll
                for (int nt = 0; nt < 8; ++nt) {
                    asm volatile(
                        "mma.sync.aligned.m16n8k16.row.col.f32.bf16.bf16.f32 "
                        "{%0,%1,%2,%3},{%4,%5,%6,%7},{%8,%9},{%0,%1,%2,%3};"
                        : "+f"(acc[mt][nt][0]), "+f"(acc[mt][nt][1]),
                          "+f"(acc[mt][nt][2]), "+f"(acc[mt][nt][3])
                        : "r"(af[mt][0]), "r"(af[mt][1]), "r"(af[mt][2]), "r"(af[mt][3]),
                          "r"(bfr[nt][0]), "r"(bfr[nt][1]));
                }
        }
    }
}

// ---------------------------------------------------------------------------
// Plain GEMM: C = A @ W^T + bias, optional ReLU; writes fp32 Cf and/or bf16 Cb
// ---------------------------------------------------------------------------
__global__ __launch_bounds__(256) void gemm_bf16(
    const __nv_bfloat16* __restrict__ A, const __nv_bfloat16* __restrict__ W,
    const float* __restrict__ bias, float* __restrict__ Cf,
    __nv_bfloat16* __restrict__ Cb, int N, int K, int relu)
{
    extern __shared__ __align__(16) char dyn[];
    __nv_bfloat16* As = (__nv_bfloat16*)dyn;
    __nv_bfloat16* Bs = As + 3 * TILE;

    const int m0 = blockIdx.y * 128, n0 = blockIdx.x * 128;
    const int t = threadIdx.x, warp = t >> 5, lane = t & 31;
    const int g = lane >> 2, tig = lane & 3;
    const int wm = (warp >> 1) * 32, wn = (warp & 1) * 64;

    float acc[2][8][4];
    gemm_core(A, W, K, m0, n0, As, Bs, acc);

#pragma unroll
    for (int mt = 0; mt < 2; ++mt) {
#pragma unroll
        for (int nt = 0; nt < 8; ++nt) {
            int col = n0 + wn + nt * 8 + 2 * tig;
            float b0v = bias[col], b1v = bias[col + 1];
            int row = m0 + wm + mt * 16 + g;
            float2 v0 = make_float2(acc[mt][nt][0] + b0v, acc[mt][nt][1] + b1v);
            float2 v1 = make_float2(acc[mt][nt][2] + b0v, acc[mt][nt][3] + b1v);
            if (relu) {
                v0.x = fmaxf(v0.x, 0.f); v0.y = fmaxf(v0.y, 0.f);
                v1.x = fmaxf(v1.x, 0.f); v1.y = fmaxf(v1.y, 0.f);
            }
            if (Cf) {
                *(float2*)(Cf + (size_t)row * N + col)       = v0;
                *(float2*)(Cf + (size_t)(row + 8) * N + col) = v1;
            }
            if (Cb) {
                *(__nv_bfloat162*)(Cb + (size_t)row * N + col) =
                    __floats2bfloat162_rn(v0.x, v0.y);
                *(__nv_bfloat162*)(Cb + (size_t)(row + 8) * N + col) =
                    __floats2bfloat162_rn(v1.x, v1.y);
            }
        }
    }
}

// ---------------------------------------------------------------------------
// GEMM + residual + LayerNorm fused. N == 128 (one block covers the full
// feature dim). Y (fp32) is residual input AND normalized output; Ybf shadow.
//   Y = LN(Y + A@W^T + bias) * lng + lnb
// ---------------------------------------------------------------------------
__global__ __launch_bounds__(256) void gemm_ln(
    const __nv_bfloat16* __restrict__ A, const __nv_bfloat16* __restrict__ W,
    const float* __restrict__ bias, const float* __restrict__ lng,
    const float* __restrict__ lnb, float* __restrict__ Y,
    __nv_bfloat16* __restrict__ Ybf, int K)
{
    extern __shared__ __align__(16) char dyn[];
    __nv_bfloat16* As = (__nv_bfloat16*)dyn;
    __nv_bfloat16* Bs = As + 3 * TILE;
    float* redS = (float*)(dyn + 3 * TILE * 2 * 2);  // [2][128]
    float* redQ = redS + 256;                         // [2][128]

    const int m0 = blockIdx.y * 128;
    const int t = threadIdx.x, warp = t >> 5, lane = t & 31;
    const int g = lane >> 2, tig = lane & 3;
    const int wm = (warp >> 1) * 32, wn = (warp & 1) * 64;
    const int cw = warp & 1;

    float acc[2][8][4];
    gemm_core(A, W, K, m0, 0, As, Bs, acc);

    // v = acc + bias + residual; accumulate row partials
#pragma unroll
    for (int mt = 0; mt < 2; ++mt) {
        int r0 = wm + mt * 16 + g, r1 = r0 + 8;
        float s0 = 0.f, q0 = 0.f, s1 = 0.f, q1 = 0.f;
#pragma unroll
        for (int nt = 0; nt < 8; ++nt) {
            int col = wn + nt * 8 + 2 * tig;
            float2 bv = *(const float2*)(bias + col);
            float2 y0 = *(const float2*)(Y + (size_t)(m0 + r0) * D + col);
            float2 y1 = *(const float2*)(Y + (size_t)(m0 + r1) * D + col);
            float a0 = acc[mt][nt][0] + bv.x + y0.x;
            float a1 = acc[mt][nt][1] + bv.y + y0.y;
            float a2 = acc[mt][nt][2] + bv.x + y1.x;
            float a3 = acc[mt][nt][3] + bv.y + y1.y;
            acc[mt][nt][0] = a0; acc[mt][nt][1] = a1;
            acc[mt][nt][2] = a2; acc[mt][nt][3] = a3;
            s0 += a0 + a1; q0 += a0 * a0 + a1 * a1;
            s1 += a2 + a3; q1 += a2 * a2 + a3 * a3;
        }
#pragma unroll
        for (int o = 1; o <= 2; o <<= 1) {
            s0 += __shfl_xor_sync(0xffffffffu, s0, o);
            q0 += __shfl_xor_sync(0xffffffffu, q0, o);
            s1 += __shfl_xor_sync(0xffffffffu, s1, o);
            q1 += __shfl_xor_sync(0xffffffffu, q1, o);
        }
        if (tig == 0) {
            redS[cw * 128 + r0] = s0; redQ[cw * 128 + r0] = q0;
            redS[cw * 128 + r1] = s1; redQ[cw * 128 + r1] = q1;
        }
    }
    __syncthreads();

#pragma unroll
    for (int mt = 0; mt < 2; ++mt) {
        int r0 = wm + mt * 16 + g, r1 = r0 + 8;
        float S0 = redS[r0] + redS[128 + r0], Q0 = redQ[r0] + redQ[128 + r0];
        float S1 = redS[r1] + redS[128 + r1], Q1 = redQ[r1] + redQ[128 + r1];
        float mu0 = S0 * (1.f / 128.f), mu1 = S1 * (1.f / 128.f);
        float iv0 = rsqrtf(Q0 * (1.f / 128.f) - mu0 * mu0 + 1e-5f);
        float iv1 = rsqrtf(Q1 * (1.f / 128.f) - mu1 * mu1 + 1e-5f);
#pragma unroll
        for (int nt = 0; nt < 8; ++nt) {
            int col = wn + nt * 8 + 2 * tig;
            float2 gv = *(const float2*)(lng + col);
            float2 bv = *(const float2*)(lnb + col);
            float o0 = (acc[mt][nt][0] - mu0) * iv0 * gv.x + bv.x;
            float o1 = (acc[mt][nt][1] - mu0) * iv0 * gv.y + bv.y;
            float o2 = (acc[mt][nt][2] - mu1) * iv1 * gv.x + bv.x;
            float o3 = (acc[mt][nt][3] - mu1) * iv1 * gv.y + bv.y;
            *(float2*)(Y + (size_t)(m0 + r0) * D + col) = make_float2(o0, o1);
            *(float2*)(Y + (size_t)(m0 + r1) * D + col) = make_float2(o2, o3);
            *(__nv_bfloat162*)(Ybf + (size_t)(m0 + r0) * D + col) =
                __floats2bfloat162_rn(o0, o1);
            *(__nv_bfloat162*)(Ybf + (size_t)(m0 + r1) * D + col) =
                __floats2bfloat162_rn(o2, o3);
        }
    }
}

// ---------------------------------------------------------------------------
// One-shot fp32 -> bf16 conversion of x + all weights
// ---------------------------------------------------------------------------
#define CVT_TOTAL 2818048
__global__ void cvt_all(const float* __restrict__ x, const float* __restrict__ wfc,
                        const float* __restrict__ qkvw, const float* __restrict__ outw,
                        const float* __restrict__ ff1w, const float* __restrict__ ff2w)
{
    int i = (blockIdx.x * 256 + threadIdx.x) * 4;
    if (i >= CVT_TOTAL) return;
    const float* s; __nv_bfloat16* d; int off;
    if      (i < 1572864) { s = x;    d = g_xbf;     off = i; }
    else if (i < 1638400) { s = wfc;  d = g_wfc_bf;  off = i - 1572864; }
    else if (i < 1736704) { s = qkvw; d = g_qkvw_bf; off = i - 1638400; }
    else if (i < 1769472) { s = outw; d = g_outw_bf; off = i - 1736704; }
    else if (i < 2293760) { s = ff1w; d = g_ff1w_bf; off = i - 1769472; }
    else                  { s = ff2w; d = g_ff2w_bf; off = i - 2293760; }
    float4 v = *(const float4*)(s + off);
    *(__nv_bfloat162*)(d + off)     = __floats2bfloat162_rn(v.x, v.y);
    *(__nv_bfloat162*)(d + off + 2) = __floats2bfloat162_rn(v.z, v.w);
}

// ---------------------------------------------------------------------------
// Scatter h0 -> packed tokens with fused positional encoding
// ---------------------------------------------------------------------------
__global__ void scatter_kernel()
{
    int n = blockIdx.x;
    int s = 0;
    while (n >= 64 * (s + 1) * (s + 2)) s++;
    int r = n - 64 * s * (s + 1);
    int P = s + 1;
    int b = r / P;
    int t = r - b * P;
    int d = threadIdx.x;
    float freq = expf((float)(d & ~1) * (-9.210340371976184f / 128.f));
    float arg  = (float)t * freq;
    float pe   = (d & 1) ? cosf(arg) : sinf(arg);
    float v = g_h0[(b * SEQT + t) * D + d] + pe;
    g_Y[n * D + d]   = v;
    g_Ybf[n * D + d] = __float2bfloat16(v);
}

// ---------------------------------------------------------------------------
// Attention: one block per (s,b); warp w handles head w. bf16 qkv in,
// fp32 math, bf16 ctx out. Single load phase + one barrier.
// ---------------------------------------------------------------------------
__global__ __launch_bounds__(128) void attn_kernel()
{
    __shared__ float qs[NH][SEQT][DH], ks[NH][SEQT][DH], vs[NH][SEQT][DH];

    int blk = blockIdx.x;
    int s = blk >> 7;
    int b = blk & 127;
    int P = s + 1;
    int base = 64 * s * (s + 1) + b * P;
    int tid  = threadIdx.x;
    int h    = tid >> 5;
    int lane = tid & 31;

    for (int t = 0; t < P; ++t) {
        const __nv_bfloat16* row = g_qkvbf + (size_t)(base + t) * (3 * D);
        int hh = tid >> 5, dd = tid & 31;
        qs[hh][t][dd] = __bfloat162float(row[tid]);
        ks[hh][t][dd] = __bfloat162float(row[tid + D]);
        vs[hh][t][dd] = __bfloat162float(row[tid + 2 * D]);
    }
    __syncthreads();

    for (int t = 0; t < P; ++t) {
        float sc = -1e30f;
        if (lane < P) {
            float a = 0.f;
#pragma unroll
            for (int dd = 0; dd < DH; ++dd) a += qs[h][t][dd] * ks[h][lane][dd];
            sc = a * 0.17677669529663687f;  // 1/sqrt(32)
        }
        float m = sc;
        for (int o = 16; o; o >>= 1) m = fmaxf(m, __shfl_xor_sync(0xffffffffu, m, o));
        float e = (lane < P) ? expf(sc - m) : 0.f;
        float sum = e;
        for (int o = 16; o; o >>= 1) sum += __shfl_xor_sync(0xffffffffu, sum, o);
        float p = e / sum;
        float c = 0.f;
        for (int j = 0; j < P; ++j)
            c += __shfl_sync(0xffffffffu, p, j) * vs[h][j][lane];
        g_ctxbf[(size_t)(base + t) * D + h * DH + lane] = __float2bfloat16(c);
    }
}

// ---------------------------------------------------------------------------
// Classifier + log_softmax, reads last-token rows of Y directly
// ---------------------------------------------------------------------------
__global__ __launch_bounds__(64) void cls_kernel(
    const float* __restrict__ Wc1, const float* __restrict__ bc1,
    const float* __restrict__ Wc2, const float* __restrict__ bc2,
    float* __restrict__ out)
{
    __shared__ float c1[NC];
    __shared__ float lrow[D];
    int n = blockIdx.x;              // b*SEQT + s
    int b = n / SEQT;
    int s = n % SEQT;
    int src = 64 * s * (s + 1) + b * (s + 1) + s;
    int o = threadIdx.x;

    for (int d = o; d < D; d += NC) lrow[d] = g_Y[(size_t)src * D + d];
    __syncthreads();

    float a = bc1[o];
    for (int d = 0; d < D; ++d) a += lrow[d] * Wc1[o * D + d];
    c1[o] = fmaxf(a, 0.f);
    __syncthreads();

    if (o == 0) {
        float l0 = bc2[0], l1 = bc2[1];
        for (int j = 0; j < NC; ++j) {
            l0 += c1[j] * Wc2[j];
            l1 += c1[j] * Wc2[NC + j];
        }
        float m   = fmaxf(l0, l1);
        float lse = m + logf(expf(l0 - m) + expf(l1 - m));
        out[n * 2 + 0] = l0 - lse;
        out[n * 2 + 1] = l1 - lse;
    }
}

// ---------------------------------------------------------------------------
extern "C" void kernel_launch(void* const* d_in, const int* in_sizes, int n_in,
                              void* d_out, int out_size)
{
    const float* x     = (const float*)d_in[0];
    const float* W_fc  = (const float*)d_in[1];
    const float* b_fc  = (const float*)d_in[2];
    const float* qkv_w = (const float*)d_in[3];
    const float* qkv_b = (const float*)d_in[4];
    const float* out_w = (const float*)d_in[5];
    const float* out_b = (const float*)d_in[6];
    const float* ln1_g = (const float*)d_in[7];
    const float* ln1_b = (const float*)d_in[8];
    const float* ln2_g = (const float*)d_in[9];
    const float* ln2_b = (const float*)d_in[10];
    const float* ff1_w = (const float*)d_in[11];
    const float* ff1_b = (const float*)d_in[12];
    const float* ff2_w = (const float*)d_in[13];
    const float* ff2_b = (const float*)d_in[14];
    const float* Wc1   = (const float*)d_in[15];
    const float* bc1   = (const float*)d_in[16];
    const float* Wc2   = (const float*)d_in[17];
    const float* bc2   = (const float*)d_in[18];

    static int inited = 0;
    if (!inited) {
        cudaFuncSetAttribute(gemm_bf16, cudaFuncAttributeMaxDynamicSharedMemorySize,
                             GEMM_SMEM);
        cudaFuncSetAttribute(gemm_ln, cudaFuncAttributeMaxDynamicSharedMemorySize,
                             GEMM_SMEM_LN);
        inited = 1;
    }

    void* p;
    cudaGetSymbolAddress(&p, g_h0);      float* h0  = (float*)p;
    cudaGetSymbolAddress(&p, g_Y);       float* Y   = (float*)p;
    cudaGetSymbolAddress(&p, g_xbf);     __nv_bfloat16* xbf   = (__nv_bfloat16*)p;
    cudaGetSymbolAddress(&p, g_wfc_bf);  __nv_bfloat16* wfcb  = (__nv_bfloat16*)p;
    cudaGetSymbolAddress(&p, g_qkvw_bf); __nv_bfloat16* qkvwb = (__nv_bfloat16*)p;
    cudaGetSymbolAddress(&p, g_outw_bf); __nv_bfloat16* outwb = (__nv_bfloat16*)p;
    cudaGetSymbolAddress(&p, g_ff1w_bf); __nv_bfloat16* ff1wb = (__nv_bfloat16*)p;
    cudaGetSymbolAddress(&p, g_ff2w_bf); __nv_bfloat16* ff2wb = (__nv_bfloat16*)p;
    cudaGetSymbolAddress(&p, g_Ybf);     __nv_bfloat16* ybf   = (__nv_bfloat16*)p;
    cudaGetSymbolAddress(&p, g_qkvbf);   __nv_bfloat16* qkvb  = (__nv_bfloat16*)p;
    cudaGetSymbolAddress(&p, g_ctxbf);   __nv_bfloat16* ctxb  = (__nv_bfloat16*)p;
    cudaGetSymbolAddress(&p, g_Hbf);     __nv_bfloat16* hbf   = (__nv_bfloat16*)p;

    cvt_all<<<(CVT_TOTAL / 4 + 255) / 256, 256>>>(x, W_fc, qkv_w, out_w, ff1_w, ff2_w);

    // fc: h0 = relu(x @ W_fc^T + b_fc); scatter adds PE and packs
    gemm_bf16<<<dim3(1, NBT / 128), 256, GEMM_SMEM>>>(xbf, wfcb, b_fc, h0, nullptr,
                                                      D, DIN, 1);
    scatter_kernel<<<NT, D>>>();

    for (int l = 0; l < 2; ++l) {
        gemm_bf16<<<dim3(3, NT / 128), 256, GEMM_SMEM>>>(
            ybf, qkvwb + (size_t)l * 3 * D * D, qkv_b + l * 3 * D,
            nullptr, qkvb, 3 * D, D, 0);
        attn_kernel<<<S_STEPS * BATCH, 128>>>();
        gemm_ln<<<dim3(1, NT / 128), 256, GEMM_SMEM_LN>>>(
            ctxb, outwb + (size_t)l * D * D, out_b + l * D,
            ln1_g + l * D, ln1_b + l * D, Y, ybf, D);
        gemm_bf16<<<dim3(DFF / 128, NT / 128), 256, GEMM_SMEM>>>(
            ybf, ff1wb + (size_t)l * DFF * D, ff1_b + l * DFF,
            nullptr, hbf, DFF, D, 1);
        gemm_ln<<<dim3(1, NT / 128), 256, GEMM_SMEM_LN>>>(
            hbf, ff2wb + (size_t)l * D * DFF, ff2_b + l * D,
            ln2_g + l * D, ln2_b + l * D, Y, ybf, DFF);
    }

    cls_kernel<<<NBT, NC>>>(Wc1, bc1, Wc2, bc2, (float*)d_out);
}

// round 5
// speedup vs baseline: 1.4772x; 1.4772x over previous
#include <cuda_runtime.h>
#include <cuda_bf16.h>
#include <math.h>
#include <stdint.h>

// Problem constants
#define S_STEPS 24
#define BATCH   128
#define SEQT    24
#define DIN     512
#define D       128
#define DFF     2048
#define NH      4
#define DH      32
#define NC      64
#define NT      38400  // BATCH * S*(S+1)/2
#define NBT     3072   // BATCH*SEQT

// fp32 scratch
__device__ float g_h0[NBT * D];
__device__ float g_Y[NT * D];

// bf16 buffers
__device__ __nv_bfloat16 g_xbf[NBT * DIN];
__device__ __nv_bfloat16 g_wfc_bf[D * DIN];
__device__ __nv_bfloat16 g_qkvw_bf[2 * 3 * D * D];
__device__ __nv_bfloat16 g_outw_bf[2 * D * D];
__device__ __nv_bfloat16 g_ff1w_bf[2 * DFF * D];
__device__ __nv_bfloat16 g_ff2w_bf[2 * D * DFF];
__device__ __nv_bfloat16 g_Ybf[NT * D];
__device__ __nv_bfloat16 g_qkvbf[NT * 3 * D];
__device__ __nv_bfloat16 g_ctxbf[NT * D];
__device__ __nv_bfloat16 g_Hbf[(size_t)NT * DFF];

__device__ __forceinline__ uint32_t smem_u32(const void* p) {
    return (uint32_t)__cvta_generic_to_shared(p);
}

// ---------------------------------------------------------------------------
// bf16 GEMM core: 128x128 block tile, BK=32, 256 threads (8 warps 4x2),
// 3-stage cp.async pipeline, ldmatrix fragments, m16n8k16 bf16 mma.
// A[M,K] row-major, W[N,K] row-major (C = A @ W^T). K % 32 == 0, K >= 64.
// ---------------------------------------------------------------------------
#define SSTR 40                 // smem row stride in bf16 (32 + 8 pad)
#define TILE (128 * SSTR)       // elems per stage per operand
#define GEMM_SMEM  (3 * TILE * 2 * 2)            // 61440 B
#define GEMM_SMEM_LN (GEMM_SMEM + 512 * 4)       // + reduction arrays

__device__ __forceinline__ void gemm_core(
    const __nv_bfloat16* __restrict__ A, const __nv_bfloat16* __restrict__ W,
    int K, int m0, int n0, __nv_bfloat16* As, __nv_bfloat16* Bs,
    float (&acc)[2][8][4])
{
    const int t = threadIdx.x, warp = t >> 5, lane = t & 31;
    const int wm = (warp >> 1) * 32, wn = (warp & 1) * 64;
    const int ldrow = t >> 2, ldch = (t & 3) * 8;
    const int xr = lane & 15, xc = (lane >> 4) * 8;

#pragma unroll
    for (int i = 0; i < 2; ++i)
#pragma unroll
        for (int j = 0; j < 8; ++j)
#pragma unroll
            for (int k = 0; k < 4; ++k) acc[i][j][k] = 0.f;

    auto issue = [&](int k0, int st) {
        __nv_bfloat16* as = As + st * TILE;
        __nv_bfloat16* bs = Bs + st * TILE;
#pragma unroll
        for (int r = 0; r < 2; ++r) {
            int row = ldrow + 64 * r;
            const __nv_bfloat16* ga = A + (size_t)(m0 + row) * K + k0 + ldch;
            asm volatile("cp.async.cg.shared.global [%0], [%1], 16;"
                :: "r"(smem_u32(&as[row * SSTR + ldch])), "l"(ga));
            const __nv_bfloat16* gb = W + (size_t)(n0 + row) * K + k0 + ldch;
            asm volatile("cp.async.cg.shared.global [%0], [%1], 16;"
                :: "r"(smem_u32(&bs[row * SSTR + ldch])), "l"(gb));
        }
        asm volatile("cp.async.commit_group;");
    };

    const int KT = K >> 5;
    issue(0, 0);
    issue(32, 1);
    for (int kt = 0; kt < KT; ++kt) {
        if (kt + 1 < KT) { asm volatile("cp.async.wait_group 1;"); }
        else             { asm volatile("cp.async.wait_group 0;"); }
        __syncthreads();
        if (kt + 2 < KT) issue((kt + 2) << 5, (kt + 2) % 3);

        const __nv_bfloat16* as = As + (kt % 3) * TILE;
        const __nv_bfloat16* bs = Bs + (kt % 3) * TILE;
#pragma unroll
        for (int ks = 0; ks < 32; ks += 16) {
            uint32_t af[2][4];
#pragma unroll
            for (int mt = 0; mt < 2; ++mt) {
                uint32_t ad = smem_u32(&as[(wm + mt * 16 + xr) * SSTR + ks + xc]);
                asm volatile("ldmatrix.sync.aligned.m8n8.x4.shared.b16 {%0,%1,%2,%3},[%4];"
                    : "=r"(af[mt][0]), "=r"(af[mt][1]), "=r"(af[mt][2]), "=r"(af[mt][3])
                    : "r"(ad));
            }
            uint32_t bfr[8][2];
#pragma unroll
            for (int np = 0; np < 4; ++np) {
                uint32_t bd = smem_u32(&bs[(wn + np * 16 + xr) * SSTR + ks + xc]);
                uint32_t r0, r1, r2, r3;
                asm volatile("ldmatrix.sync.aligned.m8n8.x4.shared.b16 {%0,%1,%2,%3},[%4];"
                    : "=r"(r0), "=r"(r1), "=r"(r2), "=r"(r3) : "r"(bd));
                bfr[2 * np][0] = r0; bfr[2 * np + 1][0] = r1;
                bfr[2 * np][1] = r2; bfr[2 * np + 1][1] = r3;
            }
#pragma unroll
            for (int mt = 0; mt < 2; ++mt)
#pragma unroll
                for (int nt = 0; nt < 8; ++nt) {
                    asm volatile(
                        "mma.sync.aligned.m16n8k16.row.col.f32.bf16.bf16.f32 "
                        "{%0,%1,%2,%3},{%4,%5,%6,%7},{%8,%9},{%0,%1,%2,%3};"
                        : "+f"(acc[mt][nt][0]), "+f"(acc[mt][nt][1]),
                          "+f"(acc[mt][nt][2]), "+f"(acc[mt][nt][3])
                        : "r"(af[mt][0]), "r"(af[mt][1]), "r"(af[mt][2]), "r"(af[mt][3]),
                          "r"(bfr[nt][0]), "r"(bfr[nt][1]));
                }
        }
    }
}

// ---------------------------------------------------------------------------
// Plain GEMM: C = A @ W^T + bias, optional ReLU; writes fp32 Cf and/or bf16 Cb
// ---------------------------------------------------------------------------
__global__ __launch_bounds__(256) void gemm_bf16(
    const __nv_bfloat16* __restrict__ A, const __nv_bfloat16* __restrict__ W,
    const float* __restrict__ bias, float* __restrict__ Cf,
    __nv_bfloat16* __restrict__ Cb, int N, int K, int relu)
{
    extern __shared__ __align__(16) char dyn[];
    __nv_bfloat16* As = (__nv_bfloat16*)dyn;
    __nv_bfloat16* Bs = As + 3 * TILE;

    const int m0 = blockIdx.y * 128, n0 = blockIdx.x * 128;
    const int t = threadIdx.x, warp = t >> 5, lane = t & 31;
    const int g = lane >> 2, tig = lane & 3;
    const int wm = (warp >> 1) * 32, wn = (warp & 1) * 64;

    float acc[2][8][4];
    gemm_core(A, W, K, m0, n0, As, Bs, acc);

#pragma unroll
    for (int mt = 0; mt < 2; ++mt) {
#pragma unroll
        for (int nt = 0; nt < 8; ++nt) {
            int col = n0 + wn + nt * 8 + 2 * tig;
            float b0v = bias[col], b1v = bias[col + 1];
            int row = m0 + wm + mt * 16 + g;
            float2 v0 = make_float2(acc[mt][nt][0] + b0v, acc[mt][nt][1] + b1v);
            float2 v1 = make_float2(acc[mt][nt][2] + b0v, acc[mt][nt][3] + b1v);
            if (relu) {
                v0.x = fmaxf(v0.x, 0.f); v0.y = fmaxf(v0.y, 0.f);
                v1.x = fmaxf(v1.x, 0.f); v1.y = fmaxf(v1.y, 0.f);
            }
            if (Cf) {
                *(float2*)(Cf + (size_t)row * N + col)       = v0;
                *(float2*)(Cf + (size_t)(row + 8) * N + col) = v1;
            }
            if (Cb) {
                *(__nv_bfloat162*)(Cb + (size_t)row * N + col) =
                    __floats2bfloat162_rn(v0.x, v0.y);
                *(__nv_bfloat162*)(Cb + (size_t)(row + 8) * N + col) =
                    __floats2bfloat162_rn(v1.x, v1.y);
            }
        }
    }
}

// ---------------------------------------------------------------------------
// GEMM + residual + LayerNorm fused. N == 128 (one block covers the full
// feature dim). Y (fp32) is residual input AND normalized output; Ybf shadow.
//   Y = LN(Y + A@W^T + bias) * lng + lnb
// ---------------------------------------------------------------------------
__global__ __launch_bounds__(256) void gemm_ln(
    const __nv_bfloat16* __restrict__ A, const __nv_bfloat16* __restrict__ W,
    const float* __restrict__ bias, const float* __restrict__ lng,
    const float* __restrict__ lnb, float* __restrict__ Y,
    __nv_bfloat16* __restrict__ Ybf, int K)
{
    extern __shared__ __align__(16) char dyn[];
    __nv_bfloat16* As = (__nv_bfloat16*)dyn;
    __nv_bfloat16* Bs = As + 3 * TILE;
    float* redS = (float*)(dyn + 3 * TILE * 2 * 2);  // [2][128]
    float* redQ = redS + 256;                         // [2][128]

    const int m0 = blockIdx.y * 128;
    const int t = threadIdx.x, warp = t >> 5, lane = t & 31;
    const int g = lane >> 2, tig = lane & 3;
    const int wm = (warp >> 1) * 32, wn = (warp & 1) * 64;
    const int cw = warp & 1;

    float acc[2][8][4];
    gemm_core(A, W, K, m0, 0, As, Bs, acc);

#pragma unroll
    for (int mt = 0; mt < 2; ++mt) {
        int r0 = wm + mt * 16 + g, r1 = r0 + 8;
        float s0 = 0.f, q0 = 0.f, s1 = 0.f, q1 = 0.f;
#pragma unroll
        for (int nt = 0; nt < 8; ++nt) {
            int col = wn + nt * 8 + 2 * tig;
            float2 bv = *(const float2*)(bias + col);
            float2 y0 = *(const float2*)(Y + (size_t)(m0 + r0) * D + col);
            float2 y1 = *(const float2*)(Y + (size_t)(m0 + r1) * D + col);
            float a0 = acc[mt][nt][0] + bv.x + y0.x;
            float a1 = acc[mt][nt][1] + bv.y + y0.y;
            float a2 = acc[mt][nt][2] + bv.x + y1.x;
            float a3 = acc[mt][nt][3] + bv.y + y1.y;
            acc[mt][nt][0] = a0; acc[mt][nt][1] = a1;
            acc[mt][nt][2] = a2; acc[mt][nt][3] = a3;
            s0 += a0 + a1; q0 += a0 * a0 + a1 * a1;
            s1 += a2 + a3; q1 += a2 * a2 + a3 * a3;
        }
#pragma unroll
        for (int o = 1; o <= 2; o <<= 1) {
            s0 += __shfl_xor_sync(0xffffffffu, s0, o);
            q0 += __shfl_xor_sync(0xffffffffu, q0, o);
            s1 += __shfl_xor_sync(0xffffffffu, s1, o);
            q1 += __shfl_xor_sync(0xffffffffu, q1, o);
        }
        if (tig == 0) {
            redS[cw * 128 + r0] = s0; redQ[cw * 128 + r0] = q0;
            redS[cw * 128 + r1] = s1; redQ[cw * 128 + r1] = q1;
        }
    }
    __syncthreads();

#pragma unroll
    for (int mt = 0; mt < 2; ++mt) {
        int r0 = wm + mt * 16 + g, r1 = r0 + 8;
        float S0 = redS[r0] + redS[128 + r0], Q0 = redQ[r0] + redQ[128 + r0];
        float S1 = redS[r1] + redS[128 + r1], Q1 = redQ[r1] + redQ[128 + r1];
        float mu0 = S0 * (1.f / 128.f), mu1 = S1 * (1.f / 128.f);
        float iv0 = rsqrtf(Q0 * (1.f / 128.f) - mu0 * mu0 + 1e-5f);
        float iv1 = rsqrtf(Q1 * (1.f / 128.f) - mu1 * mu1 + 1e-5f);
#pragma unroll
        for (int nt = 0; nt < 8; ++nt) {
            int col = wn + nt * 8 + 2 * tig;
            float2 gv = *(const float2*)(lng + col);
            float2 bv = *(const float2*)(lnb + col);
            float o0 = (acc[mt][nt][0] - mu0) * iv0 * gv.x + bv.x;
            float o1 = (acc[mt][nt][1] - mu0) * iv0 * gv.y + bv.y;
            float o2 = (acc[mt][nt][2] - mu1) * iv1 * gv.x + bv.x;
            float o3 = (acc[mt][nt][3] - mu1) * iv1 * gv.y + bv.y;
            *(float2*)(Y + (size_t)(m0 + r0) * D + col) = make_float2(o0, o1);
            *(float2*)(Y + (size_t)(m0 + r1) * D + col) = make_float2(o2, o3);
            *(__nv_bfloat162*)(Ybf + (size_t)(m0 + r0) * D + col) =
                __floats2bfloat162_rn(o0, o1);
            *(__nv_bfloat162*)(Ybf + (size_t)(m0 + r1) * D + col) =
                __floats2bfloat162_rn(o2, o3);
        }
    }
}

// ---------------------------------------------------------------------------
// One-shot fp32 -> bf16 conversion of x + all weights
// ---------------------------------------------------------------------------
#define CVT_TOTAL 2818048
__global__ void cvt_all(const float* __restrict__ x, const float* __restrict__ wfc,
                        const float* __restrict__ qkvw, const float* __restrict__ outw,
                        const float* __restrict__ ff1w, const float* __restrict__ ff2w)
{
    int i = (blockIdx.x * 256 + threadIdx.x) * 4;
    if (i >= CVT_TOTAL) return;
    const float* s; __nv_bfloat16* d; int off;
    if      (i < 1572864) { s = x;    d = g_xbf;     off = i; }
    else if (i < 1638400) { s = wfc;  d = g_wfc_bf;  off = i - 1572864; }
    else if (i < 1736704) { s = qkvw; d = g_qkvw_bf; off = i - 1638400; }
    else if (i < 1769472) { s = outw; d = g_outw_bf; off = i - 1736704; }
    else if (i < 2293760) { s = ff1w; d = g_ff1w_bf; off = i - 1769472; }
    else                  { s = ff2w; d = g_ff2w_bf; off = i - 2293760; }
    float4 v = *(const float4*)(s + off);
    *(__nv_bfloat162*)(d + off)     = __floats2bfloat162_rn(v.x, v.y);
    *(__nv_bfloat162*)(d + off + 2) = __floats2bfloat162_rn(v.z, v.w);
}

// ---------------------------------------------------------------------------
// Scatter h0 -> packed tokens with fused positional encoding
// ---------------------------------------------------------------------------
__global__ void scatter_kernel()
{
    int n = blockIdx.x;
    int s = 0;
    while (n >= 64 * (s + 1) * (s + 2)) s++;
    int r = n - 64 * s * (s + 1);
    int P = s + 1;
    int b = r / P;
    int t = r - b * P;
    int d = threadIdx.x;
    float freq = expf((float)(d & ~1) * (-9.210340371976184f / 128.f));
    float arg  = (float)t * freq;
    float pe   = (d & 1) ? cosf(arg) : sinf(arg);
    float v = g_h0[(b * SEQT + t) * D + d] + pe;
    g_Y[n * D + d]   = v;
    g_Ybf[n * D + d] = __float2bfloat16(v);
}

// ---------------------------------------------------------------------------
// Attention (round-3 shape: small smem, 4 warps share rows, per-head loop).
// bf16 qkv in, fp32 math, bf16 ctx out.
// ---------------------------------------------------------------------------
__global__ __launch_bounds__(128) void attn_kernel()
{
    __shared__ float qs[SEQT][DH], ks[SEQT][DH], vs[SEQT][DH];
    __shared__ float ps[4][32];

    int q = blockIdx.x;
    int s = q >> 7;
    int b = q & 127;
    int P = s + 1;
    int base = 64 * s * (s + 1) + b * P;
    int tid  = threadIdx.x;
    int w    = tid >> 5;
    int lane = tid & 31;

    for (int h = 0; h < NH; ++h) {
        for (int i = tid; i < P * DH; i += 128) {
            int t = i >> 5, dd = i & 31;
            const __nv_bfloat16* row =
                g_qkvbf + (size_t)(base + t) * (3 * D) + h * DH + dd;
            qs[t][dd] = __bfloat162float(row[0]);
            ks[t][dd] = __bfloat162float(row[D]);
            vs[t][dd] = __bfloat162float(row[2 * D]);
        }
        __syncthreads();

        for (int t = w; t < P; t += 4) {
            float sc = -1e30f;
            if (lane < P) {
                float a = 0.f;
#pragma unroll
                for (int dd = 0; dd < DH; ++dd) a += qs[t][dd] * ks[lane][dd];
                sc = a * 0.17677669529663687f;  // 1/sqrt(32)
            }
            float m = sc;
            for (int o = 16; o; o >>= 1) m = fmaxf(m, __shfl_xor_sync(0xffffffffu, m, o));
            float e = (lane < P) ? expf(sc - m) : 0.f;
            float sum = e;
            for (int o = 16; o; o >>= 1) sum += __shfl_xor_sync(0xffffffffu, sum, o);
            ps[w][lane] = e / sum;
            __syncwarp();
            float c = 0.f;
            for (int j = 0; j < P; ++j) c += ps[w][j] * vs[j][lane];
            g_ctxbf[(size_t)(base + t) * D + h * DH + lane] = __float2bfloat16(c);
            __syncwarp();
        }
        __syncthreads();
    }
}

// ---------------------------------------------------------------------------
// Classifier + log_softmax, reads last-token rows of Y directly
// ---------------------------------------------------------------------------
__global__ __launch_bounds__(64) void cls_kernel(
    const float* __restrict__ Wc1, const float* __restrict__ bc1,
    const float* __restrict__ Wc2, const float* __restrict__ bc2,
    float* __restrict__ out)
{
    __shared__ float c1[NC];
    __shared__ float lrow[D];
    int n = blockIdx.x;              // b*SEQT + s
    int b = n / SEQT;
    int s = n % SEQT;
    int src = 64 * s * (s + 1) + b * (s + 1) + s;
    int o = threadIdx.x;

    for (int d = o; d < D; d += NC) lrow[d] = g_Y[(size_t)src * D + d];
    __syncthreads();

    float a = bc1[o];
    for (int d = 0; d < D; ++d) a += lrow[d] * Wc1[o * D + d];
    c1[o] = fmaxf(a, 0.f);
    __syncthreads();

    if (o == 0) {
        float l0 = bc2[0], l1 = bc2[1];
        for (int j = 0; j < NC; ++j) {
            l0 += c1[j] * Wc2[j];
            l1 += c1[j] * Wc2[NC + j];
        }
        float m   = fmaxf(l0, l1);
        float lse = m + logf(expf(l0 - m) + expf(l1 - m));
        out[n * 2 + 0] = l0 - lse;
        out[n * 2 + 1] = l1 - lse;
    }
}

// ---------------------------------------------------------------------------
extern "C" void kernel_launch(void* const* d_in, const int* in_sizes, int n_in,
                              void* d_out, int out_size)
{
    const float* x     = (const float*)d_in[0];
    const float* W_fc  = (const float*)d_in[1];
    const float* b_fc  = (const float*)d_in[2];
    const float* qkv_w = (const float*)d_in[3];
    const float* qkv_b = (const float*)d_in[4];
    const float* out_w = (const float*)d_in[5];
    const float* out_b = (const float*)d_in[6];
    const float* ln1_g = (const float*)d_in[7];
    const float* ln1_b = (const float*)d_in[8];
    const float* ln2_g = (const float*)d_in[9];
    const float* ln2_b = (const float*)d_in[10];
    const float* ff1_w = (const float*)d_in[11];
    const float* ff1_b = (const float*)d_in[12];
    const float* ff2_w = (const float*)d_in[13];
    const float* ff2_b = (const float*)d_in[14];
    const float* Wc1   = (const float*)d_in[15];
    const float* bc1   = (const float*)d_in[16];
    const float* Wc2   = (const float*)d_in[17];
    const float* bc2   = (const float*)d_in[18];

    cudaFuncSetAttribute(gemm_bf16, cudaFuncAttributeMaxDynamicSharedMemorySize,
                         GEMM_SMEM);
    cudaFuncSetAttribute(gemm_ln, cudaFuncAttributeMaxDynamicSharedMemorySize,
                         GEMM_SMEM_LN);

    void* p;
    cudaGetSymbolAddress(&p, g_h0);      float* h0  = (float*)p;
    cudaGetSymbolAddress(&p, g_Y);       float* Y   = (float*)p;
    cudaGetSymbolAddress(&p, g_xbf);     __nv_bfloat16* xbf   = (__nv_bfloat16*)p;
    cudaGetSymbolAddress(&p, g_wfc_bf);  __nv_bfloat16* wfcb  = (__nv_bfloat16*)p;
    cudaGetSymbolAddress(&p, g_qkvw_bf); __nv_bfloat16* qkvwb = (__nv_bfloat16*)p;
    cudaGetSymbolAddress(&p, g_outw_bf); __nv_bfloat16* outwb = (__nv_bfloat16*)p;
    cudaGetSymbolAddress(&p, g_ff1w_bf); __nv_bfloat16* ff1wb = (__nv_bfloat16*)p;
    cudaGetSymbolAddress(&p, g_ff2w_bf); __nv_bfloat16* ff2wb = (__nv_bfloat16*)p;
    cudaGetSymbolAddress(&p, g_Ybf);     __nv_bfloat16* ybf   = (__nv_bfloat16*)p;
    cudaGetSymbolAddress(&p, g_qkvbf);   __nv_bfloat16* qkvb  = (__nv_bfloat16*)p;
    cudaGetSymbolAddress(&p, g_ctxbf);   __nv_bfloat16* ctxb  = (__nv_bfloat16*)p;
    cudaGetSymbolAddress(&p, g_Hbf);     __nv_bfloat16* hbf   = (__nv_bfloat16*)p;

    cvt_all<<<(CVT_TOTAL / 4 + 255) / 256, 256>>>(x, W_fc, qkv_w, out_w, ff1_w, ff2_w);

    // fc: h0 = relu(x @ W_fc^T + b_fc); scatter adds PE and packs
    gemm_bf16<<<dim3(1, NBT / 128), 256, GEMM_SMEM>>>(xbf, wfcb, b_fc, h0, nullptr,
                                                      D, DIN, 1);
    scatter_kernel<<<NT, D>>>();

    for (int l = 0; l < 2; ++l) {
        gemm_bf16<<<dim3(3, NT / 128), 256, GEMM_SMEM>>>(
            ybf, qkvwb + (size_t)l * 3 * D * D, qkv_b + l * 3 * D,
            nullptr, qkvb, 3 * D, D, 0);
        attn_kernel<<<S_STEPS * BATCH, 128>>>();
        gemm_ln<<<dim3(1, NT / 128), 256, GEMM_SMEM_LN>>>(
            ctxb, outwb + (size_t)l * D * D, out_b + l * D,
            ln1_g + l * D, ln1_b + l * D, Y, ybf, D);
        gemm_bf16<<<dim3(DFF / 128, NT / 128), 256, GEMM_SMEM>>>(
            ybf, ff1wb + (size_t)l * DFF * D, ff1_b + l * DFF,
            nullptr, hbf, DFF, D, 1);
        gemm_ln<<<dim3(1, NT / 128), 256, GEMM_SMEM_LN>>>(
            hbf, ff2wb + (size_t)l * D * DFF, ff2_b + l * D,
            ln2_g + l * D, ln2_b + l * D, Y, ybf, DFF);
    }

    cls_kernel<<<NBT, NC>>>(Wc1, bc1, Wc2, bc2, (float*)d_out);
}

// round 6
// speedup vs baseline: 1.4772x; 1.0001x over previous
#include <cuda_runtime.h>
#include <cuda_bf16.h>
#include <math.h>
#include <stdint.h>

// Problem constants
#define S_STEPS 24
#define BATCH   128
#define SEQT    24
#define DIN     512
#define D       128
#define DFF     2048
#define NH      4
#define DH      32
#define NC      64
#define NT      38400  // BATCH * S*(S+1)/2
#define NBT     3072   // BATCH*SEQT

// fp32 scratch
__device__ float g_h0[NBT * D];
__device__ float g_Y[NT * D];

// bf16 buffers
__device__ __nv_bfloat16 g_xbf[NBT * DIN];
__device__ __nv_bfloat16 g_wfc_bf[D * DIN];
__device__ __nv_bfloat16 g_qkvw_bf[2 * 3 * D * D];
__device__ __nv_bfloat16 g_outw_bf[2 * D * D];
__device__ __nv_bfloat16 g_ff1w_bf[2 * DFF * D];
__device__ __nv_bfloat16 g_ff2w_bf[2 * D * DFF];
__device__ __nv_bfloat16 g_Ybf[NT * D];
__device__ __nv_bfloat16 g_qkvbf[NT * 3 * D];
__device__ __nv_bfloat16 g_ctxbf[NT * D];
__device__ __nv_bfloat16 g_Hbf[(size_t)NT * DFF];

__device__ __forceinline__ uint32_t smem_u32(const void* p) {
    return (uint32_t)__cvta_generic_to_shared(p);
}

// ---------------------------------------------------------------------------
// bf16 GEMM core: 128x128 block tile, BK=32, 512 threads (16 warps, 4x4 grid,
// warp tile 32x32), 3-stage cp.async pipeline, ldmatrix, m16n8k16 bf16 mma.
// A[M,K] row-major, W[N,K] row-major (C = A @ W^T). K % 32 == 0, K >= 64.
// ---------------------------------------------------------------------------
#define SSTR 40                 // smem row stride in bf16 (32 + 8 pad)
#define TILE (128 * SSTR)       // elems per stage per operand
#define GEMM_SMEM  (3 * TILE * 2 * 2)            // 61440 B
#define GEMM_SMEM_LN (GEMM_SMEM + 1024 * 4)      // + [4][128] x2 fp32 reductions

__device__ __forceinline__ void gemm_core(
    const __nv_bfloat16* __restrict__ A, const __nv_bfloat16* __restrict__ W,
    int K, int m0, int n0, __nv_bfloat16* As, __nv_bfloat16* Bs,
    float (&acc)[2][4][4])
{
    const int t = threadIdx.x, warp = t >> 5, lane = t & 31;
    const int wm = (warp >> 2) * 32, wn = (warp & 3) * 32;
    const int ldrow = t >> 2, ldch = (t & 3) * 8;
    const int xr = lane & 15, xc = (lane >> 4) * 8;

#pragma unroll
    for (int i = 0; i < 2; ++i)
#pragma unroll
        for (int j = 0; j < 4; ++j)
#pragma unroll
            for (int k = 0; k < 4; ++k) acc[i][j][k] = 0.f;

    auto issue = [&](int k0, int st) {
        __nv_bfloat16* as = As + st * TILE;
        __nv_bfloat16* bs = Bs + st * TILE;
        const __nv_bfloat16* ga = A + (size_t)(m0 + ldrow) * K + k0 + ldch;
        asm volatile("cp.async.cg.shared.global [%0], [%1], 16;"
            :: "r"(smem_u32(&as[ldrow * SSTR + ldch])), "l"(ga));
        const __nv_bfloat16* gb = W + (size_t)(n0 + ldrow) * K + k0 + ldch;
        asm volatile("cp.async.cg.shared.global [%0], [%1], 16;"
            :: "r"(smem_u32(&bs[ldrow * SSTR + ldch])), "l"(gb));
        asm volatile("cp.async.commit_group;");
    };

    const int KT = K >> 5;
    issue(0, 0);
    issue(32, 1);
    for (int kt = 0; kt < KT; ++kt) {
        if (kt + 1 < KT) { asm volatile("cp.async.wait_group 1;"); }
        else             { asm volatile("cp.async.wait_group 0;"); }
        __syncthreads();
        if (kt + 2 < KT) issue((kt + 2) << 5, (kt + 2) % 3);

        const __nv_bfloat16* as = As + (kt % 3) * TILE;
        const __nv_bfloat16* bs = Bs + (kt % 3) * TILE;
#pragma unroll
        for (int ks = 0; ks < 32; ks += 16) {
            uint32_t af[2][4];
#pragma unroll
            for (int mt = 0; mt < 2; ++mt) {
                uint32_t ad = smem_u32(&as[(wm + mt * 16 + xr) * SSTR + ks + xc]);
                asm volatile("ldmatrix.sync.aligned.m8n8.x4.shared.b16 {%0,%1,%2,%3},[%4];"
                    : "=r"(af[mt][0]), "=r"(af[mt][1]), "=r"(af[mt][2]), "=r"(af[mt][3])
                    : "r"(ad));
            }
            uint32_t bfr[4][2];
#pragma unroll
            for (int np = 0; np < 2; ++np) {
                uint32_t bd = smem_u32(&bs[(wn + np * 16 + xr) * SSTR + ks + xc]);
                uint32_t r0, r1, r2, r3;
                asm volatile("ldmatrix.sync.aligned.m8n8.x4.shared.b16 {%0,%1,%2,%3},[%4];"
                    : "=r"(r0), "=r"(r1), "=r"(r2), "=r"(r3) : "r"(bd));
                bfr[2 * np][0] = r0; bfr[2 * np + 1][0] = r1;
                bfr[2 * np][1] = r2; bfr[2 * np + 1][1] = r3;
            }
#pragma unroll
            for (int mt = 0; mt < 2; ++mt)
#pragma unroll
                for (int nt = 0; nt < 4; ++nt) {
                    asm volatile(
                        "mma.sync.aligned.m16n8k16.row.col.f32.bf16.bf16.f32 "
                        "{%0,%1,%2,%3},{%4,%5,%6,%7},{%8,%9},{%0,%1,%2,%3};"
                        : "+f"(acc[mt][nt][0]), "+f"(acc[mt][nt][1]),
                          "+f"(acc[mt][nt][2]), "+f"(acc[mt][nt][3])
                        : "r"(af[mt][0]), "r"(af[mt][1]), "r"(af[mt][2]), "r"(af[mt][3]),
                          "r"(bfr[nt][0]), "r"(bfr[nt][1]));
                }
        }
    }
}

// ---------------------------------------------------------------------------
// Plain GEMM: C = A @ W^T + bias, optional ReLU; writes fp32 Cf and/or bf16 Cb
// ---------------------------------------------------------------------------
__global__ __launch_bounds__(512, 2) void gemm_bf16(
    const __nv_bfloat16* __restrict__ A, const __nv_bfloat16* __restrict__ W,
    const float* __restrict__ bias, float* __restrict__ Cf,
    __nv_bfloat16* __restrict__ Cb, int N, int K, int relu)
{
    extern __shared__ __align__(16) char dyn[];
    __nv_bfloat16* As = (__nv_bfloat16*)dyn;
    __nv_bfloat16* Bs = As + 3 * TILE;

    const int m0 = blockIdx.y * 128, n0 = blockIdx.x * 128;
    const int t = threadIdx.x, warp = t >> 5, lane = t & 31;
    const int g = lane >> 2, tig = lane & 3;
    const int wm = (warp >> 2) * 32, wn = (warp & 3) * 32;

    float acc[2][4][4];
    gemm_core(A, W, K, m0, n0, As, Bs, acc);

#pragma unroll
    for (int mt = 0; mt < 2; ++mt) {
#pragma unroll
        for (int nt = 0; nt < 4; ++nt) {
            int col = n0 + wn + nt * 8 + 2 * tig;
            float b0v = bias[col], b1v = bias[col + 1];
            int row = m0 + wm + mt * 16 + g;
            float2 v0 = make_float2(acc[mt][nt][0] + b0v, acc[mt][nt][1] + b1v);
            float2 v1 = make_float2(acc[mt][nt][2] + b0v, acc[mt][nt][3] + b1v);
            if (relu) {
                v0.x = fmaxf(v0.x, 0.f); v0.y = fmaxf(v0.y, 0.f);
                v1.x = fmaxf(v1.x, 0.f); v1.y = fmaxf(v1.y, 0.f);
            }
            if (Cf) {
                *(float2*)(Cf + (size_t)row * N + col)       = v0;
                *(float2*)(Cf + (size_t)(row + 8) * N + col) = v1;
            }
            if (Cb) {
                *(__nv_bfloat162*)(Cb + (size_t)row * N + col) =
                    __floats2bfloat162_rn(v0.x, v0.y);
                *(__nv_bfloat162*)(Cb + (size_t)(row + 8) * N + col) =
                    __floats2bfloat162_rn(v1.x, v1.y);
            }
        }
    }
}

// ---------------------------------------------------------------------------
// GEMM + residual + LayerNorm fused. N == 128 (block covers full feature dim).
//   Y = LN(Y + A@W^T + bias) * lng + lnb     (Y fp32 in/out, Ybf shadow)
// ---------------------------------------------------------------------------
__global__ __launch_bounds__(512, 2) void gemm_ln(
    const __nv_bfloat16* __restrict__ A, const __nv_bfloat16* __restrict__ W,
    const float* __restrict__ bias, const float* __restrict__ lng,
    const float* __restrict__ lnb, float* __restrict__ Y,
    __nv_bfloat16* __restrict__ Ybf, int K)
{
    extern __shared__ __align__(16) char dyn[];
    __nv_bfloat16* As = (__nv_bfloat16*)dyn;
    __nv_bfloat16* Bs = As + 3 * TILE;
    float* redS = (float*)(dyn + 3 * TILE * 2 * 2);  // [4][128]
    float* redQ = redS + 512;                         // [4][128]

    const int m0 = blockIdx.y * 128;
    const int t = threadIdx.x, warp = t >> 5, lane = t & 31;
    const int g = lane >> 2, tig = lane & 3;
    const int wm = (warp >> 2) * 32, wn = (warp & 3) * 32;
    const int cw = warp & 3;

    float acc[2][4][4];
    gemm_core(A, W, K, m0, 0, As, Bs, acc);

#pragma unroll
    for (int mt = 0; mt < 2; ++mt) {
        int r0 = wm + mt * 16 + g, r1 = r0 + 8;
        float s0 = 0.f, q0 = 0.f, s1 = 0.f, q1 = 0.f;
#pragma unroll
        for (int nt = 0; nt < 4; ++nt) {
            int col = wn + nt * 8 + 2 * tig;
            float2 bv = *(const float2*)(bias + col);
            float2 y0 = *(const float2*)(Y + (size_t)(m0 + r0) * D + col);
            float2 y1 = *(const float2*)(Y + (size_t)(m0 + r1) * D + col);
            float a0 = acc[mt][nt][0] + bv.x + y0.x;
            float a1 = acc[mt][nt][1] + bv.y + y0.y;
            float a2 = acc[mt][nt][2] + bv.x + y1.x;
            float a3 = acc[mt][nt][3] + bv.y + y1.y;
            acc[mt][nt][0] = a0; acc[mt][nt][1] = a1;
            acc[mt][nt][2] = a2; acc[mt][nt][3] = a3;
            s0 += a0 + a1; q0 += a0 * a0 + a1 * a1;
            s1 += a2 + a3; q1 += a2 * a2 + a3 * a3;
        }
#pragma unroll
        for (int o = 1; o <= 2; o <<= 1) {
            s0 += __shfl_xor_sync(0xffffffffu, s0, o);
            q0 += __shfl_xor_sync(0xffffffffu, q0, o);
            s1 += __shfl_xor_sync(0xffffffffu, s1, o);
            q1 += __shfl_xor_sync(0xffffffffu, q1, o);
        }
        if (tig == 0) {
            redS[cw * 128 + r0] = s0; redQ[cw * 128 + r0] = q0;
            redS[cw * 128 + r1] = s1; redQ[cw * 128 + r1] = q1;
        }
    }
    __syncthreads();

#pragma unroll
    for (int mt = 0; mt < 2; ++mt) {
        int r0 = wm + mt * 16 + g, r1 = r0 + 8;
        float S0 = redS[r0] + redS[128 + r0] + redS[256 + r0] + redS[384 + r0];
        float Q0 = redQ[r0] + redQ[128 + r0] + redQ[256 + r0] + redQ[384 + r0];
        float S1 = redS[r1] + redS[128 + r1] + redS[256 + r1] + redS[384 + r1];
        float Q1 = redQ[r1] + redQ[128 + r1] + redQ[256 + r1] + redQ[384 + r1];
        float mu0 = S0 * (1.f / 128.f), mu1 = S1 * (1.f / 128.f);
        float iv0 = rsqrtf(Q0 * (1.f / 128.f) - mu0 * mu0 + 1e-5f);
        float iv1 = rsqrtf(Q1 * (1.f / 128.f) - mu1 * mu1 + 1e-5f);
#pragma unroll
        for (int nt = 0; nt < 4; ++nt) {
            int col = wn + nt * 8 + 2 * tig;
            float2 gv = *(const float2*)(lng + col);
            float2 bv = *(const float2*)(lnb + col);
            float o0 = (acc[mt][nt][0] - mu0) * iv0 * gv.x + bv.x;
            float o1 = (acc[mt][nt][1] - mu0) * iv0 * gv.y + bv.y;
            float o2 = (acc[mt][nt][2] - mu1) * iv1 * gv.x + bv.x;
            float o3 = (acc[mt][nt][3] - mu1) * iv1 * gv.y + bv.y;
            *(float2*)(Y + (size_t)(m0 + r0) * D + col) = make_float2(o0, o1);
            *(float2*)(Y + (size_t)(m0 + r1) * D + col) = make_float2(o2, o3);
            *(__nv_bfloat162*)(Ybf + (size_t)(m0 + r0) * D + col) =
                __floats2bfloat162_rn(o0, o1);
            *(__nv_bfloat162*)(Ybf + (size_t)(m0 + r1) * D + col) =
                __floats2bfloat162_rn(o2, o3);
        }
    }
}

// ---------------------------------------------------------------------------
// One-shot fp32 -> bf16 conversion of x + all weights
// ---------------------------------------------------------------------------
#define CVT_TOTAL 2818048
__global__ void cvt_all(const float* __restrict__ x, const float* __restrict__ wfc,
                        const float* __restrict__ qkvw, const float* __restrict__ outw,
                        const float* __restrict__ ff1w, const float* __restrict__ ff2w)
{
    int i = (blockIdx.x * 256 + threadIdx.x) * 4;
    if (i >= CVT_TOTAL) return;
    const float* s; __nv_bfloat16* d; int off;
    if      (i < 1572864) { s = x;    d = g_xbf;     off = i; }
    else if (i < 1638400) { s = wfc;  d = g_wfc_bf;  off = i - 1572864; }
    else if (i < 1736704) { s = qkvw; d = g_qkvw_bf; off = i - 1638400; }
    else if (i < 1769472) { s = outw; d = g_outw_bf; off = i - 1736704; }
    else if (i < 2293760) { s = ff1w; d = g_ff1w_bf; off = i - 1769472; }
    else                  { s = ff2w; d = g_ff2w_bf; off = i - 2293760; }
    float4 v = *(const float4*)(s + off);
    *(__nv_bfloat162*)(d + off)     = __floats2bfloat162_rn(v.x, v.y);
    *(__nv_bfloat162*)(d + off + 2) = __floats2bfloat162_rn(v.z, v.w);
}

// ---------------------------------------------------------------------------
// Scatter h0 -> packed tokens with fused positional encoding
// ---------------------------------------------------------------------------
__global__ void scatter_kernel()
{
    int n = blockIdx.x;
    int s = 0;
    while (n >= 64 * (s + 1) * (s + 2)) s++;
    int r = n - 64 * s * (s + 1);
    int P = s + 1;
    int b = r / P;
    int t = r - b * P;
    int d = threadIdx.x;
    float freq = expf((float)(d & ~1) * (-9.210340371976184f / 128.f));
    float arg  = (float)t * freq;
    float pe   = (d & 1) ? cosf(arg) : sinf(arg);
    float v = g_h0[(b * SEQT + t) * D + d] + pe;
    g_Y[n * D + d]   = v;
    g_Ybf[n * D + d] = __float2bfloat16(v);
}

// ---------------------------------------------------------------------------
// Attention: small smem, 4 warps share query rows, per-head loop.
// bf16 qkv in, fp32 math, bf16 ctx out.
// ---------------------------------------------------------------------------
__global__ __launch_bounds__(128) void attn_kernel()
{
    __shared__ float qs[SEQT][DH], ks[SEQT][DH], vs[SEQT][DH];
    __shared__ float ps[4][32];

    int q = blockIdx.x;
    int s = q >> 7;
    int b = q & 127;
    int P = s + 1;
    int base = 64 * s * (s + 1) + b * P;
    int tid  = threadIdx.x;
    int w    = tid >> 5;
    int lane = tid & 31;

    for (int h = 0; h < NH; ++h) {
        for (int i = tid; i < P * DH; i += 128) {
            int t = i >> 5, dd = i & 31;
            const __nv_bfloat16* row =
                g_qkvbf + (size_t)(base + t) * (3 * D) + h * DH + dd;
            qs[t][dd] = __bfloat162float(row[0]);
            ks[t][dd] = __bfloat162float(row[D]);
            vs[t][dd] = __bfloat162float(row[2 * D]);
        }
        __syncthreads();

        for (int t = w; t < P; t += 4) {
            float sc = -1e30f;
            if (lane < P) {
                float a = 0.f;
#pragma unroll
                for (int dd = 0; dd < DH; ++dd) a += qs[t][dd] * ks[lane][dd];
                sc = a * 0.17677669529663687f;  // 1/sqrt(32)
            }
            float m = sc;
            for (int o = 16; o; o >>= 1) m = fmaxf(m, __shfl_xor_sync(0xffffffffu, m, o));
            float e = (lane < P) ? expf(sc - m) : 0.f;
            float sum = e;
            for (int o = 16; o; o >>= 1) sum += __shfl_xor_sync(0xffffffffu, sum, o);
            ps[w][lane] = e / sum;
            __syncwarp();
            float c = 0.f;
            for (int j = 0; j < P; ++j) c += ps[w][j] * vs[j][lane];
            g_ctxbf[(size_t)(base + t) * D + h * DH + lane] = __float2bfloat16(c);
            __syncwarp();
        }
        __syncthreads();
    }
}

// ---------------------------------------------------------------------------
// Classifier + log_softmax, reads last-token rows of Y directly
// ---------------------------------------------------------------------------
__global__ __launch_bounds__(64) void cls_kernel(
    const float* __restrict__ Wc1, const float* __restrict__ bc1,
    const float* __restrict__ Wc2, const float* __restrict__ bc2,
    float* __restrict__ out)
{
    __shared__ float c1[NC];
    __shared__ float lrow[D];
    int n = blockIdx.x;              // b*SEQT + s
    int b = n / SEQT;
    int s = n % SEQT;
    int src = 64 * s * (s + 1) + b * (s + 1) + s;
    int o = threadIdx.x;

    for (int d = o; d < D; d += NC) lrow[d] = g_Y[(size_t)src * D + d];
    __syncthreads();

    float a = bc1[o];
    for (int d = 0; d < D; ++d) a += lrow[d] * Wc1[o * D + d];
    c1[o] = fmaxf(a, 0.f);
    __syncthreads();

    if (o == 0) {
        float l0 = bc2[0], l1 = bc2[1];
        for (int j = 0; j < NC; ++j) {
            l0 += c1[j] * Wc2[j];
            l1 += c1[j] * Wc2[NC + j];
        }
        float m   = fmaxf(l0, l1);
        float lse = m + logf(expf(l0 - m) + expf(l1 - m));
        out[n * 2 + 0] = l0 - lse;
        out[n * 2 + 1] = l1 - lse;
    }
}

// ---------------------------------------------------------------------------
extern "C" void kernel_launch(void* const* d_in, const int* in_sizes, int n_in,
                              void* d_out, int out_size)
{
    const float* x     = (const float*)d_in[0];
    const float* W_fc  = (const float*)d_in[1];
    const float* b_fc  = (const float*)d_in[2];
    const float* qkv_w = (const float*)d_in[3];
    const float* qkv_b = (const float*)d_in[4];
    const float* out_w = (const float*)d_in[5];
    const float* out_b = (const float*)d_in[6];
    const float* ln1_g = (const float*)d_in[7];
    const float* ln1_b = (const float*)d_in[8];
    const float* ln2_g = (const float*)d_in[9];
    const float* ln2_b = (const float*)d_in[10];
    const float* ff1_w = (const float*)d_in[11];
    const float* ff1_b = (const float*)d_in[12];
    const float* ff2_w = (const float*)d_in[13];
    const float* ff2_b = (const float*)d_in[14];
    const float* Wc1   = (const float*)d_in[15];
    const float* bc1   = (const float*)d_in[16];
    const float* Wc2   = (const float*)d_in[17];
    const float* bc2   = (const float*)d_in[18];

    cudaFuncSetAttribute(gemm_bf16, cudaFuncAttributeMaxDynamicSharedMemorySize,
                         GEMM_SMEM);
    cudaFuncSetAttribute(gemm_ln, cudaFuncAttributeMaxDynamicSharedMemorySize,
                         GEMM_SMEM_LN);

    void* p;
    cudaGetSymbolAddress(&p, g_h0);      float* h0  = (float*)p;
    cudaGetSymbolAddress(&p, g_Y);       float* Y   = (float*)p;
    cudaGetSymbolAddress(&p, g_xbf);     __nv_bfloat16* xbf   = (__nv_bfloat16*)p;
    cudaGetSymbolAddress(&p, g_wfc_bf);  __nv_bfloat16* wfcb  = (__nv_bfloat16*)p;
    cudaGetSymbolAddress(&p, g_qkvw_bf); __nv_bfloat16* qkvwb = (__nv_bfloat16*)p;
    cudaGetSymbolAddress(&p, g_outw_bf); __nv_bfloat16* outwb = (__nv_bfloat16*)p;
    cudaGetSymbolAddress(&p, g_ff1w_bf); __nv_bfloat16* ff1wb = (__nv_bfloat16*)p;
    cudaGetSymbolAddress(&p, g_ff2w_bf); __nv_bfloat16* ff2wb = (__nv_bfloat16*)p;
    cudaGetSymbolAddress(&p, g_Ybf);     __nv_bfloat16* ybf   = (__nv_bfloat16*)p;
    cudaGetSymbolAddress(&p, g_qkvbf);   __nv_bfloat16* qkvb  = (__nv_bfloat16*)p;
    cudaGetSymbolAddress(&p, g_ctxbf);   __nv_bfloat16* ctxb  = (__nv_bfloat16*)p;
    cudaGetSymbolAddress(&p, g_Hbf);     __nv_bfloat16* hbf   = (__nv_bfloat16*)p;

    cvt_all<<<(CVT_TOTAL / 4 + 255) / 256, 256>>>(x, W_fc, qkv_w, out_w, ff1_w, ff2_w);

    // fc: h0 = relu(x @ W_fc^T + b_fc); scatter adds PE and packs
    gemm_bf16<<<dim3(1, NBT / 128), 512, GEMM_SMEM>>>(xbf, wfcb, b_fc, h0, nullptr,
                                                      D, DIN, 1);
    scatter_kernel<<<NT, D>>>();

    for (int l = 0; l < 2; ++l) {
        gemm_bf16<<<dim3(3, NT / 128), 512, GEMM_SMEM>>>(
            ybf, qkvwb + (size_t)l * 3 * D * D, qkv_b + l * 3 * D,
            nullptr, qkvb, 3 * D, D, 0);
        attn_kernel<<<S_STEPS * BATCH, 128>>>();
        gemm_ln<<<dim3(1, NT / 128), 512, GEMM_SMEM_LN>>>(
            ctxb, outwb + (size_t)l * D * D, out_b + l * D,
            ln1_g + l * D, ln1_b + l * D, Y, ybf, D);
        gemm_bf16<<<dim3(DFF / 128, NT / 128), 512, GEMM_SMEM>>>(
            ybf, ff1wb + (size_t)l * DFF * D, ff1_b + l * DFF,
            nullptr, hbf, DFF, D, 1);
        gemm_ln<<<dim3(1, NT / 128), 512, GEMM_SMEM_LN>>>(
            hbf, ff2wb + (size_t)l * D * DFF, ff2_b + l * D,
            ln2_g + l * D, ln2_b + l * D, Y, ybf, DFF);
    }

    cls_kernel<<<NBT, NC>>>(Wc1, bc1, Wc2, bc2, (float*)d_out);
}

// round 8
// speedup vs baseline: 1.4773x; 1.0001x over previous
#include <cuda_runtime.h>
#include <cuda_bf16.h>
#include <math.h>
#include <stdint.h>

// Problem constants
#define S_STEPS 24
#define BATCH   128
#define SEQT    24
#define DIN     512
#define D       128
#define DFF     2048
#define NH      4
#define DH      32
#define NC      64
#define NT      38400  // BATCH * S*(S+1)/2
#define NBT     3072   // BATCH*SEQT

// fp32 scratch
__device__ float g_h0[NBT * D];
__device__ float g_Y[NT * D];

// bf16 buffers
__device__ __nv_bfloat16 g_xbf[NBT * DIN];
__device__ __nv_bfloat16 g_wfc_bf[D * DIN];
__device__ __nv_bfloat16 g_qkvw_bf[2 * 3 * D * D];
__device__ __nv_bfloat16 g_outw_bf[2 * D * D];
__device__ __nv_bfloat16 g_ff1w_bf[2 * DFF * D];
__device__ __nv_bfloat16 g_ff2w_bf[2 * D * DFF];
__device__ __nv_bfloat16 g_Ybf[NT * D];
__device__ __nv_bfloat16 g_qkvbf[NT * 3 * D];
__device__ __nv_bfloat16 g_ctxbf[NT * D];
__device__ __nv_bfloat16 g_Hbf[(size_t)NT * DFF];

__device__ __forceinline__ uint32_t smem_u32(const void* p) {
    return (uint32_t)__cvta_generic_to_shared(p);
}

// ---------------------------------------------------------------------------
// bf16 GEMM core: 128x128 block tile, BK=32, 128 threads (4 warps, 2x2 grid,
// warp tile 64x64), 3-stage cp.async pipeline, ldmatrix, m16n8k16 bf16 mma.
// A[M,K] row-major, W[N,K] row-major (C = A @ W^T). K % 32 == 0, K >= 64.
// ---------------------------------------------------------------------------
#define SSTR 40                 // smem row stride in bf16 (32 + 8 pad)
#define TILE (128 * SSTR)       // elems per stage per operand
#define GEMM_SMEM  (3 * TILE * 2 * 2)            // 61440 B
#define GEMM_SMEM_LN (GEMM_SMEM + 512 * 4)       // + [2][128] x2 fp32 reductions

__device__ __forceinline__ void gemm_core(
    const __nv_bfloat16* __restrict__ A, const __nv_bfloat16* __restrict__ W,
    int K, int m0, int n0, __nv_bfloat16* As, __nv_bfloat16* Bs,
    float (&acc)[4][8][4])
{
    const int t = threadIdx.x, warp = t >> 5, lane = t & 31;
    const int wm = (warp >> 1) * 64, wn = (warp & 1) * 64;
    const int xr = lane & 15, xc = (lane >> 4) * 8;

#pragma unroll
    for (int i = 0; i < 4; ++i)
#pragma unroll
        for (int j = 0; j < 8; ++j)
#pragma unroll
            for (int k = 0; k < 4; ++k) acc[i][j][k] = 0.f;

    // per stage: A 512 chunks (128 rows x 4x16B) + B 512; 128 threads x 8
    auto issue = [&](int k0, int st) {
        __nv_bfloat16* as = As + st * TILE;
        __nv_bfloat16* bs = Bs + st * TILE;
#pragma unroll
        for (int r = 0; r < 8; ++r) {
            int idx = t + r * 128;           // 0..1023
            int op  = idx >> 9;              // 0=A, 1=B
            int rem = idx & 511;
            int row = rem >> 2, c8 = (rem & 3) * 8;
            uint32_t dst = smem_u32((op ? bs : as) + row * SSTR + c8);
            const __nv_bfloat16* src = op
                ? (W + (size_t)(n0 + row) * K + k0 + c8)
                : (A + (size_t)(m0 + row) * K + k0 + c8);
            asm volatile("cp.async.cg.shared.global [%0], [%1], 16;"
                :: "r"(dst), "l"(src));
        }
        asm volatile("cp.async.commit_group;");
    };

    const int KT = K >> 5;
    issue(0, 0);
    issue(32, 1);
    for (int kt = 0; kt < KT; ++kt) {
        if (kt + 1 < KT) { asm volatile("cp.async.wait_group 1;"); }
        else             { asm volatile("cp.async.wait_group 0;"); }
        __syncthreads();
        if (kt + 2 < KT) issue((kt + 2) << 5, (kt + 2) % 3);

        const __nv_bfloat16* as = As + (kt % 3) * TILE;
        const __nv_bfloat16* bs = Bs + (kt % 3) * TILE;

        uint32_t af[2][4][4];   // [slice][mi][frag]
        uint32_t bfr[2][8][2];  // [slice][ni][frag]
#pragma unroll
        for (int si = 0; si < 2; ++si) {
            int ks = si * 16;
#pragma unroll
            for (int mi = 0; mi < 4; ++mi) {
                uint32_t ad = smem_u32(&as[(wm + mi * 16 + xr) * SSTR + ks + xc]);
                asm volatile("ldmatrix.sync.aligned.m8n8.x4.shared.b16 {%0,%1,%2,%3},[%4];"
                    : "=r"(af[si][mi][0]), "=r"(af[si][mi][1]),
                      "=r"(af[si][mi][2]), "=r"(af[si][mi][3])
                    : "r"(ad));
            }
#pragma unroll
            for (int np = 0; np < 4; ++np) {
                uint32_t bd = smem_u32(&bs[(wn + np * 16 + xr) * SSTR + ks + xc]);
                uint32_t r0, r1, r2, r3;
                asm volatile("ldmatrix.sync.aligned.m8n8.x4.shared.b16 {%0,%1,%2,%3},[%4];"
                    : "=r"(r0), "=r"(r1), "=r"(r2), "=r"(r3) : "r"(bd));
                bfr[si][2 * np][0] = r0; bfr[si][2 * np + 1][0] = r1;
                bfr[si][2 * np][1] = r2; bfr[si][2 * np + 1][1] = r3;
            }
        }
#pragma unroll
        for (int si = 0; si < 2; ++si)
#pragma unroll
            for (int mi = 0; mi < 4; ++mi)
#pragma unroll
                for (int ni = 0; ni < 8; ++ni) {
                    asm volatile(
                        "mma.sync.aligned.m16n8k16.row.col.f32.bf16.bf16.f32 "
                        "{%0,%1,%2,%3},{%4,%5,%6,%7},{%8,%9},{%0,%1,%2,%3};"
                        : "+f"(acc[mi][ni][0]), "+f"(acc[mi][ni][1]),
                          "+f"(acc[mi][ni][2]), "+f"(acc[mi][ni][3])
                        : "r"(af[si][mi][0]), "r"(af[si][mi][1]),
                          "r"(af[si][mi][2]), "r"(af[si][mi][3]),
                          "r"(bfr[si][ni][0]), "r"(bfr[si][ni][1]));
                }
    }
}

// ---------------------------------------------------------------------------
// Plain GEMM: C = A @ W^T + bias, optional ReLU; writes fp32 Cf and/or bf16 Cb
// ---------------------------------------------------------------------------
__global__ __launch_bounds__(128, 2) void gemm_bf16(
    const __nv_bfloat16* __restrict__ A, const __nv_bfloat16* __restrict__ W,
    const float* __restrict__ bias, float* __restrict__ Cf,
    __nv_bfloat16* __restrict__ Cb, int N, int K, int relu)
{
    extern __shared__ __align__(16) char dyn[];
    __nv_bfloat16* As = (__nv_bfloat16*)dyn;
    __nv_bfloat16* Bs = As + 3 * TILE;

    const int m0 = blockIdx.y * 128, n0 = blockIdx.x * 128;
    const int t = threadIdx.x, warp = t >> 5, lane = t & 31;
    const int g = lane >> 2, tig = lane & 3;
    const int wm = (warp >> 1) * 64, wn = (warp & 1) * 64;

    float acc[4][8][4];
    gemm_core(A, W, K, m0, n0, As, Bs, acc);

#pragma unroll
    for (int mi = 0; mi < 4; ++mi) {
#pragma unroll
        for (int ni = 0; ni < 8; ++ni) {
            int col = n0 + wn + ni * 8 + 2 * tig;
            float b0v = bias[col], b1v = bias[col + 1];
            int row = m0 + wm + mi * 16 + g;
            float2 v0 = make_float2(acc[mi][ni][0] + b0v, acc[mi][ni][1] + b1v);
            float2 v1 = make_float2(acc[mi][ni][2] + b0v, acc[mi][ni][3] + b1v);
            if (relu) {
                v0.x = fmaxf(v0.x, 0.f); v0.y = fmaxf(v0.y, 0.f);
                v1.x = fmaxf(v1.x, 0.f); v1.y = fmaxf(v1.y, 0.f);
            }
            if (Cf) {
                *(float2*)(Cf + (size_t)row * N + col)       = v0;
                *(float2*)(Cf + (size_t)(row + 8) * N + col) = v1;
            }
            if (Cb) {
                *(__nv_bfloat162*)(Cb + (size_t)row * N + col) =
                    __floats2bfloat162_rn(v0.x, v0.y);
                *(__nv_bfloat162*)(Cb + (size_t)(row + 8) * N + col) =
                    __floats2bfloat162_rn(v1.x, v1.y);
            }
        }
    }
}

// ---------------------------------------------------------------------------
// GEMM + residual + LayerNorm fused. N == 128 (block covers full feature dim).
//   Y = LN(Y + A@W^T + bias) * lng + lnb     (Y fp32 in/out, Ybf shadow)
// ---------------------------------------------------------------------------
__global__ __launch_bounds__(128, 2) void gemm_ln(
    const __nv_bfloat16* __restrict__ A, const __nv_bfloat16* __restrict__ W,
    const float* __restrict__ bias, const float* __restrict__ lng,
    const float* __restrict__ lnb, float* __restrict__ Y,
    __nv_bfloat16* __restrict__ Ybf, int K)
{
    extern __shared__ __align__(16) char dyn[];
    __nv_bfloat16* As = (__nv_bfloat16*)dyn;
    __nv_bfloat16* Bs = As + 3 * TILE;
    float* redS = (float*)(dyn + 3 * TILE * 2 * 2);  // [2][128]
    float* redQ = redS + 256;                         // [2][128]

    const int m0 = blockIdx.y * 128;
    const int t = threadIdx.x, warp = t >> 5, lane = t & 31;
    const int g = lane >> 2, tig = lane & 3;
    const int wm = (warp >> 1) * 64, wn = (warp & 1) * 64;
    const int cw = warp & 1;

    float acc[4][8][4];
    gemm_core(A, W, K, m0, 0, As, Bs, acc);

#pragma unroll
    for (int mi = 0; mi < 4; ++mi) {
        int r0 = wm + mi * 16 + g, r1 = r0 + 8;
        float s0 = 0.f, q0 = 0.f, s1 = 0.f, q1 = 0.f;
#pragma unroll
        for (int ni = 0; ni < 8; ++ni) {
            int col = wn + ni * 8 + 2 * tig;
            float2 bv = *(const float2*)(bias + col);
            float2 y0 = *(const float2*)(Y + (size_t)(m0 + r0) * D + col);
            float2 y1 = *(const float2*)(Y + (size_t)(m0 + r1) * D + col);
            float a0 = acc[mi][ni][0] + bv.x + y0.x;
            float a1 = acc[mi][ni][1] + bv.y + y0.y;
            float a2 = acc[mi][ni][2] + bv.x + y1.x;
            float a3 = acc[mi][ni][3] + bv.y + y1.y;
            acc[mi][ni][0] = a0; acc[mi][ni][1] = a1;
            acc[mi][ni][2] = a2; acc[mi][ni][3] = a3;
            s0 += a0 + a1; q0 += a0 * a0 + a1 * a1;
            s1 += a2 + a3; q1 += a2 * a2 + a3 * a3;
        }
#pragma unroll
        for (int o = 1; o <= 2; o <<= 1) {
            s0 += __shfl_xor_sync(0xffffffffu, s0, o);
            q0 += __shfl_xor_sync(0xffffffffu, q0, o);
            s1 += __shfl_xor_sync(0xffffffffu, s1, o);
            q1 += __shfl_xor_sync(0xffffffffu, q1, o);
        }
        if (tig == 0) {
            redS[cw * 128 + r0] = s0; redQ[cw * 128 + r0] = q0;
            redS[cw * 128 + r1] = s1; redQ[cw * 128 + r1] = q1;
        }
    }
    __syncthreads();

#pragma unroll
    for (int mi = 0; mi < 4; ++mi) {
        int r0 = wm + mi * 16 + g, r1 = r0 + 8;
        float S0 = redS[r0] + redS[128 + r0], Q0 = redQ[r0] + redQ[128 + r0];
        float S1 = redS[r1] + redS[128 + r1], Q1 = redQ[r1] + redQ[128 + r1];
        float mu0 = S0 * (1.f / 128.f), mu1 = S1 * (1.f / 128.f);
        float iv0 = rsqrtf(Q0 * (1.f / 128.f) - mu0 * mu0 + 1e-5f);
        float iv1 = rsqrtf(Q1 * (1.f / 128.f) - mu1 * mu1 + 1e-5f);
#pragma unroll
        for (int ni = 0; ni < 8; ++ni) {
            int col = wn + ni * 8 + 2 * tig;
            float2 gv = *(const float2*)(lng + col);
            float2 bv = *(const float2*)(lnb + col);
            float o0 = (acc[mi][ni][0] - mu0) * iv0 * gv.x + bv.x;
            float o1 = (acc[mi][ni][1] - mu0) * iv0 * gv.y + bv.y;
            float o2 = (acc[mi][ni][2] - mu1) * iv1 * gv.x + bv.x;
            float o3 = (acc[mi][ni][3] - mu1) * iv1 * gv.y + bv.y;
            *(float2*)(Y + (size_t)(m0 + r0) * D + col) = make_float2(o0, o1);
            *(float2*)(Y + (size_t)(m0 + r1) * D + col) = make_float2(o2, o3);
            *(__nv_bfloat162*)(Ybf + (size_t)(m0 + r0) * D + col) =
                __floats2bfloat162_rn(o0, o1);
            *(__nv_bfloat162*)(Ybf + (size_t)(m0 + r1) * D + col) =
                __floats2bfloat162_rn(o2, o3);
        }
    }
}

// ---------------------------------------------------------------------------
// One-shot fp32 -> bf16 conversion of x + all weights
// ---------------------------------------------------------------------------
#define CVT_TOTAL 2818048
__global__ void cvt_all(const float* __restrict__ x, const float* __restrict__ wfc,
                        const float* __restrict__ qkvw, const float* __restrict__ outw,
                        const float* __restrict__ ff1w, const float* __restrict__ ff2w)
{
    int i = (blockIdx.x * 256 + threadIdx.x) * 4;
    if (i >= CVT_TOTAL) return;
    const float* s; __nv_bfloat16* d; int off;
    if      (i < 1572864) { s = x;    d = g_xbf;     off = i; }
    else if (i < 1638400) { s = wfc;  d = g_wfc_bf;  off = i - 1572864; }
    else if (i < 1736704) { s = qkvw; d = g_qkvw_bf; off = i - 1638400; }
    else if (i < 1769472) { s = outw; d = g_outw_bf; off = i - 1736704; }
    else if (i < 2293760) { s = ff1w; d = g_ff1w_bf; off = i - 1769472; }
    else                  { s = ff2w; d = g_ff2w_bf; off = i - 2293760; }
    float4 v = *(const float4*)(s + off);
    *(__nv_bfloat162*)(d + off)     = __floats2bfloat162_rn(v.x, v.y);
    *(__nv_bfloat162*)(d + off + 2) = __floats2bfloat162_rn(v.z, v.w);
}

// ---------------------------------------------------------------------------
// Scatter h0 -> packed tokens with fused positional encoding
// ---------------------------------------------------------------------------
__global__ void scatter_kernel()
{
    int n = blockIdx.x;
    int s = 0;
    while (n >= 64 * (s + 1) * (s + 2)) s++;
    int r = n - 64 * s * (s + 1);
    int P = s + 1;
    int b = r / P;
    int t = r - b * P;
    int d = threadIdx.x;
    float freq = expf((float)(d & ~1) * (-9.210340371976184f / 128.f));
    float arg  = (float)t * freq;
    float pe   = (d & 1) ? cosf(arg) : sinf(arg);
    float v = g_h0[(b * SEQT + t) * D + d] + pe;
    g_Y[n * D + d]   = v;
    g_Ybf[n * D + d] = __float2bfloat16(v);
}

// ---------------------------------------------------------------------------
// Attention: small smem, 4 warps share query rows, per-head loop.
// bf16 qkv in, fp32 math, bf16 ctx out.
// ---------------------------------------------------------------------------
__global__ __launch_bounds__(128) void attn_kernel()
{
    __shared__ float qs[SEQT][DH], ks[SEQT][DH], vs[SEQT][DH];
    __shared__ float ps[4][32];

    int q = blockIdx.x;
    int s = q >> 7;
    int b = q & 127;
    int P = s + 1;
    int base = 64 * s * (s + 1) + b * P;
    int tid  = threadIdx.x;
    int w    = tid >> 5;
    int lane = tid & 31;

    for (int h = 0; h < NH; ++h) {
        for (int i = tid; i < P * DH; i += 128) {
            int t = i >> 5, dd = i & 31;
            const __nv_bfloat16* row =
                g_qkvbf + (size_t)(base + t) * (3 * D) + h * DH + dd;
            qs[t][dd] = __bfloat162float(row[0]);
            ks[t][dd] = __bfloat162float(row[D]);
            vs[t][dd] = __bfloat162float(row[2 * D]);
        }
        __syncthreads();

        for (int t = w; t < P; t += 4) {
            float sc = -1e30f;
            if (lane < P) {
                float a = 0.f;
#pragma unroll
                for (int dd = 0; dd < DH; ++dd) a += qs[t][dd] * ks[lane][dd];
                sc = a * 0.17677669529663687f;  // 1/sqrt(32)
            }
            float m = sc;
            for (int o = 16; o; o >>= 1) m = fmaxf(m, __shfl_xor_sync(0xffffffffu, m, o));
            float e = (lane < P) ? expf(sc - m) : 0.f;
            float sum = e;
            for (int o = 16; o; o >>= 1) sum += __shfl_xor_sync(0xffffffffu, sum, o);
            ps[w][lane] = e / sum;
            __syncwarp();
            float c = 0.f;
            for (int j = 0; j < P; ++j) c += ps[w][j] * vs[j][lane];
            g_ctxbf[(size_t)(base + t) * D + h * DH + lane] = __float2bfloat16(c);
            __syncwarp();
        }
        __syncthreads();
    }
}

// ---------------------------------------------------------------------------
// Classifier + log_softmax, reads last-token rows of Y directly
// ---------------------------------------------------------------------------
__global__ __launch_bounds__(64) void cls_kernel(
    const float* __restrict__ Wc1, const float* __restrict__ bc1,
    const float* __restrict__ Wc2, const float* __restrict__ bc2,
    float* __restrict__ out)
{
    __shared__ float c1[NC];
    __shared__ float lrow[D];
    int n = blockIdx.x;              // b*SEQT + s
    int b = n / SEQT;
    int s = n % SEQT;
    int src = 64 * s * (s + 1) + b * (s + 1) + s;
    int o = threadIdx.x;

    for (int d = o; d < D; d += NC) lrow[d] = g_Y[(size_t)src * D + d];
    __syncthreads();

    float a = bc1[o];
    for (int d = 0; d < D; ++d) a += lrow[d] * Wc1[o * D + d];
    c1[o] = fmaxf(a, 0.f);
    __syncthreads();

    if (o == 0) {
        float l0 = bc2[0], l1 = bc2[1];
        for (int j = 0; j < NC; ++j) {
            l0 += c1[j] * Wc2[j];
            l1 += c1[j] * Wc2[NC + j];
        }
        float m   = fmaxf(l0, l1);
        float lse = m + logf(expf(l0 - m) + expf(l1 - m));
        out[n * 2 + 0] = l0 - lse;
        out[n * 2 + 1] = l1 - lse;
    }
}

// ---------------------------------------------------------------------------
extern "C" void kernel_launch(void* const* d_in, const int* in_sizes, int n_in,
                              void* d_out, int out_size)
{
    const float* x     = (const float*)d_in[0];
    const float* W_fc  = (const float*)d_in[1];
    const float* b_fc  = (const float*)d_in[2];
    const float* qkv_w = (const float*)d_in[3];
    const float* qkv_b = (const float*)d_in[4];
    const float* out_w = (const float*)d_in[5];
    const float* out_b = (const float*)d_in[6];
    const float* ln1_g = (const float*)d_in[7];
    const float* ln1_b = (const float*)d_in[8];
    const float* ln2_g = (const float*)d_in[9];
    const float* ln2_b = (const float*)d_in[10];
    const float* ff1_w = (const float*)d_in[11];
    const float* ff1_b = (const float*)d_in[12];
    const float* ff2_w = (const float*)d_in[13];
    const float* ff2_b = (const float*)d_in[14];
    const float* Wc1   = (const float*)d_in[15];
    const float* bc1   = (const float*)d_in[16];
    const float* Wc2   = (const float*)d_in[17];
    const float* bc2   = (const float*)d_in[18];

    cudaFuncSetAttribute(gemm_bf16, cudaFuncAttributeMaxDynamicSharedMemorySize,
                         GEMM_SMEM);
    cudaFuncSetAttribute(gemm_ln, cudaFuncAttributeMaxDynamicSharedMemorySize,
                         GEMM_SMEM_LN);

    void* p;
    cudaGetSymbolAddress(&p, g_h0);      float* h0  = (float*)p;
    cudaGetSymbolAddress(&p, g_Y);       float* Y   = (float*)p;
    cudaGetSymbolAddress(&p, g_xbf);     __nv_bfloat16* xbf   = (__nv_bfloat16*)p;
    cudaGetSymbolAddress(&p, g_wfc_bf);  __nv_bfloat16* wfcb  = (__nv_bfloat16*)p;
    cudaGetSymbolAddress(&p, g_qkvw_bf); __nv_bfloat16* qkvwb = (__nv_bfloat16*)p;
    cudaGetSymbolAddress(&p, g_outw_bf); __nv_bfloat16* outwb = (__nv_bfloat16*)p;
    cudaGetSymbolAddress(&p, g_ff1w_bf); __nv_bfloat16* ff1wb = (__nv_bfloat16*)p;
    cudaGetSymbolAddress(&p, g_ff2w_bf); __nv_bfloat16* ff2wb = (__nv_bfloat16*)p;
    cudaGetSymbolAddress(&p, g_Ybf);     __nv_bfloat16* ybf   = (__nv_bfloat16*)p;
    cudaGetSymbolAddress(&p, g_qkvbf);   __nv_bfloat16* qkvb  = (__nv_bfloat16*)p;
    cudaGetSymbolAddress(&p, g_ctxbf);   __nv_bfloat16* ctxb  = (__nv_bfloat16*)p;
    cudaGetSymbolAddress(&p, g_Hbf);     __nv_bfloat16* hbf   = (__nv_bfloat16*)p;

    cvt_all<<<(CVT_TOTAL / 4 + 255) / 256, 256>>>(x, W_fc, qkv_w, out_w, ff1_w, ff2_w);

    // fc: h0 = relu(x @ W_fc^T + b_fc); scatter adds PE and packs
    gemm_bf16<<<dim3(1, NBT / 128), 128, GEMM_SMEM>>>(xbf, wfcb, b_fc, h0, nullptr,
                                                      D, DIN, 1);
    scatter_kernel<<<NT, D>>>();

    for (int l = 0; l < 2; ++l) {
        gemm_bf16<<<dim3(3, NT / 128), 128, GEMM_SMEM>>>(
            ybf, qkvwb + (size_t)l * 3 * D * D, qkv_b + l * 3 * D,
            nullptr, qkvb, 3 * D, D, 0);
        attn_kernel<<<S_STEPS * BATCH, 128>>>();
        gemm_ln<<<dim3(1, NT / 128), 128, GEMM_SMEM_LN>>>(
            ctxb, outwb + (size_t)l * D * D, out_b + l * D,
            ln1_g + l * D, ln1_b + l * D, Y, ybf, D);
        gemm_bf16<<<dim3(DFF / 128, NT / 128), 128, GEMM_SMEM>>>(
            ybf, ff1wb + (size_t)l * DFF * D, ff1_b + l * DFF,
            nullptr, hbf, DFF, D, 1);
        gemm_ln<<<dim3(1, NT / 128), 128, GEMM_SMEM_LN>>>(
            hbf, ff2wb + (size_t)l * D * DFF, ff2_b + l * D,
            ln2_g + l * D, ln2_b + l * D, Y, ybf, DFF);
    }

    cls_kernel<<<NBT, NC>>>(Wc1, bc1, Wc2, bc2, (float*)d_out);
}

// round 9
// speedup vs baseline: 2.1306x; 1.4422x over previous
#include <cuda_runtime.h>
#include <cuda_bf16.h>
#include <math.h>
#include <stdint.h>

// Problem constants
#define S_STEPS 24
#define BATCH   128
#define SEQT    24
#define DIN     512
#define D       128
#define DFF     2048
#define NH      4
#define DH      32
#define NC      64
#define NT      38400  // BATCH * S*(S+1)/2
#define NBT     3072   // BATCH*SEQT

// fp32 scratch
__device__ float g_h0[NBT * D];
__device__ float g_Y[NT * D];
__device__ float g_Ylast[NBT * D];

// bf16 buffers
__device__ __nv_bfloat16 g_xbf[NBT * DIN];
__device__ __nv_bfloat16 g_wfc_bf[D * DIN];
__device__ __nv_bfloat16 g_qkvw_bf[2 * 3 * D * D];
__device__ __nv_bfloat16 g_outw_bf[2 * D * D];
__device__ __nv_bfloat16 g_ff1w_bf[2 * DFF * D];
__device__ __nv_bfloat16 g_ff2w_bf[2 * D * DFF];
__device__ __nv_bfloat16 g_h0pbf[NBT * D];         // compact h0 + PE
__device__ __nv_bfloat16 g_qkv0bf[NBT * 3 * D];    // compact layer-0 qkv
__device__ __nv_bfloat16 g_Ybf[NT * D];
__device__ __nv_bfloat16 g_qkvbf[NT * 3 * D];      // layer-1 qkv (full)
__device__ __nv_bfloat16 g_ctxbf[NT * D];          // layer-0 ctx (full)
__device__ __nv_bfloat16 g_ctxlastbf[NBT * D];     // layer-1 ctx (last tokens)
__device__ __nv_bfloat16 g_Ylastbf[NBT * D];
__device__ __nv_bfloat16 g_Hbf[(size_t)NT * DFF];

__device__ __forceinline__ uint32_t smem_u32(const void* p) {
    return (uint32_t)__cvta_generic_to_shared(p);
}

// ---------------------------------------------------------------------------
// bf16 GEMM core: 128x128 block tile, BK=32, 128 threads (4 warps, 2x2 grid,
// warp tile 64x64), 3-stage cp.async pipeline, ldmatrix, m16n8k16 bf16 mma.
// A[M,K] row-major, W[N,K] row-major (C = A @ W^T). K % 32 == 0, K >= 64.
// ---------------------------------------------------------------------------
#define SSTR 40
#define TILE (128 * SSTR)
#define GEMM_SMEM  (3 * TILE * 2 * 2)
#define GEMM_SMEM_LN (GEMM_SMEM + 512 * 4)

__device__ __forceinline__ void gemm_core(
    const __nv_bfloat16* __restrict__ A, const __nv_bfloat16* __restrict__ W,
    int K, int m0, int n0, __nv_bfloat16* As, __nv_bfloat16* Bs,
    float (&acc)[4][8][4])
{
    const int t = threadIdx.x, warp = t >> 5, lane = t & 31;
    const int wm = (warp >> 1) * 64, wn = (warp & 1) * 64;
    const int xr = lane & 15, xc = (lane >> 4) * 8;

#pragma unroll
    for (int i = 0; i < 4; ++i)
#pragma unroll
        for (int j = 0; j < 8; ++j)
#pragma unroll
            for (int k = 0; k < 4; ++k) acc[i][j][k] = 0.f;

    auto issue = [&](int k0, int st) {
        __nv_bfloat16* as = As + st * TILE;
        __nv_bfloat16* bs = Bs + st * TILE;
#pragma unroll
        for (int r = 0; r < 8; ++r) {
            int idx = t + r * 128;
            int op  = idx >> 9;
            int rem = idx & 511;
            int row = rem >> 2, c8 = (rem & 3) * 8;
            uint32_t dst = smem_u32((op ? bs : as) + row * SSTR + c8);
            const __nv_bfloat16* src = op
                ? (W + (size_t)(n0 + row) * K + k0 + c8)
                : (A + (size_t)(m0 + row) * K + k0 + c8);
            asm volatile("cp.async.cg.shared.global [%0], [%1], 16;"
                :: "r"(dst), "l"(src));
        }
        asm volatile("cp.async.commit_group;");
    };

    const int KT = K >> 5;
    issue(0, 0);
    issue(32, 1);
    for (int kt = 0; kt < KT; ++kt) {
        if (kt + 1 < KT) { asm volatile("cp.async.wait_group 1;"); }
        else             { asm volatile("cp.async.wait_group 0;"); }
        __syncthreads();
        if (kt + 2 < KT) issue((kt + 2) << 5, (kt + 2) % 3);

        const __nv_bfloat16* as = As + (kt % 3) * TILE;
        const __nv_bfloat16* bs = Bs + (kt % 3) * TILE;

        uint32_t af[2][4][4];
        uint32_t bfr[2][8][2];
#pragma unroll
        for (int si = 0; si < 2; ++si) {
            int ks = si * 16;
#pragma unroll
            for (int mi = 0; mi < 4; ++mi) {
                uint32_t ad = smem_u32(&as[(wm + mi * 16 + xr) * SSTR + ks + xc]);
                asm volatile("ldmatrix.sync.aligned.m8n8.x4.shared.b16 {%0,%1,%2,%3},[%4];"
                    : "=r"(af[si][mi][0]), "=r"(af[si][mi][1]),
                      "=r"(af[si][mi][2]), "=r"(af[si][mi][3])
                    : "r"(ad));
            }
#pragma unroll
            for (int np = 0; np < 4; ++np) {
                uint32_t bd = smem_u32(&bs[(wn + np * 16 + xr) * SSTR + ks + xc]);
                uint32_t r0, r1, r2, r3;
                asm volatile("ldmatrix.sync.aligned.m8n8.x4.shared.b16 {%0,%1,%2,%3},[%4];"
                    : "=r"(r0), "=r"(r1), "=r"(r2), "=r"(r3) : "r"(bd));
                bfr[si][2 * np][0] = r0; bfr[si][2 * np + 1][0] = r1;
                bfr[si][2 * np][1] = r2; bfr[si][2 * np + 1][1] = r3;
            }
        }
#pragma unroll
        for (int si = 0; si < 2; ++si)
#pragma unroll
            for (int mi = 0; mi < 4; ++mi)
#pragma unroll
                for (int ni = 0; ni < 8; ++ni) {
                    asm volatile(
                        "mma.sync.aligned.m16n8k16.row.col.f32.bf16.bf16.f32 "
                        "{%0,%1,%2,%3},{%4,%5,%6,%7},{%8,%9},{%0,%1,%2,%3};"
                        : "+f"(acc[mi][ni][0]), "+f"(acc[mi][ni][1]),
                          "+f"(acc[mi][ni][2]), "+f"(acc[mi][ni][3])
                        : "r"(af[si][mi][0]), "r"(af[si][mi][1]),
                          "r"(af[si][mi][2]), "r"(af[si][mi][3]),
                          "r"(bfr[si][ni][0]), "r"(bfr[si][ni][1]));
                }
    }
}

// ---------------------------------------------------------------------------
// Plain GEMM: C = A @ W^T + bias, optional ReLU; writes fp32 Cf and/or bf16 Cb
// ---------------------------------------------------------------------------
__global__ __launch_bounds__(128, 2) void gemm_bf16(
    const __nv_bfloat16* __restrict__ A, const __nv_bfloat16* __restrict__ W,
    const float* __restrict__ bias, float* __restrict__ Cf,
    __nv_bfloat16* __restrict__ Cb, int N, int K, int relu)
{
    extern __shared__ __align__(16) char dyn[];
    __nv_bfloat16* As = (__nv_bfloat16*)dyn;
    __nv_bfloat16* Bs = As + 3 * TILE;

    const int m0 = blockIdx.y * 128, n0 = blockIdx.x * 128;
    const int t = threadIdx.x, warp = t >> 5, lane = t & 31;
    const int g = lane >> 2, tig = lane & 3;
    const int wm = (warp >> 1) * 64, wn = (warp & 1) * 64;

    float acc[4][8][4];
    gemm_core(A, W, K, m0, n0, As, Bs, acc);

#pragma unroll
    for (int mi = 0; mi < 4; ++mi) {
#pragma unroll
        for (int ni = 0; ni < 8; ++ni) {
            int col = n0 + wn + ni * 8 + 2 * tig;
            float b0v = bias[col], b1v = bias[col + 1];
            int row = m0 + wm + mi * 16 + g;
            float2 v0 = make_float2(acc[mi][ni][0] + b0v, acc[mi][ni][1] + b1v);
            float2 v1 = make_float2(acc[mi][ni][2] + b0v, acc[mi][ni][3] + b1v);
            if (relu) {
                v0.x = fmaxf(v0.x, 0.f); v0.y = fmaxf(v0.y, 0.f);
                v1.x = fmaxf(v1.x, 0.f); v1.y = fmaxf(v1.y, 0.f);
            }
            if (Cf) {
                *(float2*)(Cf + (size_t)row * N + col)       = v0;
                *(float2*)(Cf + (size_t)(row + 8) * N + col) = v1;
            }
            if (Cb) {
                *(__nv_bfloat162*)(Cb + (size_t)row * N + col) =
                    __floats2bfloat162_rn(v0.x, v0.y);
                *(__nv_bfloat162*)(Cb + (size_t)(row + 8) * N + col) =
                    __floats2bfloat162_rn(v1.x, v1.y);
            }
        }
    }
}

// ---------------------------------------------------------------------------
// GEMM + residual + LayerNorm fused. N == 128.
//   Y = LN(Y + A@W^T + bias) * lng + lnb     (Y fp32 in/out, Ybf shadow)
// ---------------------------------------------------------------------------
__global__ __launch_bounds__(128, 2) void gemm_ln(
    const __nv_bfloat16* __restrict__ A, const __nv_bfloat16* __restrict__ W,
    const float* __restrict__ bias, const float* __restrict__ lng,
    const float* __restrict__ lnb, float* __restrict__ Y,
    __nv_bfloat16* __restrict__ Ybf, int K)
{
    extern __shared__ __align__(16) char dyn[];
    __nv_bfloat16* As = (__nv_bfloat16*)dyn;
    __nv_bfloat16* Bs = As + 3 * TILE;
    float* redS = (float*)(dyn + 3 * TILE * 2 * 2);  // [2][128]
    float* redQ = redS + 256;                         // [2][128]

    const int m0 = blockIdx.y * 128;
    const int t = threadIdx.x, warp = t >> 5, lane = t & 31;
    const int g = lane >> 2, tig = lane & 3;
    const int wm = (warp >> 1) * 64, wn = (warp & 1) * 64;
    const int cw = warp & 1;

    float acc[4][8][4];
    gemm_core(A, W, K, m0, 0, As, Bs, acc);

#pragma unroll
    for (int mi = 0; mi < 4; ++mi) {
        int r0 = wm + mi * 16 + g, r1 = r0 + 8;
        float s0 = 0.f, q0 = 0.f, s1 = 0.f, q1 = 0.f;
#pragma unroll
        for (int ni = 0; ni < 8; ++ni) {
            int col = wn + ni * 8 + 2 * tig;
            float2 bv = *(const float2*)(bias + col);
            float2 y0 = *(const float2*)(Y + (size_t)(m0 + r0) * D + col);
            float2 y1 = *(const float2*)(Y + (size_t)(m0 + r1) * D + col);
            float a0 = acc[mi][ni][0] + bv.x + y0.x;
            float a1 = acc[mi][ni][1] + bv.y + y0.y;
            float a2 = acc[mi][ni][2] + bv.x + y1.x;
            float a3 = acc[mi][ni][3] + bv.y + y1.y;
            acc[mi][ni][0] = a0; acc[mi][ni][1] = a1;
            acc[mi][ni][2] = a2; acc[mi][ni][3] = a3;
            s0 += a0 + a1; q0 += a0 * a0 + a1 * a1;
            s1 += a2 + a3; q1 += a2 * a2 + a3 * a3;
        }
#pragma unroll
        for (int o = 1; o <= 2; o <<= 1) {
            s0 += __shfl_xor_sync(0xffffffffu, s0, o);
            q0 += __shfl_xor_sync(0xffffffffu, q0, o);
            s1 += __shfl_xor_sync(0xffffffffu, s1, o);
            q1 += __shfl_xor_sync(0xffffffffu, q1, o);
        }
        if (tig == 0) {
            redS[cw * 128 + r0] = s0; redQ[cw * 128 + r0] = q0;
            redS[cw * 128 + r1] = s1; redQ[cw * 128 + r1] = q1;
        }
    }
    __syncthreads();

#pragma unroll
    for (int mi = 0; mi < 4; ++mi) {
        int r0 = wm + mi * 16 + g, r1 = r0 + 8;
        float S0 = redS[r0] + redS[128 + r0], Q0 = redQ[r0] + redQ[128 + r0];
        float S1 = redS[r1] + redS[128 + r1], Q1 = redQ[r1] + redQ[128 + r1];
        float mu0 = S0 * (1.f / 128.f), mu1 = S1 * (1.f / 128.f);
        float iv0 = rsqrtf(Q0 * (1.f / 128.f) - mu0 * mu0 + 1e-5f);
        float iv1 = rsqrtf(Q1 * (1.f / 128.f) - mu1 * mu1 + 1e-5f);
#pragma unroll
        for (int ni = 0; ni < 8; ++ni) {
            int col = wn + ni * 8 + 2 * tig;
            float2 gv = *(const float2*)(lng + col);
            float2 bv = *(const float2*)(lnb + col);
            float o0 = (acc[mi][ni][0] - mu0) * iv0 * gv.x + bv.x;
            float o1 = (acc[mi][ni][1] - mu0) * iv0 * gv.y + bv.y;
            float o2 = (acc[mi][ni][2] - mu1) * iv1 * gv.x + bv.x;
            float o3 = (acc[mi][ni][3] - mu1) * iv1 * gv.y + bv.y;
            *(float2*)(Y + (size_t)(m0 + r0) * D + col) = make_float2(o0, o1);
            *(float2*)(Y + (size_t)(m0 + r1) * D + col) = make_float2(o2, o3);
            *(__nv_bfloat162*)(Ybf + (size_t)(m0 + r0) * D + col) =
                __floats2bfloat162_rn(o0, o1);
            *(__nv_bfloat162*)(Ybf + (size_t)(m0 + r1) * D + col) =
                __floats2bfloat162_rn(o2, o3);
        }
    }
}

// ---------------------------------------------------------------------------
// One-shot fp32 -> bf16 conversion of x + all weights
// ---------------------------------------------------------------------------
#define CVT_TOTAL 2818048
__global__ void cvt_all(const float* __restrict__ x, const float* __restrict__ wfc,
                        const float* __restrict__ qkvw, const float* __restrict__ outw,
                        const float* __restrict__ ff1w, const float* __restrict__ ff2w)
{
    int i = (blockIdx.x * 256 + threadIdx.x) * 4;
    if (i >= CVT_TOTAL) return;
    const float* s; __nv_bfloat16* d; int off;
    if      (i < 1572864) { s = x;    d = g_xbf;     off = i; }
    else if (i < 1638400) { s = wfc;  d = g_wfc_bf;  off = i - 1572864; }
    else if (i < 1736704) { s = qkvw; d = g_qkvw_bf; off = i - 1638400; }
    else if (i < 1769472) { s = outw; d = g_outw_bf; off = i - 1736704; }
    else if (i < 2293760) { s = ff1w; d = g_ff1w_bf; off = i - 1769472; }
    else                  { s = ff2w; d = g_ff2w_bf; off = i - 2293760; }
    float4 v = *(const float4*)(s + off);
    *(__nv_bfloat162*)(d + off)     = __floats2bfloat162_rn(v.x, v.y);
    *(__nv_bfloat162*)(d + off + 2) = __floats2bfloat162_rn(v.z, v.w);
}

// ---------------------------------------------------------------------------
// Scatter h0+PE -> packed fp32 Y; on the s==23 pass also emit compact bf16 h0p
// ---------------------------------------------------------------------------
__global__ void scatter_kernel()
{
    int n = blockIdx.x;
    int s = 0;
    while (n >= 64 * (s + 1) * (s + 2)) s++;
    int r = n - 64 * s * (s + 1);
    int P = s + 1;
    int b = r / P;
    int t = r - b * P;
    int d = threadIdx.x;
    float freq = expf((float)(d & ~1) * (-9.210340371976184f / 128.f));
    float arg  = (float)t * freq;
    float pe   = (d & 1) ? cosf(arg) : sinf(arg);
    float v = g_h0[(b * SEQT + t) * D + d] + pe;
    g_Y[n * D + d] = v;
    if (s == SEQT - 1)
        g_h0pbf[(b * SEQT + t) * D + d] = __float2bfloat16(v);
}

// ---------------------------------------------------------------------------
// Layer-0 attention: reads COMPACT qkv0 (per-(b,t), identical across steps),
// writes packed ctx for all NT tokens. One block per (s,b).
// ---------------------------------------------------------------------------
__global__ __launch_bounds__(128) void attn0_kernel()
{
    __shared__ float qs[SEQT][DH], ks[SEQT][DH], vs[SEQT][DH];
    __shared__ float ps[4][32];

    int q = blockIdx.x;
    int s = q >> 7;
    int b = q & 127;
    int P = s + 1;
    int dst = 64 * s * (s + 1) + b * P;
    int tid  = threadIdx.x;
    int w    = tid >> 5;
    int lane = tid & 31;

    for (int h = 0; h < NH; ++h) {
        for (int i = tid; i < P * DH; i += 128) {
            int t = i >> 5, dd = i & 31;
            const __nv_bfloat16* row =
                g_qkv0bf + (size_t)(b * SEQT + t) * (3 * D) + h * DH + dd;
            qs[t][dd] = __bfloat162float(row[0]);
            ks[t][dd] = __bfloat162float(row[D]);
            vs[t][dd] = __bfloat162float(row[2 * D]);
        }
        __syncthreads();

        for (int t = w; t < P; t += 4) {
            float sc = -1e30f;
            if (lane < P) {
                float a = 0.f;
#pragma unroll
                for (int dd = 0; dd < DH; ++dd) a += qs[t][dd] * ks[lane][dd];
                sc = a * 0.17677669529663687f;
            }
            float m = sc;
            for (int o = 16; o; o >>= 1) m = fmaxf(m, __shfl_xor_sync(0xffffffffu, m, o));
            float e = (lane < P) ? expf(sc - m) : 0.f;
            float sum = e;
            for (int o = 16; o; o >>= 1) sum += __shfl_xor_sync(0xffffffffu, sum, o);
            ps[w][lane] = e / sum;
            __syncwarp();
            float c = 0.f;
            for (int j = 0; j < P; ++j) c += ps[w][j] * vs[j][lane];
            g_ctxbf[(size_t)(dst + t) * D + h * DH + lane] = __float2bfloat16(c);
            __syncwarp();
        }
        __syncthreads();
    }
}

// ---------------------------------------------------------------------------
// Layer-1 attention, LAST query only. One block per (s,b); warp = head.
// Reads full packed qkv1; writes compact ctx_last[b*SEQT+s].
// ---------------------------------------------------------------------------
__global__ __launch_bounds__(128) void attn1_kernel()
{
    __shared__ float qs[NH][DH];
    __shared__ float ps[NH][32];

    int q = blockIdx.x;
    int s = q >> 7;
    int b = q & 127;
    int P = s + 1;
    int base = 64 * s * (s + 1) + b * P;
    int tid  = threadIdx.x;
    int h    = tid >> 5;
    int lane = tid & 31;

    qs[h][lane] = __bfloat162float(
        g_qkvbf[(size_t)(base + s) * (3 * D) + h * DH + lane]);
    __syncthreads();

    float sc = -1e30f;
    if (lane < P) {
        const __nv_bfloat16* krow =
            g_qkvbf + (size_t)(base + lane) * (3 * D) + D + h * DH;
        float a = 0.f;
#pragma unroll
        for (int dd = 0; dd < DH; ++dd) a += qs[h][dd] * __bfloat162float(krow[dd]);
        sc = a * 0.17677669529663687f;
    }
    float m = sc;
    for (int o = 16; o; o >>= 1) m = fmaxf(m, __shfl_xor_sync(0xffffffffu, m, o));
    float e = (lane < P) ? expf(sc - m) : 0.f;
    float sum = e;
    for (int o = 16; o; o >>= 1) sum += __shfl_xor_sync(0xffffffffu, sum, o);
    ps[h][lane] = e / sum;
    __syncwarp();

    float c = 0.f;
    for (int j = 0; j < P; ++j)
        c += ps[h][j] * __bfloat162float(
                 g_qkvbf[(size_t)(base + j) * (3 * D) + 2 * D + h * DH + lane]);
    g_ctxlastbf[(size_t)(b * SEQT + s) * D + h * DH + lane] = __float2bfloat16(c);
}

// ---------------------------------------------------------------------------
// Gather last-token rows of packed Y into compact Ylast
// ---------------------------------------------------------------------------
__global__ void gather_last()
{
    int n = blockIdx.x;              // b*SEQT + s
    int b = n / SEQT;
    int s = n % SEQT;
    int src = 64 * s * (s + 1) + b * (s + 1) + s;
    g_Ylast[n * D + threadIdx.x] = g_Y[(size_t)src * D + threadIdx.x];
}

// ---------------------------------------------------------------------------
// Classifier + log_softmax, reads compact Ylast
// ---------------------------------------------------------------------------
__global__ __launch_bounds__(64) void cls_kernel(
    const float* __restrict__ Wc1, const float* __restrict__ bc1,
    const float* __restrict__ Wc2, const float* __restrict__ bc2,
    float* __restrict__ out)
{
    __shared__ float c1[NC];
    __shared__ float lrow[D];
    int n = blockIdx.x;
    int o = threadIdx.x;

    for (int d = o; d < D; d += NC) lrow[d] = g_Ylast[n * D + d];
    __syncthreads();

    float a = bc1[o];
    for (int d = 0; d < D; ++d) a += lrow[d] * Wc1[o * D + d];
    c1[o] = fmaxf(a, 0.f);
    __syncthreads();

    if (o == 0) {
        float l0 = bc2[0], l1 = bc2[1];
        for (int j = 0; j < NC; ++j) {
            l0 += c1[j] * Wc2[j];
            l1 += c1[j] * Wc2[NC + j];
        }
        float m   = fmaxf(l0, l1);
        float lse = m + logf(expf(l0 - m) + expf(l1 - m));
        out[n * 2 + 0] = l0 - lse;
        out[n * 2 + 1] = l1 - lse;
    }
}

// ---------------------------------------------------------------------------
extern "C" void kernel_launch(void* const* d_in, const int* in_sizes, int n_in,
                              void* d_out, int out_size)
{
    const float* x     = (const float*)d_in[0];
    const float* W_fc  = (const float*)d_in[1];
    const float* b_fc  = (const float*)d_in[2];
    const float* qkv_w = (const float*)d_in[3];
    const float* qkv_b = (const float*)d_in[4];
    const float* out_w = (const float*)d_in[5];
    const float* out_b = (const float*)d_in[6];
    const float* ln1_g = (const float*)d_in[7];
    const float* ln1_b = (const float*)d_in[8];
    const float* ln2_g = (const float*)d_in[9];
    const float* ln2_b = (const float*)d_in[10];
    const float* ff1_w = (const float*)d_in[11];
    const float* ff1_b = (const float*)d_in[12];
    const float* ff2_w = (const float*)d_in[13];
    const float* ff2_b = (const float*)d_in[14];
    const float* Wc1   = (const float*)d_in[15];
    const float* bc1   = (const float*)d_in[16];
    const float* Wc2   = (const float*)d_in[17];
    const float* bc2   = (const float*)d_in[18];

    cudaFuncSetAttribute(gemm_bf16, cudaFuncAttributeMaxDynamicSharedMemorySize,
                         GEMM_SMEM);
    cudaFuncSetAttribute(gemm_ln, cudaFuncAttributeMaxDynamicSharedMemorySize,
                         GEMM_SMEM_LN);

    void* p;
    cudaGetSymbolAddress(&p, g_h0);       float* h0    = (float*)p;
    cudaGetSymbolAddress(&p, g_Y);        float* Y     = (float*)p;
    cudaGetSymbolAddress(&p, g_Ylast);    float* Ylast = (float*)p;
    cudaGetSymbolAddress(&p, g_xbf);      __nv_bfloat16* xbf   = (__nv_bfloat16*)p;
    cudaGetSymbolAddress(&p, g_wfc_bf);   __nv_bfloat16* wfcb  = (__nv_bfloat16*)p;
    cudaGetSymbolAddress(&p, g_qkvw_bf);  __nv_bfloat16* qkvwb = (__nv_bfloat16*)p;
    cudaGetSymbolAddress(&p, g_outw_bf);  __nv_bfloat16* outwb = (__nv_bfloat16*)p;
    cudaGetSymbolAddress(&p, g_ff1w_bf);  __nv_bfloat16* ff1wb = (__nv_bfloat16*)p;
    cudaGetSymbolAddress(&p, g_ff2w_bf);  __nv_bfloat16* ff2wb = (__nv_bfloat16*)p;
    cudaGetSymbolAddress(&p, g_h0pbf);    __nv_bfloat16* h0pb  = (__nv_bfloat16*)p;
    cudaGetSymbolAddress(&p, g_qkv0bf);   __nv_bfloat16* qkv0b = (__nv_bfloat16*)p;
    cudaGetSymbolAddress(&p, g_Ybf);      __nv_bfloat16* ybf   = (__nv_bfloat16*)p;
    cudaGetSymbolAddress(&p, g_qkvbf);    __nv_bfloat16* qkvb  = (__nv_bfloat16*)p;
    cudaGetSymbolAddress(&p, g_ctxbf);    __nv_bfloat16* ctxb  = (__nv_bfloat16*)p;
    cudaGetSymbolAddress(&p, g_ctxlastbf);__nv_bfloat16* ctxlb = (__nv_bfloat16*)p;
    cudaGetSymbolAddress(&p, g_Ylastbf);  __nv_bfloat16* ylbf  = (__nv_bfloat16*)p;
    cudaGetSymbolAddress(&p, g_Hbf);      __nv_bfloat16* hbf   = (__nv_bfloat16*)p;

    cvt_all<<<(CVT_TOTAL / 4 + 255) / 256, 256>>>(x, W_fc, qkv_w, out_w, ff1_w, ff2_w);

    // fc: h0 = relu(x @ W_fc^T + b_fc); scatter adds PE, packs Y, emits h0p
    gemm_bf16<<<dim3(1, NBT / 128), 128, GEMM_SMEM>>>(xbf, wfcb, b_fc, h0, nullptr,
                                                      D, DIN, 1);
    scatter_kernel<<<NT, D>>>();

    // ---- layer 0 (full token set; qkv computed once on unique tokens) ----
    gemm_bf16<<<dim3(3, NBT / 128), 128, GEMM_SMEM>>>(
        h0pb, qkvwb, qkv_b, nullptr, qkv0b, 3 * D, D, 0);
    attn0_kernel<<<S_STEPS * BATCH, 128>>>();
    gemm_ln<<<dim3(1, NT / 128), 128, GEMM_SMEM_LN>>>(
        ctxb, outwb, out_b, ln1_g, ln1_b, Y, ybf, D);
    gemm_bf16<<<dim3(DFF / 128, NT / 128), 128, GEMM_SMEM>>>(
        ybf, ff1wb, ff1_b, nullptr, hbf, DFF, D, 1);
    gemm_ln<<<dim3(1, NT / 128), 128, GEMM_SMEM_LN>>>(
        hbf, ff2wb, ff2_b, ln2_g, ln2_b, Y, ybf, DFF);

    // ---- layer 1 (K/V full; everything else last-token only) ----
    gemm_bf16<<<dim3(3, NT / 128), 128, GEMM_SMEM>>>(
        ybf, qkvwb + (size_t)3 * D * D, qkv_b + 3 * D, nullptr, qkvb, 3 * D, D, 0);
    attn1_kernel<<<S_STEPS * BATCH, 128>>>();
    gather_last<<<NBT, D>>>();
    gemm_ln<<<dim3(1, NBT / 128), 128, GEMM_SMEM_LN>>>(
        ctxlb, outwb + (size_t)D * D, out_b + D,
        ln1_g + D, ln1_b + D, Ylast, ylbf, D);
    gemm_bf16<<<dim3(DFF / 128, NBT / 128), 128, GEMM_SMEM>>>(
        ylbf, ff1wb + (size_t)DFF * D, ff1_b + DFF, nullptr, hbf, DFF, D, 1);
    gemm_ln<<<dim3(1, NBT / 128), 128, GEMM_SMEM_LN>>>(
        hbf, ff2wb + (size_t)D * DFF, ff2_b + D,
        ln2_g + D, ln2_b + D, Ylast, ylbf, DFF);

    cls_kernel<<<NBT, NC>>>(Wc1, bc1, Wc2, bc2, (float*)d_out);
}

// round 10
// speedup vs baseline: 2.2338x; 1.0485x over previous
#include <cuda_runtime.h>
#include <cuda_bf16.h>
#include <math.h>
#include <stdint.h>

// Problem constants
#define S_STEPS 24
#define BATCH   128
#define SEQT    24
#define DIN     512
#define D       128
#define DFF     2048
#define NH      4
#define DH      32
#define NC      64
#define NT      38400  // BATCH * S*(S+1)/2
#define NBT     3072   // BATCH*SEQT

// fp32 scratch
__device__ float g_h0[NBT * D];
__device__ float g_Y[NT * D];
__device__ float g_Ylast[NBT * D];

// bf16 buffers
__device__ __nv_bfloat16 g_xbf[NBT * DIN];
__device__ __nv_bfloat16 g_wfc_bf[D * DIN];
__device__ __nv_bfloat16 g_qkvw_bf[2 * 3 * D * D];
__device__ __nv_bfloat16 g_outw_bf[2 * D * D];
__device__ __nv_bfloat16 g_ff1w_bf[2 * DFF * D];
__device__ __nv_bfloat16 g_ff2w_bf[2 * D * DFF];
__device__ __nv_bfloat16 g_h0pbf[NBT * D];
__device__ __nv_bfloat16 g_qkv0bf[NBT * 3 * D];
__device__ __nv_bfloat16 g_Ybf[NT * D];
__device__ __nv_bfloat16 g_qkvbf[NT * 3 * D];
__device__ __nv_bfloat16 g_ctxbf[NT * D];
__device__ __nv_bfloat16 g_ctxlastbf[NBT * D];
__device__ __nv_bfloat16 g_Ylastbf[NBT * D];
__device__ __nv_bfloat16 g_Hbf[(size_t)NT * DFF];

__device__ __forceinline__ uint32_t smem_u32(const void* p) {
    return (uint32_t)__cvta_generic_to_shared(p);
}

// ---------------------------------------------------------------------------
// bf16 GEMM core (M-tile 128): BK=32, 128 threads (4 warps 2x2, warp 64x64),
// 3-stage cp.async, ldmatrix, m16n8k16. A[M,K], W[N,K] row-major. K%32==0.
// ---------------------------------------------------------------------------
#define SSTR 40
#define TILE (128 * SSTR)
#define GEMM_SMEM  (3 * TILE * 2 * 2)

__device__ __forceinline__ void gemm_core(
    const __nv_bfloat16* __restrict__ A, const __nv_bfloat16* __restrict__ W,
    int K, int m0, int n0, __nv_bfloat16* As, __nv_bfloat16* Bs,
    float (&acc)[4][8][4])
{
    const int t = threadIdx.x, warp = t >> 5, lane = t & 31;
    const int wm = (warp >> 1) * 64, wn = (warp & 1) * 64;
    const int xr = lane & 15, xc = (lane >> 4) * 8;

#pragma unroll
    for (int i = 0; i < 4; ++i)
#pragma unroll
        for (int j = 0; j < 8; ++j)
#pragma unroll
            for (int k = 0; k < 4; ++k) acc[i][j][k] = 0.f;

    auto issue = [&](int k0, int st) {
        __nv_bfloat16* as = As + st * TILE;
        __nv_bfloat16* bs = Bs + st * TILE;
#pragma unroll
        for (int r = 0; r < 8; ++r) {
            int idx = t + r * 128;
            int op  = idx >> 9;
            int rem = idx & 511;
            int row = rem >> 2, c8 = (rem & 3) * 8;
            uint32_t dst = smem_u32((op ? bs : as) + row * SSTR + c8);
            const __nv_bfloat16* src = op
                ? (W + (size_t)(n0 + row) * K + k0 + c8)
                : (A + (size_t)(m0 + row) * K + k0 + c8);
            asm volatile("cp.async.cg.shared.global [%0], [%1], 16;"
                :: "r"(dst), "l"(src));
        }
        asm volatile("cp.async.commit_group;");
    };

    const int KT = K >> 5;
    issue(0, 0);
    issue(32, 1);
    for (int kt = 0; kt < KT; ++kt) {
        if (kt + 1 < KT) { asm volatile("cp.async.wait_group 1;"); }
        else             { asm volatile("cp.async.wait_group 0;"); }
        __syncthreads();
        if (kt + 2 < KT) issue((kt + 2) << 5, (kt + 2) % 3);

        const __nv_bfloat16* as = As + (kt % 3) * TILE;
        const __nv_bfloat16* bs = Bs + (kt % 3) * TILE;

        uint32_t af[2][4][4];
        uint32_t bfr[2][8][2];
#pragma unroll
        for (int si = 0; si < 2; ++si) {
            int ks = si * 16;
#pragma unroll
            for (int mi = 0; mi < 4; ++mi) {
                uint32_t ad = smem_u32(&as[(wm + mi * 16 + xr) * SSTR + ks + xc]);
                asm volatile("ldmatrix.sync.aligned.m8n8.x4.shared.b16 {%0,%1,%2,%3},[%4];"
                    : "=r"(af[si][mi][0]), "=r"(af[si][mi][1]),
                      "=r"(af[si][mi][2]), "=r"(af[si][mi][3])
                    : "r"(ad));
            }
#pragma unroll
            for (int np = 0; np < 4; ++np) {
                uint32_t bd = smem_u32(&bs[(wn + np * 16 + xr) * SSTR + ks + xc]);
                uint32_t r0, r1, r2, r3;
                asm volatile("ldmatrix.sync.aligned.m8n8.x4.shared.b16 {%0,%1,%2,%3},[%4];"
                    : "=r"(r0), "=r"(r1), "=r"(r2), "=r"(r3) : "r"(bd));
                bfr[si][2 * np][0] = r0; bfr[si][2 * np + 1][0] = r1;
                bfr[si][2 * np][1] = r2; bfr[si][2 * np + 1][1] = r3;
            }
        }
#pragma unroll
        for (int si = 0; si < 2; ++si)
#pragma unroll
            for (int mi = 0; mi < 4; ++mi)
#pragma unroll
                for (int ni = 0; ni < 8; ++ni) {
                    asm volatile(
                        "mma.sync.aligned.m16n8k16.row.col.f32.bf16.bf16.f32 "
                        "{%0,%1,%2,%3},{%4,%5,%6,%7},{%8,%9},{%0,%1,%2,%3};"
                        : "+f"(acc[mi][ni][0]), "+f"(acc[mi][ni][1]),
                          "+f"(acc[mi][ni][2]), "+f"(acc[mi][ni][3])
                        : "r"(af[si][mi][0]), "r"(af[si][mi][1]),
                          "r"(af[si][mi][2]), "r"(af[si][mi][3]),
                          "r"(bfr[si][ni][0]), "r"(bfr[si][ni][1]));
                }
    }
}

// ---------------------------------------------------------------------------
// Plain GEMM (M-tile 128): C = A @ W^T + bias, optional ReLU
// ---------------------------------------------------------------------------
__global__ __launch_bounds__(128, 2) void gemm_bf16(
    const __nv_bfloat16* __restrict__ A, const __nv_bfloat16* __restrict__ W,
    const float* __restrict__ bias, float* __restrict__ Cf,
    __nv_bfloat16* __restrict__ Cb, int N, int K, int relu)
{
    extern __shared__ __align__(16) char dyn[];
    __nv_bfloat16* As = (__nv_bfloat16*)dyn;
    __nv_bfloat16* Bs = As + 3 * TILE;

    const int m0 = blockIdx.y * 128, n0 = blockIdx.x * 128;
    const int t = threadIdx.x, warp = t >> 5, lane = t & 31;
    const int g = lane >> 2, tig = lane & 3;
    const int wm = (warp >> 1) * 64, wn = (warp & 1) * 64;

    float acc[4][8][4];
    gemm_core(A, W, K, m0, n0, As, Bs, acc);

#pragma unroll
    for (int mi = 0; mi < 4; ++mi) {
#pragma unroll
        for (int ni = 0; ni < 8; ++ni) {
            int col = n0 + wn + ni * 8 + 2 * tig;
            float b0v = bias[col], b1v = bias[col + 1];
            int row = m0 + wm + mi * 16 + g;
            float2 v0 = make_float2(acc[mi][ni][0] + b0v, acc[mi][ni][1] + b1v);
            float2 v1 = make_float2(acc[mi][ni][2] + b0v, acc[mi][ni][3] + b1v);
            if (relu) {
                v0.x = fmaxf(v0.x, 0.f); v0.y = fmaxf(v0.y, 0.f);
                v1.x = fmaxf(v1.x, 0.f); v1.y = fmaxf(v1.y, 0.f);
            }
            if (Cf) {
                *(float2*)(Cf + (size_t)row * N + col)       = v0;
                *(float2*)(Cf + (size_t)(row + 8) * N + col) = v1;
            }
            if (Cb) {
                *(__nv_bfloat162*)(Cb + (size_t)row * N + col) =
                    __floats2bfloat162_rn(v0.x, v0.y);
                *(__nv_bfloat162*)(Cb + (size_t)(row + 8) * N + col) =
                    __floats2bfloat162_rn(v1.x, v1.y);
            }
        }
    }
}

// ---------------------------------------------------------------------------
// GEMM + residual + LayerNorm, M-tile 64 (3 CTAs/SM -> capacity 444 tiles).
// N == 128.  Yout = LN(res + A@W^T + bias) * lng + lnb; Ybf bf16 shadow.
// gather != 0: residual row comes from packed g_Y via last-token index map;
// otherwise residual row n of Rres. Output row n of Yout/Ybf (compact).
// ---------------------------------------------------------------------------
#define TILE_A64 (64 * SSTR)
#define GEMM_SMEM_LN64 (3 * (TILE_A64 + TILE) * 2 + 1024)

__global__ __launch_bounds__(128, 3) void gemm_ln64(
    const __nv_bfloat16* __restrict__ A, const __nv_bfloat16* __restrict__ W,
    const float* __restrict__ bias, const float* __restrict__ lng,
    const float* __restrict__ lnb, const float* __restrict__ Rres,
    float* __restrict__ Yout, __nv_bfloat16* __restrict__ Ybf,
    int K, int gather)
{
    extern __shared__ __align__(16) char dyn[];
    __nv_bfloat16* As = (__nv_bfloat16*)dyn;                  // 3 x 64 x SSTR
    __nv_bfloat16* Bs = As + 3 * TILE_A64;                    // 3 x 128 x SSTR
    float* redS = (float*)(dyn + 3 * (TILE_A64 + TILE) * 2);  // [2][64]
    float* redQ = redS + 128;                                 // [2][64]

    const int m0 = blockIdx.y * 64;
    const int t = threadIdx.x, warp = t >> 5, lane = t & 31;
    const int g = lane >> 2, tig = lane & 3;
    const int wm = (warp >> 1) * 32, wn = (warp & 1) * 64;
    const int cw = warp & 1;
    const int xr = lane & 15, xc = (lane >> 4) * 8;

    float acc[2][8][4];
#pragma unroll
    for (int i = 0; i < 2; ++i)
#pragma unroll
        for (int j = 0; j < 8; ++j)
#pragma unroll
            for (int k = 0; k < 4; ++k) acc[i][j][k] = 0.f;

    auto issue = [&](int k0, int st) {
        __nv_bfloat16* as = As + st * TILE_A64;
        __nv_bfloat16* bs = Bs + st * TILE;
#pragma unroll
        for (int r = 0; r < 6; ++r) {
            int idx = t + r * 128;            // 0..767
            if (idx < 256) {
                int row = idx >> 2, c8 = (idx & 3) * 8;
                asm volatile("cp.async.cg.shared.global [%0], [%1], 16;"
                    :: "r"(smem_u32(as + row * SSTR + c8)),
                       "l"(A + (size_t)(m0 + row) * K + k0 + c8));
            } else {
                int rem = idx - 256;
                int row = rem >> 2, c8 = (rem & 3) * 8;
                asm volatile("cp.async.cg.shared.global [%0], [%1], 16;"
                    :: "r"(smem_u32(bs + row * SSTR + c8)),
                       "l"(W + (size_t)row * K + k0 + c8));
            }
        }
        asm volatile("cp.async.commit_group;");
    };

    const int KT = K >> 5;
    issue(0, 0);
    issue(32, 1);
    for (int kt = 0; kt < KT; ++kt) {
        if (kt + 1 < KT) { asm volatile("cp.async.wait_group 1;"); }
        else             { asm volatile("cp.async.wait_group 0;"); }
        __syncthreads();
        if (kt + 2 < KT) issue((kt + 2) << 5, (kt + 2) % 3);

        const __nv_bfloat16* as = As + (kt % 3) * TILE_A64;
        const __nv_bfloat16* bs = Bs + (kt % 3) * TILE;
#pragma unroll
        for (int si = 0; si < 2; ++si) {
            int ks = si * 16;
            uint32_t af[2][4];
#pragma unroll
            for (int mi = 0; mi < 2; ++mi) {
                uint32_t ad = smem_u32(&as[(wm + mi * 16 + xr) * SSTR + ks + xc]);
                asm volatile("ldmatrix.sync.aligned.m8n8.x4.shared.b16 {%0,%1,%2,%3},[%4];"
                    : "=r"(af[mi][0]), "=r"(af[mi][1]), "=r"(af[mi][2]), "=r"(af[mi][3])
                    : "r"(ad));
            }
            uint32_t bfr[8][2];
#pragma unroll
            for (int np = 0; np < 4; ++np) {
                uint32_t bd = smem_u32(&bs[(wn + np * 16 + xr) * SSTR + ks + xc]);
                uint32_t r0, r1, r2, r3;
                asm volatile("ldmatrix.sync.aligned.m8n8.x4.shared.b16 {%0,%1,%2,%3},[%4];"
                    : "=r"(r0), "=r"(r1), "=r"(r2), "=r"(r3) : "r"(bd));
                bfr[2 * np][0] = r0; bfr[2 * np + 1][0] = r1;
                bfr[2 * np][1] = r2; bfr[2 * np + 1][1] = r3;
            }
#pragma unroll
            for (int mi = 0; mi < 2; ++mi)
#pragma unroll
                for (int ni = 0; ni < 8; ++ni) {
                    asm volatile(
                        "mma.sync.aligned.m16n8k16.row.col.f32.bf16.bf16.f32 "
                        "{%0,%1,%2,%3},{%4,%5,%6,%7},{%8,%9},{%0,%1,%2,%3};"
                        : "+f"(acc[mi][ni][0]), "+f"(acc[mi][ni][1]),
                          "+f"(acc[mi][ni][2]), "+f"(acc[mi][ni][3])
                        : "r"(af[mi][0]), "r"(af[mi][1]),
                          "r"(af[mi][2]), "r"(af[mi][3]),
                          "r"(bfr[ni][0]), "r"(bfr[ni][1]));
                }
        }
    }

    // residual row address helper
    auto res_row = [&](int n) -> const float* {
        if (gather) {
            int b = n / SEQT, s = n - b * SEQT;
            int src = 64 * s * (s + 1) + b * (s + 1) + s;
            return Rres + (size_t)src * D;
        }
        return Rres + (size_t)n * D;
    };

#pragma unroll
    for (int mi = 0; mi < 2; ++mi) {
        int r0 = wm + mi * 16 + g, r1 = r0 + 8;
        const float* R0 = res_row(m0 + r0);
        const float* R1 = res_row(m0 + r1);
        float s0 = 0.f, q0 = 0.f, s1 = 0.f, q1 = 0.f;
#pragma unroll
        for (int ni = 0; ni < 8; ++ni) {
            int col = wn + ni * 8 + 2 * tig;
            float2 bv = *(const float2*)(bias + col);
            float2 y0 = *(const float2*)(R0 + col);
            float2 y1 = *(const float2*)(R1 + col);
            float a0 = acc[mi][ni][0] + bv.x + y0.x;
            float a1 = acc[mi][ni][1] + bv.y + y0.y;
            float a2 = acc[mi][ni][2] + bv.x + y1.x;
            float a3 = acc[mi][ni][3] + bv.y + y1.y;
            acc[mi][ni][0] = a0; acc[mi][ni][1] = a1;
            acc[mi][ni][2] = a2; acc[mi][ni][3] = a3;
            s0 += a0 + a1; q0 += a0 * a0 + a1 * a1;
            s1 += a2 + a3; q1 += a2 * a2 + a3 * a3;
        }
#pragma unroll
        for (int o = 1; o <= 2; o <<= 1) {
            s0 += __shfl_xor_sync(0xffffffffu, s0, o);
            q0 += __shfl_xor_sync(0xffffffffu, q0, o);
            s1 += __shfl_xor_sync(0xffffffffu, s1, o);
            q1 += __shfl_xor_sync(0xffffffffu, q1, o);
        }
        if (tig == 0) {
            redS[cw * 64 + r0] = s0; redQ[cw * 64 + r0] = q0;
            redS[cw * 64 + r1] = s1; redQ[cw * 64 + r1] = q1;
        }
    }
    __syncthreads();

#pragma unroll
    for (int mi = 0; mi < 2; ++mi) {
        int r0 = wm + mi * 16 + g, r1 = r0 + 8;
        float S0 = redS[r0] + redS[64 + r0], Q0 = redQ[r0] + redQ[64 + r0];
        float S1 = redS[r1] + redS[64 + r1], Q1 = redQ[r1] + redQ[64 + r1];
        float mu0 = S0 * (1.f / 128.f), mu1 = S1 * (1.f / 128.f);
        float iv0 = rsqrtf(Q0 * (1.f / 128.f) - mu0 * mu0 + 1e-5f);
        float iv1 = rsqrtf(Q1 * (1.f / 128.f) - mu1 * mu1 + 1e-5f);
#pragma unroll
        for (int ni = 0; ni < 8; ++ni) {
            int col = wn + ni * 8 + 2 * tig;
            float2 gv = *(const float2*)(lng + col);
            float2 bv = *(const float2*)(lnb + col);
            float o0 = (acc[mi][ni][0] - mu0) * iv0 * gv.x + bv.x;
            float o1 = (acc[mi][ni][1] - mu0) * iv0 * gv.y + bv.y;
            float o2 = (acc[mi][ni][2] - mu1) * iv1 * gv.x + bv.x;
            float o3 = (acc[mi][ni][3] - mu1) * iv1 * gv.y + bv.y;
            *(float2*)(Yout + (size_t)(m0 + r0) * D + col) = make_float2(o0, o1);
            *(float2*)(Yout + (size_t)(m0 + r1) * D + col) = make_float2(o2, o3);
            *(__nv_bfloat162*)(Ybf + (size_t)(m0 + r0) * D + col) =
                __floats2bfloat162_rn(o0, o1);
            *(__nv_bfloat162*)(Ybf + (size_t)(m0 + r1) * D + col) =
                __floats2bfloat162_rn(o2, o3);
        }
    }
}

// ---------------------------------------------------------------------------
// One-shot fp32 -> bf16 conversion of x + all weights
// ---------------------------------------------------------------------------
#define CVT_TOTAL 2818048
__global__ void cvt_all(const float* __restrict__ x, const float* __restrict__ wfc,
                        const float* __restrict__ qkvw, const float* __restrict__ outw,
                        const float* __restrict__ ff1w, const float* __restrict__ ff2w)
{
    int i = (blockIdx.x * 256 + threadIdx.x) * 4;
    if (i >= CVT_TOTAL) return;
    const float* s; __nv_bfloat16* d; int off;
    if      (i < 1572864) { s = x;    d = g_xbf;     off = i; }
    else if (i < 1638400) { s = wfc;  d = g_wfc_bf;  off = i - 1572864; }
    else if (i < 1736704) { s = qkvw; d = g_qkvw_bf; off = i - 1638400; }
    else if (i < 1769472) { s = outw; d = g_outw_bf; off = i - 1736704; }
    else if (i < 2293760) { s = ff1w; d = g_ff1w_bf; off = i - 1769472; }
    else                  { s = ff2w; d = g_ff2w_bf; off = i - 2293760; }
    float4 v = *(const float4*)(s + off);
    *(__nv_bfloat162*)(d + off)     = __floats2bfloat162_rn(v.x, v.y);
    *(__nv_bfloat162*)(d + off + 2) = __floats2bfloat162_rn(v.z, v.w);
}

// ---------------------------------------------------------------------------
// Scatter h0+PE -> packed fp32 Y; s==23 pass also emits compact bf16 h0p
// ---------------------------------------------------------------------------
__global__ void scatter_kernel()
{
    int n = blockIdx.x;
    int s = 0;
    while (n >= 64 * (s + 1) * (s + 2)) s++;
    int r = n - 64 * s * (s + 1);
    int P = s + 1;
    int b = r / P;
    int t = r - b * P;
    int d = threadIdx.x;
    float freq = expf((float)(d & ~1) * (-9.210340371976184f / 128.f));
    float arg  = (float)t * freq;
    float pe   = (d & 1) ? cosf(arg) : sinf(arg);
    float v = g_h0[(b * SEQT + t) * D + d] + pe;
    g_Y[n * D + d] = v;
    if (s == SEQT - 1)
        g_h0pbf[(b * SEQT + t) * D + d] = __float2bfloat16(v);
}

// ---------------------------------------------------------------------------
// Layer-0 attention: reads compact qkv0, writes packed ctx for all NT tokens.
// ---------------------------------------------------------------------------
__global__ __launch_bounds__(128) void attn0_kernel()
{
    __shared__ float qs[SEQT][DH], ks[SEQT][DH], vs[SEQT][DH];
    __shared__ float ps[4][32];

    int q = blockIdx.x;
    int s = q >> 7;
    int b = q & 127;
    int P = s + 1;
    int dst = 64 * s * (s + 1) + b * P;
    int tid  = threadIdx.x;
    int w    = tid >> 5;
    int lane = tid & 31;

    for (int h = 0; h < NH; ++h) {
        for (int i = tid; i < P * DH; i += 128) {
            int t = i >> 5, dd = i & 31;
            const __nv_bfloat16* row =
                g_qkv0bf + (size_t)(b * SEQT + t) * (3 * D) + h * DH + dd;
            qs[t][dd] = __bfloat162float(row[0]);
            ks[t][dd] = __bfloat162float(row[D]);
            vs[t][dd] = __bfloat162float(row[2 * D]);
        }
        __syncthreads();

        for (int t = w; t < P; t += 4) {
            float sc = -1e30f;
            if (lane < P) {
                float a = 0.f;
#pragma unroll
                for (int dd = 0; dd < DH; ++dd) a += qs[t][dd] * ks[lane][dd];
                sc = a * 0.17677669529663687f;
            }
            float m = sc;
            for (int o = 16; o; o >>= 1) m = fmaxf(m, __shfl_xor_sync(0xffffffffu, m, o));
            float e = (lane < P) ? expf(sc - m) : 0.f;
            float sum = e;
            for (int o = 16; o; o >>= 1) sum += __shfl_xor_sync(0xffffffffu, sum, o);
            ps[w][lane] = e / sum;
            __syncwarp();
            float c = 0.f;
            for (int j = 0; j < P; ++j) c += ps[w][j] * vs[j][lane];
            g_ctxbf[(size_t)(dst + t) * D + h * DH + lane] = __float2bfloat16(c);
            __syncwarp();
        }
        __syncthreads();
    }
}

// ---------------------------------------------------------------------------
// Layer-1 attention, LAST query only. Writes compact ctx_last[b*SEQT+s].
// ---------------------------------------------------------------------------
__global__ __launch_bounds__(128) void attn1_kernel()
{
    __shared__ float qs[NH][DH];
    __shared__ float ps[NH][32];

    int q = blockIdx.x;
    int s = q >> 7;
    int b = q & 127;
    int P = s + 1;
    int base = 64 * s * (s + 1) + b * P;
    int tid  = threadIdx.x;
    int h    = tid >> 5;
    int lane = tid & 31;

    qs[h][lane] = __bfloat162float(
        g_qkvbf[(size_t)(base + s) * (3 * D) + h * DH + lane]);
    __syncthreads();

    float sc = -1e30f;
    if (lane < P) {
        const __nv_bfloat16* krow =
            g_qkvbf + (size_t)(base + lane) * (3 * D) + D + h * DH;
        float a = 0.f;
#pragma unroll
        for (int dd = 0; dd < DH; ++dd) a += qs[h][dd] * __bfloat162float(krow[dd]);
        sc = a * 0.17677669529663687f;
    }
    float m = sc;
    for (int o = 16; o; o >>= 1) m = fmaxf(m, __shfl_xor_sync(0xffffffffu, m, o));
    float e = (lane < P) ? expf(sc - m) : 0.f;
    float sum = e;
    for (int o = 16; o; o >>= 1) sum += __shfl_xor_sync(0xffffffffu, sum, o);
    ps[h][lane] = e / sum;
    __syncwarp();

    float c = 0.f;
    for (int j = 0; j < P; ++j)
        c += ps[h][j] * __bfloat162float(
                 g_qkvbf[(size_t)(base + j) * (3 * D) + 2 * D + h * DH + lane]);
    g_ctxlastbf[(size_t)(b * SEQT + s) * D + h * DH + lane] = __float2bfloat16(c);
}

// ---------------------------------------------------------------------------
// Classifier + log_softmax, reads compact Ylast
// ---------------------------------------------------------------------------
__global__ __launch_bounds__(64) void cls_kernel(
    const float* __restrict__ Wc1, const float* __restrict__ bc1,
    const float* __restrict__ Wc2, const float* __restrict__ bc2,
    float* __restrict__ out)
{
    __shared__ float c1[NC];
    __shared__ float lrow[D];
    int n = blockIdx.x;
    int o = threadIdx.x;

    for (int d = o; d < D; d += NC) lrow[d] = g_Ylast[n * D + d];
    __syncthreads();

    float a = bc1[o];
    for (int d = 0; d < D; ++d) a += lrow[d] * Wc1[o * D + d];
    c1[o] = fmaxf(a, 0.f);
    __syncthreads();

    if (o == 0) {
        float l0 = bc2[0], l1 = bc2[1];
        for (int j = 0; j < NC; ++j) {
            l0 += c1[j] * Wc2[j];
            l1 += c1[j] * Wc2[NC + j];
        }
        float m   = fmaxf(l0, l1);
        float lse = m + logf(expf(l0 - m) + expf(l1 - m));
        out[n * 2 + 0] = l0 - lse;
        out[n * 2 + 1] = l1 - lse;
    }
}

// ---------------------------------------------------------------------------
extern "C" void kernel_launch(void* const* d_in, const int* in_sizes, int n_in,
                              void* d_out, int out_size)
{
    const float* x     = (const float*)d_in[0];
    const float* W_fc  = (const float*)d_in[1];
    const float* b_fc  = (const float*)d_in[2];
    const float* qkv_w = (const float*)d_in[3];
    const float* qkv_b = (const float*)d_in[4];
    const float* out_w = (const float*)d_in[5];
    const float* out_b = (const float*)d_in[6];
    const float* ln1_g = (const float*)d_in[7];
    const float* ln1_b = (const float*)d_in[8];
    const float* ln2_g = (const float*)d_in[9];
    const float* ln2_b = (const float*)d_in[10];
    const float* ff1_w = (const float*)d_in[11];
    const float* ff1_b = (const float*)d_in[12];
    const float* ff2_w = (const float*)d_in[13];
    const float* ff2_b = (const float*)d_in[14];
    const float* Wc1   = (const float*)d_in[15];
    const float* bc1   = (const float*)d_in[16];
    const float* Wc2   = (const float*)d_in[17];
    const float* bc2   = (const float*)d_in[18];

    cudaFuncSetAttribute(gemm_bf16, cudaFuncAttributeMaxDynamicSharedMemorySize,
                         GEMM_SMEM);
    cudaFuncSetAttribute(gemm_ln64, cudaFuncAttributeMaxDynamicSharedMemorySize,
                         GEMM_SMEM_LN64);

    void* p;
    cudaGetSymbolAddress(&p, g_h0);       float* h0    = (float*)p;
    cudaGetSymbolAddress(&p, g_Y);        float* Y     = (float*)p;
    cudaGetSymbolAddress(&p, g_Ylast);    float* Ylast = (float*)p;
    cudaGetSymbolAddress(&p, g_xbf);      __nv_bfloat16* xbf   = (__nv_bfloat16*)p;
    cudaGetSymbolAddress(&p, g_wfc_bf);   __nv_bfloat16* wfcb  = (__nv_bfloat16*)p;
    cudaGetSymbolAddress(&p, g_qkvw_bf);  __nv_bfloat16* qkvwb = (__nv_bfloat16*)p;
    cudaGetSymbolAddress(&p, g_outw_bf);  __nv_bfloat16* outwb = (__nv_bfloat16*)p;
    cudaGetSymbolAddress(&p, g_ff1w_bf);  __nv_bfloat16* ff1wb = (__nv_bfloat16*)p;
    cudaGetSymbolAddress(&p, g_ff2w_bf);  __nv_bfloat16* ff2wb = (__nv_bfloat16*)p;
    cudaGetSymbolAddress(&p, g_h0pbf);    __nv_bfloat16* h0pb  = (__nv_bfloat16*)p;
    cudaGetSymbolAddress(&p, g_qkv0bf);   __nv_bfloat16* qkv0b = (__nv_bfloat16*)p;
    cudaGetSymbolAddress(&p, g_Ybf);      __nv_bfloat16* ybf   = (__nv_bfloat16*)p;
    cudaGetSymbolAddress(&p, g_qkvbf);    __nv_bfloat16* qkvb  = (__nv_bfloat16*)p;
    cudaGetSymbolAddress(&p, g_ctxbf);    __nv_bfloat16* ctxb  = (__nv_bfloat16*)p;
    cudaGetSymbolAddress(&p, g_ctxlastbf);__nv_bfloat16* ctxlb = (__nv_bfloat16*)p;
    cudaGetSymbolAddress(&p, g_Ylastbf);  __nv_bfloat16* ylbf  = (__nv_bfloat16*)p;
    cudaGetSymbolAddress(&p, g_Hbf);      __nv_bfloat16* hbf   = (__nv_bfloat16*)p;

    cvt_all<<<(CVT_TOTAL / 4 + 255) / 256, 256>>>(x, W_fc, qkv_w, out_w, ff1_w, ff2_w);

    // fc: h0 = relu(x @ W_fc^T + b_fc); scatter adds PE, packs Y, emits h0p
    gemm_bf16<<<dim3(1, NBT / 128), 128, GEMM_SMEM>>>(xbf, wfcb, b_fc, h0, nullptr,
                                                      D, DIN, 1);
    scatter_kernel<<<NT, D>>>();

    // ---- layer 0 (full token set; qkv computed once on unique tokens) ----
    gemm_bf16<<<dim3(3, NBT / 128), 128, GEMM_SMEM>>>(
        h0pb, qkvwb, qkv_b, nullptr, qkv0b, 3 * D, D, 0);
    attn0_kernel<<<S_STEPS * BATCH, 128>>>();
    gemm_ln64<<<dim3(1, NT / 64), 128, GEMM_SMEM_LN64>>>(
        ctxb, outwb, out_b, ln1_g, ln1_b, Y, Y, ybf, D, 0);
    gemm_bf16<<<dim3(DFF / 128, NT / 128), 128, GEMM_SMEM>>>(
        ybf, ff1wb, ff1_b, nullptr, hbf, DFF, D, 1);
    gemm_ln64<<<dim3(1, NT / 64), 128, GEMM_SMEM_LN64>>>(
        hbf, ff2wb, ff2_b, ln2_g, ln2_b, Y, Y, ybf, DFF, 0);

    // ---- layer 1 (K/V full; everything else last-token only) ----
    gemm_bf16<<<dim3(3, NT / 128), 128, GEMM_SMEM>>>(
        ybf, qkvwb + (size_t)3 * D * D, qkv_b + 3 * D, nullptr, qkvb, 3 * D, D, 0);
    attn1_kernel<<<S_STEPS * BATCH, 128>>>();
    gemm_ln64<<<dim3(1, NBT / 64), 128, GEMM_SMEM_LN64>>>(
        ctxlb, outwb + (size_t)D * D, out_b + D,
        ln1_g + D, ln1_b + D, Y, Ylast, ylbf, D, 1);
    gemm_bf16<<<dim3(DFF / 128, NBT / 128), 128, GEMM_SMEM>>>(
        ylbf, ff1wb + (size_t)DFF * D, ff1_b + DFF, nullptr, hbf, DFF, D, 1);
    gemm_ln64<<<dim3(1, NBT / 64), 128, GEMM_SMEM_LN64>>>(
        hbf, ff2wb + (size_t)D * DFF, ff2_b + D,
        ln2_g + D, ln2_b + D, Ylast, Ylast, ylbf, DFF, 0);

    cls_kernel<<<NBT, NC>>>(Wc1, bc1, Wc2, bc2, (float*)d_out);
}

// round 11
// speedup vs baseline: 2.2500x; 1.0072x over previous
#include <cuda_runtime.h>
#include <cuda_bf16.h>
#include <math.h>
#include <stdint.h>

// Problem constants
#define S_STEPS 24
#define BATCH   128
#define SEQT    24
#define DIN     512
#define D       128
#define DFF     2048
#define NH      4
#define DH      32
#define NC      64
#define NT      38400  // BATCH * S*(S+1)/2
#define NBT     3072   // BATCH*SEQT
#define KVS     256    // layer-1 kv row stride

// fp32 scratch
__device__ float g_h0[NBT * D];
__device__ float g_Y[NT * D];
__device__ float g_Ylast[NBT * D];
__device__ float g_part[2ull * NT * D];   // split-K partials for ff2 l0

// bf16 buffers
__device__ __nv_bfloat16 g_xbf[NBT * DIN];
__device__ __nv_bfloat16 g_wfc_bf[D * DIN];
__device__ __nv_bfloat16 g_qkvw_bf[2 * 3 * D * D];
__device__ __nv_bfloat16 g_outw_bf[2 * D * D];
__device__ __nv_bfloat16 g_ff1w_bf[2 * DFF * D];
__device__ __nv_bfloat16 g_ff2w_bf[2 * D * DFF];
__device__ __nv_bfloat16 g_h0pbf[NBT * D];
__device__ __nv_bfloat16 g_qkv0bf[NBT * 3 * D];
__device__ __nv_bfloat16 g_Ybf[NT * D];
__device__ __nv_bfloat16 g_kv1bf[NT * KVS];        // layer-1 K|V (stride 256)
__device__ __nv_bfloat16 g_q1bf[NBT * D];          // layer-1 Q, last tokens
__device__ __nv_bfloat16 g_ylast0bf[NBT * D];      // Y_l0 at last tokens
__device__ __nv_bfloat16 g_ctxbf[NT * D];
__device__ __nv_bfloat16 g_ctxlastbf[NBT * D];
__device__ __nv_bfloat16 g_Ylastbf[NBT * D];
__device__ __nv_bfloat16 g_Hbf[(size_t)NT * DFF];

__device__ __forceinline__ uint32_t smem_u32(const void* p) {
    return (uint32_t)__cvta_generic_to_shared(p);
}

// ---------------------------------------------------------------------------
// bf16 GEMM core (M-tile 128): BK=32, 128 threads (4 warps 2x2, warp 64x64),
// 3-stage cp.async, ldmatrix, m16n8k16. A[M,K], W[N,K] row-major. K%32==0.
// ---------------------------------------------------------------------------
#define SSTR 40
#define TILE (128 * SSTR)
#define GEMM_SMEM  (3 * TILE * 2 * 2)

__device__ __forceinline__ void gemm_core(
    const __nv_bfloat16* __restrict__ A, const __nv_bfloat16* __restrict__ W,
    int K, int m0, int n0, __nv_bfloat16* As, __nv_bfloat16* Bs,
    float (&acc)[4][8][4])
{
    const int t = threadIdx.x, warp = t >> 5, lane = t & 31;
    const int wm = (warp >> 1) * 64, wn = (warp & 1) * 64;
    const int xr = lane & 15, xc = (lane >> 4) * 8;

#pragma unroll
    for (int i = 0; i < 4; ++i)
#pragma unroll
        for (int j = 0; j < 8; ++j)
#pragma unroll
            for (int k = 0; k < 4; ++k) acc[i][j][k] = 0.f;

    auto issue = [&](int k0, int st) {
        __nv_bfloat16* as = As + st * TILE;
        __nv_bfloat16* bs = Bs + st * TILE;
#pragma unroll
        for (int r = 0; r < 8; ++r) {
            int idx = t + r * 128;
            int op  = idx >> 9;
            int rem = idx & 511;
            int row = rem >> 2, c8 = (rem & 3) * 8;
            uint32_t dst = smem_u32((op ? bs : as) + row * SSTR + c8);
            const __nv_bfloat16* src = op
                ? (W + (size_t)(n0 + row) * K + k0 + c8)
                : (A + (size_t)(m0 + row) * K + k0 + c8);
            asm volatile("cp.async.cg.shared.global [%0], [%1], 16;"
                :: "r"(dst), "l"(src));
        }
        asm volatile("cp.async.commit_group;");
    };

    const int KT = K >> 5;
    issue(0, 0);
    issue(32, 1);
    for (int kt = 0; kt < KT; ++kt) {
        if (kt + 1 < KT) { asm volatile("cp.async.wait_group 1;"); }
        else             { asm volatile("cp.async.wait_group 0;"); }
        __syncthreads();
        if (kt + 2 < KT) issue((kt + 2) << 5, (kt + 2) % 3);

        const __nv_bfloat16* as = As + (kt % 3) * TILE;
        const __nv_bfloat16* bs = Bs + (kt % 3) * TILE;

        uint32_t af[2][4][4];
        uint32_t bfr[2][8][2];
#pragma unroll
        for (int si = 0; si < 2; ++si) {
            int ks = si * 16;
#pragma unroll
            for (int mi = 0; mi < 4; ++mi) {
                uint32_t ad = smem_u32(&as[(wm + mi * 16 + xr) * SSTR + ks + xc]);
                asm volatile("ldmatrix.sync.aligned.m8n8.x4.shared.b16 {%0,%1,%2,%3},[%4];"
                    : "=r"(af[si][mi][0]), "=r"(af[si][mi][1]),
                      "=r"(af[si][mi][2]), "=r"(af[si][mi][3])
                    : "r"(ad));
            }
#pragma unroll
            for (int np = 0; np < 4; ++np) {
                uint32_t bd = smem_u32(&bs[(wn + np * 16 + xr) * SSTR + ks + xc]);
                uint32_t r0, r1, r2, r3;
                asm volatile("ldmatrix.sync.aligned.m8n8.x4.shared.b16 {%0,%1,%2,%3},[%4];"
                    : "=r"(r0), "=r"(r1), "=r"(r2), "=r"(r3) : "r"(bd));
                bfr[si][2 * np][0] = r0; bfr[si][2 * np + 1][0] = r1;
                bfr[si][2 * np][1] = r2; bfr[si][2 * np + 1][1] = r3;
            }
        }
#pragma unroll
        for (int si = 0; si < 2; ++si)
#pragma unroll
            for (int mi = 0; mi < 4; ++mi)
#pragma unroll
                for (int ni = 0; ni < 8; ++ni) {
                    asm volatile(
                        "mma.sync.aligned.m16n8k16.row.col.f32.bf16.bf16.f32 "
                        "{%0,%1,%2,%3},{%4,%5,%6,%7},{%8,%9},{%0,%1,%2,%3};"
                        : "+f"(acc[mi][ni][0]), "+f"(acc[mi][ni][1]),
                          "+f"(acc[mi][ni][2]), "+f"(acc[mi][ni][3])
                        : "r"(af[si][mi][0]), "r"(af[si][mi][1]),
                          "r"(af[si][mi][2]), "r"(af[si][mi][3]),
                          "r"(bfr[si][ni][0]), "r"(bfr[si][ni][1]));
                }
    }
}

// ---------------------------------------------------------------------------
// Plain GEMM (M-tile 128): C = A @ W^T + bias, optional ReLU
// ---------------------------------------------------------------------------
__global__ __launch_bounds__(128, 2) void gemm_bf16(
    const __nv_bfloat16* __restrict__ A, const __nv_bfloat16* __restrict__ W,
    const float* __restrict__ bias, float* __restrict__ Cf,
    __nv_bfloat16* __restrict__ Cb, int N, int K, int relu)
{
    extern __shared__ __align__(16) char dyn[];
    __nv_bfloat16* As = (__nv_bfloat16*)dyn;
    __nv_bfloat16* Bs = As + 3 * TILE;

    const int m0 = blockIdx.y * 128, n0 = blockIdx.x * 128;
    const int t = threadIdx.x, warp = t >> 5, lane = t & 31;
    const int g = lane >> 2, tig = lane & 3;
    const int wm = (warp >> 1) * 64, wn = (warp & 1) * 64;

    float acc[4][8][4];
    gemm_core(A, W, K, m0, n0, As, Bs, acc);

#pragma unroll
    for (int mi = 0; mi < 4; ++mi) {
#pragma unroll
        for (int ni = 0; ni < 8; ++ni) {
            int col = n0 + wn + ni * 8 + 2 * tig;
            float b0v = bias[col], b1v = bias[col + 1];
            int row = m0 + wm + mi * 16 + g;
            float2 v0 = make_float2(acc[mi][ni][0] + b0v, acc[mi][ni][1] + b1v);
            float2 v1 = make_float2(acc[mi][ni][2] + b0v, acc[mi][ni][3] + b1v);
            if (relu) {
                v0.x = fmaxf(v0.x, 0.f); v0.y = fmaxf(v0.y, 0.f);
                v1.x = fmaxf(v1.x, 0.f); v1.y = fmaxf(v1.y, 0.f);
            }
            if (Cf) {
                *(float2*)(Cf + (size_t)row * N + col)       = v0;
                *(float2*)(Cf + (size_t)(row + 8) * N + col) = v1;
            }
            if (Cb) {
                *(__nv_bfloat162*)(Cb + (size_t)row * N + col) =
                    __floats2bfloat162_rn(v0.x, v0.y);
                *(__nv_bfloat162*)(Cb + (size_t)(row + 8) * N + col) =
                    __floats2bfloat162_rn(v1.x, v1.y);
            }
        }
    }
}

// ---------------------------------------------------------------------------
// GEMM + residual + LayerNorm, M-tile 64 (3 CTAs/SM). N == 128.
// gather != 0: residual row via last-token index map into packed Rres.
// ---------------------------------------------------------------------------
#define TILE_A64 (64 * SSTR)
#define GEMM_SMEM_LN64 (3 * (TILE_A64 + TILE) * 2 + 1024)

__global__ __launch_bounds__(128, 3) void gemm_ln64(
    const __nv_bfloat16* __restrict__ A, const __nv_bfloat16* __restrict__ W,
    const float* __restrict__ bias, const float* __restrict__ lng,
    const float* __restrict__ lnb, const float* __restrict__ Rres,
    float* __restrict__ Yout, __nv_bfloat16* __restrict__ Ybf,
    int K, int gather)
{
    extern __shared__ __align__(16) char dyn[];
    __nv_bfloat16* As = (__nv_bfloat16*)dyn;
    __nv_bfloat16* Bs = As + 3 * TILE_A64;
    float* redS = (float*)(dyn + 3 * (TILE_A64 + TILE) * 2);  // [2][64]
    float* redQ = redS + 128;                                 // [2][64]

    const int m0 = blockIdx.y * 64;
    const int t = threadIdx.x, warp = t >> 5, lane = t & 31;
    const int g = lane >> 2, tig = lane & 3;
    const int wm = (warp >> 1) * 32, wn = (warp & 1) * 64;
    const int cw = warp & 1;
    const int xr = lane & 15, xc = (lane >> 4) * 8;

    float acc[2][8][4];
#pragma unroll
    for (int i = 0; i < 2; ++i)
#pragma unroll
        for (int j = 0; j < 8; ++j)
#pragma unroll
            for (int k = 0; k < 4; ++k) acc[i][j][k] = 0.f;

    auto issue = [&](int k0, int st) {
        __nv_bfloat16* as = As + st * TILE_A64;
        __nv_bfloat16* bs = Bs + st * TILE;
#pragma unroll
        for (int r = 0; r < 6; ++r) {
            int idx = t + r * 128;
            if (idx < 256) {
                int row = idx >> 2, c8 = (idx & 3) * 8;
                asm volatile("cp.async.cg.shared.global [%0], [%1], 16;"
                    :: "r"(smem_u32(as + row * SSTR + c8)),
                       "l"(A + (size_t)(m0 + row) * K + k0 + c8));
            } else {
                int rem = idx - 256;
                int row = rem >> 2, c8 = (rem & 3) * 8;
                asm volatile("cp.async.cg.shared.global [%0], [%1], 16;"
                    :: "r"(smem_u32(bs + row * SSTR + c8)),
                       "l"(W + (size_t)row * K + k0 + c8));
            }
        }
        asm volatile("cp.async.commit_group;");
    };

    const int KT = K >> 5;
    issue(0, 0);
    issue(32, 1);
    for (int kt = 0; kt < KT; ++kt) {
        if (kt + 1 < KT) { asm volatile("cp.async.wait_group 1;"); }
        else             { asm volatile("cp.async.wait_group 0;"); }
        __syncthreads();
        if (kt + 2 < KT) issue((kt + 2) << 5, (kt + 2) % 3);

        const __nv_bfloat16* as = As + (kt % 3) * TILE_A64;
        const __nv_bfloat16* bs = Bs + (kt % 3) * TILE;
#pragma unroll
        for (int si = 0; si < 2; ++si) {
            int ks = si * 16;
            uint32_t af[2][4];
#pragma unroll
            for (int mi = 0; mi < 2; ++mi) {
                uint32_t ad = smem_u32(&as[(wm + mi * 16 + xr) * SSTR + ks + xc]);
                asm volatile("ldmatrix.sync.aligned.m8n8.x4.shared.b16 {%0,%1,%2,%3},[%4];"
                    : "=r"(af[mi][0]), "=r"(af[mi][1]), "=r"(af[mi][2]), "=r"(af[mi][3])
                    : "r"(ad));
            }
            uint32_t bfr[8][2];
#pragma unroll
            for (int np = 0; np < 4; ++np) {
                uint32_t bd = smem_u32(&bs[(wn + np * 16 + xr) * SSTR + ks + xc]);
                uint32_t r0, r1, r2, r3;
                asm volatile("ldmatrix.sync.aligned.m8n8.x4.shared.b16 {%0,%1,%2,%3},[%4];"
                    : "=r"(r0), "=r"(r1), "=r"(r2), "=r"(r3) : "r"(bd));
                bfr[2 * np][0] = r0; bfr[2 * np + 1][0] = r1;
                bfr[2 * np][1] = r2; bfr[2 * np + 1][1] = r3;
            }
#pragma unroll
            for (int mi = 0; mi < 2; ++mi)
#pragma unroll
                for (int ni = 0; ni < 8; ++ni) {
                    asm volatile(
                        "mma.sync.aligned.m16n8k16.row.col.f32.bf16.bf16.f32 "
                        "{%0,%1,%2,%3},{%4,%5,%6,%7},{%8,%9},{%0,%1,%2,%3};"
                        : "+f"(acc[mi][ni][0]), "+f"(acc[mi][ni][1]),
                          "+f"(acc[mi][ni][2]), "+f"(acc[mi][ni][3])
                        : "r"(af[mi][0]), "r"(af[mi][1]),
                          "r"(af[mi][2]), "r"(af[mi][3]),
                          "r"(bfr[ni][0]), "r"(bfr[ni][1]));
                }
        }
    }

    auto res_row = [&](int n) -> const float* {
        if (gather) {
            int b = n / SEQT, s = n - b * SEQT;
            int src = 64 * s * (s + 1) + b * (s + 1) + s;
            return Rres + (size_t)src * D;
        }
        return Rres + (size_t)n * D;
    };

#pragma unroll
    for (int mi = 0; mi < 2; ++mi) {
        int r0 = wm + mi * 16 + g, r1 = r0 + 8;
        const float* R0 = res_row(m0 + r0);
        const float* R1 = res_row(m0 + r1);
        float s0 = 0.f, q0 = 0.f, s1 = 0.f, q1 = 0.f;
#pragma unroll
        for (int ni = 0; ni < 8; ++ni) {
            int col = wn + ni * 8 + 2 * tig;
            float2 bv = *(const float2*)(bias + col);
            float2 y0 = *(const float2*)(R0 + col);
            float2 y1 = *(const float2*)(R1 + col);
            float a0 = acc[mi][ni][0] + bv.x + y0.x;
            float a1 = acc[mi][ni][1] + bv.y + y0.y;
            float a2 = acc[mi][ni][2] + bv.x + y1.x;
            float a3 = acc[mi][ni][3] + bv.y + y1.y;
            acc[mi][ni][0] = a0; acc[mi][ni][1] = a1;
            acc[mi][ni][2] = a2; acc[mi][ni][3] = a3;
            s0 += a0 + a1; q0 += a0 * a0 + a1 * a1;
            s1 += a2 + a3; q1 += a2 * a2 + a3 * a3;
        }
#pragma unroll
        for (int o = 1; o <= 2; o <<= 1) {
            s0 += __shfl_xor_sync(0xffffffffu, s0, o);
            q0 += __shfl_xor_sync(0xffffffffu, q0, o);
            s1 += __shfl_xor_sync(0xffffffffu, s1, o);
            q1 += __shfl_xor_sync(0xffffffffu, q1, o);
        }
        if (tig == 0) {
            redS[cw * 64 + r0] = s0; redQ[cw * 64 + r0] = q0;
            redS[cw * 64 + r1] = s1; redQ[cw * 64 + r1] = q1;
        }
    }
    __syncthreads();

#pragma unroll
    for (int mi = 0; mi < 2; ++mi) {
        int r0 = wm + mi * 16 + g, r1 = r0 + 8;
        float S0 = redS[r0] + redS[64 + r0], Q0 = redQ[r0] + redQ[64 + r0];
        float S1 = redS[r1] + redS[64 + r1], Q1 = redQ[r1] + redQ[64 + r1];
        float mu0 = S0 * (1.f / 128.f), mu1 = S1 * (1.f / 128.f);
        float iv0 = rsqrtf(Q0 * (1.f / 128.f) - mu0 * mu0 + 1e-5f);
        float iv1 = rsqrtf(Q1 * (1.f / 128.f) - mu1 * mu1 + 1e-5f);
#pragma unroll
        for (int ni = 0; ni < 8; ++ni) {
            int col = wn + ni * 8 + 2 * tig;
            float2 gv = *(const float2*)(lng + col);
            float2 bv = *(const float2*)(lnb + col);
            float o0 = (acc[mi][ni][0] - mu0) * iv0 * gv.x + bv.x;
            float o1 = (acc[mi][ni][1] - mu0) * iv0 * gv.y + bv.y;
            float o2 = (acc[mi][ni][2] - mu1) * iv1 * gv.x + bv.x;
            float o3 = (acc[mi][ni][3] - mu1) * iv1 * gv.y + bv.y;
            *(float2*)(Yout + (size_t)(m0 + r0) * D + col) = make_float2(o0, o1);
            *(float2*)(Yout + (size_t)(m0 + r1) * D + col) = make_float2(o2, o3);
            *(__nv_bfloat162*)(Ybf + (size_t)(m0 + r0) * D + col) =
                __floats2bfloat162_rn(o0, o1);
            *(__nv_bfloat162*)(Ybf + (size_t)(m0 + r1) * D + col) =
                __floats2bfloat162_rn(o2, o3);
        }
    }
}

// ---------------------------------------------------------------------------
// Split-K partial GEMM, M-tile 64, N=128, fp32 partial out (no bias).
// blockIdx.z = K-part (parts of Kpart each); ld = full row stride.
// ---------------------------------------------------------------------------
#define GEMM_SMEM_P64 (3 * (TILE_A64 + TILE) * 2)

__global__ __launch_bounds__(128, 3) void gemm_part64(
    const __nv_bfloat16* __restrict__ A, const __nv_bfloat16* __restrict__ W,
    float* __restrict__ P, int ld, int Kpart, int Mtot)
{
    extern __shared__ __align__(16) char dyn[];
    __nv_bfloat16* As = (__nv_bfloat16*)dyn;
    __nv_bfloat16* Bs = As + 3 * TILE_A64;

    const int m0 = blockIdx.y * 64;
    const int part = blockIdx.z;
    A += (size_t)part * Kpart;
    W += (size_t)part * Kpart;
    P += (size_t)part * Mtot * D;

    const int t = threadIdx.x, warp = t >> 5, lane = t & 31;
    const int g = lane >> 2, tig = lane & 3;
    const int wm = (warp >> 1) * 32, wn = (warp & 1) * 64;
    const int xr = lane & 15, xc = (lane >> 4) * 8;

    float acc[2][8][4];
#pragma unroll
    for (int i = 0; i < 2; ++i)
#pragma unroll
        for (int j = 0; j < 8; ++j)
#pragma unroll
            for (int k = 0; k < 4; ++k) acc[i][j][k] = 0.f;

    auto issue = [&](int k0, int st) {
        __nv_bfloat16* as = As + st * TILE_A64;
        __nv_bfloat16* bs = Bs + st * TILE;
#pragma unroll
        for (int r = 0; r < 6; ++r) {
            int idx = t + r * 128;
            if (idx < 256) {
                int row = idx >> 2, c8 = (idx & 3) * 8;
                asm volatile("cp.async.cg.shared.global [%0], [%1], 16;"
                    :: "r"(smem_u32(as + row * SSTR + c8)),
                       "l"(A + (size_t)(m0 + row) * ld + k0 + c8));
            } else {
                int rem = idx - 256;
                int row = rem >> 2, c8 = (rem & 3) * 8;
                asm volatile("cp.async.cg.shared.global [%0], [%1], 16;"
                    :: "r"(smem_u32(bs + row * SSTR + c8)),
                       "l"(W + (size_t)row * ld + k0 + c8));
            }
        }
        asm volatile("cp.async.commit_group;");
    };

    const int KT = Kpart >> 5;
    issue(0, 0);
    issue(32, 1);
    for (int kt = 0; kt < KT; ++kt) {
        if (kt + 1 < KT) { asm volatile("cp.async.wait_group 1;"); }
        else             { asm volatile("cp.async.wait_group 0;"); }
        __syncthreads();
        if (kt + 2 < KT) issue((kt + 2) << 5, (kt + 2) % 3);

        const __nv_bfloat16* as = As + (kt % 3) * TILE_A64;
        const __nv_bfloat16* bs = Bs + (kt % 3) * TILE;
#pragma unroll
        for (int si = 0; si < 2; ++si) {
            int ks = si * 16;
            uint32_t af[2][4];
#pragma unroll
            for (int mi = 0; mi < 2; ++mi) {
                uint32_t ad = smem_u32(&as[(wm + mi * 16 + xr) * SSTR + ks + xc]);
                asm volatile("ldmatrix.sync.aligned.m8n8.x4.shared.b16 {%0,%1,%2,%3},[%4];"
                    : "=r"(af[mi][0]), "=r"(af[mi][1]), "=r"(af[mi][2]), "=r"(af[mi][3])
                    : "r"(ad));
            }
            uint32_t bfr[8][2];
#pragma unroll
            for (int np = 0; np < 4; ++np) {
                uint32_t bd = smem_u32(&bs[(wn + np * 16 + xr) * SSTR + ks + xc]);
                uint32_t r0, r1, r2, r3;
                asm volatile("ldmatrix.sync.aligned.m8n8.x4.shared.b16 {%0,%1,%2,%3},[%4];"
                    : "=r"(r0), "=r"(r1), "=r"(r2), "=r"(r3) : "r"(bd));
                bfr[2 * np][0] = r0; bfr[2 * np + 1][0] = r1;
                bfr[2 * np][1] = r2; bfr[2 * np + 1][1] = r3;
            }
#pragma unroll
            for (int mi = 0; mi < 2; ++mi)
#pragma unroll
                for (int ni = 0; ni < 8; ++ni) {
                    asm volatile(
                        "mma.sync.aligned.m16n8k16.row.col.f32.bf16.bf16.f32 "
                        "{%0,%1,%2,%3},{%4,%5,%6,%7},{%8,%9},{%0,%1,%2,%3};"
                        : "+f"(acc[mi][ni][0]), "+f"(acc[mi][ni][1]),
                          "+f"(acc[mi][ni][2]), "+f"(acc[mi][ni][3])
                        : "r"(af[mi][0]), "r"(af[mi][1]),
                          "r"(af[mi][2]), "r"(af[mi][3]),
                          "r"(bfr[ni][0]), "r"(bfr[ni][1]));
                }
        }
    }

#pragma unroll
    for (int mi = 0; mi < 2; ++mi) {
        int r0 = wm + mi * 16 + g, r1 = r0 + 8;
#pragma unroll
        for (int ni = 0; ni < 8; ++ni) {
            int col = wn + ni * 8 + 2 * tig;
            *(float2*)(P + (size_t)(m0 + r0) * D + col) =
                make_float2(acc[mi][ni][0], acc[mi][ni][1]);
            *(float2*)(P + (size_t)(m0 + r1) * D + col) =
                make_float2(acc[mi][ni][2], acc[mi][ni][3]);
        }
    }
}

// ---------------------------------------------------------------------------
// Combine split-K partials + residual + LayerNorm (warp per row):
//   Y = LN(Y + P0 + P1 + bias) * lng + lnb ; Ybf shadow
// ---------------------------------------------------------------------------
__global__ __launch_bounds__(128) void ln_combine(
    const float* __restrict__ bias, const float* __restrict__ lng,
    const float* __restrict__ lnb)
{
    int n    = blockIdx.x * 4 + (threadIdx.x >> 5);
    int lane = threadIdx.x & 31;
    float v[4], s = 0.f, q = 0.f;
#pragma unroll
    for (int i = 0; i < 4; ++i) {
        int d = lane + 32 * i;
        size_t off = (size_t)n * D + d;
        v[i] = g_Y[off] + g_part[off] + g_part[(size_t)NT * D + off] + bias[d];
        s += v[i]; q += v[i] * v[i];
    }
    for (int o = 16; o; o >>= 1) {
        s += __shfl_xor_sync(0xffffffffu, s, o);
        q += __shfl_xor_sync(0xffffffffu, q, o);
    }
    float mu = s * (1.f / 128.f);
    float iv = rsqrtf(q * (1.f / 128.f) - mu * mu + 1e-5f);
#pragma unroll
    for (int i = 0; i < 4; ++i) {
        int d = lane + 32 * i;
        size_t off = (size_t)n * D + d;
        float o = (v[i] - mu) * iv * lng[d] + lnb[d];
        g_Y[off]   = o;
        g_Ybf[off] = __float2bfloat16(o);
    }
}

// ---------------------------------------------------------------------------
// One-shot fp32 -> bf16 conversion of x + all weights
// ---------------------------------------------------------------------------
#define CVT_TOTAL 2818048
__global__ void cvt_all(const float* __restrict__ x, const float* __restrict__ wfc,
                        const float* __restrict__ qkvw, const float* __restrict__ outw,
                        const float* __restrict__ ff1w, const float* __restrict__ ff2w)
{
    int i = (blockIdx.x * 256 + threadIdx.x) * 4;
    if (i >= CVT_TOTAL) return;
    const float* s; __nv_bfloat16* d; int off;
    if      (i < 1572864) { s = x;    d = g_xbf;     off = i; }
    else if (i < 1638400) { s = wfc;  d = g_wfc_bf;  off = i - 1572864; }
    else if (i < 1736704) { s = qkvw; d = g_qkvw_bf; off = i - 1638400; }
    else if (i < 1769472) { s = outw; d = g_outw_bf; off = i - 1736704; }
    else if (i < 2293760) { s = ff1w; d = g_ff1w_bf; off = i - 1769472; }
    else                  { s = ff2w; d = g_ff2w_bf; off = i - 2293760; }
    float4 v = *(const float4*)(s + off);
    *(__nv_bfloat162*)(d + off)     = __floats2bfloat162_rn(v.x, v.y);
    *(__nv_bfloat162*)(d + off + 2) = __floats2bfloat162_rn(v.z, v.w);
}

// ---------------------------------------------------------------------------
// Scatter h0+PE -> packed fp32 Y; s==23 pass also emits compact bf16 h0p
// ---------------------------------------------------------------------------
__global__ void scatter_kernel()
{
    int n = blockIdx.x;
    int s = 0;
    while (n >= 64 * (s + 1) * (s + 2)) s++;
    int r = n - 64 * s * (s + 1);
    int P = s + 1;
    int b = r / P;
    int t = r - b * P;
    int d = threadIdx.x;
    float freq = expf((float)(d & ~1) * (-9.210340371976184f / 128.f));
    float arg  = (float)t * freq;
    float pe   = (d & 1) ? cosf(arg) : sinf(arg);
    float v = g_h0[(b * SEQT + t) * D + d] + pe;
    g_Y[n * D + d] = v;
    if (s == SEQT - 1)
        g_h0pbf[(b * SEQT + t) * D + d] = __float2bfloat16(v);
}

// ---------------------------------------------------------------------------
// Layer-0 attention: reads compact qkv0, writes packed ctx for all NT tokens.
// ---------------------------------------------------------------------------
__global__ __launch_bounds__(128) void attn0_kernel()
{
    __shared__ float qs[SEQT][DH], ks[SEQT][DH], vs[SEQT][DH];
    __shared__ float ps[4][32];

    int q = blockIdx.x;
    int s = q >> 7;
    int b = q & 127;
    int P = s + 1;
    int dst = 64 * s * (s + 1) + b * P;
    int tid  = threadIdx.x;
    int w    = tid >> 5;
    int lane = tid & 31;

    for (int h = 0; h < NH; ++h) {
        for (int i = tid; i < P * DH; i += 128) {
            int t = i >> 5, dd = i & 31;
            const __nv_bfloat16* row =
                g_qkv0bf + (size_t)(b * SEQT + t) * (3 * D) + h * DH + dd;
            qs[t][dd] = __bfloat162float(row[0]);
            ks[t][dd] = __bfloat162float(row[D]);
            vs[t][dd] = __bfloat162float(row[2 * D]);
        }
        __syncthreads();

        for (int t = w; t < P; t += 4) {
            float sc = -1e30f;
            if (lane < P) {
                float a = 0.f;
#pragma unroll
                for (int dd = 0; dd < DH; ++dd) a += qs[t][dd] * ks[lane][dd];
                sc = a * 0.17677669529663687f;
            }
            float m = sc;
            for (int o = 16; o; o >>= 1) m = fmaxf(m, __shfl_xor_sync(0xffffffffu, m, o));
            float e = (lane < P) ? expf(sc - m) : 0.f;
            float sum = e;
            for (int o = 16; o; o >>= 1) sum += __shfl_xor_sync(0xffffffffu, sum, o);
            ps[w][lane] = e / sum;
            __syncwarp();
            float c = 0.f;
            for (int j = 0; j < P; ++j) c += ps[w][j] * vs[j][lane];
            g_ctxbf[(size_t)(dst + t) * D + h * DH + lane] = __float2bfloat16(c);
            __syncwarp();
        }
        __syncthreads();
    }
}

// ---------------------------------------------------------------------------
// Gather last-token rows of packed Ybf into compact bf16 ylast0
// ---------------------------------------------------------------------------
__global__ void gather_lastY()
{
    int n = blockIdx.x;              // b*SEQT + s
    int b = n / SEQT;
    int s = n % SEQT;
    int src = 64 * s * (s + 1) + b * (s + 1) + s;
    g_ylast0bf[n * D + threadIdx.x] = g_Ybf[(size_t)src * D + threadIdx.x];
}

// ---------------------------------------------------------------------------
// Layer-1 attention, LAST query only. Q compact, K/V stride-256 packed.
// ---------------------------------------------------------------------------
__global__ __launch_bounds__(128) void attn1_kernel()
{
    __shared__ float qs[NH][DH];
    __shared__ float ps[NH][32];

    int q = blockIdx.x;
    int s = q >> 7;
    int b = q & 127;
    int P = s + 1;
    int base = 64 * s * (s + 1) + b * P;
    int tid  = threadIdx.x;
    int h    = tid >> 5;
    int lane = tid & 31;

    qs[h][lane] = __bfloat162float(
        g_q1bf[(size_t)(b * SEQT + s) * D + h * DH + lane]);
    __syncthreads();

    float sc = -1e30f;
    if (lane < P) {
        const __nv_bfloat16* krow = g_kv1bf + (size_t)(base + lane) * KVS + h * DH;
        float a = 0.f;
#pragma unroll
        for (int dd = 0; dd < DH; ++dd) a += qs[h][dd] * __bfloat162float(krow[dd]);
        sc = a * 0.17677669529663687f;
    }
    float m = sc;
    for (int o = 16; o; o >>= 1) m = fmaxf(m, __shfl_xor_sync(0xffffffffu, m, o));
    float e = (lane < P) ? expf(sc - m) : 0.f;
    float sum = e;
    for (int o = 16; o; o >>= 1) sum += __shfl_xor_sync(0xffffffffu, sum, o);
    ps[h][lane] = e / sum;
    __syncwarp();

    float c = 0.f;
    for (int j = 0; j < P; ++j)
        c += ps[h][j] * __bfloat162float(
                 g_kv1bf[(size_t)(base + j) * KVS + D + h * DH + lane]);
    g_ctxlastbf[(size_t)(b * SEQT + s) * D + h * DH + lane] = __float2bfloat16(c);
}

// ---------------------------------------------------------------------------
// Classifier + log_softmax, reads compact Ylast
// ---------------------------------------------------------------------------
__global__ __launch_bounds__(64) void cls_kernel(
    const float* __restrict__ Wc1, const float* __restrict__ bc1,
    const float* __restrict__ Wc2, const float* __restrict__ bc2,
    float* __restrict__ out)
{
    __shared__ float c1[NC];
    __shared__ float lrow[D];
    int n = blockIdx.x;
    int o = threadIdx.x;

    for (int d = o; d < D; d += NC) lrow[d] = g_Ylast[n * D + d];
    __syncthreads();

    float a = bc1[o];
    for (int d = 0; d < D; ++d) a += lrow[d] * Wc1[o * D + d];
    c1[o] = fmaxf(a, 0.f);
    __syncthreads();

    if (o == 0) {
        float l0 = bc2[0], l1 = bc2[1];
        for (int j = 0; j < NC; ++j) {
            l0 += c1[j] * Wc2[j];
            l1 += c1[j] * Wc2[NC + j];
        }
        float m   = fmaxf(l0, l1);
        float lse = m + logf(expf(l0 - m) + expf(l1 - m));
        out[n * 2 + 0] = l0 - lse;
        out[n * 2 + 1] = l1 - lse;
    }
}

// ---------------------------------------------------------------------------
extern "C" void kernel_launch(void* const* d_in, const int* in_sizes, int n_in,
                              void* d_out, int out_size)
{
    const float* x     = (const float*)d_in[0];
    const float* W_fc  = (const float*)d_in[1];
    const float* b_fc  = (const float*)d_in[2];
    const float* qkv_w = (const float*)d_in[3];
    const float* qkv_b = (const float*)d_in[4];
    const float* out_w = (const float*)d_in[5];
    const float* out_b = (const float*)d_in[6];
    const float* ln1_g = (const float*)d_in[7];
    const float* ln1_b = (const float*)d_in[8];
    const float* ln2_g = (const float*)d_in[9];
    const float* ln2_b = (const float*)d_in[10];
    const float* ff1_w = (const float*)d_in[11];
    const float* ff1_b = (const float*)d_in[12];
    const float* ff2_w = (const float*)d_in[13];
    const float* ff2_b = (const float*)d_in[14];
    const float* Wc1   = (const float*)d_in[15];
    const float* bc1   = (const float*)d_in[16];
    const float* Wc2   = (const float*)d_in[17];
    const float* bc2   = (const float*)d_in[18];

    cudaFuncSetAttribute(gemm_bf16, cudaFuncAttributeMaxDynamicSharedMemorySize,
                         GEMM_SMEM);
    cudaFuncSetAttribute(gemm_ln64, cudaFuncAttributeMaxDynamicSharedMemorySize,
                         GEMM_SMEM_LN64);
    cudaFuncSetAttribute(gemm_part64, cudaFuncAttributeMaxDynamicSharedMemorySize,
                         GEMM_SMEM_P64);

    void* p;
    cudaGetSymbolAddress(&p, g_h0);       float* h0    = (float*)p;
    cudaGetSymbolAddress(&p, g_Y);        float* Y     = (float*)p;
    cudaGetSymbolAddress(&p, g_Ylast);    float* Ylast = (float*)p;
    cudaGetSymbolAddress(&p, g_part);     float* part  = (float*)p;
    cudaGetSymbolAddress(&p, g_xbf);      __nv_bfloat16* xbf   = (__nv_bfloat16*)p;
    cudaGetSymbolAddress(&p, g_wfc_bf);   __nv_bfloat16* wfcb  = (__nv_bfloat16*)p;
    cudaGetSymbolAddress(&p, g_qkvw_bf);  __nv_bfloat16* qkvwb = (__nv_bfloat16*)p;
    cudaGetSymbolAddress(&p, g_outw_bf);  __nv_bfloat16* outwb = (__nv_bfloat16*)p;
    cudaGetSymbolAddress(&p, g_ff1w_bf);  __nv_bfloat16* ff1wb = (__nv_bfloat16*)p;
    cudaGetSymbolAddress(&p, g_ff2w_bf);  __nv_bfloat16* ff2wb = (__nv_bfloat16*)p;
    cudaGetSymbolAddress(&p, g_h0pbf);    __nv_bfloat16* h0pb  = (__nv_bfloat16*)p;
    cudaGetSymbolAddress(&p, g_qkv0bf);   __nv_bfloat16* qkv0b = (__nv_bfloat16*)p;
    cudaGetSymbolAddress(&p, g_Ybf);      __nv_bfloat16* ybf   = (__nv_bfloat16*)p;
    cudaGetSymbolAddress(&p, g_kv1bf);    __nv_bfloat16* kv1b  = (__nv_bfloat16*)p;
    cudaGetSymbolAddress(&p, g_q1bf);     __nv_bfloat16* q1b   = (__nv_bfloat16*)p;
    cudaGetSymbolAddress(&p, g_ylast0bf); __nv_bfloat16* yl0b  = (__nv_bfloat16*)p;
    cudaGetSymbolAddress(&p, g_ctxbf);    __nv_bfloat16* ctxb  = (__nv_bfloat16*)p;
    cudaGetSymbolAddress(&p, g_ctxlastbf);__nv_bfloat16* ctxlb = (__nv_bfloat16*)p;
    cudaGetSymbolAddress(&p, g_Ylastbf);  __nv_bfloat16* ylbf  = (__nv_bfloat16*)p;
    cudaGetSymbolAddress(&p, g_Hbf);      __nv_bfloat16* hbf   = (__nv_bfloat16*)p;

    cvt_all<<<(CVT_TOTAL / 4 + 255) / 256, 256>>>(x, W_fc, qkv_w, out_w, ff1_w, ff2_w);

    // fc: h0 = relu(x @ W_fc^T + b_fc); scatter adds PE, packs Y, emits h0p
    gemm_bf16<<<dim3(1, NBT / 128), 128, GEMM_SMEM>>>(xbf, wfcb, b_fc, h0, nullptr,
                                                      D, DIN, 1);
    scatter_kernel<<<NT, D>>>();

    // ---- layer 0 ----
    gemm_bf16<<<dim3(3, NBT / 128), 128, GEMM_SMEM>>>(
        h0pb, qkvwb, qkv_b, nullptr, qkv0b, 3 * D, D, 0);
    attn0_kernel<<<S_STEPS * BATCH, 128>>>();
    gemm_ln64<<<dim3(1, NT / 64), 128, GEMM_SMEM_LN64>>>(
        ctxb, outwb, out_b, ln1_g, ln1_b, Y, Y, ybf, D, 0);
    gemm_bf16<<<dim3(DFF / 128, NT / 128), 128, GEMM_SMEM>>>(
        ybf, ff1wb, ff1_b, nullptr, hbf, DFF, D, 1);
    // ff2 l0: split-K x2 partials + combine
    gemm_part64<<<dim3(1, NT / 64, 2), 128, GEMM_SMEM_P64>>>(
        hbf, ff2wb, part, DFF, DFF / 2, NT);
    ln_combine<<<NT / 4, 128>>>(ff2_b, ln2_g, ln2_b);

    // ---- layer 1 (K/V full; Q + tail last-token only) ----
    gemm_bf16<<<dim3(2, NT / 128), 128, GEMM_SMEM>>>(
        ybf, qkvwb + (size_t)3 * D * D + (size_t)D * D, qkv_b + 3 * D + D,
        nullptr, kv1b, KVS, D, 0);
    gather_lastY<<<NBT, D>>>();
    gemm_bf16<<<dim3(1, NBT / 128), 128, GEMM_SMEM>>>(
        yl0b, qkvwb + (size_t)3 * D * D, qkv_b + 3 * D, nullptr, q1b, D, D, 0);
    attn1_kernel<<<S_STEPS * BATCH, 128>>>();
    gemm_ln64<<<dim3(1, NBT / 64), 128, GEMM_SMEM_LN64>>>(
        ctxlb, outwb + (size_t)D * D, out_b + D,
        ln1_g + D, ln1_b + D, Y, Ylast, ylbf, D, 1);
    gemm_bf16<<<dim3(DFF / 128, NBT / 128), 128, GEMM_SMEM>>>(
        ylbf, ff1wb + (size_t)DFF * D, ff1_b + DFF, nullptr, hbf, DFF, D, 1);
    gemm_ln64<<<dim3(1, NBT / 64), 128, GEMM_SMEM_LN64>>>(
        hbf, ff2wb + (size_t)D * DFF, ff2_b + D,
        ln2_g + D, ln2_b + D, Ylast, Ylast, ylbf, DFF, 0);

    cls_kernel<<<NBT, NC>>>(Wc1, bc1, Wc2, bc2, (float*)d_out);
}

// round 12
// speedup vs baseline: 2.3570x; 1.0475x over previous
#include <cuda_runtime.h>
#include <cuda_bf16.h>
#include <math.h>
#include <stdint.h>

// Problem constants
#define S_STEPS 24
#define BATCH   128
#define SEQT    24
#define DIN     512
#define D       128
#define DFF     2048
#define NH      4
#define DH      32
#define NC      64
#define NT      38400  // BATCH * S*(S+1)/2
#define NBT     3072   // BATCH*SEQT
#define KVS     256    // layer-1 kv row stride

// fp32 scratch
__device__ float g_h0[NBT * D];
__device__ float g_Y[NT * D];
__device__ float g_Ylast[NBT * D];
__device__ float g_part[2ull * NT * D];   // split-K partials (fc, ff2 l0)

// bf16 buffers
__device__ __nv_bfloat16 g_xbf[NBT * DIN];
__device__ __nv_bfloat16 g_wfc_bf[D * DIN];
__device__ __nv_bfloat16 g_qkvw_bf[2 * 3 * D * D];
__device__ __nv_bfloat16 g_outw_bf[2 * D * D];
__device__ __nv_bfloat16 g_ff1w_bf[2 * DFF * D];
__device__ __nv_bfloat16 g_ff2w_bf[2 * D * DFF];
__device__ __nv_bfloat16 g_h0pbf[NBT * D];
__device__ __nv_bfloat16 g_qkv0bf[NBT * 3 * D];
__device__ __nv_bfloat16 g_Ybf[NT * D];
__device__ __nv_bfloat16 g_kv1bf[NT * KVS];
__device__ __nv_bfloat16 g_q1bf[NBT * D];
__device__ __nv_bfloat16 g_ylast0bf[NBT * D];
__device__ __nv_bfloat16 g_ctxbf[NT * D];
__device__ __nv_bfloat16 g_ctxlastbf[NBT * D];
__device__ __nv_bfloat16 g_Ylastbf[NBT * D];
__device__ __nv_bfloat16 g_Hbf[(size_t)NT * DFF];

__device__ __forceinline__ uint32_t smem_u32(const void* p) {
    return (uint32_t)__cvta_generic_to_shared(p);
}

#define SSTR 40
#define TILE (128 * SSTR)
#define TILE_A64 (64 * SSTR)
#define GEMM_SMEM  (3 * TILE * 2 * 2)
#define GEMM_SMEM_LN64 (3 * (TILE_A64 + TILE) * 2 + 1024)
#define GEMM_SMEM_64   (3 * (TILE_A64 + TILE) * 2)

// ---------------------------------------------------------------------------
// M128 gemm core: 4 warps 2x2, warp 64x64, 3-stage cp.async, m16n8k16
// ---------------------------------------------------------------------------
__device__ __forceinline__ void gemm_core(
    const __nv_bfloat16* __restrict__ A, const __nv_bfloat16* __restrict__ W,
    int K, int m0, int n0, __nv_bfloat16* As, __nv_bfloat16* Bs,
    float (&acc)[4][8][4])
{
    const int t = threadIdx.x, warp = t >> 5, lane = t & 31;
    const int wm = (warp >> 1) * 64, wn = (warp & 1) * 64;
    const int xr = lane & 15, xc = (lane >> 4) * 8;

#pragma unroll
    for (int i = 0; i < 4; ++i)
#pragma unroll
        for (int j = 0; j < 8; ++j)
#pragma unroll
            for (int k = 0; k < 4; ++k) acc[i][j][k] = 0.f;

    auto issue = [&](int k0, int st) {
        __nv_bfloat16* as = As + st * TILE;
        __nv_bfloat16* bs = Bs + st * TILE;
#pragma unroll
        for (int r = 0; r < 8; ++r) {
            int idx = t + r * 128;
            int op  = idx >> 9;
            int rem = idx & 511;
            int row = rem >> 2, c8 = (rem & 3) * 8;
            uint32_t dst = smem_u32((op ? bs : as) + row * SSTR + c8);
            const __nv_bfloat16* src = op
                ? (W + (size_t)(n0 + row) * K + k0 + c8)
                : (A + (size_t)(m0 + row) * K + k0 + c8);
            asm volatile("cp.async.cg.shared.global [%0], [%1], 16;"
                :: "r"(dst), "l"(src));
        }
        asm volatile("cp.async.commit_group;");
    };

    const int KT = K >> 5;
    issue(0, 0);
    issue(32, 1);
    for (int kt = 0; kt < KT; ++kt) {
        if (kt + 1 < KT) { asm volatile("cp.async.wait_group 1;"); }
        else             { asm volatile("cp.async.wait_group 0;"); }
        __syncthreads();
        if (kt + 2 < KT) issue((kt + 2) << 5, (kt + 2) % 3);

        const __nv_bfloat16* as = As + (kt % 3) * TILE;
        const __nv_bfloat16* bs = Bs + (kt % 3) * TILE;

        uint32_t af[2][4][4];
        uint32_t bfr[2][8][2];
#pragma unroll
        for (int si = 0; si < 2; ++si) {
            int ks = si * 16;
#pragma unroll
            for (int mi = 0; mi < 4; ++mi) {
                uint32_t ad = smem_u32(&as[(wm + mi * 16 + xr) * SSTR + ks + xc]);
                asm volatile("ldmatrix.sync.aligned.m8n8.x4.shared.b16 {%0,%1,%2,%3},[%4];"
                    : "=r"(af[si][mi][0]), "=r"(af[si][mi][1]),
                      "=r"(af[si][mi][2]), "=r"(af[si][mi][3])
                    : "r"(ad));
            }
#pragma unroll
            for (int np = 0; np < 4; ++np) {
                uint32_t bd = smem_u32(&bs[(wn + np * 16 + xr) * SSTR + ks + xc]);
                uint32_t r0, r1, r2, r3;
                asm volatile("ldmatrix.sync.aligned.m8n8.x4.shared.b16 {%0,%1,%2,%3},[%4];"
                    : "=r"(r0), "=r"(r1), "=r"(r2), "=r"(r3) : "r"(bd));
                bfr[si][2 * np][0] = r0; bfr[si][2 * np + 1][0] = r1;
                bfr[si][2 * np][1] = r2; bfr[si][2 * np + 1][1] = r3;
            }
        }
#pragma unroll
        for (int si = 0; si < 2; ++si)
#pragma unroll
            for (int mi = 0; mi < 4; ++mi)
#pragma unroll
                for (int ni = 0; ni < 8; ++ni) {
                    asm volatile(
                        "mma.sync.aligned.m16n8k16.row.col.f32.bf16.bf16.f32 "
                        "{%0,%1,%2,%3},{%4,%5,%6,%7},{%8,%9},{%0,%1,%2,%3};"
                        : "+f"(acc[mi][ni][0]), "+f"(acc[mi][ni][1]),
                          "+f"(acc[mi][ni][2]), "+f"(acc[mi][ni][3])
                        : "r"(af[si][mi][0]), "r"(af[si][mi][1]),
                          "r"(af[si][mi][2]), "r"(af[si][mi][3]),
                          "r"(bfr[si][ni][0]), "r"(bfr[si][ni][1]));
                }
    }
}

// ---------------------------------------------------------------------------
// M64 gemm core: 4 warps (2x2), warp 32x64. Used by all M64 kernels.
// ld = row stride of A and W in elements (>= K span used).
// ---------------------------------------------------------------------------
__device__ __forceinline__ void gemm_core64(
    const __nv_bfloat16* __restrict__ A, const __nv_bfloat16* __restrict__ W,
    int ld, int K, int m0, __nv_bfloat16* As, __nv_bfloat16* Bs,
    float (&acc)[2][8][4])
{
    const int t = threadIdx.x, warp = t >> 5, lane = t & 31;
    const int wm = (warp >> 1) * 32, wn = (warp & 1) * 64;
    const int xr = lane & 15, xc = (lane >> 4) * 8;

#pragma unroll
    for (int i = 0; i < 2; ++i)
#pragma unroll
        for (int j = 0; j < 8; ++j)
#pragma unroll
            for (int k = 0; k < 4; ++k) acc[i][j][k] = 0.f;

    auto issue = [&](int k0, int st) {
        __nv_bfloat16* as = As + st * TILE_A64;
        __nv_bfloat16* bs = Bs + st * TILE;
#pragma unroll
        for (int r = 0; r < 6; ++r) {
            int idx = t + r * 128;
            if (idx < 256) {
                int row = idx >> 2, c8 = (idx & 3) * 8;
                asm volatile("cp.async.cg.shared.global [%0], [%1], 16;"
                    :: "r"(smem_u32(as + row * SSTR + c8)),
                       "l"(A + (size_t)(m0 + row) * ld + k0 + c8));
            } else {
                int rem = idx - 256;
                int row = rem >> 2, c8 = (rem & 3) * 8;
                asm volatile("cp.async.cg.shared.global [%0], [%1], 16;"
                    :: "r"(smem_u32(bs + row * SSTR + c8)),
                       "l"(W + (size_t)row * ld + k0 + c8));
            }
        }
        asm volatile("cp.async.commit_group;");
    };

    const int KT = K >> 5;
    issue(0, 0);
    issue(32, 1);
    for (int kt = 0; kt < KT; ++kt) {
        if (kt + 1 < KT) { asm volatile("cp.async.wait_group 1;"); }
        else             { asm volatile("cp.async.wait_group 0;"); }
        __syncthreads();
        if (kt + 2 < KT) issue((kt + 2) << 5, (kt + 2) % 3);

        const __nv_bfloat16* as = As + (kt % 3) * TILE_A64;
        const __nv_bfloat16* bs = Bs + (kt % 3) * TILE;
#pragma unroll
        for (int si = 0; si < 2; ++si) {
            int ks = si * 16;
            uint32_t af[2][4];
#pragma unroll
            for (int mi = 0; mi < 2; ++mi) {
                uint32_t ad = smem_u32(&as[(wm + mi * 16 + xr) * SSTR + ks + xc]);
                asm volatile("ldmatrix.sync.aligned.m8n8.x4.shared.b16 {%0,%1,%2,%3},[%4];"
                    : "=r"(af[mi][0]), "=r"(af[mi][1]), "=r"(af[mi][2]), "=r"(af[mi][3])
                    : "r"(ad));
            }
            uint32_t bfr[8][2];
#pragma unroll
            for (int np = 0; np < 4; ++np) {
                uint32_t bd = smem_u32(&bs[(wn + np * 16 + xr) * SSTR + ks + xc]);
                uint32_t r0, r1, r2, r3;
                asm volatile("ldmatrix.sync.aligned.m8n8.x4.shared.b16 {%0,%1,%2,%3},[%4];"
                    : "=r"(r0), "=r"(r1), "=r"(r2), "=r"(r3) : "r"(bd));
                bfr[2 * np][0] = r0; bfr[2 * np + 1][0] = r1;
                bfr[2 * np][1] = r2; bfr[2 * np + 1][1] = r3;
            }
#pragma unroll
            for (int mi = 0; mi < 2; ++mi)
#pragma unroll
                for (int ni = 0; ni < 8; ++ni) {
                    asm volatile(
                        "mma.sync.aligned.m16n8k16.row.col.f32.bf16.bf16.f32 "
                        "{%0,%1,%2,%3},{%4,%5,%6,%7},{%8,%9},{%0,%1,%2,%3};"
                        : "+f"(acc[mi][ni][0]), "+f"(acc[mi][ni][1]),
                          "+f"(acc[mi][ni][2]), "+f"(acc[mi][ni][3])
                        : "r"(af[mi][0]), "r"(af[mi][1]),
                          "r"(af[mi][2]), "r"(af[mi][3]),
                          "r"(bfr[ni][0]), "r"(bfr[ni][1]));
                }
        }
    }
}

// ---------------------------------------------------------------------------
// Plain GEMM (M128): C = A @ W^T + bias, optional ReLU
// ---------------------------------------------------------------------------
__global__ __launch_bounds__(128, 2) void gemm_bf16(
    const __nv_bfloat16* __restrict__ A, const __nv_bfloat16* __restrict__ W,
    const float* __restrict__ bias, float* __restrict__ Cf,
    __nv_bfloat16* __restrict__ Cb, int N, int K, int relu)
{
    extern __shared__ __align__(16) char dyn[];
    __nv_bfloat16* As = (__nv_bfloat16*)dyn;
    __nv_bfloat16* Bs = As + 3 * TILE;

    const int m0 = blockIdx.y * 128, n0 = blockIdx.x * 128;
    const int t = threadIdx.x, warp = t >> 5, lane = t & 31;
    const int g = lane >> 2, tig = lane & 3;
    const int wm = (warp >> 1) * 64, wn = (warp & 1) * 64;

    float acc[4][8][4];
    gemm_core(A, W, K, m0, n0, As, Bs, acc);

#pragma unroll
    for (int mi = 0; mi < 4; ++mi) {
#pragma unroll
        for (int ni = 0; ni < 8; ++ni) {
            int col = n0 + wn + ni * 8 + 2 * tig;
            float b0v = bias[col], b1v = bias[col + 1];
            int row = m0 + wm + mi * 16 + g;
            float2 v0 = make_float2(acc[mi][ni][0] + b0v, acc[mi][ni][1] + b1v);
            float2 v1 = make_float2(acc[mi][ni][2] + b0v, acc[mi][ni][3] + b1v);
            if (relu) {
                v0.x = fmaxf(v0.x, 0.f); v0.y = fmaxf(v0.y, 0.f);
                v1.x = fmaxf(v1.x, 0.f); v1.y = fmaxf(v1.y, 0.f);
            }
            if (Cf) {
                *(float2*)(Cf + (size_t)row * N + col)       = v0;
                *(float2*)(Cf + (size_t)(row + 8) * N + col) = v1;
            }
            if (Cb) {
                *(__nv_bfloat162*)(Cb + (size_t)row * N + col) =
                    __floats2bfloat162_rn(v0.x, v0.y);
                *(__nv_bfloat162*)(Cb + (size_t)(row + 8) * N + col) =
                    __floats2bfloat162_rn(v1.x, v1.y);
            }
        }
    }
}

// ---------------------------------------------------------------------------
// Plain GEMM (M64): C = A @ W^T + bias, optional ReLU. Grid (N/128, M/64).
// ---------------------------------------------------------------------------
__global__ __launch_bounds__(128, 3) void gemm64(
    const __nv_bfloat16* __restrict__ A, const __nv_bfloat16* __restrict__ W,
    const float* __restrict__ bias, float* __restrict__ Cf,
    __nv_bfloat16* __restrict__ Cb, int N, int K, int relu)
{
    extern __shared__ __align__(16) char dyn[];
    __nv_bfloat16* As = (__nv_bfloat16*)dyn;
    __nv_bfloat16* Bs = As + 3 * TILE_A64;

    const int m0 = blockIdx.y * 64, n0 = blockIdx.x * 128;
    const int t = threadIdx.x, warp = t >> 5, lane = t & 31;
    const int g = lane >> 2, tig = lane & 3;
    const int wm = (warp >> 1) * 32, wn = (warp & 1) * 64;

    float acc[2][8][4];
    gemm_core64(A, W + (size_t)n0 * K, K, K, m0, As, Bs, acc);

#pragma unroll
    for (int mi = 0; mi < 2; ++mi) {
#pragma unroll
        for (int ni = 0; ni < 8; ++ni) {
            int col = n0 + wn + ni * 8 + 2 * tig;
            float b0v = bias[col], b1v = bias[col + 1];
            int row = m0 + wm + mi * 16 + g;
            float2 v0 = make_float2(acc[mi][ni][0] + b0v, acc[mi][ni][1] + b1v);
            float2 v1 = make_float2(acc[mi][ni][2] + b0v, acc[mi][ni][3] + b1v);
            if (relu) {
                v0.x = fmaxf(v0.x, 0.f); v0.y = fmaxf(v0.y, 0.f);
                v1.x = fmaxf(v1.x, 0.f); v1.y = fmaxf(v1.y, 0.f);
            }
            if (Cf) {
                *(float2*)(Cf + (size_t)row * N + col)       = v0;
                *(float2*)(Cf + (size_t)(row + 8) * N + col) = v1;
            }
            if (Cb) {
                *(__nv_bfloat162*)(Cb + (size_t)row * N + col) =
                    __floats2bfloat162_rn(v0.x, v0.y);
                *(__nv_bfloat162*)(Cb + (size_t)(row + 8) * N + col) =
                    __floats2bfloat162_rn(v1.x, v1.y);
            }
        }
    }
}

// ---------------------------------------------------------------------------
// GEMM + residual + LayerNorm, M64. N == 128.
// gather != 0: residual row via last-token index map into packed Rres.
// ---------------------------------------------------------------------------
__global__ __launch_bounds__(128, 3) void gemm_ln64(
    const __nv_bfloat16* __restrict__ A, const __nv_bfloat16* __restrict__ W,
    const float* __restrict__ bias, const float* __restrict__ lng,
    const float* __restrict__ lnb, const float* __restrict__ Rres,
    float* __restrict__ Yout, __nv_bfloat16* __restrict__ Ybf,
    int K, int gather)
{
    extern __shared__ __align__(16) char dyn[];
    __nv_bfloat16* As = (__nv_bfloat16*)dyn;
    __nv_bfloat16* Bs = As + 3 * TILE_A64;
    float* redS = (float*)(dyn + 3 * (TILE_A64 + TILE) * 2);  // [2][64]
    float* redQ = redS + 128;

    const int m0 = blockIdx.y * 64;
    const int t = threadIdx.x, warp = t >> 5, lane = t & 31;
    const int g = lane >> 2, tig = lane & 3;
    const int wm = (warp >> 1) * 32, wn = (warp & 1) * 64;
    const int cw = warp & 1;

    float acc[2][8][4];
    gemm_core64(A, W, K, K, m0, As, Bs, acc);

    auto res_row = [&](int n) -> const float* {
        if (gather) {
            int b = n / SEQT, s = n - b * SEQT;
            int src = 64 * s * (s + 1) + b * (s + 1) + s;
            return Rres + (size_t)src * D;
        }
        return Rres + (size_t)n * D;
    };

#pragma unroll
    for (int mi = 0; mi < 2; ++mi) {
        int r0 = wm + mi * 16 + g, r1 = r0 + 8;
        const float* R0 = res_row(m0 + r0);
        const float* R1 = res_row(m0 + r1);
        float s0 = 0.f, q0 = 0.f, s1 = 0.f, q1 = 0.f;
#pragma unroll
        for (int ni = 0; ni < 8; ++ni) {
            int col = wn + ni * 8 + 2 * tig;
            float2 bv = *(const float2*)(bias + col);
            float2 y0 = *(const float2*)(R0 + col);
            float2 y1 = *(const float2*)(R1 + col);
            float a0 = acc[mi][ni][0] + bv.x + y0.x;
            float a1 = acc[mi][ni][1] + bv.y + y0.y;
            float a2 = acc[mi][ni][2] + bv.x + y1.x;
            float a3 = acc[mi][ni][3] + bv.y + y1.y;
            acc[mi][ni][0] = a0; acc[mi][ni][1] = a1;
            acc[mi][ni][2] = a2; acc[mi][ni][3] = a3;
            s0 += a0 + a1; q0 += a0 * a0 + a1 * a1;
            s1 += a2 + a3; q1 += a2 * a2 + a3 * a3;
        }
#pragma unroll
        for (int o = 1; o <= 2; o <<= 1) {
            s0 += __shfl_xor_sync(0xffffffffu, s0, o);
            q0 += __shfl_xor_sync(0xffffffffu, q0, o);
            s1 += __shfl_xor_sync(0xffffffffu, s1, o);
            q1 += __shfl_xor_sync(0xffffffffu, q1, o);
        }
        if (tig == 0) {
            redS[cw * 64 + r0] = s0; redQ[cw * 64 + r0] = q0;
            redS[cw * 64 + r1] = s1; redQ[cw * 64 + r1] = q1;
        }
    }
    __syncthreads();

#pragma unroll
    for (int mi = 0; mi < 2; ++mi) {
        int r0 = wm + mi * 16 + g, r1 = r0 + 8;
        float S0 = redS[r0] + redS[64 + r0], Q0 = redQ[r0] + redQ[64 + r0];
        float S1 = redS[r1] + redS[64 + r1], Q1 = redQ[r1] + redQ[64 + r1];
        float mu0 = S0 * (1.f / 128.f), mu1 = S1 * (1.f / 128.f);
        float iv0 = rsqrtf(Q0 * (1.f / 128.f) - mu0 * mu0 + 1e-5f);
        float iv1 = rsqrtf(Q1 * (1.f / 128.f) - mu1 * mu1 + 1e-5f);
#pragma unroll
        for (int ni = 0; ni < 8; ++ni) {
            int col = wn + ni * 8 + 2 * tig;
            float2 gv = *(const float2*)(lng + col);
            float2 bv = *(const float2*)(lnb + col);
            float o0 = (acc[mi][ni][0] - mu0) * iv0 * gv.x + bv.x;
            float o1 = (acc[mi][ni][1] - mu0) * iv0 * gv.y + bv.y;
            float o2 = (acc[mi][ni][2] - mu1) * iv1 * gv.x + bv.x;
            float o3 = (acc[mi][ni][3] - mu1) * iv1 * gv.y + bv.y;
            *(float2*)(Yout + (size_t)(m0 + r0) * D + col) = make_float2(o0, o1);
            *(float2*)(Yout + (size_t)(m0 + r1) * D + col) = make_float2(o2, o3);
            *(__nv_bfloat162*)(Ybf + (size_t)(m0 + r0) * D + col) =
                __floats2bfloat162_rn(o0, o1);
            *(__nv_bfloat162*)(Ybf + (size_t)(m0 + r1) * D + col) =
                __floats2bfloat162_rn(o2, o3);
        }
    }
}

// ---------------------------------------------------------------------------
// Split-K partial GEMM, M64, N=128, fp32 partials (no bias). blockIdx.z=part.
// ---------------------------------------------------------------------------
__global__ __launch_bounds__(128, 3) void gemm_part64(
    const __nv_bfloat16* __restrict__ A, const __nv_bfloat16* __restrict__ W,
    float* __restrict__ P, int ld, int Kpart, int Mtot)
{
    extern __shared__ __align__(16) char dyn[];
    __nv_bfloat16* As = (__nv_bfloat16*)dyn;
    __nv_bfloat16* Bs = As + 3 * TILE_A64;

    const int m0 = blockIdx.y * 64;
    const int part = blockIdx.z;
    A += (size_t)part * Kpart;
    W += (size_t)part * Kpart;
    P += (size_t)part * Mtot * D;

    const int t = threadIdx.x, warp = t >> 5, lane = t & 31;
    const int g = lane >> 2, tig = lane & 3;
    const int wm = (warp >> 1) * 32, wn = (warp & 1) * 64;

    float acc[2][8][4];
    gemm_core64(A, W, ld, Kpart, m0, As, Bs, acc);

#pragma unroll
    for (int mi = 0; mi < 2; ++mi) {
        int r0 = wm + mi * 16 + g, r1 = r0 + 8;
#pragma unroll
        for (int ni = 0; ni < 8; ++ni) {
            int col = wn + ni * 8 + 2 * tig;
            *(float2*)(P + (size_t)(m0 + r0) * D + col) =
                make_float2(acc[mi][ni][0], acc[mi][ni][1]);
            *(float2*)(P + (size_t)(m0 + r1) * D + col) =
                make_float2(acc[mi][ni][2], acc[mi][ni][3]);
        }
    }
}

// ---------------------------------------------------------------------------
// fc combine: h0 = relu(P0+P1+P2+P3 + b_fc) + PE(t,d); writes fp32 + bf16
// ---------------------------------------------------------------------------
__global__ void fc_combine(const float* __restrict__ bias)
{
    int i = blockIdx.x * 256 + threadIdx.x;       // 0 .. NBT*D-1
    if (i >= NBT * D) return;
    int n = i >> 7, d = i & 127;
    int t = n % SEQT;
    float v = g_part[i] + g_part[NBT * D + i] + g_part[2 * NBT * D + i]
            + g_part[3 * NBT * D + i] + bias[d];
    v = fmaxf(v, 0.f);
    float freq = expf((float)(d & ~1) * (-9.210340371976184f / 128.f));
    float arg  = (float)t * freq;
    v += (d & 1) ? cosf(arg) : sinf(arg);
    g_h0[i]    = v;
    g_h0pbf[i] = __float2bfloat16(v);
}

// ---------------------------------------------------------------------------
// Combine split-K partials + residual + LayerNorm (ff2 l0)
// ---------------------------------------------------------------------------
__global__ __launch_bounds__(128) void ln_combine(
    const float* __restrict__ bias, const float* __restrict__ lng,
    const float* __restrict__ lnb)
{
    int n    = blockIdx.x * 4 + (threadIdx.x >> 5);
    int lane = threadIdx.x & 31;
    float v[4], s = 0.f, q = 0.f;
#pragma unroll
    for (int i = 0; i < 4; ++i) {
        int d = lane + 32 * i;
        size_t off = (size_t)n * D + d;
        v[i] = g_Y[off] + g_part[off] + g_part[(size_t)NT * D + off] + bias[d];
        s += v[i]; q += v[i] * v[i];
    }
    for (int o = 16; o; o >>= 1) {
        s += __shfl_xor_sync(0xffffffffu, s, o);
        q += __shfl_xor_sync(0xffffffffu, q, o);
    }
    float mu = s * (1.f / 128.f);
    float iv = rsqrtf(q * (1.f / 128.f) - mu * mu + 1e-5f);
#pragma unroll
    for (int i = 0; i < 4; ++i) {
        int d = lane + 32 * i;
        size_t off = (size_t)n * D + d;
        float o = (v[i] - mu) * iv * lng[d] + lnb[d];
        g_Y[off]   = o;
        g_Ybf[off] = __float2bfloat16(o);
    }
}

// ---------------------------------------------------------------------------
// One-shot fp32 -> bf16 conversion of x + all weights
// ---------------------------------------------------------------------------
#define CVT_TOTAL 2818048
__global__ void cvt_all(const float* __restrict__ x, const float* __restrict__ wfc,
                        const float* __restrict__ qkvw, const float* __restrict__ outw,
                        const float* __restrict__ ff1w, const float* __restrict__ ff2w)
{
    int i = (blockIdx.x * 256 + threadIdx.x) * 4;
    if (i >= CVT_TOTAL) return;
    const float* s; __nv_bfloat16* d; int off;
    if      (i < 1572864) { s = x;    d = g_xbf;     off = i; }
    else if (i < 1638400) { s = wfc;  d = g_wfc_bf;  off = i - 1572864; }
    else if (i < 1736704) { s = qkvw; d = g_qkvw_bf; off = i - 1638400; }
    else if (i < 1769472) { s = outw; d = g_outw_bf; off = i - 1736704; }
    else if (i < 2293760) { s = ff1w; d = g_ff1w_bf; off = i - 1769472; }
    else                  { s = ff2w; d = g_ff2w_bf; off = i - 2293760; }
    float4 v = *(const float4*)(s + off);
    *(__nv_bfloat162*)(d + off)     = __floats2bfloat162_rn(v.x, v.y);
    *(__nv_bfloat162*)(d + off + 2) = __floats2bfloat162_rn(v.z, v.w);
}

// ---------------------------------------------------------------------------
// Scatter h0 (PE already applied) -> packed fp32 Y (pure copy)
// ---------------------------------------------------------------------------
__global__ void scatter_kernel()
{
    int n = blockIdx.x;
    int s = 0;
    while (n >= 64 * (s + 1) * (s + 2)) s++;
    int r = n - 64 * s * (s + 1);
    int P = s + 1;
    int b = r / P;
    int t = r - b * P;
    g_Y[n * D + threadIdx.x] = g_h0[(b * SEQT + t) * D + threadIdx.x];
}

// ---------------------------------------------------------------------------
// Layer-0 attention (compact qkv0 -> packed ctx)
// ---------------------------------------------------------------------------
__global__ __launch_bounds__(128) void attn0_kernel()
{
    __shared__ float qs[SEQT][DH], ks[SEQT][DH], vs[SEQT][DH];
    __shared__ float ps[4][32];

    int q = blockIdx.x;
    int s = q >> 7;
    int b = q & 127;
    int P = s + 1;
    int dst = 64 * s * (s + 1) + b * P;
    int tid  = threadIdx.x;
    int w    = tid >> 5;
    int lane = tid & 31;

    for (int h = 0; h < NH; ++h) {
        for (int i = tid; i < P * DH; i += 128) {
            int t = i >> 5, dd = i & 31;
            const __nv_bfloat16* row =
                g_qkv0bf + (size_t)(b * SEQT + t) * (3 * D) + h * DH + dd;
            qs[t][dd] = __bfloat162float(row[0]);
            ks[t][dd] = __bfloat162float(row[D]);
            vs[t][dd] = __bfloat162float(row[2 * D]);
        }
        __syncthreads();

        for (int t = w; t < P; t += 4) {
            float sc = -1e30f;
            if (lane < P) {
                float a = 0.f;
#pragma unroll
                for (int dd = 0; dd < DH; ++dd) a += qs[t][dd] * ks[lane][dd];
                sc = a * 0.17677669529663687f;
            }
            float m = sc;
            for (int o = 16; o; o >>= 1) m = fmaxf(m, __shfl_xor_sync(0xffffffffu, m, o));
            float e = (lane < P) ? expf(sc - m) : 0.f;
            float sum = e;
            for (int o = 16; o; o >>= 1) sum += __shfl_xor_sync(0xffffffffu, sum, o);
            ps[w][lane] = e / sum;
            __syncwarp();
            float c = 0.f;
            for (int j = 0; j < P; ++j) c += ps[w][j] * vs[j][lane];
            g_ctxbf[(size_t)(dst + t) * D + h * DH + lane] = __float2bfloat16(c);
            __syncwarp();
        }
        __syncthreads();
    }
}

// ---------------------------------------------------------------------------
// Gather last-token rows of packed Ybf into compact bf16 ylast0
// ---------------------------------------------------------------------------
__global__ void gather_lastY()
{
    int n = blockIdx.x;
    int b = n / SEQT;
    int s = n % SEQT;
    int src = 64 * s * (s + 1) + b * (s + 1) + s;
    g_ylast0bf[n * D + threadIdx.x] = g_Ybf[(size_t)src * D + threadIdx.x];
}

// ---------------------------------------------------------------------------
// Layer-1 attention, LAST query only
// ---------------------------------------------------------------------------
__global__ __launch_bounds__(128) void attn1_kernel()
{
    __shared__ float qs[NH][DH];
    __shared__ float ps[NH][32];

    int q = blockIdx.x;
    int s = q >> 7;
    int b = q & 127;
    int P = s + 1;
    int base = 64 * s * (s + 1) + b * P;
    int tid  = threadIdx.x;
    int h    = tid >> 5;
    int lane = tid & 31;

    qs[h][lane] = __bfloat162float(
        g_q1bf[(size_t)(b * SEQT + s) * D + h * DH + lane]);
    __syncthreads();

    float sc = -1e30f;
    if (lane < P) {
        const __nv_bfloat16* krow = g_kv1bf + (size_t)(base + lane) * KVS + h * DH;
        float a = 0.f;
#pragma unroll
        for (int dd = 0; dd < DH; ++dd) a += qs[h][dd] * __bfloat162float(krow[dd]);
        sc = a * 0.17677669529663687f;
    }
    float m = sc;
    for (int o = 16; o; o >>= 1) m = fmaxf(m, __shfl_xor_sync(0xffffffffu, m, o));
    float e = (lane < P) ? expf(sc - m) : 0.f;
    float sum = e;
    for (int o = 16; o; o >>= 1) sum += __shfl_xor_sync(0xffffffffu, sum, o);
    ps[h][lane] = e / sum;
    __syncwarp();

    float c = 0.f;
    for (int j = 0; j < P; ++j)
        c += ps[h][j] * __bfloat162float(
                 g_kv1bf[(size_t)(base + j) * KVS + D + h * DH + lane]);
    g_ctxlastbf[(size_t)(b * SEQT + s) * D + h * DH + lane] = __float2bfloat16(c);
}

// ---------------------------------------------------------------------------
// Classifier + log_softmax (parallel second stage)
// ---------------------------------------------------------------------------
__global__ __launch_bounds__(64) void cls_kernel(
    const float* __restrict__ Wc1, const float* __restrict__ bc1,
    const float* __restrict__ Wc2, const float* __restrict__ bc2,
    float* __restrict__ out)
{
    __shared__ float c1[NC];
    __shared__ float lrow[D];
    __shared__ float red[2][2][2];  // [warp][logit]
    int n = blockIdx.x;
    int o = threadIdx.x;
    int w = o >> 5, lane = o & 31;

    for (int d = o; d < D; d += NC) lrow[d] = g_Ylast[n * D + d];
    __syncthreads();

    float a = bc1[o];
    for (int d = 0; d < D; ++d) a += lrow[d] * Wc1[o * D + d];
    float c = fmaxf(a, 0.f);
    c1[o] = c;

    float p0 = c * Wc2[o];
    float p1 = c * Wc2[NC + o];
    for (int off = 16; off; off >>= 1) {
        p0 += __shfl_xor_sync(0xffffffffu, p0, off);
        p1 += __shfl_xor_sync(0xffffffffu, p1, off);
    }
    if (lane == 0) { red[w][0][0] = p0; red[w][1][0] = p1; }
    __syncthreads();

    if (o == 0) {
        float l0 = bc2[0] + red[0][0][0] + red[1][0][0];
        float l1 = bc2[1] + red[0][1][0] + red[1][1][0];
        float m   = fmaxf(l0, l1);
        float lse = m + logf(expf(l0 - m) + expf(l1 - m));
        out[n * 2 + 0] = l0 - lse;
        out[n * 2 + 1] = l1 - lse;
    }
}

// ---------------------------------------------------------------------------
extern "C" void kernel_launch(void* const* d_in, const int* in_sizes, int n_in,
                              void* d_out, int out_size)
{
    const float* x     = (const float*)d_in[0];
    const float* W_fc  = (const float*)d_in[1];
    const float* b_fc  = (const float*)d_in[2];
    const float* qkv_w = (const float*)d_in[3];
    const float* qkv_b = (const float*)d_in[4];
    const float* out_w = (const float*)d_in[5];
    const float* out_b = (const float*)d_in[6];
    const float* ln1_g = (const float*)d_in[7];
    const float* ln1_b = (const float*)d_in[8];
    const float* ln2_g = (const float*)d_in[9];
    const float* ln2_b = (const float*)d_in[10];
    const float* ff1_w = (const float*)d_in[11];
    const float* ff1_b = (const float*)d_in[12];
    const float* ff2_w = (const float*)d_in[13];
    const float* ff2_b = (const float*)d_in[14];
    const float* Wc1   = (const float*)d_in[15];
    const float* bc1   = (const float*)d_in[16];
    const float* Wc2   = (const float*)d_in[17];
    const float* bc2   = (const float*)d_in[18];

    cudaFuncSetAttribute(gemm_bf16, cudaFuncAttributeMaxDynamicSharedMemorySize,
                         GEMM_SMEM);
    cudaFuncSetAttribute(gemm64, cudaFuncAttributeMaxDynamicSharedMemorySize,
                         GEMM_SMEM_64);
    cudaFuncSetAttribute(gemm_ln64, cudaFuncAttributeMaxDynamicSharedMemorySize,
                         GEMM_SMEM_LN64);
    cudaFuncSetAttribute(gemm_part64, cudaFuncAttributeMaxDynamicSharedMemorySize,
                         GEMM_SMEM_64);

    void* p;
    cudaGetSymbolAddress(&p, g_Y);        float* Y     = (float*)p;
    cudaGetSymbolAddress(&p, g_Ylast);    float* Ylast = (float*)p;
    cudaGetSymbolAddress(&p, g_part);     float* part  = (float*)p;
    cudaGetSymbolAddress(&p, g_xbf);      __nv_bfloat16* xbf   = (__nv_bfloat16*)p;
    cudaGetSymbolAddress(&p, g_wfc_bf);   __nv_bfloat16* wfcb  = (__nv_bfloat16*)p;
    cudaGetSymbolAddress(&p, g_qkvw_bf);  __nv_bfloat16* qkvwb = (__nv_bfloat16*)p;
    cudaGetSymbolAddress(&p, g_outw_bf);  __nv_bfloat16* outwb = (__nv_bfloat16*)p;
    cudaGetSymbolAddress(&p, g_ff1w_bf);  __nv_bfloat16* ff1wb = (__nv_bfloat16*)p;
    cudaGetSymbolAddress(&p, g_ff2w_bf);  __nv_bfloat16* ff2wb = (__nv_bfloat16*)p;
    cudaGetSymbolAddress(&p, g_h0pbf);    __nv_bfloat16* h0pb  = (__nv_bfloat16*)p;
    cudaGetSymbolAddress(&p, g_qkv0bf);   __nv_bfloat16* qkv0b = (__nv_bfloat16*)p;
    cudaGetSymbolAddress(&p, g_Ybf);      __nv_bfloat16* ybf   = (__nv_bfloat16*)p;
    cudaGetSymbolAddress(&p, g_kv1bf);    __nv_bfloat16* kv1b  = (__nv_bfloat16*)p;
    cudaGetSymbolAddress(&p, g_q1bf);     __nv_bfloat16* q1b   = (__nv_bfloat16*)p;
    cudaGetSymbolAddress(&p, g_ylast0bf); __nv_bfloat16* yl0b  = (__nv_bfloat16*)p;
    cudaGetSymbolAddress(&p, g_ctxbf);    __nv_bfloat16* ctxb  = (__nv_bfloat16*)p;
    cudaGetSymbolAddress(&p, g_ctxlastbf);__nv_bfloat16* ctxlb = (__nv_bfloat16*)p;
    cudaGetSymbolAddress(&p, g_Ylastbf);  __nv_bfloat16* ylbf  = (__nv_bfloat16*)p;
    cudaGetSymbolAddress(&p, g_Hbf);      __nv_bfloat16* hbf   = (__nv_bfloat16*)p;

    cvt_all<<<(CVT_TOTAL / 4 + 255) / 256, 256>>>(x, W_fc, qkv_w, out_w, ff1_w, ff2_w);

    // fc: split-K x4, combine applies bias+ReLU+PE; scatter packs fp32 Y
    gemm_part64<<<dim3(1, NBT / 64, 4), 128, GEMM_SMEM_64>>>(
        xbf, wfcb, part, DIN, DIN / 4, NBT);
    fc_combine<<<(NBT * D + 255) / 256, 256>>>(b_fc);
    scatter_kernel<<<NT, D>>>();

    // ---- layer 0 ----
    gemm64<<<dim3(3, NBT / 64), 128, GEMM_SMEM_64>>>(
        h0pb, qkvwb, qkv_b, nullptr, qkv0b, 3 * D, D, 0);
    attn0_kernel<<<S_STEPS * BATCH, 128>>>();
    gemm_ln64<<<dim3(1, NT / 64), 128, GEMM_SMEM_LN64>>>(
        ctxb, outwb, out_b, ln1_g, ln1_b, Y, Y, ybf, D, 0);
    gemm_bf16<<<dim3(DFF / 128, NT / 128), 128, GEMM_SMEM>>>(
        ybf, ff1wb, ff1_b, nullptr, hbf, DFF, D, 1);
    gemm_part64<<<dim3(1, NT / 64, 2), 128, GEMM_SMEM_64>>>(
        hbf, ff2wb, part, DFF, DFF / 2, NT);
    ln_combine<<<NT / 4, 128>>>(ff2_b, ln2_g, ln2_b);

    // ---- layer 1 (K/V full; Q + tail last-token only) ----
    gemm_bf16<<<dim3(2, NT / 128), 128, GEMM_SMEM>>>(
        ybf, qkvwb + (size_t)3 * D * D + (size_t)D * D, qkv_b + 3 * D + D,
        nullptr, kv1b, KVS, D, 0);
    gather_lastY<<<NBT, D>>>();
    gemm64<<<dim3(1, NBT / 64), 128, GEMM_SMEM_64>>>(
        yl0b, qkvwb + (size_t)3 * D * D, qkv_b + 3 * D, nullptr, q1b, D, D, 0);
    attn1_kernel<<<S_STEPS * BATCH, 128>>>();
    gemm_ln64<<<dim3(1, NBT / 64), 128, GEMM_SMEM_LN64>>>(
        ctxlb, outwb + (size_t)D * D, out_b + D,
        ln1_g + D, ln1_b + D, Y, Ylast, ylbf, D, 1);
    gemm_bf16<<<dim3(DFF / 128, NBT / 128), 128, GEMM_SMEM>>>(
        ylbf, ff1wb + (size_t)DFF * D, ff1_b + DFF, nullptr, hbf, DFF, D, 1);
    gemm_ln64<<<dim3(1, NBT / 64), 128, GEMM_SMEM_LN64>>>(
        hbf, ff2wb + (size_t)D * DFF, ff2_b + D,
        ln2_g + D, ln2_b + D, Ylast, Ylast, ylbf, DFF, 0);

    cls_kernel<<<NBT, NC>>>(Wc1, bc1, Wc2, bc2, (float*)d_out);
}

// round 13
// speedup vs baseline: 2.8073x; 1.1911x over previous
#include <cuda_runtime.h>
#include <cuda_bf16.h>
#include <math.h>
#include <stdint.h>

// Problem constants
#define S_STEPS 24
#define BATCH   128
#define SEQT    24
#define DIN     512
#define D       128
#define DFF     2048
#define NH      4
#define DH      32
#define NC      64
#define NT      38400  // BATCH * S*(S+1)/2
#define NBT     3072   // BATCH*SEQT
#define KVS     256    // layer-1 kv row stride

// fp32 scratch
__device__ float g_h0[NBT * D];
__device__ float g_Y[NT * D];
__device__ float g_Ylast[NBT * D];
__device__ float g_part[2ull * NT * D];   // split-K partials (fc, ff2 l0)

// bf16 buffers
__device__ __nv_bfloat16 g_xbf[NBT * DIN];
__device__ __nv_bfloat16 g_wfc_bf[D * DIN];
__device__ __nv_bfloat16 g_qkvw_bf[2 * 3 * D * D];
__device__ __nv_bfloat16 g_outw_bf[2 * D * D];
__device__ __nv_bfloat16 g_ff1w_bf[2 * DFF * D];
__device__ __nv_bfloat16 g_ff2w_bf[2 * D * DFF];
__device__ __nv_bfloat16 g_h0pbf[NBT * D];
__device__ __nv_bfloat16 g_qkv0bf[NBT * 3 * D];
__device__ __nv_bfloat16 g_Ybf[NT * D];
__device__ __nv_bfloat16 g_kv1bf[NT * KVS];
__device__ __nv_bfloat16 g_q1bf[NBT * D];
__device__ __nv_bfloat16 g_ylast0bf[NBT * D];
__device__ __nv_bfloat16 g_ctxbf[NT * D];
__device__ __nv_bfloat16 g_ctxlastbf[NBT * D];
__device__ __nv_bfloat16 g_Ylastbf[NBT * D];
__device__ __nv_bfloat16 g_Hbf[(size_t)NT * DFF];

__device__ __forceinline__ uint32_t smem_u32(const void* p) {
    return (uint32_t)__cvta_generic_to_shared(p);
}

#define SSTR 40
#define TILE (128 * SSTR)
#define TILE_A64 (64 * SSTR)
#define GEMM_SMEM  (3 * TILE * 2 * 2)
#define GEMM_SMEM_LN64 (3 * (TILE_A64 + TILE) * 2 + 1024)
#define GEMM_SMEM_64   (3 * (TILE_A64 + TILE) * 2)

// ---------------------------------------------------------------------------
// M128 gemm core: 4 warps 2x2, warp 64x64, 3-stage cp.async, m16n8k16
// ---------------------------------------------------------------------------
__device__ __forceinline__ void gemm_core(
    const __nv_bfloat16* __restrict__ A, const __nv_bfloat16* __restrict__ W,
    int K, int m0, int n0, __nv_bfloat16* As, __nv_bfloat16* Bs,
    float (&acc)[4][8][4])
{
    const int t = threadIdx.x, warp = t >> 5, lane = t & 31;
    const int wm = (warp >> 1) * 64, wn = (warp & 1) * 64;
    const int xr = lane & 15, xc = (lane >> 4) * 8;

#pragma unroll
    for (int i = 0; i < 4; ++i)
#pragma unroll
        for (int j = 0; j < 8; ++j)
#pragma unroll
            for (int k = 0; k < 4; ++k) acc[i][j][k] = 0.f;

    auto issue = [&](int k0, int st) {
        __nv_bfloat16* as = As + st * TILE;
        __nv_bfloat16* bs = Bs + st * TILE;
#pragma unroll
        for (int r = 0; r < 8; ++r) {
            int idx = t + r * 128;
            int op  = idx >> 9;
            int rem = idx & 511;
            int row = rem >> 2, c8 = (rem & 3) * 8;
            uint32_t dst = smem_u32((op ? bs : as) + row * SSTR + c8);
            const __nv_bfloat16* src = op
                ? (W + (size_t)(n0 + row) * K + k0 + c8)
                : (A + (size_t)(m0 + row) * K + k0 + c8);
            asm volatile("cp.async.cg.shared.global [%0], [%1], 16;"
                :: "r"(dst), "l"(src));
        }
        asm volatile("cp.async.commit_group;");
    };

    const int KT = K >> 5;
    issue(0, 0);
    issue(32, 1);
    for (int kt = 0; kt < KT; ++kt) {
        if (kt + 1 < KT) { asm volatile("cp.async.wait_group 1;"); }
        else             { asm volatile("cp.async.wait_group 0;"); }
        __syncthreads();
        if (kt + 2 < KT) issue((kt + 2) << 5, (kt + 2) % 3);

        const __nv_bfloat16* as = As + (kt % 3) * TILE;
        const __nv_bfloat16* bs = Bs + (kt % 3) * TILE;

        uint32_t af[2][4][4];
        uint32_t bfr[2][8][2];
#pragma unroll
        for (int si = 0; si < 2; ++si) {
            int ks = si * 16;
#pragma unroll
            for (int mi = 0; mi < 4; ++mi) {
                uint32_t ad = smem_u32(&as[(wm + mi * 16 + xr) * SSTR + ks + xc]);
                asm volatile("ldmatrix.sync.aligned.m8n8.x4.shared.b16 {%0,%1,%2,%3},[%4];"
                    : "=r"(af[si][mi][0]), "=r"(af[si][mi][1]),
                      "=r"(af[si][mi][2]), "=r"(af[si][mi][3])
                    : "r"(ad));
            }
#pragma unroll
            for (int np = 0; np < 4; ++np) {
                uint32_t bd = smem_u32(&bs[(wn + np * 16 + xr) * SSTR + ks + xc]);
                uint32_t r0, r1, r2, r3;
                asm volatile("ldmatrix.sync.aligned.m8n8.x4.shared.b16 {%0,%1,%2,%3},[%4];"
                    : "=r"(r0), "=r"(r1), "=r"(r2), "=r"(r3) : "r"(bd));
                bfr[si][2 * np][0] = r0; bfr[si][2 * np + 1][0] = r1;
                bfr[si][2 * np][1] = r2; bfr[si][2 * np + 1][1] = r3;
            }
        }
#pragma unroll
        for (int si = 0; si < 2; ++si)
#pragma unroll
            for (int mi = 0; mi < 4; ++mi)
#pragma unroll
                for (int ni = 0; ni < 8; ++ni) {
                    asm volatile(
                        "mma.sync.aligned.m16n8k16.row.col.f32.bf16.bf16.f32 "
                        "{%0,%1,%2,%3},{%4,%5,%6,%7},{%8,%9},{%0,%1,%2,%3};"
                        : "+f"(acc[mi][ni][0]), "+f"(acc[mi][ni][1]),
                          "+f"(acc[mi][ni][2]), "+f"(acc[mi][ni][3])
                        : "r"(af[si][mi][0]), "r"(af[si][mi][1]),
                          "r"(af[si][mi][2]), "r"(af[si][mi][3]),
                          "r"(bfr[si][ni][0]), "r"(bfr[si][ni][1]));
                }
    }
}

// ---------------------------------------------------------------------------
// M64 gemm core: 4 warps (2x2), warp 32x64.
// ---------------------------------------------------------------------------
__device__ __forceinline__ void gemm_core64(
    const __nv_bfloat16* __restrict__ A, const __nv_bfloat16* __restrict__ W,
    int ld, int K, int m0, __nv_bfloat16* As, __nv_bfloat16* Bs,
    float (&acc)[2][8][4])
{
    const int t = threadIdx.x, warp = t >> 5, lane = t & 31;
    const int wm = (warp >> 1) * 32, wn = (warp & 1) * 64;
    const int xr = lane & 15, xc = (lane >> 4) * 8;

#pragma unroll
    for (int i = 0; i < 2; ++i)
#pragma unroll
        for (int j = 0; j < 8; ++j)
#pragma unroll
            for (int k = 0; k < 4; ++k) acc[i][j][k] = 0.f;

    auto issue = [&](int k0, int st) {
        __nv_bfloat16* as = As + st * TILE_A64;
        __nv_bfloat16* bs = Bs + st * TILE;
#pragma unroll
        for (int r = 0; r < 6; ++r) {
            int idx = t + r * 128;
            if (idx < 256) {
                int row = idx >> 2, c8 = (idx & 3) * 8;
                asm volatile("cp.async.cg.shared.global [%0], [%1], 16;"
                    :: "r"(smem_u32(as + row * SSTR + c8)),
                       "l"(A + (size_t)(m0 + row) * ld + k0 + c8));
            } else {
                int rem = idx - 256;
                int row = rem >> 2, c8 = (rem & 3) * 8;
                asm volatile("cp.async.cg.shared.global [%0], [%1], 16;"
                    :: "r"(smem_u32(bs + row * SSTR + c8)),
                       "l"(W + (size_t)row * ld + k0 + c8));
            }
        }
        asm volatile("cp.async.commit_group;");
    };

    const int KT = K >> 5;
    issue(0, 0);
    issue(32, 1);
    for (int kt = 0; kt < KT; ++kt) {
        if (kt + 1 < KT) { asm volatile("cp.async.wait_group 1;"); }
        else             { asm volatile("cp.async.wait_group 0;"); }
        __syncthreads();
        if (kt + 2 < KT) issue((kt + 2) << 5, (kt + 2) % 3);

        const __nv_bfloat16* as = As + (kt % 3) * TILE_A64;
        const __nv_bfloat16* bs = Bs + (kt % 3) * TILE;
#pragma unroll
        for (int si = 0; si < 2; ++si) {
            int ks = si * 16;
            uint32_t af[2][4];
#pragma unroll
            for (int mi = 0; mi < 2; ++mi) {
                uint32_t ad = smem_u32(&as[(wm + mi * 16 + xr) * SSTR + ks + xc]);
                asm volatile("ldmatrix.sync.aligned.m8n8.x4.shared.b16 {%0,%1,%2,%3},[%4];"
                    : "=r"(af[mi][0]), "=r"(af[mi][1]), "=r"(af[mi][2]), "=r"(af[mi][3])
                    : "r"(ad));
            }
            uint32_t bfr[8][2];
#pragma unroll
            for (int np = 0; np < 4; ++np) {
                uint32_t bd = smem_u32(&bs[(wn + np * 16 + xr) * SSTR + ks + xc]);
                uint32_t r0, r1, r2, r3;
                asm volatile("ldmatrix.sync.aligned.m8n8.x4.shared.b16 {%0,%1,%2,%3},[%4];"
                    : "=r"(r0), "=r"(r1), "=r"(r2), "=r"(r3) : "r"(bd));
                bfr[2 * np][0] = r0; bfr[2 * np + 1][0] = r1;
                bfr[2 * np][1] = r2; bfr[2 * np + 1][1] = r3;
            }
#pragma unroll
            for (int mi = 0; mi < 2; ++mi)
#pragma unroll
                for (int ni = 0; ni < 8; ++ni) {
                    asm volatile(
                        "mma.sync.aligned.m16n8k16.row.col.f32.bf16.bf16.f32 "
                        "{%0,%1,%2,%3},{%4,%5,%6,%7},{%8,%9},{%0,%1,%2,%3};"
                        : "+f"(acc[mi][ni][0]), "+f"(acc[mi][ni][1]),
                          "+f"(acc[mi][ni][2]), "+f"(acc[mi][ni][3])
                        : "r"(af[mi][0]), "r"(af[mi][1]),
                          "r"(af[mi][2]), "r"(af[mi][3]),
                          "r"(bfr[ni][0]), "r"(bfr[ni][1]));
                }
        }
    }
}

// ---------------------------------------------------------------------------
// Plain GEMM (M128)
// ---------------------------------------------------------------------------
__global__ __launch_bounds__(128, 2) void gemm_bf16(
    const __nv_bfloat16* __restrict__ A, const __nv_bfloat16* __restrict__ W,
    const float* __restrict__ bias, float* __restrict__ Cf,
    __nv_bfloat16* __restrict__ Cb, int N, int K, int relu)
{
    extern __shared__ __align__(16) char dyn[];
    __nv_bfloat16* As = (__nv_bfloat16*)dyn;
    __nv_bfloat16* Bs = As + 3 * TILE;

    const int m0 = blockIdx.y * 128, n0 = blockIdx.x * 128;
    const int t = threadIdx.x, warp = t >> 5, lane = t & 31;
    const int g = lane >> 2, tig = lane & 3;
    const int wm = (warp >> 1) * 64, wn = (warp & 1) * 64;

    float acc[4][8][4];
    gemm_core(A, W, K, m0, n0, As, Bs, acc);

#pragma unroll
    for (int mi = 0; mi < 4; ++mi) {
#pragma unroll
        for (int ni = 0; ni < 8; ++ni) {
            int col = n0 + wn + ni * 8 + 2 * tig;
            float b0v = bias[col], b1v = bias[col + 1];
            int row = m0 + wm + mi * 16 + g;
            float2 v0 = make_float2(acc[mi][ni][0] + b0v, acc[mi][ni][1] + b1v);
            float2 v1 = make_float2(acc[mi][ni][2] + b0v, acc[mi][ni][3] + b1v);
            if (relu) {
                v0.x = fmaxf(v0.x, 0.f); v0.y = fmaxf(v0.y, 0.f);
                v1.x = fmaxf(v1.x, 0.f); v1.y = fmaxf(v1.y, 0.f);
            }
            if (Cf) {
                *(float2*)(Cf + (size_t)row * N + col)       = v0;
                *(float2*)(Cf + (size_t)(row + 8) * N + col) = v1;
            }
            if (Cb) {
                *(__nv_bfloat162*)(Cb + (size_t)row * N + col) =
                    __floats2bfloat162_rn(v0.x, v0.y);
                *(__nv_bfloat162*)(Cb + (size_t)(row + 8) * N + col) =
                    __floats2bfloat162_rn(v1.x, v1.y);
            }
        }
    }
}

// ---------------------------------------------------------------------------
// Plain GEMM (M64). Grid (N/128, M/64).
// ---------------------------------------------------------------------------
__global__ __launch_bounds__(128, 3) void gemm64(
    const __nv_bfloat16* __restrict__ A, const __nv_bfloat16* __restrict__ W,
    const float* __restrict__ bias, float* __restrict__ Cf,
    __nv_bfloat16* __restrict__ Cb, int N, int K, int relu)
{
    extern __shared__ __align__(16) char dyn[];
    __nv_bfloat16* As = (__nv_bfloat16*)dyn;
    __nv_bfloat16* Bs = As + 3 * TILE_A64;

    const int m0 = blockIdx.y * 64, n0 = blockIdx.x * 128;
    const int t = threadIdx.x, warp = t >> 5, lane = t & 31;
    const int g = lane >> 2, tig = lane & 3;
    const int wm = (warp >> 1) * 32, wn = (warp & 1) * 64;

    float acc[2][8][4];
    gemm_core64(A, W + (size_t)n0 * K, K, K, m0, As, Bs, acc);

#pragma unroll
    for (int mi = 0; mi < 2; ++mi) {
#pragma unroll
        for (int ni = 0; ni < 8; ++ni) {
            int col = n0 + wn + ni * 8 + 2 * tig;
            float b0v = bias[col], b1v = bias[col + 1];
            int row = m0 + wm + mi * 16 + g;
            float2 v0 = make_float2(acc[mi][ni][0] + b0v, acc[mi][ni][1] + b1v);
            float2 v1 = make_float2(acc[mi][ni][2] + b0v, acc[mi][ni][3] + b1v);
            if (relu) {
                v0.x = fmaxf(v0.x, 0.f); v0.y = fmaxf(v0.y, 0.f);
                v1.x = fmaxf(v1.x, 0.f); v1.y = fmaxf(v1.y, 0.f);
            }
            if (Cf) {
                *(float2*)(Cf + (size_t)row * N + col)       = v0;
                *(float2*)(Cf + (size_t)(row + 8) * N + col) = v1;
            }
            if (Cb) {
                *(__nv_bfloat162*)(Cb + (size_t)row * N + col) =
                    __floats2bfloat162_rn(v0.x, v0.y);
                *(__nv_bfloat162*)(Cb + (size_t)(row + 8) * N + col) =
                    __floats2bfloat162_rn(v1.x, v1.y);
            }
        }
    }
}

// ---------------------------------------------------------------------------
// GEMM + residual + LayerNorm, M64. N == 128.
// ---------------------------------------------------------------------------
__global__ __launch_bounds__(128, 3) void gemm_ln64(
    const __nv_bfloat16* __restrict__ A, const __nv_bfloat16* __restrict__ W,
    const float* __restrict__ bias, const float* __restrict__ lng,
    const float* __restrict__ lnb, const float* __restrict__ Rres,
    float* __restrict__ Yout, __nv_bfloat16* __restrict__ Ybf,
    int K, int gather)
{
    extern __shared__ __align__(16) char dyn[];
    __nv_bfloat16* As = (__nv_bfloat16*)dyn;
    __nv_bfloat16* Bs = As + 3 * TILE_A64;
    float* redS = (float*)(dyn + 3 * (TILE_A64 + TILE) * 2);  // [2][64]
    float* redQ = redS + 128;

    const int m0 = blockIdx.y * 64;
    const int t = threadIdx.x, warp = t >> 5, lane = t & 31;
    const int g = lane >> 2, tig = lane & 3;
    const int wm = (warp >> 1) * 32, wn = (warp & 1) * 64;
    const int cw = warp & 1;

    float acc[2][8][4];
    gemm_core64(A, W, K, K, m0, As, Bs, acc);

    auto res_row = [&](int n) -> const float* {
        if (gather) {
            int b = n / SEQT, s = n - b * SEQT;
            int src = 64 * s * (s + 1) + b * (s + 1) + s;
            return Rres + (size_t)src * D;
        }
        return Rres + (size_t)n * D;
    };

#pragma unroll
    for (int mi = 0; mi < 2; ++mi) {
        int r0 = wm + mi * 16 + g, r1 = r0 + 8;
        const float* R0 = res_row(m0 + r0);
        const float* R1 = res_row(m0 + r1);
        float s0 = 0.f, q0 = 0.f, s1 = 0.f, q1 = 0.f;
#pragma unroll
        for (int ni = 0; ni < 8; ++ni) {
            int col = wn + ni * 8 + 2 * tig;
            float2 bv = *(const float2*)(bias + col);
            float2 y0 = *(const float2*)(R0 + col);
            float2 y1 = *(const float2*)(R1 + col);
            float a0 = acc[mi][ni][0] + bv.x + y0.x;
            float a1 = acc[mi][ni][1] + bv.y + y0.y;
            float a2 = acc[mi][ni][2] + bv.x + y1.x;
            float a3 = acc[mi][ni][3] + bv.y + y1.y;
            acc[mi][ni][0] = a0; acc[mi][ni][1] = a1;
            acc[mi][ni][2] = a2; acc[mi][ni][3] = a3;
            s0 += a0 + a1; q0 += a0 * a0 + a1 * a1;
            s1 += a2 + a3; q1 += a2 * a2 + a3 * a3;
        }
#pragma unroll
        for (int o = 1; o <= 2; o <<= 1) {
            s0 += __shfl_xor_sync(0xffffffffu, s0, o);
            q0 += __shfl_xor_sync(0xffffffffu, q0, o);
            s1 += __shfl_xor_sync(0xffffffffu, s1, o);
            q1 += __shfl_xor_sync(0xffffffffu, q1, o);
        }
        if (tig == 0) {
            redS[cw * 64 + r0] = s0; redQ[cw * 64 + r0] = q0;
            redS[cw * 64 + r1] = s1; redQ[cw * 64 + r1] = q1;
        }
    }
    __syncthreads();

#pragma unroll
    for (int mi = 0; mi < 2; ++mi) {
        int r0 = wm + mi * 16 + g, r1 = r0 + 8;
        float S0 = redS[r0] + redS[64 + r0], Q0 = redQ[r0] + redQ[64 + r0];
        float S1 = redS[r1] + redS[64 + r1], Q1 = redQ[r1] + redQ[64 + r1];
        float mu0 = S0 * (1.f / 128.f), mu1 = S1 * (1.f / 128.f);
        float iv0 = rsqrtf(Q0 * (1.f / 128.f) - mu0 * mu0 + 1e-5f);
        float iv1 = rsqrtf(Q1 * (1.f / 128.f) - mu1 * mu1 + 1e-5f);
#pragma unroll
        for (int ni = 0; ni < 8; ++ni) {
            int col = wn + ni * 8 + 2 * tig;
            float2 gv = *(const float2*)(lng + col);
            float2 bv = *(const float2*)(lnb + col);
            float o0 = (acc[mi][ni][0] - mu0) * iv0 * gv.x + bv.x;
            float o1 = (acc[mi][ni][1] - mu0) * iv0 * gv.y + bv.y;
            float o2 = (acc[mi][ni][2] - mu1) * iv1 * gv.x + bv.x;
            float o3 = (acc[mi][ni][3] - mu1) * iv1 * gv.y + bv.y;
            *(float2*)(Yout + (size_t)(m0 + r0) * D + col) = make_float2(o0, o1);
            *(float2*)(Yout + (size_t)(m0 + r1) * D + col) = make_float2(o2, o3);
            *(__nv_bfloat162*)(Ybf + (size_t)(m0 + r0) * D + col) =
                __floats2bfloat162_rn(o0, o1);
            *(__nv_bfloat162*)(Ybf + (size_t)(m0 + r1) * D + col) =
                __floats2bfloat162_rn(o2, o3);
        }
    }
}

// ---------------------------------------------------------------------------
// Split-K partial GEMM, M64, N=128, fp32 partials. blockIdx.z = part.
// ---------------------------------------------------------------------------
__global__ __launch_bounds__(128, 3) void gemm_part64(
    const __nv_bfloat16* __restrict__ A, const __nv_bfloat16* __restrict__ W,
    float* __restrict__ P, int ld, int Kpart, int Mtot)
{
    extern __shared__ __align__(16) char dyn[];
    __nv_bfloat16* As = (__nv_bfloat16*)dyn;
    __nv_bfloat16* Bs = As + 3 * TILE_A64;

    const int m0 = blockIdx.y * 64;
    const int part = blockIdx.z;
    A += (size_t)part * Kpart;
    W += (size_t)part * Kpart;
    P += (size_t)part * Mtot * D;

    const int t = threadIdx.x, warp = t >> 5, lane = t & 31;
    const int g = lane >> 2, tig = lane & 3;
    const int wm = (warp >> 1) * 32, wn = (warp & 1) * 64;

    float acc[2][8][4];
    gemm_core64(A, W, ld, Kpart, m0, As, Bs, acc);

#pragma unroll
    for (int mi = 0; mi < 2; ++mi) {
        int r0 = wm + mi * 16 + g, r1 = r0 + 8;
#pragma unroll
        for (int ni = 0; ni < 8; ++ni) {
            int col = wn + ni * 8 + 2 * tig;
            *(float2*)(P + (size_t)(m0 + r0) * D + col) =
                make_float2(acc[mi][ni][0], acc[mi][ni][1]);
            *(float2*)(P + (size_t)(m0 + r1) * D + col) =
                make_float2(acc[mi][ni][2], acc[mi][ni][3]);
        }
    }
}

// ---------------------------------------------------------------------------
// fc combine: h0 = relu(P0..P3 + b_fc) + PE; writes fp32 + bf16
// ---------------------------------------------------------------------------
__global__ void fc_combine(const float* __restrict__ bias)
{
    int i = blockIdx.x * 256 + threadIdx.x;
    if (i >= NBT * D) return;
    int n = i >> 7, d = i & 127;
    int t = n % SEQT;
    float v = g_part[i] + g_part[NBT * D + i] + g_part[2 * NBT * D + i]
            + g_part[3 * NBT * D + i] + bias[d];
    v = fmaxf(v, 0.f);
    float freq = expf((float)(d & ~1) * (-9.210340371976184f / 128.f));
    float arg  = (float)t * freq;
    v += (d & 1) ? cosf(arg) : sinf(arg);
    g_h0[i]    = v;
    g_h0pbf[i] = __float2bfloat16(v);
}

// ---------------------------------------------------------------------------
// ff2-l0 combine + residual + LayerNorm
// ---------------------------------------------------------------------------
__global__ __launch_bounds__(128) void ln_combine(
    const float* __restrict__ bias, const float* __restrict__ lng,
    const float* __restrict__ lnb)
{
    int n    = blockIdx.x * 4 + (threadIdx.x >> 5);
    int lane = threadIdx.x & 31;
    float v[4], s = 0.f, q = 0.f;
#pragma unroll
    for (int i = 0; i < 4; ++i) {
        int d = lane + 32 * i;
        size_t off = (size_t)n * D + d;
        v[i] = g_Y[off] + g_part[off] + g_part[(size_t)NT * D + off] + bias[d];
        s += v[i]; q += v[i] * v[i];
    }
    for (int o = 16; o; o >>= 1) {
        s += __shfl_xor_sync(0xffffffffu, s, o);
        q += __shfl_xor_sync(0xffffffffu, q, o);
    }
    float mu = s * (1.f / 128.f);
    float iv = rsqrtf(q * (1.f / 128.f) - mu * mu + 1e-5f);
#pragma unroll
    for (int i = 0; i < 4; ++i) {
        int d = lane + 32 * i;
        size_t off = (size_t)n * D + d;
        float o = (v[i] - mu) * iv * lng[d] + lnb[d];
        g_Y[off]   = o;
        g_Ybf[off] = __float2bfloat16(o);
    }
}

// ---------------------------------------------------------------------------
// One-shot fp32 -> bf16 conversion
// ---------------------------------------------------------------------------
#define CVT_TOTAL 2818048
__global__ void cvt_all(const float* __restrict__ x, const float* __restrict__ wfc,
                        const float* __restrict__ qkvw, const float* __restrict__ outw,
                        const float* __restrict__ ff1w, const float* __restrict__ ff2w)
{
    int i = (blockIdx.x * 256 + threadIdx.x) * 4;
    if (i >= CVT_TOTAL) return;
    const float* s; __nv_bfloat16* d; int off;
    if      (i < 1572864) { s = x;    d = g_xbf;     off = i; }
    else if (i < 1638400) { s = wfc;  d = g_wfc_bf;  off = i - 1572864; }
    else if (i < 1736704) { s = qkvw; d = g_qkvw_bf; off = i - 1638400; }
    else if (i < 1769472) { s = outw; d = g_outw_bf; off = i - 1736704; }
    else if (i < 2293760) { s = ff1w; d = g_ff1w_bf; off = i - 1769472; }
    else                  { s = ff2w; d = g_ff2w_bf; off = i - 2293760; }
    float4 v = *(const float4*)(s + off);
    *(__nv_bfloat162*)(d + off)     = __floats2bfloat162_rn(v.x, v.y);
    *(__nv_bfloat162*)(d + off + 2) = __floats2bfloat162_rn(v.z, v.w);
}

// ---------------------------------------------------------------------------
// Scatter h0 -> packed Y. One thread per float4; closed-form step index.
// ---------------------------------------------------------------------------
__global__ void scatter_kernel()
{
    int i = blockIdx.x * 256 + threadIdx.x;     // float4 index, 0..NT*32-1
    if (i >= NT * 32) return;
    int n = i >> 5, c = i & 31;
    int u = n >> 6;
    int s = (int)((sqrtf((float)(4 * u + 1)) - 1.f) * 0.5f);
    while (64 * (s + 1) * (s + 2) <= n) s++;
    while (64 * s * (s + 1) > n) s--;
    int r = n - 64 * s * (s + 1);
    int P = s + 1;
    int b = r / P;
    int t = r - b * P;
    ((float4*)g_Y)[(size_t)n * 32 + c] =
        ((const float4*)g_h0)[(size_t)(b * SEQT + t) * 32 + c];
}

// ---------------------------------------------------------------------------
// Layer-0 attention (compact qkv0 -> packed ctx)
// ---------------------------------------------------------------------------
__global__ __launch_bounds__(128) void attn0_kernel()
{
    __shared__ float qs[SEQT][DH], ks[SEQT][DH], vs[SEQT][DH];
    __shared__ float ps[4][32];

    int q = blockIdx.x;
    int s = q >> 7;
    int b = q & 127;
    int P = s + 1;
    int dst = 64 * s * (s + 1) + b * P;
    int tid  = threadIdx.x;
    int w    = tid >> 5;
    int lane = tid & 31;

    for (int h = 0; h < NH; ++h) {
        for (int i = tid; i < P * DH; i += 128) {
            int t = i >> 5, dd = i & 31;
            const __nv_bfloat16* row =
                g_qkv0bf + (size_t)(b * SEQT + t) * (3 * D) + h * DH + dd;
            qs[t][dd] = __bfloat162float(row[0]);
            ks[t][dd] = __bfloat162float(row[D]);
            vs[t][dd] = __bfloat162float(row[2 * D]);
        }
        __syncthreads();

        for (int t = w; t < P; t += 4) {
            float sc = -1e30f;
            if (lane < P) {
                float a = 0.f;
#pragma unroll
                for (int dd = 0; dd < DH; ++dd) a += qs[t][dd] * ks[lane][dd];
                sc = a * 0.17677669529663687f;
            }
            float m = sc;
            for (int o = 16; o; o >>= 1) m = fmaxf(m, __shfl_xor_sync(0xffffffffu, m, o));
            float e = (lane < P) ? expf(sc - m) : 0.f;
            float sum = e;
            for (int o = 16; o; o >>= 1) sum += __shfl_xor_sync(0xffffffffu, sum, o);
            ps[w][lane] = e / sum;
            __syncwarp();
            float c = 0.f;
            for (int j = 0; j < P; ++j) c += ps[w][j] * vs[j][lane];
            g_ctxbf[(size_t)(dst + t) * D + h * DH + lane] = __float2bfloat16(c);
            __syncwarp();
        }
        __syncthreads();
    }
}

// ---------------------------------------------------------------------------
// Gather last-token rows of packed Ybf into compact bf16 ylast0
// ---------------------------------------------------------------------------
__global__ void gather_lastY()
{
    int n = blockIdx.x;
    int b = n / SEQT;
    int s = n % SEQT;
    int src = 64 * s * (s + 1) + b * (s + 1) + s;
    g_ylast0bf[n * D + threadIdx.x] = g_Ybf[(size_t)src * D + threadIdx.x];
}

// ---------------------------------------------------------------------------
// Layer-1 attention, LAST query only
// ---------------------------------------------------------------------------
__global__ __launch_bounds__(128) void attn1_kernel()
{
    __shared__ float qs[NH][DH];
    __shared__ float ps[NH][32];

    int q = blockIdx.x;
    int s = q >> 7;
    int b = q & 127;
    int P = s + 1;
    int base = 64 * s * (s + 1) + b * P;
    int tid  = threadIdx.x;
    int h    = tid >> 5;
    int lane = tid & 31;

    qs[h][lane] = __bfloat162float(
        g_q1bf[(size_t)(b * SEQT + s) * D + h * DH + lane]);
    __syncthreads();

    float sc = -1e30f;
    if (lane < P) {
        const __nv_bfloat16* krow = g_kv1bf + (size_t)(base + lane) * KVS + h * DH;
        float a = 0.f;
#pragma unroll
        for (int dd = 0; dd < DH; ++dd) a += qs[h][dd] * __bfloat162float(krow[dd]);
        sc = a * 0.17677669529663687f;
    }
    float m = sc;
    for (int o = 16; o; o >>= 1) m = fmaxf(m, __shfl_xor_sync(0xffffffffu, m, o));
    float e = (lane < P) ? expf(sc - m) : 0.f;
    float sum = e;
    for (int o = 16; o; o >>= 1) sum += __shfl_xor_sync(0xffffffffu, sum, o);
    ps[h][lane] = e / sum;
    __syncwarp();

    float c = 0.f;
    for (int j = 0; j < P; ++j)
        c += ps[h][j] * __bfloat162float(
                 g_kv1bf[(size_t)(base + j) * KVS + D + h * DH + lane]);
    g_ctxlastbf[(size_t)(b * SEQT + s) * D + h * DH + lane] = __float2bfloat16(c);
}

// ---------------------------------------------------------------------------
// Classifier + log_softmax: 16 tokens per block, Wc1 staged in smem once.
// ---------------------------------------------------------------------------
#define CLS_TPB 16
__global__ __launch_bounds__(128) void cls_kernel(
    const float* __restrict__ Wc1, const float* __restrict__ bc1,
    const float* __restrict__ Wc2, const float* __restrict__ bc2,
    float* __restrict__ out)
{
    __shared__ float w1s[NC * D];          // 32 KB
    __shared__ float rows[CLS_TPB][D];     // 8 KB
    __shared__ float c1s[CLS_TPB][NC];     // 4 KB

    int n0 = blockIdx.x * CLS_TPB;
    int t  = threadIdx.x;

    // stage Wc1 (2048 float4) and the 16 token rows (512 float4)
    for (int i = t; i < NC * D / 4; i += 128)
        ((float4*)w1s)[i] = ((const float4*)Wc1)[i];
    for (int i = t; i < CLS_TPB * D / 4; i += 128) {
        int tok = i >> 5, c = i & 31;
        ((float4*)rows[tok])[c] =
            ((const float4*)(g_Ylast + (size_t)(n0 + tok) * D))[c];
    }
    __syncthreads();

    // stage 1: c1s[tok][o] = relu(rows[tok] . Wc1[o] + bc1[o])
#pragma unroll
    for (int p = 0; p < CLS_TPB * NC / 128; ++p) {
        int pair = t + p * 128;
        int tok = pair >> 6, o = pair & 63;
        float a = bc1[o];
        const float* wr = w1s + o * D;
        const float* rr = rows[tok];
#pragma unroll
        for (int d = 0; d < D; ++d) a += rr[d] * wr[d];
        c1s[tok][o] = fmaxf(a, 0.f);
    }
    __syncthreads();

    // stage 2: logits + log_softmax (threads 0..15, one token each)
    if (t < CLS_TPB) {
        float l0 = bc2[0], l1 = bc2[1];
#pragma unroll
        for (int j = 0; j < NC; ++j) {
            float c = c1s[t][j];
            l0 += c * Wc2[j];
            l1 += c * Wc2[NC + j];
        }
        float m   = fmaxf(l0, l1);
        float lse = m + logf(expf(l0 - m) + expf(l1 - m));
        out[(n0 + t) * 2 + 0] = l0 - lse;
        out[(n0 + t) * 2 + 1] = l1 - lse;
    }
}

// ---------------------------------------------------------------------------
extern "C" void kernel_launch(void* const* d_in, const int* in_sizes, int n_in,
                              void* d_out, int out_size)
{
    const float* x     = (const float*)d_in[0];
    const float* W_fc  = (const float*)d_in[1];
    const float* b_fc  = (const float*)d_in[2];
    const float* qkv_w = (const float*)d_in[3];
    const float* qkv_b = (const float*)d_in[4];
    const float* out_w = (const float*)d_in[5];
    const float* out_b = (const float*)d_in[6];
    const float* ln1_g = (const float*)d_in[7];
    const float* ln1_b = (const float*)d_in[8];
    const float* ln2_g = (const float*)d_in[9];
    const float* ln2_b = (const float*)d_in[10];
    const float* ff1_w = (const float*)d_in[11];
    const float* ff1_b = (const float*)d_in[12];
    const float* ff2_w = (const float*)d_in[13];
    const float* ff2_b = (const float*)d_in[14];
    const float* Wc1   = (const float*)d_in[15];
    const float* bc1   = (const float*)d_in[16];
    const float* Wc2   = (const float*)d_in[17];
    const float* bc2   = (const float*)d_in[18];

    cudaFuncSetAttribute(gemm_bf16, cudaFuncAttributeMaxDynamicSharedMemorySize,
                         GEMM_SMEM);
    cudaFuncSetAttribute(gemm64, cudaFuncAttributeMaxDynamicSharedMemorySize,
                         GEMM_SMEM_64);
    cudaFuncSetAttribute(gemm_ln64, cudaFuncAttributeMaxDynamicSharedMemorySize,
                         GEMM_SMEM_LN64);
    cudaFuncSetAttribute(gemm_part64, cudaFuncAttributeMaxDynamicSharedMemorySize,
                         GEMM_SMEM_64);

    void* p;
    cudaGetSymbolAddress(&p, g_Y);        float* Y     = (float*)p;
    cudaGetSymbolAddress(&p, g_Ylast);    float* Ylast = (float*)p;
    cudaGetSymbolAddress(&p, g_part);     float* part  = (float*)p;
    cudaGetSymbolAddress(&p, g_xbf);      __nv_bfloat16* xbf   = (__nv_bfloat16*)p;
    cudaGetSymbolAddress(&p, g_wfc_bf);   __nv_bfloat16* wfcb  = (__nv_bfloat16*)p;
    cudaGetSymbolAddress(&p, g_qkvw_bf);  __nv_bfloat16* qkvwb = (__nv_bfloat16*)p;
    cudaGetSymbolAddress(&p, g_outw_bf);  __nv_bfloat16* outwb = (__nv_bfloat16*)p;
    cudaGetSymbolAddress(&p, g_ff1w_bf);  __nv_bfloat16* ff1wb = (__nv_bfloat16*)p;
    cudaGetSymbolAddress(&p, g_ff2w_bf);  __nv_bfloat16* ff2wb = (__nv_bfloat16*)p;
    cudaGetSymbolAddress(&p, g_h0pbf);    __nv_bfloat16* h0pb  = (__nv_bfloat16*)p;
    cudaGetSymbolAddress(&p, g_qkv0bf);   __nv_bfloat16* qkv0b = (__nv_bfloat16*)p;
    cudaGetSymbolAddress(&p, g_Ybf);      __nv_bfloat16* ybf   = (__nv_bfloat16*)p;
    cudaGetSymbolAddress(&p, g_kv1bf);    __nv_bfloat16* kv1b  = (__nv_bfloat16*)p;
    cudaGetSymbolAddress(&p, g_q1bf);     __nv_bfloat16* q1b   = (__nv_bfloat16*)p;
    cudaGetSymbolAddress(&p, g_ylast0bf); __nv_bfloat16* yl0b  = (__nv_bfloat16*)p;
    cudaGetSymbolAddress(&p, g_ctxbf);    __nv_bfloat16* ctxb  = (__nv_bfloat16*)p;
    cudaGetSymbolAddress(&p, g_ctxlastbf);__nv_bfloat16* ctxlb = (__nv_bfloat16*)p;
    cudaGetSymbolAddress(&p, g_Ylastbf);  __nv_bfloat16* ylbf  = (__nv_bfloat16*)p;
    cudaGetSymbolAddress(&p, g_Hbf);      __nv_bfloat16* hbf   = (__nv_bfloat16*)p;

    cvt_all<<<(CVT_TOTAL / 4 + 255) / 256, 256>>>(x, W_fc, qkv_w, out_w, ff1_w, ff2_w);

    // fc: split-K x4, combine applies bias+ReLU+PE; scatter packs fp32 Y
    gemm_part64<<<dim3(1, NBT / 64, 4), 128, GEMM_SMEM_64>>>(
        xbf, wfcb, part, DIN, DIN / 4, NBT);
    fc_combine<<<(NBT * D + 255) / 256, 256>>>(b_fc);
    scatter_kernel<<<(NT * 32 + 255) / 256, 256>>>();

    // ---- layer 0 ----
    gemm64<<<dim3(3, NBT / 64), 128, GEMM_SMEM_64>>>(
        h0pb, qkvwb, qkv_b, nullptr, qkv0b, 3 * D, D, 0);
    attn0_kernel<<<S_STEPS * BATCH, 128>>>();
    gemm_ln64<<<dim3(1, NT / 64), 128, GEMM_SMEM_LN64>>>(
        ctxb, outwb, out_b, ln1_g, ln1_b, Y, Y, ybf, D, 0);
    gemm_bf16<<<dim3(DFF / 128, NT / 128), 128, GEMM_SMEM>>>(
        ybf, ff1wb, ff1_b, nullptr, hbf, DFF, D, 1);
    gemm_part64<<<dim3(1, NT / 64, 2), 128, GEMM_SMEM_64>>>(
        hbf, ff2wb, part, DFF, DFF / 2, NT);
    ln_combine<<<NT / 4, 128>>>(ff2_b, ln2_g, ln2_b);

    // ---- layer 1 (K/V full; Q + tail last-token only) ----
    gemm_bf16<<<dim3(2, NT / 128), 128, GEMM_SMEM>>>(
        ybf, qkvwb + (size_t)3 * D * D + (size_t)D * D, qkv_b + 3 * D + D,
        nullptr, kv1b, KVS, D, 0);
    gather_lastY<<<NBT, D>>>();
    gemm64<<<dim3(1, NBT / 64), 128, GEMM_SMEM_64>>>(
        yl0b, qkvwb + (size_t)3 * D * D, qkv_b + 3 * D, nullptr, q1b, D, D, 0);
    attn1_kernel<<<S_STEPS * BATCH, 128>>>();
    gemm_ln64<<<dim3(1, NBT / 64), 128, GEMM_SMEM_LN64>>>(
        ctxlb, outwb + (size_t)D * D, out_b + D,
        ln1_g + D, ln1_b + D, Y, Ylast, ylbf, D, 1);
    gemm_bf16<<<dim3(DFF / 128, NBT / 128), 128, GEMM_SMEM>>>(
        ylbf, ff1wb + (size_t)DFF * D, ff1_b + DFF, nullptr, hbf, DFF, D, 1);
    gemm_ln64<<<dim3(1, NBT / 64), 128, GEMM_SMEM_LN64>>>(
        hbf, ff2wb + (size_t)D * DFF, ff2_b + D,
        ln2_g + D, ln2_b + D, Ylast, Ylast, ylbf, DFF, 0);

    cls_kernel<<<NBT / CLS_TPB, 128>>>(Wc1, bc1, Wc2, bc2, (float*)d_out);
}

// round 14
// speedup vs baseline: 3.3936x; 1.2088x over previous
#include <cuda_runtime.h>
#include <cuda_bf16.h>
#include <math.h>
#include <stdint.h>

// Problem constants
#define S_STEPS 24
#define BATCH   128
#define SEQT    24
#define DIN     512
#define D       128
#define DFF     2048
#define NH      4
#define DH      32
#define NC      64
#define NT      38400  // BATCH * S*(S+1)/2
#define NBT     3072   // BATCH*SEQT
#define KVS     256    // layer-1 kv row stride

// fp32 scratch
__device__ float g_h0[NBT * D];
__device__ float g_Y[NT * D];
__device__ float g_Ylast[NBT * D];
__device__ float g_part[2ull * NT * D];   // split-K partials (fc, ff2 l0)

// bf16 buffers
__device__ __nv_bfloat16 g_xbf[NBT * DIN];
__device__ __nv_bfloat16 g_wfc_bf[D * DIN];
__device__ __nv_bfloat16 g_qkvw_bf[2 * 3 * D * D];
__device__ __nv_bfloat16 g_outw_bf[2 * D * D];
__device__ __nv_bfloat16 g_ff1w_bf[2 * DFF * D];
__device__ __nv_bfloat16 g_ff2w_bf[2 * D * DFF];
__device__ __nv_bfloat16 g_h0pbf[NBT * D];
__device__ __nv_bfloat16 g_qkv0bf[NBT * 3 * D];
__device__ __nv_bfloat16 g_Ybf[NT * D];
__device__ __nv_bfloat16 g_kv1bf[NT * KVS];
__device__ __nv_bfloat16 g_q1bf[NBT * D];
__device__ __nv_bfloat16 g_ylast0bf[NBT * D];
__device__ __nv_bfloat16 g_ctxbf[NT * D];
__device__ __nv_bfloat16 g_ctxlastbf[NBT * D];
__device__ __nv_bfloat16 g_Ylastbf[NBT * D];
__device__ __nv_bfloat16 g_Hbf[(size_t)NT * DFF];

__device__ __forceinline__ uint32_t smem_u32(const void* p) {
    return (uint32_t)__cvta_generic_to_shared(p);
}

#define SSTR 40
#define TILE (128 * SSTR)
#define TILE_A64 (64 * SSTR)
#define GEMM_SMEM  (3 * TILE * 2 * 2)
#define GEMM_SMEM_LN64 (3 * (TILE_A64 + TILE) * 2 + 1024)
#define GEMM_SMEM_64   (3 * (TILE_A64 + TILE) * 2)

// ---------------------------------------------------------------------------
// M128 gemm core: 4 warps 2x2, warp 64x64, 3-stage cp.async, m16n8k16
// ---------------------------------------------------------------------------
__device__ __forceinline__ void gemm_core(
    const __nv_bfloat16* __restrict__ A, const __nv_bfloat16* __restrict__ W,
    int K, int m0, int n0, __nv_bfloat16* As, __nv_bfloat16* Bs,
    float (&acc)[4][8][4])
{
    const int t = threadIdx.x, warp = t >> 5, lane = t & 31;
    const int wm = (warp >> 1) * 64, wn = (warp & 1) * 64;
    const int xr = lane & 15, xc = (lane >> 4) * 8;

#pragma unroll
    for (int i = 0; i < 4; ++i)
#pragma unroll
        for (int j = 0; j < 8; ++j)
#pragma unroll
            for (int k = 0; k < 4; ++k) acc[i][j][k] = 0.f;

    auto issue = [&](int k0, int st) {
        __nv_bfloat16* as = As + st * TILE;
        __nv_bfloat16* bs = Bs + st * TILE;
#pragma unroll
        for (int r = 0; r < 8; ++r) {
            int idx = t + r * 128;
            int op  = idx >> 9;
            int rem = idx & 511;
            int row = rem >> 2, c8 = (rem & 3) * 8;
            uint32_t dst = smem_u32((op ? bs : as) + row * SSTR + c8);
            const __nv_bfloat16* src = op
                ? (W + (size_t)(n0 + row) * K + k0 + c8)
                : (A + (size_t)(m0 + row) * K + k0 + c8);
            asm volatile("cp.async.cg.shared.global [%0], [%1], 16;"
                :: "r"(dst), "l"(src));
        }
        asm volatile("cp.async.commit_group;");
    };

    const int KT = K >> 5;
    issue(0, 0);
    issue(32, 1);
    for (int kt = 0; kt < KT; ++kt) {
        if (kt + 1 < KT) { asm volatile("cp.async.wait_group 1;"); }
        else             { asm volatile("cp.async.wait_group 0;"); }
        __syncthreads();
        if (kt + 2 < KT) issue((kt + 2) << 5, (kt + 2) % 3);

        const __nv_bfloat16* as = As + (kt % 3) * TILE;
        const __nv_bfloat16* bs = Bs + (kt % 3) * TILE;

        uint32_t af[2][4][4];
        uint32_t bfr[2][8][2];
#pragma unroll
        for (int si = 0; si < 2; ++si) {
            int ks = si * 16;
#pragma unroll
            for (int mi = 0; mi < 4; ++mi) {
                uint32_t ad = smem_u32(&as[(wm + mi * 16 + xr) * SSTR + ks + xc]);
                asm volatile("ldmatrix.sync.aligned.m8n8.x4.shared.b16 {%0,%1,%2,%3},[%4];"
                    : "=r"(af[si][mi][0]), "=r"(af[si][mi][1]),
                      "=r"(af[si][mi][2]), "=r"(af[si][mi][3])
                    : "r"(ad));
            }
#pragma unroll
            for (int np = 0; np < 4; ++np) {
                uint32_t bd = smem_u32(&bs[(wn + np * 16 + xr) * SSTR + ks + xc]);
                uint32_t r0, r1, r2, r3;
                asm volatile("ldmatrix.sync.aligned.m8n8.x4.shared.b16 {%0,%1,%2,%3},[%4];"
                    : "=r"(r0), "=r"(r1), "=r"(r2), "=r"(r3) : "r"(bd));
                bfr[si][2 * np][0] = r0; bfr[si][2 * np + 1][0] = r1;
                bfr[si][2 * np][1] = r2; bfr[si][2 * np + 1][1] = r3;
            }
        }
#pragma unroll
        for (int si = 0; si < 2; ++si)
#pragma unroll
            for (int mi = 0; mi < 4; ++mi)
#pragma unroll
                for (int ni = 0; ni < 8; ++ni) {
                    asm volatile(
                        "mma.sync.aligned.m16n8k16.row.col.f32.bf16.bf16.f32 "
                        "{%0,%1,%2,%3},{%4,%5,%6,%7},{%8,%9},{%0,%1,%2,%3};"
                        : "+f"(acc[mi][ni][0]), "+f"(acc[mi][ni][1]),
                          "+f"(acc[mi][ni][2]), "+f"(acc[mi][ni][3])
                        : "r"(af[si][mi][0]), "r"(af[si][mi][1]),
                          "r"(af[si][mi][2]), "r"(af[si][mi][3]),
                          "r"(bfr[si][ni][0]), "r"(bfr[si][ni][1]));
                }
    }
}

// ---------------------------------------------------------------------------
// M64 gemm core: 4 warps (2x2), warp 32x64.
// ---------------------------------------------------------------------------
__device__ __forceinline__ void gemm_core64(
    const __nv_bfloat16* __restrict__ A, const __nv_bfloat16* __restrict__ W,
    int ld, int K, int m0, __nv_bfloat16* As, __nv_bfloat16* Bs,
    float (&acc)[2][8][4])
{
    const int t = threadIdx.x, warp = t >> 5, lane = t & 31;
    const int wm = (warp >> 1) * 32, wn = (warp & 1) * 64;
    const int xr = lane & 15, xc = (lane >> 4) * 8;

#pragma unroll
    for (int i = 0; i < 2; ++i)
#pragma unroll
        for (int j = 0; j < 8; ++j)
#pragma unroll
            for (int k = 0; k < 4; ++k) acc[i][j][k] = 0.f;

    auto issue = [&](int k0, int st) {
        __nv_bfloat16* as = As + st * TILE_A64;
        __nv_bfloat16* bs = Bs + st * TILE;
#pragma unroll
        for (int r = 0; r < 6; ++r) {
            int idx = t + r * 128;
            if (idx < 256) {
                int row = idx >> 2, c8 = (idx & 3) * 8;
                asm volatile("cp.async.cg.shared.global [%0], [%1], 16;"
                    :: "r"(smem_u32(as + row * SSTR + c8)),
                       "l"(A + (size_t)(m0 + row) * ld + k0 + c8));
            } else {
                int rem = idx - 256;
                int row = rem >> 2, c8 = (rem & 3) * 8;
                asm volatile("cp.async.cg.shared.global [%0], [%1], 16;"
                    :: "r"(smem_u32(bs + row * SSTR + c8)),
                       "l"(W + (size_t)row * ld + k0 + c8));
            }
        }
        asm volatile("cp.async.commit_group;");
    };

    const int KT = K >> 5;
    issue(0, 0);
    issue(32, 1);
    for (int kt = 0; kt < KT; ++kt) {
        if (kt + 1 < KT) { asm volatile("cp.async.wait_group 1;"); }
        else             { asm volatile("cp.async.wait_group 0;"); }
        __syncthreads();
        if (kt + 2 < KT) issue((kt + 2) << 5, (kt + 2) % 3);

        const __nv_bfloat16* as = As + (kt % 3) * TILE_A64;
        const __nv_bfloat16* bs = Bs + (kt % 3) * TILE;
#pragma unroll
        for (int si = 0; si < 2; ++si) {
            int ks = si * 16;
            uint32_t af[2][4];
#pragma unroll
            for (int mi = 0; mi < 2; ++mi) {
                uint32_t ad = smem_u32(&as[(wm + mi * 16 + xr) * SSTR + ks + xc]);
                asm volatile("ldmatrix.sync.aligned.m8n8.x4.shared.b16 {%0,%1,%2,%3},[%4];"
                    : "=r"(af[mi][0]), "=r"(af[mi][1]), "=r"(af[mi][2]), "=r"(af[mi][3])
                    : "r"(ad));
            }
            uint32_t bfr[8][2];
#pragma unroll
            for (int np = 0; np < 4; ++np) {
                uint32_t bd = smem_u32(&bs[(wn + np * 16 + xr) * SSTR + ks + xc]);
                uint32_t r0, r1, r2, r3;
                asm volatile("ldmatrix.sync.aligned.m8n8.x4.shared.b16 {%0,%1,%2,%3},[%4];"
                    : "=r"(r0), "=r"(r1), "=r"(r2), "=r"(r3) : "r"(bd));
                bfr[2 * np][0] = r0; bfr[2 * np + 1][0] = r1;
                bfr[2 * np][1] = r2; bfr[2 * np + 1][1] = r3;
            }
#pragma unroll
            for (int mi = 0; mi < 2; ++mi)
#pragma unroll
                for (int ni = 0; ni < 8; ++ni) {
                    asm volatile(
                        "mma.sync.aligned.m16n8k16.row.col.f32.bf16.bf16.f32 "
                        "{%0,%1,%2,%3},{%4,%5,%6,%7},{%8,%9},{%0,%1,%2,%3};"
                        : "+f"(acc[mi][ni][0]), "+f"(acc[mi][ni][1]),
                          "+f"(acc[mi][ni][2]), "+f"(acc[mi][ni][3])
                        : "r"(af[mi][0]), "r"(af[mi][1]),
                          "r"(af[mi][2]), "r"(af[mi][3]),
                          "r"(bfr[ni][0]), "r"(bfr[ni][1]));
                }
        }
    }
}

// ---------------------------------------------------------------------------
// Plain GEMM (M128)
// ---------------------------------------------------------------------------
__global__ __launch_bounds__(128, 2) void gemm_bf16(
    const __nv_bfloat16* __restrict__ A, const __nv_bfloat16* __restrict__ W,
    const float* __restrict__ bias, float* __restrict__ Cf,
    __nv_bfloat16* __restrict__ Cb, int N, int K, int relu)
{
    extern __shared__ __align__(16) char dyn[];
    __nv_bfloat16* As = (__nv_bfloat16*)dyn;
    __nv_bfloat16* Bs = As + 3 * TILE;

    const int m0 = blockIdx.y * 128, n0 = blockIdx.x * 128;
    const int t = threadIdx.x, warp = t >> 5, lane = t & 31;
    const int g = lane >> 2, tig = lane & 3;
    const int wm = (warp >> 1) * 64, wn = (warp & 1) * 64;

    float acc[4][8][4];
    gemm_core(A, W, K, m0, n0, As, Bs, acc);

#pragma unroll
    for (int mi = 0; mi < 4; ++mi) {
#pragma unroll
        for (int ni = 0; ni < 8; ++ni) {
            int col = n0 + wn + ni * 8 + 2 * tig;
            float b0v = bias[col], b1v = bias[col + 1];
            int row = m0 + wm + mi * 16 + g;
            float2 v0 = make_float2(acc[mi][ni][0] + b0v, acc[mi][ni][1] + b1v);
            float2 v1 = make_float2(acc[mi][ni][2] + b0v, acc[mi][ni][3] + b1v);
            if (relu) {
                v0.x = fmaxf(v0.x, 0.f); v0.y = fmaxf(v0.y, 0.f);
                v1.x = fmaxf(v1.x, 0.f); v1.y = fmaxf(v1.y, 0.f);
            }
            if (Cf) {
                *(float2*)(Cf + (size_t)row * N + col)       = v0;
                *(float2*)(Cf + (size_t)(row + 8) * N + col) = v1;
            }
            if (Cb) {
                *(__nv_bfloat162*)(Cb + (size_t)row * N + col) =
                    __floats2bfloat162_rn(v0.x, v0.y);
                *(__nv_bfloat162*)(Cb + (size_t)(row + 8) * N + col) =
                    __floats2bfloat162_rn(v1.x, v1.y);
            }
        }
    }
}

// ---------------------------------------------------------------------------
// Plain GEMM (M64). Grid (N/128, M/64).
// ---------------------------------------------------------------------------
__global__ __launch_bounds__(128, 3) void gemm64(
    const __nv_bfloat16* __restrict__ A, const __nv_bfloat16* __restrict__ W,
    const float* __restrict__ bias, float* __restrict__ Cf,
    __nv_bfloat16* __restrict__ Cb, int N, int K, int relu)
{
    extern __shared__ __align__(16) char dyn[];
    __nv_bfloat16* As = (__nv_bfloat16*)dyn;
    __nv_bfloat16* Bs = As + 3 * TILE_A64;

    const int m0 = blockIdx.y * 64, n0 = blockIdx.x * 128;
    const int t = threadIdx.x, warp = t >> 5, lane = t & 31;
    const int g = lane >> 2, tig = lane & 3;
    const int wm = (warp >> 1) * 32, wn = (warp & 1) * 64;

    float acc[2][8][4];
    gemm_core64(A, W + (size_t)n0 * K, K, K, m0, As, Bs, acc);

#pragma unroll
    for (int mi = 0; mi < 2; ++mi) {
#pragma unroll
        for (int ni = 0; ni < 8; ++ni) {
            int col = n0 + wn + ni * 8 + 2 * tig;
            float b0v = bias[col], b1v = bias[col + 1];
            int row = m0 + wm + mi * 16 + g;
            float2 v0 = make_float2(acc[mi][ni][0] + b0v, acc[mi][ni][1] + b1v);
            float2 v1 = make_float2(acc[mi][ni][2] + b0v, acc[mi][ni][3] + b1v);
            if (relu) {
                v0.x = fmaxf(v0.x, 0.f); v0.y = fmaxf(v0.y, 0.f);
                v1.x = fmaxf(v1.x, 0.f); v1.y = fmaxf(v1.y, 0.f);
            }
            if (Cf) {
                *(float2*)(Cf + (size_t)row * N + col)       = v0;
                *(float2*)(Cf + (size_t)(row + 8) * N + col) = v1;
            }
            if (Cb) {
                *(__nv_bfloat162*)(Cb + (size_t)row * N + col) =
                    __floats2bfloat162_rn(v0.x, v0.y);
                *(__nv_bfloat162*)(Cb + (size_t)(row + 8) * N + col) =
                    __floats2bfloat162_rn(v1.x, v1.y);
            }
        }
    }
}

// ---------------------------------------------------------------------------
// GEMM + residual + LayerNorm, M64. N == 128.
// ---------------------------------------------------------------------------
__global__ __launch_bounds__(128, 3) void gemm_ln64(
    const __nv_bfloat16* __restrict__ A, const __nv_bfloat16* __restrict__ W,
    const float* __restrict__ bias, const float* __restrict__ lng,
    const float* __restrict__ lnb, const float* __restrict__ Rres,
    float* __restrict__ Yout, __nv_bfloat16* __restrict__ Ybf,
    int K, int gather)
{
    extern __shared__ __align__(16) char dyn[];
    __nv_bfloat16* As = (__nv_bfloat16*)dyn;
    __nv_bfloat16* Bs = As + 3 * TILE_A64;
    float* redS = (float*)(dyn + 3 * (TILE_A64 + TILE) * 2);  // [2][64]
    float* redQ = redS + 128;

    const int m0 = blockIdx.y * 64;
    const int t = threadIdx.x, warp = t >> 5, lane = t & 31;
    const int g = lane >> 2, tig = lane & 3;
    const int wm = (warp >> 1) * 32, wn = (warp & 1) * 64;
    const int cw = warp & 1;

    float acc[2][8][4];
    gemm_core64(A, W, K, K, m0, As, Bs, acc);

    auto res_row = [&](int n) -> const float* {
        if (gather) {
            int b = n / SEQT, s = n - b * SEQT;
            int src = 64 * s * (s + 1) + b * (s + 1) + s;
            return Rres + (size_t)src * D;
        }
        return Rres + (size_t)n * D;
    };

#pragma unroll
    for (int mi = 0; mi < 2; ++mi) {
        int r0 = wm + mi * 16 + g, r1 = r0 + 8;
        const float* R0 = res_row(m0 + r0);
        const float* R1 = res_row(m0 + r1);
        float s0 = 0.f, q0 = 0.f, s1 = 0.f, q1 = 0.f;
#pragma unroll
        for (int ni = 0; ni < 8; ++ni) {
            int col = wn + ni * 8 + 2 * tig;
            float2 bv = *(const float2*)(bias + col);
            float2 y0 = *(const float2*)(R0 + col);
            float2 y1 = *(const float2*)(R1 + col);
            float a0 = acc[mi][ni][0] + bv.x + y0.x;
            float a1 = acc[mi][ni][1] + bv.y + y0.y;
            float a2 = acc[mi][ni][2] + bv.x + y1.x;
            float a3 = acc[mi][ni][3] + bv.y + y1.y;
            acc[mi][ni][0] = a0; acc[mi][ni][1] = a1;
            acc[mi][ni][2] = a2; acc[mi][ni][3] = a3;
            s0 += a0 + a1; q0 += a0 * a0 + a1 * a1;
            s1 += a2 + a3; q1 += a2 * a2 + a3 * a3;
        }
#pragma unroll
        for (int o = 1; o <= 2; o <<= 1) {
            s0 += __shfl_xor_sync(0xffffffffu, s0, o);
            q0 += __shfl_xor_sync(0xffffffffu, q0, o);
            s1 += __shfl_xor_sync(0xffffffffu, s1, o);
            q1 += __shfl_xor_sync(0xffffffffu, q1, o);
        }
        if (tig == 0) {
            redS[cw * 64 + r0] = s0; redQ[cw * 64 + r0] = q0;
            redS[cw * 64 + r1] = s1; redQ[cw * 64 + r1] = q1;
        }
    }
    __syncthreads();

#pragma unroll
    for (int mi = 0; mi < 2; ++mi) {
        int r0 = wm + mi * 16 + g, r1 = r0 + 8;
        float S0 = redS[r0] + redS[64 + r0], Q0 = redQ[r0] + redQ[64 + r0];
        float S1 = redS[r1] + redS[64 + r1], Q1 = redQ[r1] + redQ[64 + r1];
        float mu0 = S0 * (1.f / 128.f), mu1 = S1 * (1.f / 128.f);
        float iv0 = rsqrtf(Q0 * (1.f / 128.f) - mu0 * mu0 + 1e-5f);
        float iv1 = rsqrtf(Q1 * (1.f / 128.f) - mu1 * mu1 + 1e-5f);
#pragma unroll
        for (int ni = 0; ni < 8; ++ni) {
            int col = wn + ni * 8 + 2 * tig;
            float2 gv = *(const float2*)(lng + col);
            float2 bv = *(const float2*)(lnb + col);
            float o0 = (acc[mi][ni][0] - mu0) * iv0 * gv.x + bv.x;
            float o1 = (acc[mi][ni][1] - mu0) * iv0 * gv.y + bv.y;
            float o2 = (acc[mi][ni][2] - mu1) * iv1 * gv.x + bv.x;
            float o3 = (acc[mi][ni][3] - mu1) * iv1 * gv.y + bv.y;
            *(float2*)(Yout + (size_t)(m0 + r0) * D + col) = make_float2(o0, o1);
            *(float2*)(Yout + (size_t)(m0 + r1) * D + col) = make_float2(o2, o3);
            *(__nv_bfloat162*)(Ybf + (size_t)(m0 + r0) * D + col) =
                __floats2bfloat162_rn(o0, o1);
            *(__nv_bfloat162*)(Ybf + (size_t)(m0 + r1) * D + col) =
                __floats2bfloat162_rn(o2, o3);
        }
    }
}

// ---------------------------------------------------------------------------
// Split-K partial GEMM, M64, N=128, fp32 partials. blockIdx.z = part.
// ---------------------------------------------------------------------------
__global__ __launch_bounds__(128, 3) void gemm_part64(
    const __nv_bfloat16* __restrict__ A, const __nv_bfloat16* __restrict__ W,
    float* __restrict__ P, int ld, int Kpart, int Mtot)
{
    extern __shared__ __align__(16) char dyn[];
    __nv_bfloat16* As = (__nv_bfloat16*)dyn;
    __nv_bfloat16* Bs = As + 3 * TILE_A64;

    const int m0 = blockIdx.y * 64;
    const int part = blockIdx.z;
    A += (size_t)part * Kpart;
    W += (size_t)part * Kpart;
    P += (size_t)part * Mtot * D;

    const int t = threadIdx.x, warp = t >> 5, lane = t & 31;
    const int g = lane >> 2, tig = lane & 3;
    const int wm = (warp >> 1) * 32, wn = (warp & 1) * 64;

    float acc[2][8][4];
    gemm_core64(A, W, ld, Kpart, m0, As, Bs, acc);

#pragma unroll
    for (int mi = 0; mi < 2; ++mi) {
        int r0 = wm + mi * 16 + g, r1 = r0 + 8;
#pragma unroll
        for (int ni = 0; ni < 8; ++ni) {
            int col = wn + ni * 8 + 2 * tig;
            *(float2*)(P + (size_t)(m0 + r0) * D + col) =
                make_float2(acc[mi][ni][0], acc[mi][ni][1]);
            *(float2*)(P + (size_t)(m0 + r1) * D + col) =
                make_float2(acc[mi][ni][2], acc[mi][ni][3]);
        }
    }
}

// ---------------------------------------------------------------------------
// fc combine: h0 = relu(P0..P3 + b_fc) + PE; writes fp32 + bf16
// ---------------------------------------------------------------------------
__global__ void fc_combine(const float* __restrict__ bias)
{
    int i = blockIdx.x * 256 + threadIdx.x;
    if (i >= NBT * D) return;
    int n = i >> 7, d = i & 127;
    int t = n % SEQT;
    float v = g_part[i] + g_part[NBT * D + i] + g_part[2 * NBT * D + i]
            + g_part[3 * NBT * D + i] + bias[d];
    v = fmaxf(v, 0.f);
    float freq = expf((float)(d & ~1) * (-9.210340371976184f / 128.f));
    float arg  = (float)t * freq;
    v += (d & 1) ? cosf(arg) : sinf(arg);
    g_h0[i]    = v;
    g_h0pbf[i] = __float2bfloat16(v);
}

// ---------------------------------------------------------------------------
// ff2-l0 combine + residual + LayerNorm
// ---------------------------------------------------------------------------
__global__ __launch_bounds__(128) void ln_combine(
    const float* __restrict__ bias, const float* __restrict__ lng,
    const float* __restrict__ lnb)
{
    int n    = blockIdx.x * 4 + (threadIdx.x >> 5);
    int lane = threadIdx.x & 31;
    float v[4], s = 0.f, q = 0.f;
#pragma unroll
    for (int i = 0; i < 4; ++i) {
        int d = lane + 32 * i;
        size_t off = (size_t)n * D + d;
        v[i] = g_Y[off] + g_part[off] + g_part[(size_t)NT * D + off] + bias[d];
        s += v[i]; q += v[i] * v[i];
    }
    for (int o = 16; o; o >>= 1) {
        s += __shfl_xor_sync(0xffffffffu, s, o);
        q += __shfl_xor_sync(0xffffffffu, q, o);
    }
    float mu = s * (1.f / 128.f);
    float iv = rsqrtf(q * (1.f / 128.f) - mu * mu + 1e-5f);
#pragma unroll
    for (int i = 0; i < 4; ++i) {
        int d = lane + 32 * i;
        size_t off = (size_t)n * D + d;
        float o = (v[i] - mu) * iv * lng[d] + lnb[d];
        g_Y[off]   = o;
        g_Ybf[off] = __float2bfloat16(o);
    }
}

// ---------------------------------------------------------------------------
// One-shot fp32 -> bf16 conversion
// ---------------------------------------------------------------------------
#define CVT_TOTAL 2818048
__global__ void cvt_all(const float* __restrict__ x, const float* __restrict__ wfc,
                        const float* __restrict__ qkvw, const float* __restrict__ outw,
                        const float* __restrict__ ff1w, const float* __restrict__ ff2w)
{
    int i = (blockIdx.x * 256 + threadIdx.x) * 4;
    if (i >= CVT_TOTAL) return;
    const float* s; __nv_bfloat16* d; int off;
    if      (i < 1572864) { s = x;    d = g_xbf;     off = i; }
    else if (i < 1638400) { s = wfc;  d = g_wfc_bf;  off = i - 1572864; }
    else if (i < 1736704) { s = qkvw; d = g_qkvw_bf; off = i - 1638400; }
    else if (i < 1769472) { s = outw; d = g_outw_bf; off = i - 1736704; }
    else if (i < 2293760) { s = ff1w; d = g_ff1w_bf; off = i - 1769472; }
    else                  { s = ff2w; d = g_ff2w_bf; off = i - 2293760; }
    float4 v = *(const float4*)(s + off);
    *(__nv_bfloat162*)(d + off)     = __floats2bfloat162_rn(v.x, v.y);
    *(__nv_bfloat162*)(d + off + 2) = __floats2bfloat162_rn(v.z, v.w);
}

// ---------------------------------------------------------------------------
// Scatter h0 -> packed Y. One thread per float4; closed-form step index.
// ---------------------------------------------------------------------------
__global__ void scatter_kernel()
{
    int i = blockIdx.x * 256 + threadIdx.x;
    if (i >= NT * 32) return;
    int n = i >> 5, c = i & 31;
    int u = n >> 6;
    int s = (int)((sqrtf((float)(4 * u + 1)) - 1.f) * 0.5f);
    while (64 * (s + 1) * (s + 2) <= n) s++;
    while (64 * s * (s + 1) > n) s--;
    int r = n - 64 * s * (s + 1);
    int P = s + 1;
    int b = r / P;
    int t = r - b * P;
    ((float4*)g_Y)[(size_t)n * 32 + c] =
        ((const float4*)g_h0)[(size_t)(b * SEQT + t) * 32 + c];
}

// ---------------------------------------------------------------------------
// Layer-0 attention, prefix-dedup: one block per (b,h); compute the 24x24
// score matrix ONCE, then per query t an online-softmax prefix scan over keys
// emits ctx for every step s >= t. Exact softmax per prefix.
// ---------------------------------------------------------------------------
__global__ __launch_bounds__(64) void attn0_kernel()
{
    __shared__ float qs[SEQT][DH], ks[SEQT][DH], vs[SEQT][DH];
    __shared__ float sc[SEQT][SEQT];

    int blk = blockIdx.x;
    int b = blk >> 2;
    int h = blk & 3;
    int tid  = threadIdx.x;
    int w    = tid >> 5;
    int lane = tid & 31;

    // load q/k/v for this (b,h): 24 rows x 32 dims each
    for (int i = tid; i < SEQT * DH; i += 64) {
        int t = i >> 5, dd = i & 31;
        const __nv_bfloat16* row =
            g_qkv0bf + (size_t)(b * SEQT + t) * (3 * D) + h * DH + dd;
        qs[t][dd] = __bfloat162float(row[0]);
        ks[t][dd] = __bfloat162float(row[D]);
        vs[t][dd] = __bfloat162float(row[2 * D]);
    }
    __syncthreads();

    // score matrix: 576 dots, 9 per thread
    for (int p = tid; p < SEQT * SEQT; p += 64) {
        int t = p / SEQT, j = p - t * SEQT;
        float a = 0.f;
#pragma unroll
        for (int dd = 0; dd < DH; ++dd) a += qs[t][dd] * ks[j][dd];
        sc[t][j] = a * 0.17677669529663687f;   // 1/sqrt(32)
    }
    __syncthreads();

    // online-softmax prefix scan: warp w handles queries t = w, w+2, ...
    for (int t = w; t < SEQT; t += 2) {
        float m = -1e30f, l = 0.f, acc = 0.f;
        for (int j = 0; j < SEQT; ++j) {
            float x = sc[t][j];
            float nm = fmaxf(m, x);
            float so = __expf(m - nm);      // 0 on first iter
            float e  = __expf(x - nm);
            l   = l * so + e;
            acc = acc * so + e * vs[j][lane];
            m = nm;
            if (j >= t) {
                int dst = 64 * j * (j + 1) + b * (j + 1) + t;
                g_ctxbf[(size_t)dst * D + h * DH + lane] =
                    __float2bfloat16(acc / l);
            }
        }
    }
}

// ---------------------------------------------------------------------------
// Gather last-token rows of packed Ybf into compact bf16 ylast0
// ---------------------------------------------------------------------------
__global__ void gather_lastY()
{
    int n = blockIdx.x;
    int b = n / SEQT;
    int s = n % SEQT;
    int src = 64 * s * (s + 1) + b * (s + 1) + s;
    g_ylast0bf[n * D + threadIdx.x] = g_Ybf[(size_t)src * D + threadIdx.x];
}

// ---------------------------------------------------------------------------
// Layer-1 attention, LAST query only
// ---------------------------------------------------------------------------
__global__ __launch_bounds__(128) void attn1_kernel()
{
    __shared__ float qs[NH][DH];
    __shared__ float ps[NH][32];

    int q = blockIdx.x;
    int s = q >> 7;
    int b = q & 127;
    int P = s + 1;
    int base = 64 * s * (s + 1) + b * P;
    int tid  = threadIdx.x;
    int h    = tid >> 5;
    int lane = tid & 31;

    qs[h][lane] = __bfloat162float(
        g_q1bf[(size_t)(b * SEQT + s) * D + h * DH + lane]);
    __syncthreads();

    float sc = -1e30f;
    if (lane < P) {
        const __nv_bfloat16* krow = g_kv1bf + (size_t)(base + lane) * KVS + h * DH;
        float a = 0.f;
#pragma unroll
        for (int dd = 0; dd < DH; ++dd) a += qs[h][dd] * __bfloat162float(krow[dd]);
        sc = a * 0.17677669529663687f;
    }
    float m = sc;
    for (int o = 16; o; o >>= 1) m = fmaxf(m, __shfl_xor_sync(0xffffffffu, m, o));
    float e = (lane < P) ? expf(sc - m) : 0.f;
    float sum = e;
    for (int o = 16; o; o >>= 1) sum += __shfl_xor_sync(0xffffffffu, sum, o);
    ps[h][lane] = e / sum;
    __syncwarp();

    float c = 0.f;
    for (int j = 0; j < P; ++j)
        c += ps[h][j] * __bfloat162float(
                 g_kv1bf[(size_t)(base + j) * KVS + D + h * DH + lane]);
    g_ctxlastbf[(size_t)(b * SEQT + s) * D + h * DH + lane] = __float2bfloat16(c);
}

// ---------------------------------------------------------------------------
// Classifier + log_softmax: 16 tokens per block, Wc1 staged in smem once.
// ---------------------------------------------------------------------------
#define CLS_TPB 16
__global__ __launch_bounds__(128) void cls_kernel(
    const float* __restrict__ Wc1, const float* __restrict__ bc1,
    const float* __restrict__ Wc2, const float* __restrict__ bc2,
    float* __restrict__ out)
{
    __shared__ float w1s[NC * D];
    __shared__ float rows[CLS_TPB][D];
    __shared__ float c1s[CLS_TPB][NC];

    int n0 = blockIdx.x * CLS_TPB;
    int t  = threadIdx.x;

    for (int i = t; i < NC * D / 4; i += 128)
        ((float4*)w1s)[i] = ((const float4*)Wc1)[i];
    for (int i = t; i < CLS_TPB * D / 4; i += 128) {
        int tok = i >> 5, c = i & 31;
        ((float4*)rows[tok])[c] =
            ((const float4*)(g_Ylast + (size_t)(n0 + tok) * D))[c];
    }
    __syncthreads();

#pragma unroll
    for (int p = 0; p < CLS_TPB * NC / 128; ++p) {
        int pair = t + p * 128;
        int tok = pair >> 6, o = pair & 63;
        float a = bc1[o];
        const float* wr = w1s + o * D;
        const float* rr = rows[tok];
#pragma unroll
        for (int d = 0; d < D; ++d) a += rr[d] * wr[d];
        c1s[tok][o] = fmaxf(a, 0.f);
    }
    __syncthreads();

    if (t < CLS_TPB) {
        float l0 = bc2[0], l1 = bc2[1];
#pragma unroll
        for (int j = 0; j < NC; ++j) {
            float c = c1s[t][j];
            l0 += c * Wc2[j];
            l1 += c * Wc2[NC + j];
        }
        float m   = fmaxf(l0, l1);
        float lse = m + logf(expf(l0 - m) + expf(l1 - m));
        out[(n0 + t) * 2 + 0] = l0 - lse;
        out[(n0 + t) * 2 + 1] = l1 - lse;
    }
}

// ---------------------------------------------------------------------------
extern "C" void kernel_launch(void* const* d_in, const int* in_sizes, int n_in,
                              void* d_out, int out_size)
{
    const float* x     = (const float*)d_in[0];
    const float* W_fc  = (const float*)d_in[1];
    const float* b_fc  = (const float*)d_in[2];
    const float* qkv_w = (const float*)d_in[3];
    const float* qkv_b = (const float*)d_in[4];
    const float* out_w = (const float*)d_in[5];
    const float* out_b = (const float*)d_in[6];
    const float* ln1_g = (const float*)d_in[7];
    const float* ln1_b = (const float*)d_in[8];
    const float* ln2_g = (const float*)d_in[9];
    const float* ln2_b = (const float*)d_in[10];
    const float* ff1_w = (const float*)d_in[11];
    const float* ff1_b = (const float*)d_in[12];
    const float* ff2_w = (const float*)d_in[13];
    const float* ff2_b = (const float*)d_in[14];
    const float* Wc1   = (const float*)d_in[15];
    const float* bc1   = (const float*)d_in[16];
    const float* Wc2   = (const float*)d_in[17];
    const float* bc2   = (const float*)d_in[18];

    cudaFuncSetAttribute(gemm_bf16, cudaFuncAttributeMaxDynamicSharedMemorySize,
                         GEMM_SMEM);
    cudaFuncSetAttribute(gemm64, cudaFuncAttributeMaxDynamicSharedMemorySize,
                         GEMM_SMEM_64);
    cudaFuncSetAttribute(gemm_ln64, cudaFuncAttributeMaxDynamicSharedMemorySize,
                         GEMM_SMEM_LN64);
    cudaFuncSetAttribute(gemm_part64, cudaFuncAttributeMaxDynamicSharedMemorySize,
                         GEMM_SMEM_64);

    void* p;
    cudaGetSymbolAddress(&p, g_Y);        float* Y     = (float*)p;
    cudaGetSymbolAddress(&p, g_Ylast);    float* Ylast = (float*)p;
    cudaGetSymbolAddress(&p, g_part);     float* part  = (float*)p;
    cudaGetSymbolAddress(&p, g_xbf);      __nv_bfloat16* xbf   = (__nv_bfloat16*)p;
    cudaGetSymbolAddress(&p, g_wfc_bf);   __nv_bfloat16* wfcb  = (__nv_bfloat16*)p;
    cudaGetSymbolAddress(&p, g_qkvw_bf);  __nv_bfloat16* qkvwb = (__nv_bfloat16*)p;
    cudaGetSymbolAddress(&p, g_outw_bf);  __nv_bfloat16* outwb = (__nv_bfloat16*)p;
    cudaGetSymbolAddress(&p, g_ff1w_bf);  __nv_bfloat16* ff1wb = (__nv_bfloat16*)p;
    cudaGetSymbolAddress(&p, g_ff2w_bf);  __nv_bfloat16* ff2wb = (__nv_bfloat16*)p;
    cudaGetSymbolAddress(&p, g_h0pbf);    __nv_bfloat16* h0pb  = (__nv_bfloat16*)p;
    cudaGetSymbolAddress(&p, g_qkv0bf);   __nv_bfloat16* qkv0b = (__nv_bfloat16*)p;
    cudaGetSymbolAddress(&p, g_Ybf);      __nv_bfloat16* ybf   = (__nv_bfloat16*)p;
    cudaGetSymbolAddress(&p, g_kv1bf);    __nv_bfloat16* kv1b  = (__nv_bfloat16*)p;
    cudaGetSymbolAddress(&p, g_q1bf);     __nv_bfloat16* q1b   = (__nv_bfloat16*)p;
    cudaGetSymbolAddress(&p, g_ylast0bf); __nv_bfloat16* yl0b  = (__nv_bfloat16*)p;
    cudaGetSymbolAddress(&p, g_ctxbf);    __nv_bfloat16* ctxb  = (__nv_bfloat16*)p;
    cudaGetSymbolAddress(&p, g_ctxlastbf);__nv_bfloat16* ctxlb = (__nv_bfloat16*)p;
    cudaGetSymbolAddress(&p, g_Ylastbf);  __nv_bfloat16* ylbf  = (__nv_bfloat16*)p;
    cudaGetSymbolAddress(&p, g_Hbf);      __nv_bfloat16* hbf   = (__nv_bfloat16*)p;

    cvt_all<<<(CVT_TOTAL / 4 + 255) / 256, 256>>>(x, W_fc, qkv_w, out_w, ff1_w, ff2_w);

    // fc: split-K x4, combine applies bias+ReLU+PE; scatter packs fp32 Y
    gemm_part64<<<dim3(1, NBT / 64, 4), 128, GEMM_SMEM_64>>>(
        xbf, wfcb, part, DIN, DIN / 4, NBT);
    fc_combine<<<(NBT * D + 255) / 256, 256>>>(b_fc);
    scatter_kernel<<<(NT * 32 + 255) / 256, 256>>>();

    // ---- layer 0 ----
    gemm64<<<dim3(3, NBT / 64), 128, GEMM_SMEM_64>>>(
        h0pb, qkvwb, qkv_b, nullptr, qkv0b, 3 * D, D, 0);
    attn0_kernel<<<BATCH * NH, 64>>>();
    gemm_ln64<<<dim3(1, NT / 64), 128, GEMM_SMEM_LN64>>>(
        ctxb, outwb, out_b, ln1_g, ln1_b, Y, Y, ybf, D, 0);
    gemm_bf16<<<dim3(DFF / 128, NT / 128), 128, GEMM_SMEM>>>(
        ybf, ff1wb, ff1_b, nullptr, hbf, DFF, D, 1);
    gemm_part64<<<dim3(1, NT / 64, 2), 128, GEMM_SMEM_64>>>(
        hbf, ff2wb, part, DFF, DFF / 2, NT);
    ln_combine<<<NT / 4, 128>>>(ff2_b, ln2_g, ln2_b);

    // ---- layer 1 (K/V full; Q + tail last-token only) ----
    gemm_bf16<<<dim3(2, NT / 128), 128, GEMM_SMEM>>>(
        ybf, qkvwb + (size_t)3 * D * D + (size_t)D * D, qkv_b + 3 * D + D,
        nullptr, kv1b, KVS, D, 0);
    gather_lastY<<<NBT, D>>>();
    gemm64<<<dim3(1, NBT / 64), 128, GEMM_SMEM_64>>>(
        yl0b, qkvwb + (size_t)3 * D * D, qkv_b + 3 * D, nullptr, q1b, D, D, 0);
    attn1_kernel<<<S_STEPS * BATCH, 128>>>();
    gemm_ln64<<<dim3(1, NBT / 64), 128, GEMM_SMEM_LN64>>>(
        ctxlb, outwb + (size_t)D * D, out_b + D,
        ln1_g + D, ln1_b + D, Y, Ylast, ylbf, D, 1);
    gemm_bf16<<<dim3(DFF / 128, NBT / 128), 128, GEMM_SMEM>>>(
        ylbf, ff1wb + (size_t)DFF * D, ff1_b + DFF, nullptr, hbf, DFF, D, 1);
    gemm_ln64<<<dim3(1, NBT / 64), 128, GEMM_SMEM_LN64>>>(
        hbf, ff2wb + (size_t)D * DFF, ff2_b + D,
        ln2_g + D, ln2_b + D, Ylast, Ylast, ylbf, DFF, 0);

    cls_kernel<<<NBT / CLS_TPB, 128>>>(Wc1, bc1, Wc2, bc2, (float*)d_out);
}

// round 15
// speedup vs baseline: 3.4424x; 1.0144x over previous
#include <cuda_runtime.h>
#include <cuda_bf16.h>
#include <math.h>
#include <stdint.h>

// Problem constants
#define S_STEPS 24
#define BATCH   128
#define SEQT    24
#define DIN     512
#define D       128
#define DFF     2048
#define NH      4
#define DH      32
#define NC      64
#define NT      38400  // BATCH * S*(S+1)/2
#define NBT     3072   // BATCH*SEQT
#define KVS     256    // layer-1 kv row stride

// fp32 scratch
__device__ float g_h0[NBT * D];
__device__ float g_Y[NT * D];
__device__ float g_Ylast[NBT * D];
__device__ float g_part[2ull * NT * D];   // split-K partials (fc, ff2 l0)

// bf16 buffers
__device__ __nv_bfloat16 g_xbf[NBT * DIN];
__device__ __nv_bfloat16 g_wfc_bf[D * DIN];
__device__ __nv_bfloat16 g_qkvw_bf[2 * 3 * D * D];
__device__ __nv_bfloat16 g_outw_bf[2 * D * D];
__device__ __nv_bfloat16 g_ff1w_bf[2 * DFF * D];
__device__ __nv_bfloat16 g_ff2w_bf[2 * D * DFF];
__device__ __nv_bfloat16 g_h0pbf[NBT * D];
__device__ __nv_bfloat16 g_qkv0bf[NBT * 3 * D];
__device__ __nv_bfloat16 g_Ybf[NT * D];
__device__ __nv_bfloat16 g_kv1bf[NT * KVS];
__device__ __nv_bfloat16 g_q1bf[NBT * D];
__device__ __nv_bfloat16 g_ctxbf[NT * D];
__device__ __nv_bfloat16 g_ctxlastbf[NBT * D];
__device__ __nv_bfloat16 g_Ylastbf[NBT * D];
__device__ __nv_bfloat16 g_Hbf[(size_t)NT * DFF];

__device__ __forceinline__ uint32_t smem_u32(const void* p) {
    return (uint32_t)__cvta_generic_to_shared(p);
}

// packed row n -> step s (closed form + integer fixup)
__device__ __forceinline__ int step_of(int n) {
    int u = n >> 6;
    int s = (int)((sqrtf((float)(4 * u + 1)) - 1.f) * 0.5f);
    while (64 * (s + 1) * (s + 2) <= n) s++;
    while (64 * s * (s + 1) > n) s--;
    return s;
}

#define SSTR 40
#define TILE (128 * SSTR)
#define TILE_A64 (64 * SSTR)
#define GEMM_SMEM  (3 * TILE * 2 * 2)
#define GEMM_SMEM_LN64 (3 * (TILE_A64 + TILE) * 2 + 1024)
#define GEMM_SMEM_64   (3 * (TILE_A64 + TILE) * 2)

// ---------------------------------------------------------------------------
// M128 gemm core: 4 warps 2x2, warp 64x64, 3-stage cp.async, m16n8k16
// ---------------------------------------------------------------------------
__device__ __forceinline__ void gemm_core(
    const __nv_bfloat16* __restrict__ A, const __nv_bfloat16* __restrict__ W,
    int K, int m0, int n0, __nv_bfloat16* As, __nv_bfloat16* Bs,
    float (&acc)[4][8][4])
{
    const int t = threadIdx.x, warp = t >> 5, lane = t & 31;
    const int wm = (warp >> 1) * 64, wn = (warp & 1) * 64;
    const int xr = lane & 15, xc = (lane >> 4) * 8;

#pragma unroll
    for (int i = 0; i < 4; ++i)
#pragma unroll
        for (int j = 0; j < 8; ++j)
#pragma unroll
            for (int k = 0; k < 4; ++k) acc[i][j][k] = 0.f;

    auto issue = [&](int k0, int st) {
        __nv_bfloat16* as = As + st * TILE;
        __nv_bfloat16* bs = Bs + st * TILE;
#pragma unroll
        for (int r = 0; r < 8; ++r) {
            int idx = t + r * 128;
            int op  = idx >> 9;
            int rem = idx & 511;
            int row = rem >> 2, c8 = (rem & 3) * 8;
            uint32_t dst = smem_u32((op ? bs : as) + row * SSTR + c8);
            const __nv_bfloat16* src = op
                ? (W + (size_t)(n0 + row) * K + k0 + c8)
                : (A + (size_t)(m0 + row) * K + k0 + c8);
            asm volatile("cp.async.cg.shared.global [%0], [%1], 16;"
                :: "r"(dst), "l"(src));
        }
        asm volatile("cp.async.commit_group;");
    };

    const int KT = K >> 5;
    issue(0, 0);
    issue(32, 1);
    for (int kt = 0; kt < KT; ++kt) {
        if (kt + 1 < KT) { asm volatile("cp.async.wait_group 1;"); }
        else             { asm volatile("cp.async.wait_group 0;"); }
        __syncthreads();
        if (kt + 2 < KT) issue((kt + 2) << 5, (kt + 2) % 3);

        const __nv_bfloat16* as = As + (kt % 3) * TILE;
        const __nv_bfloat16* bs = Bs + (kt % 3) * TILE;

        uint32_t af[2][4][4];
        uint32_t bfr[2][8][2];
#pragma unroll
        for (int si = 0; si < 2; ++si) {
            int ks = si * 16;
#pragma unroll
            for (int mi = 0; mi < 4; ++mi) {
                uint32_t ad = smem_u32(&as[(wm + mi * 16 + xr) * SSTR + ks + xc]);
                asm volatile("ldmatrix.sync.aligned.m8n8.x4.shared.b16 {%0,%1,%2,%3},[%4];"
                    : "=r"(af[si][mi][0]), "=r"(af[si][mi][1]),
                      "=r"(af[si][mi][2]), "=r"(af[si][mi][3])
                    : "r"(ad));
            }
#pragma unroll
            for (int np = 0; np < 4; ++np) {
                uint32_t bd = smem_u32(&bs[(wn + np * 16 + xr) * SSTR + ks + xc]);
                uint32_t r0, r1, r2, r3;
                asm volatile("ldmatrix.sync.aligned.m8n8.x4.shared.b16 {%0,%1,%2,%3},[%4];"
                    : "=r"(r0), "=r"(r1), "=r"(r2), "=r"(r3) : "r"(bd));
                bfr[si][2 * np][0] = r0; bfr[si][2 * np + 1][0] = r1;
                bfr[si][2 * np][1] = r2; bfr[si][2 * np + 1][1] = r3;
            }
        }
#pragma unroll
        for (int si = 0; si < 2; ++si)
#pragma unroll
            for (int mi = 0; mi < 4; ++mi)
#pragma unroll
                for (int ni = 0; ni < 8; ++ni) {
                    asm volatile(
                        "mma.sync.aligned.m16n8k16.row.col.f32.bf16.bf16.f32 "
                        "{%0,%1,%2,%3},{%4,%5,%6,%7},{%8,%9},{%0,%1,%2,%3};"
                        : "+f"(acc[mi][ni][0]), "+f"(acc[mi][ni][1]),
                          "+f"(acc[mi][ni][2]), "+f"(acc[mi][ni][3])
                        : "r"(af[si][mi][0]), "r"(af[si][mi][1]),
                          "r"(af[si][mi][2]), "r"(af[si][mi][3]),
                          "r"(bfr[si][ni][0]), "r"(bfr[si][ni][1]));
                }
    }
}

// ---------------------------------------------------------------------------
// M64 gemm core: 4 warps (2x2), warp 32x64.
// amap=1: A row index is compact (b*SEQT+s) and is mapped to the packed
// last-token row 64s(s+1)+b(s+1)+s before loading (A then has stride ld).
// ---------------------------------------------------------------------------
__device__ __forceinline__ void gemm_core64(
    const __nv_bfloat16* __restrict__ A, const __nv_bfloat16* __restrict__ W,
    int ld, int K, int m0, int amap, __nv_bfloat16* As, __nv_bfloat16* Bs,
    float (&acc)[2][8][4])
{
    const int t = threadIdx.x, warp = t >> 5, lane = t & 31;
    const int wm = (warp >> 1) * 32, wn = (warp & 1) * 64;
    const int xr = lane & 15, xc = (lane >> 4) * 8;

#pragma unroll
    for (int i = 0; i < 2; ++i)
#pragma unroll
        for (int j = 0; j < 8; ++j)
#pragma unroll
            for (int k = 0; k < 4; ++k) acc[i][j][k] = 0.f;

    auto issue = [&](int k0, int st) {
        __nv_bfloat16* as = As + st * TILE_A64;
        __nv_bfloat16* bs = Bs + st * TILE;
#pragma unroll
        for (int r = 0; r < 6; ++r) {
            int idx = t + r * 128;
            if (idx < 256) {
                int row = idx >> 2, c8 = (idx & 3) * 8;
                int grow = m0 + row;
                if (amap) {
                    int b = grow / SEQT, ss = grow - b * SEQT;
                    grow = 64 * ss * (ss + 1) + b * (ss + 1) + ss;
                }
                asm volatile("cp.async.cg.shared.global [%0], [%1], 16;"
                    :: "r"(smem_u32(as + row * SSTR + c8)),
                       "l"(A + (size_t)grow * ld + k0 + c8));
            } else {
                int rem = idx - 256;
                int row = rem >> 2, c8 = (rem & 3) * 8;
                asm volatile("cp.async.cg.shared.global [%0], [%1], 16;"
                    :: "r"(smem_u32(bs + row * SSTR + c8)),
                       "l"(W + (size_t)row * ld + k0 + c8));
            }
        }
        asm volatile("cp.async.commit_group;");
    };

    const int KT = K >> 5;
    issue(0, 0);
    issue(32, 1);
    for (int kt = 0; kt < KT; ++kt) {
        if (kt + 1 < KT) { asm volatile("cp.async.wait_group 1;"); }
        else             { asm volatile("cp.async.wait_group 0;"); }
        __syncthreads();
        if (kt + 2 < KT) issue((kt + 2) << 5, (kt + 2) % 3);

        const __nv_bfloat16* as = As + (kt % 3) * TILE_A64;
        const __nv_bfloat16* bs = Bs + (kt % 3) * TILE;
#pragma unroll
        for (int si = 0; si < 2; ++si) {
            int ks = si * 16;
            uint32_t af[2][4];
#pragma unroll
            for (int mi = 0; mi < 2; ++mi) {
                uint32_t ad = smem_u32(&as[(wm + mi * 16 + xr) * SSTR + ks + xc]);
                asm volatile("ldmatrix.sync.aligned.m8n8.x4.shared.b16 {%0,%1,%2,%3},[%4];"
                    : "=r"(af[mi][0]), "=r"(af[mi][1]), "=r"(af[mi][2]), "=r"(af[mi][3])
                    : "r"(ad));
            }
            uint32_t bfr[8][2];
#pragma unroll
            for (int np = 0; np < 4; ++np) {
                uint32_t bd = smem_u32(&bs[(wn + np * 16 + xr) * SSTR + ks + xc]);
                uint32_t r0, r1, r2, r3;
                asm volatile("ldmatrix.sync.aligned.m8n8.x4.shared.b16 {%0,%1,%2,%3},[%4];"
                    : "=r"(r0), "=r"(r1), "=r"(r2), "=r"(r3) : "r"(bd));
                bfr[2 * np][0] = r0; bfr[2 * np + 1][0] = r1;
                bfr[2 * np][1] = r2; bfr[2 * np + 1][1] = r3;
            }
#pragma unroll
            for (int mi = 0; mi < 2; ++mi)
#pragma unroll
                for (int ni = 0; ni < 8; ++ni) {
                    asm volatile(
                        "mma.sync.aligned.m16n8k16.row.col.f32.bf16.bf16.f32 "
                        "{%0,%1,%2,%3},{%4,%5,%6,%7},{%8,%9},{%0,%1,%2,%3};"
                        : "+f"(acc[mi][ni][0]), "+f"(acc[mi][ni][1]),
                          "+f"(acc[mi][ni][2]), "+f"(acc[mi][ni][3])
                        : "r"(af[mi][0]), "r"(af[mi][1]),
                          "r"(af[mi][2]), "r"(af[mi][3]),
                          "r"(bfr[ni][0]), "r"(bfr[ni][1]));
                }
        }
    }
}

// ---------------------------------------------------------------------------
// Plain GEMM (M128)
// ---------------------------------------------------------------------------
__global__ __launch_bounds__(128, 2) void gemm_bf16(
    const __nv_bfloat16* __restrict__ A, const __nv_bfloat16* __restrict__ W,
    const float* __restrict__ bias, float* __restrict__ Cf,
    __nv_bfloat16* __restrict__ Cb, int N, int K, int relu)
{
    extern __shared__ __align__(16) char dyn[];
    __nv_bfloat16* As = (__nv_bfloat16*)dyn;
    __nv_bfloat16* Bs = As + 3 * TILE;

    const int m0 = blockIdx.y * 128, n0 = blockIdx.x * 128;
    const int t = threadIdx.x, warp = t >> 5, lane = t & 31;
    const int g = lane >> 2, tig = lane & 3;
    const int wm = (warp >> 1) * 64, wn = (warp & 1) * 64;

    float acc[4][8][4];
    gemm_core(A, W, K, m0, n0, As, Bs, acc);

#pragma unroll
    for (int mi = 0; mi < 4; ++mi) {
#pragma unroll
        for (int ni = 0; ni < 8; ++ni) {
            int col = n0 + wn + ni * 8 + 2 * tig;
            float b0v = bias[col], b1v = bias[col + 1];
            int row = m0 + wm + mi * 16 + g;
            float2 v0 = make_float2(acc[mi][ni][0] + b0v, acc[mi][ni][1] + b1v);
            float2 v1 = make_float2(acc[mi][ni][2] + b0v, acc[mi][ni][3] + b1v);
            if (relu) {
                v0.x = fmaxf(v0.x, 0.f); v0.y = fmaxf(v0.y, 0.f);
                v1.x = fmaxf(v1.x, 0.f); v1.y = fmaxf(v1.y, 0.f);
            }
            if (Cf) {
                *(float2*)(Cf + (size_t)row * N + col)       = v0;
                *(float2*)(Cf + (size_t)(row + 8) * N + col) = v1;
            }
            if (Cb) {
                *(__nv_bfloat162*)(Cb + (size_t)row * N + col) =
                    __floats2bfloat162_rn(v0.x, v0.y);
                *(__nv_bfloat162*)(Cb + (size_t)(row + 8) * N + col) =
                    __floats2bfloat162_rn(v1.x, v1.y);
            }
        }
    }
}

// ---------------------------------------------------------------------------
// Plain GEMM (M64). Grid (N/128, M/64). amap per gemm_core64.
// ---------------------------------------------------------------------------
__global__ __launch_bounds__(128, 3) void gemm64(
    const __nv_bfloat16* __restrict__ A, const __nv_bfloat16* __restrict__ W,
    const float* __restrict__ bias, float* __restrict__ Cf,
    __nv_bfloat16* __restrict__ Cb, int N, int K, int ldA, int amap, int relu)
{
    extern __shared__ __align__(16) char dyn[];
    __nv_bfloat16* As = (__nv_bfloat16*)dyn;
    __nv_bfloat16* Bs = As + 3 * TILE_A64;

    const int m0 = blockIdx.y * 64, n0 = blockIdx.x * 128;
    const int t = threadIdx.x, warp = t >> 5, lane = t & 31;
    const int g = lane >> 2, tig = lane & 3;
    const int wm = (warp >> 1) * 32, wn = (warp & 1) * 64;

    float acc[2][8][4];
    // W tile pointer: rows n0..n0+127 with stride K (weights always dense)
    gemm_core64(A, W + (size_t)n0 * K, ldA, K, m0, amap, As, Bs, acc);

#pragma unroll
    for (int mi = 0; mi < 2; ++mi) {
#pragma unroll
        for (int ni = 0; ni < 8; ++ni) {
            int col = n0 + wn + ni * 8 + 2 * tig;
            float b0v = bias[col], b1v = bias[col + 1];
            int row = m0 + wm + mi * 16 + g;
            float2 v0 = make_float2(acc[mi][ni][0] + b0v, acc[mi][ni][1] + b1v);
            float2 v1 = make_float2(acc[mi][ni][2] + b0v, acc[mi][ni][3] + b1v);
            if (relu) {
                v0.x = fmaxf(v0.x, 0.f); v0.y = fmaxf(v0.y, 0.f);
                v1.x = fmaxf(v1.x, 0.f); v1.y = fmaxf(v1.y, 0.f);
            }
            if (Cf) {
                *(float2*)(Cf + (size_t)row * N + col)       = v0;
                *(float2*)(Cf + (size_t)(row + 8) * N + col) = v1;
            }
            if (Cb) {
                *(__nv_bfloat162*)(Cb + (size_t)row * N + col) =
                    __floats2bfloat162_rn(v0.x, v0.y);
                *(__nv_bfloat162*)(Cb + (size_t)(row + 8) * N + col) =
                    __floats2bfloat162_rn(v1.x, v1.y);
            }
        }
    }
}

// ---------------------------------------------------------------------------
// GEMM + residual + LayerNorm, M64. N == 128.
// gather=0: residual row n of Rres (dense)
// gather=1: residual = packed Rres at last-token map of compact row n
// gather=2: residual = g_h0 at (b*SEQT+t) derived from PACKED row n
// ---------------------------------------------------------------------------
__global__ __launch_bounds__(128, 3) void gemm_ln64(
    const __nv_bfloat16* __restrict__ A, const __nv_bfloat16* __restrict__ W,
    const float* __restrict__ bias, const float* __restrict__ lng,
    const float* __restrict__ lnb, const float* __restrict__ Rres,
    float* __restrict__ Yout, __nv_bfloat16* __restrict__ Ybf,
    int K, int gather)
{
    extern __shared__ __align__(16) char dyn[];
    __nv_bfloat16* As = (__nv_bfloat16*)dyn;
    __nv_bfloat16* Bs = As + 3 * TILE_A64;
    float* redS = (float*)(dyn + 3 * (TILE_A64 + TILE) * 2);  // [2][64]
    float* redQ = redS + 128;

    const int m0 = blockIdx.y * 64;
    const int t = threadIdx.x, warp = t >> 5, lane = t & 31;
    const int g = lane >> 2, tig = lane & 3;
    const int wm = (warp >> 1) * 32, wn = (warp & 1) * 64;
    const int cw = warp & 1;

    float acc[2][8][4];
    gemm_core64(A, W, K, K, m0, 0, As, Bs, acc);

    auto res_row = [&](int n) -> const float* {
        if (gather == 1) {
            int b = n / SEQT, s = n - b * SEQT;
            int src = 64 * s * (s + 1) + b * (s + 1) + s;
            return Rres + (size_t)src * D;
        }
        if (gather == 2) {
            int s = step_of(n);
            int r = n - 64 * s * (s + 1);
            int P = s + 1;
            int b = r / P;
            int tt = r - b * P;
            return g_h0 + (size_t)(b * SEQT + tt) * D;
        }
        return Rres + (size_t)n * D;
    };

#pragma unroll
    for (int mi = 0; mi < 2; ++mi) {
        int r0 = wm + mi * 16 + g, r1 = r0 + 8;
        const float* R0 = res_row(m0 + r0);
        const float* R1 = res_row(m0 + r1);
        float s0 = 0.f, q0 = 0.f, s1 = 0.f, q1 = 0.f;
#pragma unroll
        for (int ni = 0; ni < 8; ++ni) {
            int col = wn + ni * 8 + 2 * tig;
            float2 bv = *(const float2*)(bias + col);
            float2 y0 = *(const float2*)(R0 + col);
            float2 y1 = *(const float2*)(R1 + col);
            float a0 = acc[mi][ni][0] + bv.x + y0.x;
            float a1 = acc[mi][ni][1] + bv.y + y0.y;
            float a2 = acc[mi][ni][2] + bv.x + y1.x;
            float a3 = acc[mi][ni][3] + bv.y + y1.y;
            acc[mi][ni][0] = a0; acc[mi][ni][1] = a1;
            acc[mi][ni][2] = a2; acc[mi][ni][3] = a3;
            s0 += a0 + a1; q0 += a0 * a0 + a1 * a1;
            s1 += a2 + a3; q1 += a2 * a2 + a3 * a3;
        }
#pragma unroll
        for (int o = 1; o <= 2; o <<= 1) {
            s0 += __shfl_xor_sync(0xffffffffu, s0, o);
            q0 += __shfl_xor_sync(0xffffffffu, q0, o);
            s1 += __shfl_xor_sync(0xffffffffu, s1, o);
            q1 += __shfl_xor_sync(0xffffffffu, q1, o);
        }
        if (tig == 0) {
            redS[cw * 64 + r0] = s0; redQ[cw * 64 + r0] = q0;
            redS[cw * 64 + r1] = s1; redQ[cw * 64 + r1] = q1;
        }
    }
    __syncthreads();

#pragma unroll
    for (int mi = 0; mi < 2; ++mi) {
        int r0 = wm + mi * 16 + g, r1 = r0 + 8;
        float S0 = redS[r0] + redS[64 + r0], Q0 = redQ[r0] + redQ[64 + r0];
        float S1 = redS[r1] + redS[64 + r1], Q1 = redQ[r1] + redQ[64 + r1];
        float mu0 = S0 * (1.f / 128.f), mu1 = S1 * (1.f / 128.f);
        float iv0 = rsqrtf(Q0 * (1.f / 128.f) - mu0 * mu0 + 1e-5f);
        float iv1 = rsqrtf(Q1 * (1.f / 128.f) - mu1 * mu1 + 1e-5f);
#pragma unroll
        for (int ni = 0; ni < 8; ++ni) {
            int col = wn + ni * 8 + 2 * tig;
            float2 gv = *(const float2*)(lng + col);
            float2 bv = *(const float2*)(lnb + col);
            float o0 = (acc[mi][ni][0] - mu0) * iv0 * gv.x + bv.x;
            float o1 = (acc[mi][ni][1] - mu0) * iv0 * gv.y + bv.y;
            float o2 = (acc[mi][ni][2] - mu1) * iv1 * gv.x + bv.x;
            float o3 = (acc[mi][ni][3] - mu1) * iv1 * gv.y + bv.y;
            *(float2*)(Yout + (size_t)(m0 + r0) * D + col) = make_float2(o0, o1);
            *(float2*)(Yout + (size_t)(m0 + r1) * D + col) = make_float2(o2, o3);
            *(__nv_bfloat162*)(Ybf + (size_t)(m0 + r0) * D + col) =
                __floats2bfloat162_rn(o0, o1);
            *(__nv_bfloat162*)(Ybf + (size_t)(m0 + r1) * D + col) =
                __floats2bfloat162_rn(o2, o3);
        }
    }
}

// ---------------------------------------------------------------------------
// Split-K partial GEMM, M64, N=128, fp32 partials. blockIdx.z = part.
// ---------------------------------------------------------------------------
__global__ __launch_bounds__(128, 3) void gemm_part64(
    const __nv_bfloat16* __restrict__ A, const __nv_bfloat16* __restrict__ W,
    float* __restrict__ P, int ld, int Kpart, int Mtot)
{
    extern __shared__ __align__(16) char dyn[];
    __nv_bfloat16* As = (__nv_bfloat16*)dyn;
    __nv_bfloat16* Bs = As + 3 * TILE_A64;

    const int m0 = blockIdx.y * 64;
    const int part = blockIdx.z;
    A += (size_t)part * Kpart;
    W += (size_t)part * Kpart;
    P += (size_t)part * Mtot * D;

    const int t = threadIdx.x, warp = t >> 5, lane = t & 31;
    const int g = lane >> 2, tig = lane & 3;
    const int wm = (warp >> 1) * 32, wn = (warp & 1) * 64;

    float acc[2][8][4];
    gemm_core64(A, W, ld, Kpart, m0, 0, As, Bs, acc);

#pragma unroll
    for (int mi = 0; mi < 2; ++mi) {
        int r0 = wm + mi * 16 + g, r1 = r0 + 8;
#pragma unroll
        for (int ni = 0; ni < 8; ++ni) {
            int col = wn + ni * 8 + 2 * tig;
            *(float2*)(P + (size_t)(m0 + r0) * D + col) =
                make_float2(acc[mi][ni][0], acc[mi][ni][1]);
            *(float2*)(P + (size_t)(m0 + r1) * D + col) =
                make_float2(acc[mi][ni][2], acc[mi][ni][3]);
        }
    }
}

// ---------------------------------------------------------------------------
// fc combine: h0 = relu(P0..P3 + b_fc) + PE; writes fp32 + bf16
// ---------------------------------------------------------------------------
__global__ void fc_combine(const float* __restrict__ bias)
{
    int i = blockIdx.x * 256 + threadIdx.x;
    if (i >= NBT * D) return;
    int n = i >> 7, d = i & 127;
    int t = n % SEQT;
    float v = g_part[i] + g_part[NBT * D + i] + g_part[2 * NBT * D + i]
            + g_part[3 * NBT * D + i] + bias[d];
    v = fmaxf(v, 0.f);
    float freq = expf((float)(d & ~1) * (-9.210340371976184f / 128.f));
    float arg  = (float)t * freq;
    v += (d & 1) ? cosf(arg) : sinf(arg);
    g_h0[i]    = v;
    g_h0pbf[i] = __float2bfloat16(v);
}

// ---------------------------------------------------------------------------
// ff2-l0 combine + residual + LayerNorm
// ---------------------------------------------------------------------------
__global__ __launch_bounds__(128) void ln_combine(
    const float* __restrict__ bias, const float* __restrict__ lng,
    const float* __restrict__ lnb)
{
    int n    = blockIdx.x * 4 + (threadIdx.x >> 5);
    int lane = threadIdx.x & 31;
    float v[4], s = 0.f, q = 0.f;
#pragma unroll
    for (int i = 0; i < 4; ++i) {
        int d = lane + 32 * i;
        size_t off = (size_t)n * D + d;
        v[i] = g_Y[off] + g_part[off] + g_part[(size_t)NT * D + off] + bias[d];
        s += v[i]; q += v[i] * v[i];
    }
    for (int o = 16; o; o >>= 1) {
        s += __shfl_xor_sync(0xffffffffu, s, o);
        q += __shfl_xor_sync(0xffffffffu, q, o);
    }
    float mu = s * (1.f / 128.f);
    float iv = rsqrtf(q * (1.f / 128.f) - mu * mu + 1e-5f);
#pragma unroll
    for (int i = 0; i < 4; ++i) {
        int d = lane + 32 * i;
        size_t off = (size_t)n * D + d;
        float o = (v[i] - mu) * iv * lng[d] + lnb[d];
        g_Y[off]   = o;
        g_Ybf[off] = __float2bfloat16(o);
    }
}

// ---------------------------------------------------------------------------
// One-shot fp32 -> bf16 conversion
// ---------------------------------------------------------------------------
#define CVT_TOTAL 2818048
__global__ void cvt_all(const float* __restrict__ x, const float* __restrict__ wfc,
                        const float* __restrict__ qkvw, const float* __restrict__ outw,
                        const float* __restrict__ ff1w, const float* __restrict__ ff2w)
{
    int i = (blockIdx.x * 256 + threadIdx.x) * 4;
    if (i >= CVT_TOTAL) return;
    const float* s; __nv_bfloat16* d; int off;
    if      (i < 1572864) { s = x;    d = g_xbf;     off = i; }
    else if (i < 1638400) { s = wfc;  d = g_wfc_bf;  off = i - 1572864; }
    else if (i < 1736704) { s = qkvw; d = g_qkvw_bf; off = i - 1638400; }
    else if (i < 1769472) { s = outw; d = g_outw_bf; off = i - 1736704; }
    else if (i < 2293760) { s = ff1w; d = g_ff1w_bf; off = i - 1769472; }
    else                  { s = ff2w; d = g_ff2w_bf; off = i - 2293760; }
    float4 v = *(const float4*)(s + off);
    *(__nv_bfloat162*)(d + off)     = __floats2bfloat162_rn(v.x, v.y);
    *(__nv_bfloat162*)(d + off + 2) = __floats2bfloat162_rn(v.z, v.w);
}

// ---------------------------------------------------------------------------
// Layer-0 attention, prefix-dedup: one block per (b,h); 24x24 scores once,
// online-softmax prefix scan emits ctx for every step s >= t.
// ---------------------------------------------------------------------------
__global__ __launch_bounds__(64) void attn0_kernel()
{
    __shared__ float qs[SEQT][DH], ks[SEQT][DH], vs[SEQT][DH];
    __shared__ float sc[SEQT][SEQT];

    int blk = blockIdx.x;
    int b = blk >> 2;
    int h = blk & 3;
    int tid  = threadIdx.x;
    int w    = tid >> 5;
    int lane = tid & 31;

    for (int i = tid; i < SEQT * DH; i += 64) {
        int t = i >> 5, dd = i & 31;
        const __nv_bfloat16* row =
            g_qkv0bf + (size_t)(b * SEQT + t) * (3 * D) + h * DH + dd;
        qs[t][dd] = __bfloat162float(row[0]);
        ks[t][dd] = __bfloat162float(row[D]);
        vs[t][dd] = __bfloat162float(row[2 * D]);
    }
    __syncthreads();

    for (int p = tid; p < SEQT * SEQT; p += 64) {
        int t = p / SEQT, j = p - t * SEQT;
        float a = 0.f;
#pragma unroll
        for (int dd = 0; dd < DH; ++dd) a += qs[t][dd] * ks[j][dd];
        sc[t][j] = a * 0.17677669529663687f;
    }
    __syncthreads();

    for (int t = w; t < SEQT; t += 2) {
        float m = -1e30f, l = 0.f, acc = 0.f;
        for (int j = 0; j < SEQT; ++j) {
            float x = sc[t][j];
            float nm = fmaxf(m, x);
            float so = __expf(m - nm);
            float e  = __expf(x - nm);
            l   = l * so + e;
            acc = acc * so + e * vs[j][lane];
            m = nm;
            if (j >= t) {
                int dst = 64 * j * (j + 1) + b * (j + 1) + t;
                g_ctxbf[(size_t)dst * D + h * DH + lane] =
                    __float2bfloat16(acc / l);
            }
        }
    }
}

// ---------------------------------------------------------------------------
// Layer-1 attention, LAST query only
// ---------------------------------------------------------------------------
__global__ __launch_bounds__(128) void attn1_kernel()
{
    __shared__ float qs[NH][DH];
    __shared__ float ps[NH][32];

    int q = blockIdx.x;
    int s = q >> 7;
    int b = q & 127;
    int P = s + 1;
    int base = 64 * s * (s + 1) + b * P;
    int tid  = threadIdx.x;
    int h    = tid >> 5;
    int lane = tid & 31;

    qs[h][lane] = __bfloat162float(
        g_q1bf[(size_t)(b * SEQT + s) * D + h * DH + lane]);
    __syncthreads();

    float sc = -1e30f;
    if (lane < P) {
        const __nv_bfloat16* krow = g_kv1bf + (size_t)(base + lane) * KVS + h * DH;
        float a = 0.f;
#pragma unroll
        for (int dd = 0; dd < DH; ++dd) a += qs[h][dd] * __bfloat162float(krow[dd]);
        sc = a * 0.17677669529663687f;
    }
    float m = sc;
    for (int o = 16; o; o >>= 1) m = fmaxf(m, __shfl_xor_sync(0xffffffffu, m, o));
    float e = (lane < P) ? expf(sc - m) : 0.f;
    float sum = e;
    for (int o = 16; o; o >>= 1) sum += __shfl_xor_sync(0xffffffffu, sum, o);
    ps[h][lane] = e / sum;
    __syncwarp();

    float c = 0.f;
    for (int j = 0; j < P; ++j)
        c += ps[h][j] * __bfloat162float(
                 g_kv1bf[(size_t)(base + j) * KVS + D + h * DH + lane]);
    g_ctxlastbf[(size_t)(b * SEQT + s) * D + h * DH + lane] = __float2bfloat16(c);
}

// ---------------------------------------------------------------------------
// Classifier + log_softmax: 16 tokens per block, Wc1 staged in smem once.
// ---------------------------------------------------------------------------
#define CLS_TPB 16
__global__ __launch_bounds__(128) void cls_kernel(
    const float* __restrict__ Wc1, const float* __restrict__ bc1,
    const float* __restrict__ Wc2, const float* __restrict__ bc2,
    float* __restrict__ out)
{
    __shared__ float w1s[NC * D];
    __shared__ float rows[CLS_TPB][D];
    __shared__ float c1s[CLS_TPB][NC];

    int n0 = blockIdx.x * CLS_TPB;
    int t  = threadIdx.x;

    for (int i = t; i < NC * D / 4; i += 128)
        ((float4*)w1s)[i] = ((const float4*)Wc1)[i];
    for (int i = t; i < CLS_TPB * D / 4; i += 128) {
        int tok = i >> 5, c = i & 31;
        ((float4*)rows[tok])[c] =
            ((const float4*)(g_Ylast + (size_t)(n0 + tok) * D))[c];
    }
    __syncthreads();

#pragma unroll
    for (int p = 0; p < CLS_TPB * NC / 128; ++p) {
        int pair = t + p * 128;
        int tok = pair >> 6, o = pair & 63;
        float a = bc1[o];
        const float* wr = w1s + o * D;
        const float* rr = rows[tok];
#pragma unroll
        for (int d = 0; d < D; ++d) a += rr[d] * wr[d];
        c1s[tok][o] = fmaxf(a, 0.f);
    }
    __syncthreads();

    if (t < CLS_TPB) {
        float l0 = bc2[0], l1 = bc2[1];
#pragma unroll
        for (int j = 0; j < NC; ++j) {
            float c = c1s[t][j];
            l0 += c * Wc2[j];
            l1 += c * Wc2[NC + j];
        }
        float m   = fmaxf(l0, l1);
        float lse = m + logf(expf(l0 - m) + expf(l1 - m));
        out[(n0 + t) * 2 + 0] = l0 - lse;
        out[(n0 + t) * 2 + 1] = l1 - lse;
    }
}

// ---------------------------------------------------------------------------
extern "C" void kernel_launch(void* const* d_in, const int* in_sizes, int n_in,
                              void* d_out, int out_size)
{
    const float* x     = (const float*)d_in[0];
    const float* W_fc  = (const float*)d_in[1];
    const float* b_fc  = (const float*)d_in[2];
    const float* qkv_w = (const float*)d_in[3];
    const float* qkv_b = (const float*)d_in[4];
    const float* out_w = (const float*)d_in[5];
    const float* out_b = (const float*)d_in[6];
    const float* ln1_g = (const float*)d_in[7];
    const float* ln1_b = (const float*)d_in[8];
    const float* ln2_g = (const float*)d_in[9];
    const float* ln2_b = (const float*)d_in[10];
    const float* ff1_w = (const float*)d_in[11];
    const float* ff1_b = (const float*)d_in[12];
    const float* ff2_w = (const float*)d_in[13];
    const float* ff2_b = (const float*)d_in[14];
    const float* Wc1   = (const float*)d_in[15];
    const float* bc1   = (const float*)d_in[16];
    const float* Wc2   = (const float*)d_in[17];
    const float* bc2   = (const float*)d_in[18];

    cudaFuncSetAttribute(gemm_bf16, cudaFuncAttributeMaxDynamicSharedMemorySize,
                         GEMM_SMEM);
    cudaFuncSetAttribute(gemm64, cudaFuncAttributeMaxDynamicSharedMemorySize,
                         GEMM_SMEM_64);
    cudaFuncSetAttribute(gemm_ln64, cudaFuncAttributeMaxDynamicSharedMemorySize,
                         GEMM_SMEM_LN64);
    cudaFuncSetAttribute(gemm_part64, cudaFuncAttributeMaxDynamicSharedMemorySize,
                         GEMM_SMEM_64);

    void* p;
    cudaGetSymbolAddress(&p, g_Y);        float* Y     = (float*)p;
    cudaGetSymbolAddress(&p, g_Ylast);    float* Ylast = (float*)p;
    cudaGetSymbolAddress(&p, g_part);     float* part  = (float*)p;
    cudaGetSymbolAddress(&p, g_xbf);      __nv_bfloat16* xbf   = (__nv_bfloat16*)p;
    cudaGetSymbolAddress(&p, g_wfc_bf);   __nv_bfloat16* wfcb  = (__nv_bfloat16*)p;
    cudaGetSymbolAddress(&p, g_qkvw_bf);  __nv_bfloat16* qkvwb = (__nv_bfloat16*)p;
    cudaGetSymbolAddress(&p, g_outw_bf);  __nv_bfloat16* outwb = (__nv_bfloat16*)p;
    cudaGetSymbolAddress(&p, g_ff1w_bf);  __nv_bfloat16* ff1wb = (__nv_bfloat16*)p;
    cudaGetSymbolAddress(&p, g_ff2w_bf);  __nv_bfloat16* ff2wb = (__nv_bfloat16*)p;
    cudaGetSymbolAddress(&p, g_h0pbf);    __nv_bfloat16* h0pb  = (__nv_bfloat16*)p;
    cudaGetSymbolAddress(&p, g_qkv0bf);   __nv_bfloat16* qkv0b = (__nv_bfloat16*)p;
    cudaGetSymbolAddress(&p, g_Ybf);      __nv_bfloat16* ybf   = (__nv_bfloat16*)p;
    cudaGetSymbolAddress(&p, g_kv1bf);    __nv_bfloat16* kv1b  = (__nv_bfloat16*)p;
    cudaGetSymbolAddress(&p, g_q1bf);     __nv_bfloat16* q1b   = (__nv_bfloat16*)p;
    cudaGetSymbolAddress(&p, g_ctxbf);    __nv_bfloat16* ctxb  = (__nv_bfloat16*)p;
    cudaGetSymbolAddress(&p, g_ctxlastbf);__nv_bfloat16* ctxlb = (__nv_bfloat16*)p;
    cudaGetSymbolAddress(&p, g_Ylastbf);  __nv_bfloat16* ylbf  = (__nv_bfloat16*)p;
    cudaGetSymbolAddress(&p, g_Hbf);      __nv_bfloat16* hbf   = (__nv_bfloat16*)p;

    cvt_all<<<(CVT_TOTAL / 4 + 255) / 256, 256>>>(x, W_fc, qkv_w, out_w, ff1_w, ff2_w);

    // fc: split-K x4, combine applies bias+ReLU+PE (no packed scatter needed)
    gemm_part64<<<dim3(1, NBT / 64, 4), 128, GEMM_SMEM_64>>>(
        xbf, wfcb, part, DIN, DIN / 4, NBT);
    fc_combine<<<(NBT * D + 255) / 256, 256>>>(b_fc);

    // ---- layer 0 ----
    gemm64<<<dim3(3, NBT / 64), 128, GEMM_SMEM_64>>>(
        h0pb, qkvwb, qkv_b, nullptr, qkv0b, 3 * D, D, D, 0, 0);
    attn0_kernel<<<BATCH * NH, 64>>>();
    // proj l0: residual read straight from h0 via packed->(b,t) map
    gemm_ln64<<<dim3(1, NT / 64), 128, GEMM_SMEM_LN64>>>(
        ctxb, outwb, out_b, ln1_g, ln1_b, nullptr, Y, ybf, D, 2);
    gemm_bf16<<<dim3(DFF / 128, NT / 128), 128, GEMM_SMEM>>>(
        ybf, ff1wb, ff1_b, nullptr, hbf, DFF, D, 1);
    gemm_part64<<<dim3(1, NT / 64, 2), 128, GEMM_SMEM_64>>>(
        hbf, ff2wb, part, DFF, DFF / 2, NT);
    ln_combine<<<NT / 4, 128>>>(ff2_b, ln2_g, ln2_b);

    // ---- layer 1 (K/V full; Q + tail last-token only) ----
    gemm_bf16<<<dim3(2, NT / 128), 128, GEMM_SMEM>>>(
        ybf, qkvwb + (size_t)3 * D * D + (size_t)D * D, qkv_b + 3 * D + D,
        nullptr, kv1b, KVS, D, 0);
    // q1: A rows gathered from packed Ybf inside the GEMM (amap=1)
    gemm64<<<dim3(1, NBT / 64), 128, GEMM_SMEM_64>>>(
        ybf, qkvwb + (size_t)3 * D * D, qkv_b + 3 * D, nullptr, q1b,
        D, D, D, 1, 0);
    attn1_kernel<<<S_STEPS * BATCH, 128>>>();
    gemm_ln64<<<dim3(1, NBT / 64), 128, GEMM_SMEM_LN64>>>(
        ctxlb, outwb + (size_t)D * D, out_b + D,
        ln1_g + D, ln1_b + D, Y, Ylast, ylbf, D, 1);
    gemm_bf16<<<dim3(DFF / 128, NBT / 128), 128, GEMM_SMEM>>>(
        ylbf, ff1wb + (size_t)DFF * D, ff1_b + DFF, nullptr, hbf, DFF, D, 1);
    gemm_ln64<<<dim3(1, NBT / 64), 128, GEMM_SMEM_LN64>>>(
        hbf, ff2wb + (size_t)D * DFF, ff2_b + D,
        ln2_g + D, ln2_b + D, Ylast, Ylast, ylbf, DFF, 0);

    cls_kernel<<<NBT / CLS_TPB, 128>>>(Wc1, bc1, Wc2, bc2, (float*)d_out);
}

// round 16
// speedup vs baseline: 3.6109x; 1.0490x over previous
#include <cuda_runtime.h>
#include <cuda_bf16.h>
#include <math.h>
#include <stdint.h>

// Problem constants
#define S_STEPS 24
#define BATCH   128
#define SEQT    24
#define DIN     512
#define D       128
#define DFF     2048
#define NH      4
#define DH      32
#define NC      64
#define NT      38400  // BATCH * S*(S+1)/2
#define NBT     3072   // BATCH*SEQT
#define KVS     256    // layer-1 kv row stride

// fp32 scratch
__device__ float g_h0[NBT * D];
__device__ float g_Y[NT * D];
__device__ float g_Ylast[NBT * D];
__device__ float g_part[2ull * NT * D];   // split-K partials (fc, ff2 l0, ff2 l1)

// bf16 buffers
__device__ __nv_bfloat16 g_xbf[NBT * DIN];
__device__ __nv_bfloat16 g_wfc_bf[D * DIN];
__device__ __nv_bfloat16 g_qkvw_bf[2 * 3 * D * D];
__device__ __nv_bfloat16 g_outw_bf[2 * D * D];
__device__ __nv_bfloat16 g_ff1w_bf[2 * DFF * D];
__device__ __nv_bfloat16 g_ff2w_bf[2 * D * DFF];
__device__ __nv_bfloat16 g_h0pbf[NBT * D];
__device__ __nv_bfloat16 g_qkv0bf[NBT * 3 * D];
__device__ __nv_bfloat16 g_Ybf[NT * D];
__device__ __nv_bfloat16 g_kv1bf[NT * KVS];
__device__ __nv_bfloat16 g_q1bf[NBT * D];
__device__ __nv_bfloat16 g_ctxbf[NT * D];
__device__ __nv_bfloat16 g_ctxlastbf[NBT * D];
__device__ __nv_bfloat16 g_Ylastbf[NBT * D];
__device__ __nv_bfloat16 g_Hbf[(size_t)NT * DFF];

__device__ __forceinline__ uint32_t smem_u32(const void* p) {
    return (uint32_t)__cvta_generic_to_shared(p);
}

// packed row n -> step s (closed form + integer fixup)
__device__ __forceinline__ int step_of(int n) {
    int u = n >> 6;
    int s = (int)((sqrtf((float)(4 * u + 1)) - 1.f) * 0.5f);
    while (64 * (s + 1) * (s + 2) <= n) s++;
    while (64 * s * (s + 1) > n) s--;
    return s;
}

#define SSTR 40
#define TILE (128 * SSTR)
#define TILE_A64 (64 * SSTR)
#define GEMM_SMEM  (3 * TILE * 2 * 2)
#define GEMM_SMEM_LN64 (3 * (TILE_A64 + TILE) * 2 + 1024)
#define GEMM_SMEM_64   (3 * (TILE_A64 + TILE) * 2)

// ---------------------------------------------------------------------------
// M128 gemm core: 4 warps 2x2, warp 64x64, 3-stage cp.async, m16n8k16
// ---------------------------------------------------------------------------
__device__ __forceinline__ void gemm_core(
    const __nv_bfloat16* __restrict__ A, const __nv_bfloat16* __restrict__ W,
    int K, int m0, int n0, __nv_bfloat16* As, __nv_bfloat16* Bs,
    float (&acc)[4][8][4])
{
    const int t = threadIdx.x, warp = t >> 5, lane = t & 31;
    const int wm = (warp >> 1) * 64, wn = (warp & 1) * 64;
    const int xr = lane & 15, xc = (lane >> 4) * 8;

#pragma unroll
    for (int i = 0; i < 4; ++i)
#pragma unroll
        for (int j = 0; j < 8; ++j)
#pragma unroll
            for (int k = 0; k < 4; ++k) acc[i][j][k] = 0.f;

    auto issue = [&](int k0, int st) {
        __nv_bfloat16* as = As + st * TILE;
        __nv_bfloat16* bs = Bs + st * TILE;
#pragma unroll
        for (int r = 0; r < 8; ++r) {
            int idx = t + r * 128;
            int op  = idx >> 9;
            int rem = idx & 511;
            int row = rem >> 2, c8 = (rem & 3) * 8;
            uint32_t dst = smem_u32((op ? bs : as) + row * SSTR + c8);
            const __nv_bfloat16* src = op
                ? (W + (size_t)(n0 + row) * K + k0 + c8)
                : (A + (size_t)(m0 + row) * K + k0 + c8);
            asm volatile("cp.async.cg.shared.global [%0], [%1], 16;"
                :: "r"(dst), "l"(src));
        }
        asm volatile("cp.async.commit_group;");
    };

    const int KT = K >> 5;
    issue(0, 0);
    issue(32, 1);
    for (int kt = 0; kt < KT; ++kt) {
        if (kt + 1 < KT) { asm volatile("cp.async.wait_group 1;"); }
        else             { asm volatile("cp.async.wait_group 0;"); }
        __syncthreads();
        if (kt + 2 < KT) issue((kt + 2) << 5, (kt + 2) % 3);

        const __nv_bfloat16* as = As + (kt % 3) * TILE;
        const __nv_bfloat16* bs = Bs + (kt % 3) * TILE;

        uint32_t af[2][4][4];
        uint32_t bfr[2][8][2];
#pragma unroll
        for (int si = 0; si < 2; ++si) {
            int ks = si * 16;
#pragma unroll
            for (int mi = 0; mi < 4; ++mi) {
                uint32_t ad = smem_u32(&as[(wm + mi * 16 + xr) * SSTR + ks + xc]);
                asm volatile("ldmatrix.sync.aligned.m8n8.x4.shared.b16 {%0,%1,%2,%3},[%4];"
                    : "=r"(af[si][mi][0]), "=r"(af[si][mi][1]),
                      "=r"(af[si][mi][2]), "=r"(af[si][mi][3])
                    : "r"(ad));
            }
#pragma unroll
            for (int np = 0; np < 4; ++np) {
                uint32_t bd = smem_u32(&bs[(wn + np * 16 + xr) * SSTR + ks + xc]);
                uint32_t r0, r1, r2, r3;
                asm volatile("ldmatrix.sync.aligned.m8n8.x4.shared.b16 {%0,%1,%2,%3},[%4];"
                    : "=r"(r0), "=r"(r1), "=r"(r2), "=r"(r3) : "r"(bd));
                bfr[si][2 * np][0] = r0; bfr[si][2 * np + 1][0] = r1;
                bfr[si][2 * np][1] = r2; bfr[si][2 * np + 1][1] = r3;
            }
        }
#pragma unroll
        for (int si = 0; si < 2; ++si)
#pragma unroll
            for (int mi = 0; mi < 4; ++mi)
#pragma unroll
                for (int ni = 0; ni < 8; ++ni) {
                    asm volatile(
                        "mma.sync.aligned.m16n8k16.row.col.f32.bf16.bf16.f32 "
                        "{%0,%1,%2,%3},{%4,%5,%6,%7},{%8,%9},{%0,%1,%2,%3};"
                        : "+f"(acc[mi][ni][0]), "+f"(acc[mi][ni][1]),
                          "+f"(acc[mi][ni][2]), "+f"(acc[mi][ni][3])
                        : "r"(af[si][mi][0]), "r"(af[si][mi][1]),
                          "r"(af[si][mi][2]), "r"(af[si][mi][3]),
                          "r"(bfr[si][ni][0]), "r"(bfr[si][ni][1]));
                }
    }
}

// ---------------------------------------------------------------------------
// M64 gemm core: 4 warps (2x2), warp 32x64.
// amap=1: A row index is compact (b*SEQT+s), mapped to packed last-token row.
// ---------------------------------------------------------------------------
__device__ __forceinline__ void gemm_core64(
    const __nv_bfloat16* __restrict__ A, const __nv_bfloat16* __restrict__ W,
    int ld, int K, int m0, int amap, __nv_bfloat16* As, __nv_bfloat16* Bs,
    float (&acc)[2][8][4])
{
    const int t = threadIdx.x, warp = t >> 5, lane = t & 31;
    const int wm = (warp >> 1) * 32, wn = (warp & 1) * 64;
    const int xr = lane & 15, xc = (lane >> 4) * 8;

#pragma unroll
    for (int i = 0; i < 2; ++i)
#pragma unroll
        for (int j = 0; j < 8; ++j)
#pragma unroll
            for (int k = 0; k < 4; ++k) acc[i][j][k] = 0.f;

    auto issue = [&](int k0, int st) {
        __nv_bfloat16* as = As + st * TILE_A64;
        __nv_bfloat16* bs = Bs + st * TILE;
#pragma unroll
        for (int r = 0; r < 6; ++r) {
            int idx = t + r * 128;
            if (idx < 256) {
                int row = idx >> 2, c8 = (idx & 3) * 8;
                int grow = m0 + row;
                if (amap) {
                    int b = grow / SEQT, ss = grow - b * SEQT;
                    grow = 64 * ss * (ss + 1) + b * (ss + 1) + ss;
                }
                asm volatile("cp.async.cg.shared.global [%0], [%1], 16;"
                    :: "r"(smem_u32(as + row * SSTR + c8)),
                       "l"(A + (size_t)grow * ld + k0 + c8));
            } else {
                int rem = idx - 256;
                int row = rem >> 2, c8 = (rem & 3) * 8;
                asm volatile("cp.async.cg.shared.global [%0], [%1], 16;"
                    :: "r"(smem_u32(bs + row * SSTR + c8)),
                       "l"(W + (size_t)row * ld + k0 + c8));
            }
        }
        asm volatile("cp.async.commit_group;");
    };

    const int KT = K >> 5;
    issue(0, 0);
    issue(32, 1);
    for (int kt = 0; kt < KT; ++kt) {
        if (kt + 1 < KT) { asm volatile("cp.async.wait_group 1;"); }
        else             { asm volatile("cp.async.wait_group 0;"); }
        __syncthreads();
        if (kt + 2 < KT) issue((kt + 2) << 5, (kt + 2) % 3);

        const __nv_bfloat16* as = As + (kt % 3) * TILE_A64;
        const __nv_bfloat16* bs = Bs + (kt % 3) * TILE;
#pragma unroll
        for (int si = 0; si < 2; ++si) {
            int ks = si * 16;
            uint32_t af[2][4];
#pragma unroll
            for (int mi = 0; mi < 2; ++mi) {
                uint32_t ad = smem_u32(&as[(wm + mi * 16 + xr) * SSTR + ks + xc]);
                asm volatile("ldmatrix.sync.aligned.m8n8.x4.shared.b16 {%0,%1,%2,%3},[%4];"
                    : "=r"(af[mi][0]), "=r"(af[mi][1]), "=r"(af[mi][2]), "=r"(af[mi][3])
                    : "r"(ad));
            }
            uint32_t bfr[8][2];
#pragma unroll
            for (int np = 0; np < 4; ++np) {
                uint32_t bd = smem_u32(&bs[(wn + np * 16 + xr) * SSTR + ks + xc]);
                uint32_t r0, r1, r2, r3;
                asm volatile("ldmatrix.sync.aligned.m8n8.x4.shared.b16 {%0,%1,%2,%3},[%4];"
                    : "=r"(r0), "=r"(r1), "=r"(r2), "=r"(r3) : "r"(bd));
                bfr[2 * np][0] = r0; bfr[2 * np + 1][0] = r1;
                bfr[2 * np][1] = r2; bfr[2 * np + 1][1] = r3;
            }
#pragma unroll
            for (int mi = 0; mi < 2; ++mi)
#pragma unroll
                for (int ni = 0; ni < 8; ++ni) {
                    asm volatile(
                        "mma.sync.aligned.m16n8k16.row.col.f32.bf16.bf16.f32 "
                        "{%0,%1,%2,%3},{%4,%5,%6,%7},{%8,%9},{%0,%1,%2,%3};"
                        : "+f"(acc[mi][ni][0]), "+f"(acc[mi][ni][1]),
                          "+f"(acc[mi][ni][2]), "+f"(acc[mi][ni][3])
                        : "r"(af[mi][0]), "r"(af[mi][1]),
                          "r"(af[mi][2]), "r"(af[mi][3]),
                          "r"(bfr[ni][0]), "r"(bfr[ni][1]));
                }
        }
    }
}

// ---------------------------------------------------------------------------
// Plain GEMM (M128)
// ---------------------------------------------------------------------------
__global__ __launch_bounds__(128, 2) void gemm_bf16(
    const __nv_bfloat16* __restrict__ A, const __nv_bfloat16* __restrict__ W,
    const float* __restrict__ bias, float* __restrict__ Cf,
    __nv_bfloat16* __restrict__ Cb, int N, int K, int relu)
{
    extern __shared__ __align__(16) char dyn[];
    __nv_bfloat16* As = (__nv_bfloat16*)dyn;
    __nv_bfloat16* Bs = As + 3 * TILE;

    const int m0 = blockIdx.y * 128, n0 = blockIdx.x * 128;
    const int t = threadIdx.x, warp = t >> 5, lane = t & 31;
    const int g = lane >> 2, tig = lane & 3;
    const int wm = (warp >> 1) * 64, wn = (warp & 1) * 64;

    float acc[4][8][4];
    gemm_core(A, W, K, m0, n0, As, Bs, acc);

#pragma unroll
    for (int mi = 0; mi < 4; ++mi) {
#pragma unroll
        for (int ni = 0; ni < 8; ++ni) {
            int col = n0 + wn + ni * 8 + 2 * tig;
            float b0v = bias[col], b1v = bias[col + 1];
            int row = m0 + wm + mi * 16 + g;
            float2 v0 = make_float2(acc[mi][ni][0] + b0v, acc[mi][ni][1] + b1v);
            float2 v1 = make_float2(acc[mi][ni][2] + b0v, acc[mi][ni][3] + b1v);
            if (relu) {
                v0.x = fmaxf(v0.x, 0.f); v0.y = fmaxf(v0.y, 0.f);
                v1.x = fmaxf(v1.x, 0.f); v1.y = fmaxf(v1.y, 0.f);
            }
            if (Cf) {
                *(float2*)(Cf + (size_t)row * N + col)       = v0;
                *(float2*)(Cf + (size_t)(row + 8) * N + col) = v1;
            }
            if (Cb) {
                *(__nv_bfloat162*)(Cb + (size_t)row * N + col) =
                    __floats2bfloat162_rn(v0.x, v0.y);
                *(__nv_bfloat162*)(Cb + (size_t)(row + 8) * N + col) =
                    __floats2bfloat162_rn(v1.x, v1.y);
            }
        }
    }
}

// ---------------------------------------------------------------------------
// Plain GEMM (M64). Grid (N/128, M/64). amap per gemm_core64.
// ---------------------------------------------------------------------------
__global__ __launch_bounds__(128, 3) void gemm64(
    const __nv_bfloat16* __restrict__ A, const __nv_bfloat16* __restrict__ W,
    const float* __restrict__ bias, float* __restrict__ Cf,
    __nv_bfloat16* __restrict__ Cb, int N, int K, int ldA, int amap, int relu)
{
    extern __shared__ __align__(16) char dyn[];
    __nv_bfloat16* As = (__nv_bfloat16*)dyn;
    __nv_bfloat16* Bs = As + 3 * TILE_A64;

    const int m0 = blockIdx.y * 64, n0 = blockIdx.x * 128;
    const int t = threadIdx.x, warp = t >> 5, lane = t & 31;
    const int g = lane >> 2, tig = lane & 3;
    const int wm = (warp >> 1) * 32, wn = (warp & 1) * 64;

    float acc[2][8][4];
    gemm_core64(A, W + (size_t)n0 * K, ldA, K, m0, amap, As, Bs, acc);

#pragma unroll
    for (int mi = 0; mi < 2; ++mi) {
#pragma unroll
        for (int ni = 0; ni < 8; ++ni) {
            int col = n0 + wn + ni * 8 + 2 * tig;
            float b0v = bias[col], b1v = bias[col + 1];
            int row = m0 + wm + mi * 16 + g;
            float2 v0 = make_float2(acc[mi][ni][0] + b0v, acc[mi][ni][1] + b1v);
            float2 v1 = make_float2(acc[mi][ni][2] + b0v, acc[mi][ni][3] + b1v);
            if (relu) {
                v0.x = fmaxf(v0.x, 0.f); v0.y = fmaxf(v0.y, 0.f);
                v1.x = fmaxf(v1.x, 0.f); v1.y = fmaxf(v1.y, 0.f);
            }
            if (Cf) {
                *(float2*)(Cf + (size_t)row * N + col)       = v0;
                *(float2*)(Cf + (size_t)(row + 8) * N + col) = v1;
            }
            if (Cb) {
                *(__nv_bfloat162*)(Cb + (size_t)row * N + col) =
                    __floats2bfloat162_rn(v0.x, v0.y);
                *(__nv_bfloat162*)(Cb + (size_t)(row + 8) * N + col) =
                    __floats2bfloat162_rn(v1.x, v1.y);
            }
        }
    }
}

// ---------------------------------------------------------------------------
// GEMM + residual + LayerNorm, M64. N == 128.
// gather=0: residual row n of Rres; 1: packed last-token map; 2: h0 map
// ---------------------------------------------------------------------------
__global__ __launch_bounds__(128, 3) void gemm_ln64(
    const __nv_bfloat16* __restrict__ A, const __nv_bfloat16* __restrict__ W,
    const float* __restrict__ bias, const float* __restrict__ lng,
    const float* __restrict__ lnb, const float* __restrict__ Rres,
    float* __restrict__ Yout, __nv_bfloat16* __restrict__ Ybf,
    int K, int gather)
{
    extern __shared__ __align__(16) char dyn[];
    __nv_bfloat16* As = (__nv_bfloat16*)dyn;
    __nv_bfloat16* Bs = As + 3 * TILE_A64;
    float* redS = (float*)(dyn + 3 * (TILE_A64 + TILE) * 2);  // [2][64]
    float* redQ = redS + 128;

    const int m0 = blockIdx.y * 64;
    const int t = threadIdx.x, warp = t >> 5, lane = t & 31;
    const int g = lane >> 2, tig = lane & 3;
    const int wm = (warp >> 1) * 32, wn = (warp & 1) * 64;
    const int cw = warp & 1;

    float acc[2][8][4];
    gemm_core64(A, W, K, K, m0, 0, As, Bs, acc);

    auto res_row = [&](int n) -> const float* {
        if (gather == 1) {
            int b = n / SEQT, s = n - b * SEQT;
            int src = 64 * s * (s + 1) + b * (s + 1) + s;
            return Rres + (size_t)src * D;
        }
        if (gather == 2) {
            int s = step_of(n);
            int r = n - 64 * s * (s + 1);
            int P = s + 1;
            int b = r / P;
            int tt = r - b * P;
            return g_h0 + (size_t)(b * SEQT + tt) * D;
        }
        return Rres + (size_t)n * D;
    };

#pragma unroll
    for (int mi = 0; mi < 2; ++mi) {
        int r0 = wm + mi * 16 + g, r1 = r0 + 8;
        const float* R0 = res_row(m0 + r0);
        const float* R1 = res_row(m0 + r1);
        float s0 = 0.f, q0 = 0.f, s1 = 0.f, q1 = 0.f;
#pragma unroll
        for (int ni = 0; ni < 8; ++ni) {
            int col = wn + ni * 8 + 2 * tig;
            float2 bv = *(const float2*)(bias + col);
            float2 y0 = *(const float2*)(R0 + col);
            float2 y1 = *(const float2*)(R1 + col);
            float a0 = acc[mi][ni][0] + bv.x + y0.x;
            float a1 = acc[mi][ni][1] + bv.y + y0.y;
            float a2 = acc[mi][ni][2] + bv.x + y1.x;
            float a3 = acc[mi][ni][3] + bv.y + y1.y;
            acc[mi][ni][0] = a0; acc[mi][ni][1] = a1;
            acc[mi][ni][2] = a2; acc[mi][ni][3] = a3;
            s0 += a0 + a1; q0 += a0 * a0 + a1 * a1;
            s1 += a2 + a3; q1 += a2 * a2 + a3 * a3;
        }
#pragma unroll
        for (int o = 1; o <= 2; o <<= 1) {
            s0 += __shfl_xor_sync(0xffffffffu, s0, o);
            q0 += __shfl_xor_sync(0xffffffffu, q0, o);
            s1 += __shfl_xor_sync(0xffffffffu, s1, o);
            q1 += __shfl_xor_sync(0xffffffffu, q1, o);
        }
        if (tig == 0) {
            redS[cw * 64 + r0] = s0; redQ[cw * 64 + r0] = q0;
            redS[cw * 64 + r1] = s1; redQ[cw * 64 + r1] = q1;
        }
    }
    __syncthreads();

#pragma unroll
    for (int mi = 0; mi < 2; ++mi) {
        int r0 = wm + mi * 16 + g, r1 = r0 + 8;
        float S0 = redS[r0] + redS[64 + r0], Q0 = redQ[r0] + redQ[64 + r0];
        float S1 = redS[r1] + redS[64 + r1], Q1 = redQ[r1] + redQ[64 + r1];
        float mu0 = S0 * (1.f / 128.f), mu1 = S1 * (1.f / 128.f);
        float iv0 = rsqrtf(Q0 * (1.f / 128.f) - mu0 * mu0 + 1e-5f);
        float iv1 = rsqrtf(Q1 * (1.f / 128.f) - mu1 * mu1 + 1e-5f);
#pragma unroll
        for (int ni = 0; ni < 8; ++ni) {
            int col = wn + ni * 8 + 2 * tig;
            float2 gv = *(const float2*)(lng + col);
            float2 bv = *(const float2*)(lnb + col);
            float o0 = (acc[mi][ni][0] - mu0) * iv0 * gv.x + bv.x;
            float o1 = (acc[mi][ni][1] - mu0) * iv0 * gv.y + bv.y;
            float o2 = (acc[mi][ni][2] - mu1) * iv1 * gv.x + bv.x;
            float o3 = (acc[mi][ni][3] - mu1) * iv1 * gv.y + bv.y;
            *(float2*)(Yout + (size_t)(m0 + r0) * D + col) = make_float2(o0, o1);
            *(float2*)(Yout + (size_t)(m0 + r1) * D + col) = make_float2(o2, o3);
            *(__nv_bfloat162*)(Ybf + (size_t)(m0 + r0) * D + col) =
                __floats2bfloat162_rn(o0, o1);
            *(__nv_bfloat162*)(Ybf + (size_t)(m0 + r1) * D + col) =
                __floats2bfloat162_rn(o2, o3);
        }
    }
}

// ---------------------------------------------------------------------------
// Split-K partial GEMM, M64, N=128, fp32 partials. blockIdx.z = part.
// ---------------------------------------------------------------------------
__global__ __launch_bounds__(128, 3) void gemm_part64(
    const __nv_bfloat16* __restrict__ A, const __nv_bfloat16* __restrict__ W,
    float* __restrict__ P, int ld, int Kpart, int Mtot)
{
    extern __shared__ __align__(16) char dyn[];
    __nv_bfloat16* As = (__nv_bfloat16*)dyn;
    __nv_bfloat16* Bs = As + 3 * TILE_A64;

    const int m0 = blockIdx.y * 64;
    const int part = blockIdx.z;
    A += (size_t)part * Kpart;
    W += (size_t)part * Kpart;
    P += (size_t)part * Mtot * D;

    const int t = threadIdx.x, warp = t >> 5, lane = t & 31;
    const int g = lane >> 2, tig = lane & 3;
    const int wm = (warp >> 1) * 32, wn = (warp & 1) * 64;

    float acc[2][8][4];
    gemm_core64(A, W, ld, Kpart, m0, 0, As, Bs, acc);

#pragma unroll
    for (int mi = 0; mi < 2; ++mi) {
        int r0 = wm + mi * 16 + g, r1 = r0 + 8;
#pragma unroll
        for (int ni = 0; ni < 8; ++ni) {
            int col = wn + ni * 8 + 2 * tig;
            *(float2*)(P + (size_t)(m0 + r0) * D + col) =
                make_float2(acc[mi][ni][0], acc[mi][ni][1]);
            *(float2*)(P + (size_t)(m0 + r1) * D + col) =
                make_float2(acc[mi][ni][2], acc[mi][ni][3]);
        }
    }
}

// ---------------------------------------------------------------------------
// fc combine: h0 = relu(P0..P3 + b_fc) + PE; writes fp32 + bf16
// ---------------------------------------------------------------------------
__global__ void fc_combine(const float* __restrict__ bias)
{
    int i = blockIdx.x * 256 + threadIdx.x;
    if (i >= NBT * D) return;
    int n = i >> 7, d = i & 127;
    int t = n % SEQT;
    float v = g_part[i] + g_part[NBT * D + i] + g_part[2 * NBT * D + i]
            + g_part[3 * NBT * D + i] + bias[d];
    v = fmaxf(v, 0.f);
    float freq = expf((float)(d & ~1) * (-9.210340371976184f / 128.f));
    float arg  = (float)t * freq;
    v += (d & 1) ? cosf(arg) : sinf(arg);
    g_h0[i]    = v;
    g_h0pbf[i] = __float2bfloat16(v);
}

// ---------------------------------------------------------------------------
// ff2-l0 combine (2 parts) + residual + LayerNorm -> packed Y / Ybf
// ---------------------------------------------------------------------------
__global__ __launch_bounds__(128) void ln_combine(
    const float* __restrict__ bias, const float* __restrict__ lng,
    const float* __restrict__ lnb)
{
    int n    = blockIdx.x * 4 + (threadIdx.x >> 5);
    int lane = threadIdx.x & 31;
    float v[4], s = 0.f, q = 0.f;
#pragma unroll
    for (int i = 0; i < 4; ++i) {
        int d = lane + 32 * i;
        size_t off = (size_t)n * D + d;
        v[i] = g_Y[off] + g_part[off] + g_part[(size_t)NT * D + off] + bias[d];
        s += v[i]; q += v[i] * v[i];
    }
    for (int o = 16; o; o >>= 1) {
        s += __shfl_xor_sync(0xffffffffu, s, o);
        q += __shfl_xor_sync(0xffffffffu, q, o);
    }
    float mu = s * (1.f / 128.f);
    float iv = rsqrtf(q * (1.f / 128.f) - mu * mu + 1e-5f);
#pragma unroll
    for (int i = 0; i < 4; ++i) {
        int d = lane + 32 * i;
        size_t off = (size_t)n * D + d;
        float o = (v[i] - mu) * iv * lng[d] + lnb[d];
        g_Y[off]   = o;
        g_Ybf[off] = __float2bfloat16(o);
    }
}

// ---------------------------------------------------------------------------
// ff2-l1 combine (4 parts) + residual + LayerNorm -> Ylast / Ylastbf
// ---------------------------------------------------------------------------
__global__ __launch_bounds__(128) void ln_combine_last(
    const float* __restrict__ bias, const float* __restrict__ lng,
    const float* __restrict__ lnb)
{
    int n    = blockIdx.x * 4 + (threadIdx.x >> 5);
    int lane = threadIdx.x & 31;
    float v[4], s = 0.f, q = 0.f;
#pragma unroll
    for (int i = 0; i < 4; ++i) {
        int d = lane + 32 * i;
        size_t off = (size_t)n * D + d;
        v[i] = g_Ylast[off] + g_part[off] + g_part[(size_t)NBT * D + off]
             + g_part[2ull * NBT * D + off] + g_part[3ull * NBT * D + off]
             + bias[d];
        s += v[i]; q += v[i] * v[i];
    }
    for (int o = 16; o; o >>= 1) {
        s += __shfl_xor_sync(0xffffffffu, s, o);
        q += __shfl_xor_sync(0xffffffffu, q, o);
    }
    float mu = s * (1.f / 128.f);
    float iv = rsqrtf(q * (1.f / 128.f) - mu * mu + 1e-5f);
#pragma unroll
    for (int i = 0; i < 4; ++i) {
        int d = lane + 32 * i;
        size_t off = (size_t)n * D + d;
        float o = (v[i] - mu) * iv * lng[d] + lnb[d];
        g_Ylast[off]   = o;
        g_Ylastbf[off] = __float2bfloat16(o);
    }
}

// ---------------------------------------------------------------------------
// One-shot fp32 -> bf16 conversion
// ---------------------------------------------------------------------------
#define CVT_TOTAL 2818048
__global__ void cvt_all(const float* __restrict__ x, const float* __restrict__ wfc,
                        const float* __restrict__ qkvw, const float* __restrict__ outw,
                        const float* __restrict__ ff1w, const float* __restrict__ ff2w)
{
    int i = (blockIdx.x * 256 + threadIdx.x) * 4;
    if (i >= CVT_TOTAL) return;
    const float* s; __nv_bfloat16* d; int off;
    if      (i < 1572864) { s = x;    d = g_xbf;     off = i; }
    else if (i < 1638400) { s = wfc;  d = g_wfc_bf;  off = i - 1572864; }
    else if (i < 1736704) { s = qkvw; d = g_qkvw_bf; off = i - 1638400; }
    else if (i < 1769472) { s = outw; d = g_outw_bf; off = i - 1736704; }
    else if (i < 2293760) { s = ff1w; d = g_ff1w_bf; off = i - 1769472; }
    else                  { s = ff2w; d = g_ff2w_bf; off = i - 2293760; }
    float4 v = *(const float4*)(s + off);
    *(__nv_bfloat162*)(d + off)     = __floats2bfloat162_rn(v.x, v.y);
    *(__nv_bfloat162*)(d + off + 2) = __floats2bfloat162_rn(v.z, v.w);
}

// ---------------------------------------------------------------------------
// Layer-0 attention, prefix-dedup: one block per (b,h); 24x24 scores once,
// online-softmax prefix scan emits ctx for every step s >= t.
// ---------------------------------------------------------------------------
__global__ __launch_bounds__(64) void attn0_kernel()
{
    __shared__ float qs[SEQT][DH], ks[SEQT][DH], vs[SEQT][DH];
    __shared__ float sc[SEQT][SEQT];

    int blk = blockIdx.x;
    int b = blk >> 2;
    int h = blk & 3;
    int tid  = threadIdx.x;
    int w    = tid >> 5;
    int lane = tid & 31;

    for (int i = tid; i < SEQT * DH; i += 64) {
        int t = i >> 5, dd = i & 31;
        const __nv_bfloat16* row =
            g_qkv0bf + (size_t)(b * SEQT + t) * (3 * D) + h * DH + dd;
        qs[t][dd] = __bfloat162float(row[0]);
        ks[t][dd] = __bfloat162float(row[D]);
        vs[t][dd] = __bfloat162float(row[2 * D]);
    }
    __syncthreads();

    for (int p = tid; p < SEQT * SEQT; p += 64) {
        int t = p / SEQT, j = p - t * SEQT;
        float a = 0.f;
#pragma unroll
        for (int dd = 0; dd < DH; ++dd) a += qs[t][dd] * ks[j][dd];
        sc[t][j] = a * 0.17677669529663687f;
    }
    __syncthreads();

    for (int t = w; t < SEQT; t += 2) {
        float m = -1e30f, l = 0.f, acc = 0.f;
        for (int j = 0; j < SEQT; ++j) {
            float x = sc[t][j];
            float nm = fmaxf(m, x);
            float so = __expf(m - nm);
            float e  = __expf(x - nm);
            l   = l * so + e;
            acc = acc * so + e * vs[j][lane];
            m = nm;
            if (j >= t) {
                int dst = 64 * j * (j + 1) + b * (j + 1) + t;
                g_ctxbf[(size_t)dst * D + h * DH + lane] =
                    __float2bfloat16(acc / l);
            }
        }
    }
}

// ---------------------------------------------------------------------------
// Layer-1 attention, LAST query only
// ---------------------------------------------------------------------------
__global__ __launch_bounds__(128) void attn1_kernel()
{
    __shared__ float qs[NH][DH];
    __shared__ float ps[NH][32];

    int q = blockIdx.x;
    int s = q >> 7;
    int b = q & 127;
    int P = s + 1;
    int base = 64 * s * (s + 1) + b * P;
    int tid  = threadIdx.x;
    int h    = tid >> 5;
    int lane = tid & 31;

    qs[h][lane] = __bfloat162float(
        g_q1bf[(size_t)(b * SEQT + s) * D + h * DH + lane]);
    __syncthreads();

    float sc = -1e30f;
    if (lane < P) {
        const __nv_bfloat16* krow = g_kv1bf + (size_t)(base + lane) * KVS + h * DH;
        float a = 0.f;
#pragma unroll
        for (int dd = 0; dd < DH; ++dd) a += qs[h][dd] * __bfloat162float(krow[dd]);
        sc = a * 0.17677669529663687f;
    }
    float m = sc;
    for (int o = 16; o; o >>= 1) m = fmaxf(m, __shfl_xor_sync(0xffffffffu, m, o));
    float e = (lane < P) ? expf(sc - m) : 0.f;
    float sum = e;
    for (int o = 16; o; o >>= 1) sum += __shfl_xor_sync(0xffffffffu, sum, o);
    ps[h][lane] = e / sum;
    __syncwarp();

    float c = 0.f;
    for (int j = 0; j < P; ++j)
        c += ps[h][j] * __bfloat162float(
                 g_kv1bf[(size_t)(base + j) * KVS + D + h * DH + lane]);
    g_ctxlastbf[(size_t)(b * SEQT + s) * D + h * DH + lane] = __float2bfloat16(c);
}

// ---------------------------------------------------------------------------
// Classifier + log_softmax: 16 tokens per block, Wc1 staged in smem once.
// ---------------------------------------------------------------------------
#define CLS_TPB 16
__global__ __launch_bounds__(128) void cls_kernel(
    const float* __restrict__ Wc1, const float* __restrict__ bc1,
    const float* __restrict__ Wc2, const float* __restrict__ bc2,
    float* __restrict__ out)
{
    __shared__ float w1s[NC * D];
    __shared__ float rows[CLS_TPB][D];
    __shared__ float c1s[CLS_TPB][NC];

    int n0 = blockIdx.x * CLS_TPB;
    int t  = threadIdx.x;

    for (int i = t; i < NC * D / 4; i += 128)
        ((float4*)w1s)[i] = ((const float4*)Wc1)[i];
    for (int i = t; i < CLS_TPB * D / 4; i += 128) {
        int tok = i >> 5, c = i & 31;
        ((float4*)rows[tok])[c] =
            ((const float4*)(g_Ylast + (size_t)(n0 + tok) * D))[c];
    }
    __syncthreads();

#pragma unroll
    for (int p = 0; p < CLS_TPB * NC / 128; ++p) {
        int pair = t + p * 128;
        int tok = pair >> 6, o = pair & 63;
        float a = bc1[o];
        const float* wr = w1s + o * D;
        const float* rr = rows[tok];
#pragma unroll
        for (int d = 0; d < D; ++d) a += rr[d] * wr[d];
        c1s[tok][o] = fmaxf(a, 0.f);
    }
    __syncthreads();

    if (t < CLS_TPB) {
        float l0 = bc2[0], l1 = bc2[1];
#pragma unroll
        for (int j = 0; j < NC; ++j) {
            float c = c1s[t][j];
            l0 += c * Wc2[j];
            l1 += c * Wc2[NC + j];
        }
        float m   = fmaxf(l0, l1);
        float lse = m + logf(expf(l0 - m) + expf(l1 - m));
        out[(n0 + t) * 2 + 0] = l0 - lse;
        out[(n0 + t) * 2 + 1] = l1 - lse;
    }
}

// ---------------------------------------------------------------------------
extern "C" void kernel_launch(void* const* d_in, const int* in_sizes, int n_in,
                              void* d_out, int out_size)
{
    const float* x     = (const float*)d_in[0];
    const float* W_fc  = (const float*)d_in[1];
    const float* b_fc  = (const float*)d_in[2];
    const float* qkv_w = (const float*)d_in[3];
    const float* qkv_b = (const float*)d_in[4];
    const float* out_w = (const float*)d_in[5];
    const float* out_b = (const float*)d_in[6];
    const float* ln1_g = (const float*)d_in[7];
    const float* ln1_b = (const float*)d_in[8];
    const float* ln2_g = (const float*)d_in[9];
    const float* ln2_b = (const float*)d_in[10];
    const float* ff1_w = (const float*)d_in[11];
    const float* ff1_b = (const float*)d_in[12];
    const float* ff2_w = (const float*)d_in[13];
    const float* ff2_b = (const float*)d_in[14];
    const float* Wc1   = (const float*)d_in[15];
    const float* bc1   = (const float*)d_in[16];
    const float* Wc2   = (const float*)d_in[17];
    const float* bc2   = (const float*)d_in[18];

    cudaFuncSetAttribute(gemm_bf16, cudaFuncAttributeMaxDynamicSharedMemorySize,
                         GEMM_SMEM);
    cudaFuncSetAttribute(gemm64, cudaFuncAttributeMaxDynamicSharedMemorySize,
                         GEMM_SMEM_64);
    cudaFuncSetAttribute(gemm_ln64, cudaFuncAttributeMaxDynamicSharedMemorySize,
                         GEMM_SMEM_LN64);
    cudaFuncSetAttribute(gemm_part64, cudaFuncAttributeMaxDynamicSharedMemorySize,
                         GEMM_SMEM_64);

    void* p;
    cudaGetSymbolAddress(&p, g_Y);        float* Y     = (float*)p;
    cudaGetSymbolAddress(&p, g_Ylast);    float* Ylast = (float*)p;
    cudaGetSymbolAddress(&p, g_part);     float* part  = (float*)p;
    cudaGetSymbolAddress(&p, g_xbf);      __nv_bfloat16* xbf   = (__nv_bfloat16*)p;
    cudaGetSymbolAddress(&p, g_wfc_bf);   __nv_bfloat16* wfcb  = (__nv_bfloat16*)p;
    cudaGetSymbolAddress(&p, g_qkvw_bf);  __nv_bfloat16* qkvwb = (__nv_bfloat16*)p;
    cudaGetSymbolAddress(&p, g_outw_bf);  __nv_bfloat16* outwb = (__nv_bfloat16*)p;
    cudaGetSymbolAddress(&p, g_ff1w_bf);  __nv_bfloat16* ff1wb = (__nv_bfloat16*)p;
    cudaGetSymbolAddress(&p, g_ff2w_bf);  __nv_bfloat16* ff2wb = (__nv_bfloat16*)p;
    cudaGetSymbolAddress(&p, g_h0pbf);    __nv_bfloat16* h0pb  = (__nv_bfloat16*)p;
    cudaGetSymbolAddress(&p, g_qkv0bf);   __nv_bfloat16* qkv0b = (__nv_bfloat16*)p;
    cudaGetSymbolAddress(&p, g_Ybf);      __nv_bfloat16* ybf   = (__nv_bfloat16*)p;
    cudaGetSymbolAddress(&p, g_kv1bf);    __nv_bfloat16* kv1b  = (__nv_bfloat16*)p;
    cudaGetSymbolAddress(&p, g_q1bf);     __nv_bfloat16* q1b   = (__nv_bfloat16*)p;
    cudaGetSymbolAddress(&p, g_ctxbf);    __nv_bfloat16* ctxb  = (__nv_bfloat16*)p;
    cudaGetSymbolAddress(&p, g_ctxlastbf);__nv_bfloat16* ctxlb = (__nv_bfloat16*)p;
    cudaGetSymbolAddress(&p, g_Ylastbf);  __nv_bfloat16* ylbf  = (__nv_bfloat16*)p;
    cudaGetSymbolAddress(&p, g_Hbf);      __nv_bfloat16* hbf   = (__nv_bfloat16*)p;

    cvt_all<<<(CVT_TOTAL / 4 + 255) / 256, 256>>>(x, W_fc, qkv_w, out_w, ff1_w, ff2_w);

    // fc: split-K x4, combine applies bias+ReLU+PE
    gemm_part64<<<dim3(1, NBT / 64, 4), 128, GEMM_SMEM_64>>>(
        xbf, wfcb, part, DIN, DIN / 4, NBT);
    fc_combine<<<(NBT * D + 255) / 256, 256>>>(b_fc);

    // ---- layer 0 ----
    gemm64<<<dim3(3, NBT / 64), 128, GEMM_SMEM_64>>>(
        h0pb, qkvwb, qkv_b, nullptr, qkv0b, 3 * D, D, D, 0, 0);
    attn0_kernel<<<BATCH * NH, 64>>>();
    gemm_ln64<<<dim3(1, NT / 64), 128, GEMM_SMEM_LN64>>>(
        ctxb, outwb, out_b, ln1_g, ln1_b, nullptr, Y, ybf, D, 2);
    gemm_bf16<<<dim3(DFF / 128, NT / 128), 128, GEMM_SMEM>>>(
        ybf, ff1wb, ff1_b, nullptr, hbf, DFF, D, 1);
    gemm_part64<<<dim3(1, NT / 64, 2), 128, GEMM_SMEM_64>>>(
        hbf, ff2wb, part, DFF, DFF / 2, NT);
    ln_combine<<<NT / 4, 128>>>(ff2_b, ln2_g, ln2_b);

    // ---- layer 1 (K/V full; Q + tail last-token only) ----
    gemm_bf16<<<dim3(2, NT / 128), 128, GEMM_SMEM>>>(
        ybf, qkvwb + (size_t)3 * D * D + (size_t)D * D, qkv_b + 3 * D + D,
        nullptr, kv1b, KVS, D, 0);
    gemm64<<<dim3(1, NBT / 64), 128, GEMM_SMEM_64>>>(
        ybf, qkvwb + (size_t)3 * D * D, qkv_b + 3 * D, nullptr, q1b,
        D, D, D, 1, 0);
    attn1_kernel<<<S_STEPS * BATCH, 128>>>();
    gemm_ln64<<<dim3(1, NBT / 64), 128, GEMM_SMEM_LN64>>>(
        ctxlb, outwb + (size_t)D * D, out_b + D,
        ln1_g + D, ln1_b + D, Y, Ylast, ylbf, D, 1);
    // ff1 l1 as M64 (768 CTAs -> better tail utilization)
    gemm64<<<dim3(DFF / 128, NBT / 64), 128, GEMM_SMEM_64>>>(
        ylbf, ff1wb + (size_t)DFF * D, ff1_b + DFF, nullptr, hbf,
        DFF, D, D, 0, 1);
    // ff2 l1: split-K x4 + combine (replaces 48-CTA latency-bound launch)
    gemm_part64<<<dim3(1, NBT / 64, 4), 128, GEMM_SMEM_64>>>(
        hbf, ff2wb + (size_t)D * DFF, part, DFF, DFF / 4, NBT);
    ln_combine_last<<<NBT / 4, 128>>>(ff2_b + D, ln2_g + D, ln2_b + D);

    cls_kernel<<<NBT / CLS_TPB, 128>>>(Wc1, bc1, Wc2, bc2, (float*)d_out);
}

// round 17
// speedup vs baseline: 3.6471x; 1.0100x over previous
#include <cuda_runtime.h>
#include <cuda_bf16.h>
#include <math.h>
#include <stdint.h>

// Problem constants
#define S_STEPS 24
#define BATCH   128
#define SEQT    24
#define DIN     512
#define D       128
#define DFF     2048
#define NH      4
#define DH      32
#define NC      64
#define NT      38400  // BATCH * S*(S+1)/2
#define NBT     3072   // BATCH*SEQT
#define KVS     256    // layer-1 kv row stride

// fp32 scratch
__device__ float g_h0[NBT * D];
__device__ float g_Y[NT * D];
__device__ float g_Ylast[NBT * D];
__device__ float g_part[2ull * NT * D];   // split-K partials (fc, ff2 l0, ff2 l1)

// bf16 buffers
__device__ __nv_bfloat16 g_xbf[NBT * DIN];
__device__ __nv_bfloat16 g_wfc_bf[D * DIN];
__device__ __nv_bfloat16 g_qkvw_bf[2 * 3 * D * D];
__device__ __nv_bfloat16 g_outw_bf[2 * D * D];
__device__ __nv_bfloat16 g_ff1w_bf[2 * DFF * D];
__device__ __nv_bfloat16 g_ff2w_bf[2 * D * DFF];
__device__ __nv_bfloat16 g_h0pbf[NBT * D];
__device__ __nv_bfloat16 g_qkv0bf[NBT * 3 * D];
__device__ __nv_bfloat16 g_Ybf[NT * D];
__device__ __nv_bfloat16 g_kv1bf[NT * KVS];
__device__ __nv_bfloat16 g_q1bf[NBT * D];
__device__ __nv_bfloat16 g_ctxbf[NT * D];
__device__ __nv_bfloat16 g_ctxlastbf[NBT * D];
__device__ __nv_bfloat16 g_Ylastbf[NBT * D];
__device__ __nv_bfloat16 g_Hbf[(size_t)NT * DFF];

__device__ __forceinline__ uint32_t smem_u32(const void* p) {
    return (uint32_t)__cvta_generic_to_shared(p);
}

// packed row n -> step s (closed form + integer fixup)
__device__ __forceinline__ int step_of(int n) {
    int u = n >> 6;
    int s = (int)((sqrtf((float)(4 * u + 1)) - 1.f) * 0.5f);
    while (64 * (s + 1) * (s + 2) <= n) s++;
    while (64 * s * (s + 1) > n) s--;
    return s;
}

#define SSTR 40
#define TILE (128 * SSTR)
#define TILE_A64 (64 * SSTR)
#define GEMM_SMEM  (3 * TILE * 2 * 2)
#define GEMM_SMEM_LN64 (3 * (TILE_A64 + TILE) * 2 + 1024)
#define GEMM_SMEM_64   (3 * (TILE_A64 + TILE) * 2)

// ---------------------------------------------------------------------------
// M128 gemm core: 4 warps 2x2, warp 64x64, 3-stage cp.async, m16n8k16
// ---------------------------------------------------------------------------
__device__ __forceinline__ void gemm_core(
    const __nv_bfloat16* __restrict__ A, const __nv_bfloat16* __restrict__ W,
    int K, int m0, int n0, __nv_bfloat16* As, __nv_bfloat16* Bs,
    float (&acc)[4][8][4])
{
    const int t = threadIdx.x, warp = t >> 5, lane = t & 31;
    const int wm = (warp >> 1) * 64, wn = (warp & 1) * 64;
    const int xr = lane & 15, xc = (lane >> 4) * 8;

#pragma unroll
    for (int i = 0; i < 4; ++i)
#pragma unroll
        for (int j = 0; j < 8; ++j)
#pragma unroll
            for (int k = 0; k < 4; ++k) acc[i][j][k] = 0.f;

    auto issue = [&](int k0, int st) {
        __nv_bfloat16* as = As + st * TILE;
        __nv_bfloat16* bs = Bs + st * TILE;
#pragma unroll
        for (int r = 0; r < 8; ++r) {
            int idx = t + r * 128;
            int op  = idx >> 9;
            int rem = idx & 511;
            int row = rem >> 2, c8 = (rem & 3) * 8;
            uint32_t dst = smem_u32((op ? bs : as) + row * SSTR + c8);
            const __nv_bfloat16* src = op
                ? (W + (size_t)(n0 + row) * K + k0 + c8)
                : (A + (size_t)(m0 + row) * K + k0 + c8);
            asm volatile("cp.async.cg.shared.global [%0], [%1], 16;"
                :: "r"(dst), "l"(src));
        }
        asm volatile("cp.async.commit_group;");
    };

    const int KT = K >> 5;
    issue(0, 0);
    issue(32, 1);
    for (int kt = 0; kt < KT; ++kt) {
        if (kt + 1 < KT) { asm volatile("cp.async.wait_group 1;"); }
        else             { asm volatile("cp.async.wait_group 0;"); }
        __syncthreads();
        if (kt + 2 < KT) issue((kt + 2) << 5, (kt + 2) % 3);

        const __nv_bfloat16* as = As + (kt % 3) * TILE;
        const __nv_bfloat16* bs = Bs + (kt % 3) * TILE;

        uint32_t af[2][4][4];
        uint32_t bfr[2][8][2];
#pragma unroll
        for (int si = 0; si < 2; ++si) {
            int ks = si * 16;
#pragma unroll
            for (int mi = 0; mi < 4; ++mi) {
                uint32_t ad = smem_u32(&as[(wm + mi * 16 + xr) * SSTR + ks + xc]);
                asm volatile("ldmatrix.sync.aligned.m8n8.x4.shared.b16 {%0,%1,%2,%3},[%4];"
                    : "=r"(af[si][mi][0]), "=r"(af[si][mi][1]),
                      "=r"(af[si][mi][2]), "=r"(af[si][mi][3])
                    : "r"(ad));
            }
#pragma unroll
            for (int np = 0; np < 4; ++np) {
                uint32_t bd = smem_u32(&bs[(wn + np * 16 + xr) * SSTR + ks + xc]);
                uint32_t r0, r1, r2, r3;
                asm volatile("ldmatrix.sync.aligned.m8n8.x4.shared.b16 {%0,%1,%2,%3},[%4];"
                    : "=r"(r0), "=r"(r1), "=r"(r2), "=r"(r3) : "r"(bd));
                bfr[si][2 * np][0] = r0; bfr[si][2 * np + 1][0] = r1;
                bfr[si][2 * np][1] = r2; bfr[si][2 * np + 1][1] = r3;
            }
        }
#pragma unroll
        for (int si = 0; si < 2; ++si)
#pragma unroll
            for (int mi = 0; mi < 4; ++mi)
#pragma unroll
                for (int ni = 0; ni < 8; ++ni) {
                    asm volatile(
                        "mma.sync.aligned.m16n8k16.row.col.f32.bf16.bf16.f32 "
                        "{%0,%1,%2,%3},{%4,%5,%6,%7},{%8,%9},{%0,%1,%2,%3};"
                        : "+f"(acc[si ? mi : mi][ni][0]), "+f"(acc[mi][ni][1]),
                          "+f"(acc[mi][ni][2]), "+f"(acc[mi][ni][3])
                        : "r"(af[si][mi][0]), "r"(af[si][mi][1]),
                          "r"(af[si][mi][2]), "r"(af[si][mi][3]),
                          "r"(bfr[si][ni][0]), "r"(bfr[si][ni][1]));
                }
    }
}

// ---------------------------------------------------------------------------
// M64 gemm core: 4 warps (2x2), warp 32x64.
// amap=1: A row index is compact (b*SEQT+s), mapped to packed last-token row.
// ---------------------------------------------------------------------------
__device__ __forceinline__ void gemm_core64(
    const __nv_bfloat16* __restrict__ A, const __nv_bfloat16* __restrict__ W,
    int ld, int K, int m0, int amap, __nv_bfloat16* As, __nv_bfloat16* Bs,
    float (&acc)[2][8][4])
{
    const int t = threadIdx.x, warp = t >> 5, lane = t & 31;
    const int wm = (warp >> 1) * 32, wn = (warp & 1) * 64;
    const int xr = lane & 15, xc = (lane >> 4) * 8;

#pragma unroll
    for (int i = 0; i < 2; ++i)
#pragma unroll
        for (int j = 0; j < 8; ++j)
#pragma unroll
            for (int k = 0; k < 4; ++k) acc[i][j][k] = 0.f;

    auto issue = [&](int k0, int st) {
        __nv_bfloat16* as = As + st * TILE_A64;
        __nv_bfloat16* bs = Bs + st * TILE;
#pragma unroll
        for (int r = 0; r < 6; ++r) {
            int idx = t + r * 128;
            if (idx < 256) {
                int row = idx >> 2, c8 = (idx & 3) * 8;
                int grow = m0 + row;
                if (amap) {
                    int b = grow / SEQT, ss = grow - b * SEQT;
                    grow = 64 * ss * (ss + 1) + b * (ss + 1) + ss;
                }
                asm volatile("cp.async.cg.shared.global [%0], [%1], 16;"
                    :: "r"(smem_u32(as + row * SSTR + c8)),
                       "l"(A + (size_t)grow * ld + k0 + c8));
            } else {
                int rem = idx - 256;
                int row = rem >> 2, c8 = (rem & 3) * 8;
                asm volatile("cp.async.cg.shared.global [%0], [%1], 16;"
                    :: "r"(smem_u32(bs + row * SSTR + c8)),
                       "l"(W + (size_t)row * ld + k0 + c8));
            }
        }
        asm volatile("cp.async.commit_group;");
    };

    const int KT = K >> 5;
    issue(0, 0);
    issue(32, 1);
    for (int kt = 0; kt < KT; ++kt) {
        if (kt + 1 < KT) { asm volatile("cp.async.wait_group 1;"); }
        else             { asm volatile("cp.async.wait_group 0;"); }
        __syncthreads();
        if (kt + 2 < KT) issue((kt + 2) << 5, (kt + 2) % 3);

        const __nv_bfloat16* as = As + (kt % 3) * TILE_A64;
        const __nv_bfloat16* bs = Bs + (kt % 3) * TILE;
#pragma unroll
        for (int si = 0; si < 2; ++si) {
            int ks = si * 16;
            uint32_t af[2][4];
#pragma unroll
            for (int mi = 0; mi < 2; ++mi) {
                uint32_t ad = smem_u32(&as[(wm + mi * 16 + xr) * SSTR + ks + xc]);
                asm volatile("ldmatrix.sync.aligned.m8n8.x4.shared.b16 {%0,%1,%2,%3},[%4];"
                    : "=r"(af[mi][0]), "=r"(af[mi][1]), "=r"(af[mi][2]), "=r"(af[mi][3])
                    : "r"(ad));
            }
            uint32_t bfr[8][2];
#pragma unroll
            for (int np = 0; np < 4; ++np) {
                uint32_t bd = smem_u32(&bs[(wn + np * 16 + xr) * SSTR + ks + xc]);
                uint32_t r0, r1, r2, r3;
                asm volatile("ldmatrix.sync.aligned.m8n8.x4.shared.b16 {%0,%1,%2,%3},[%4];"
                    : "=r"(r0), "=r"(r1), "=r"(r2), "=r"(r3) : "r"(bd));
                bfr[2 * np][0] = r0; bfr[2 * np + 1][0] = r1;
                bfr[2 * np][1] = r2; bfr[2 * np + 1][1] = r3;
            }
#pragma unroll
            for (int mi = 0; mi < 2; ++mi)
#pragma unroll
                for (int ni = 0; ni < 8; ++ni) {
                    asm volatile(
                        "mma.sync.aligned.m16n8k16.row.col.f32.bf16.bf16.f32 "
                        "{%0,%1,%2,%3},{%4,%5,%6,%7},{%8,%9},{%0,%1,%2,%3};"
                        : "+f"(acc[mi][ni][0]), "+f"(acc[mi][ni][1]),
                          "+f"(acc[mi][ni][2]), "+f"(acc[mi][ni][3])
                        : "r"(af[mi][0]), "r"(af[mi][1]),
                          "r"(af[mi][2]), "r"(af[mi][3]),
                          "r"(bfr[ni][0]), "r"(bfr[ni][1]));
                }
        }
    }
}

// ---------------------------------------------------------------------------
// Plain GEMM (M128)
// ---------------------------------------------------------------------------
__global__ __launch_bounds__(128, 2) void gemm_bf16(
    const __nv_bfloat16* __restrict__ A, const __nv_bfloat16* __restrict__ W,
    const float* __restrict__ bias, float* __restrict__ Cf,
    __nv_bfloat16* __restrict__ Cb, int N, int K, int relu)
{
    extern __shared__ __align__(16) char dyn[];
    __nv_bfloat16* As = (__nv_bfloat16*)dyn;
    __nv_bfloat16* Bs = As + 3 * TILE;

    const int m0 = blockIdx.y * 128, n0 = blockIdx.x * 128;
    const int t = threadIdx.x, warp = t >> 5, lane = t & 31;
    const int g = lane >> 2, tig = lane & 3;
    const int wm = (warp >> 1) * 64, wn = (warp & 1) * 64;

    float acc[4][8][4];
    gemm_core(A, W, K, m0, n0, As, Bs, acc);

#pragma unroll
    for (int mi = 0; mi < 4; ++mi) {
#pragma unroll
        for (int ni = 0; ni < 8; ++ni) {
            int col = n0 + wn + ni * 8 + 2 * tig;
            float b0v = bias[col], b1v = bias[col + 1];
            int row = m0 + wm + mi * 16 + g;
            float2 v0 = make_float2(acc[mi][ni][0] + b0v, acc[mi][ni][1] + b1v);
            float2 v1 = make_float2(acc[mi][ni][2] + b0v, acc[mi][ni][3] + b1v);
            if (relu) {
                v0.x = fmaxf(v0.x, 0.f); v0.y = fmaxf(v0.y, 0.f);
                v1.x = fmaxf(v1.x, 0.f); v1.y = fmaxf(v1.y, 0.f);
            }
            if (Cf) {
                *(float2*)(Cf + (size_t)row * N + col)       = v0;
                *(float2*)(Cf + (size_t)(row + 8) * N + col) = v1;
            }
            if (Cb) {
                *(__nv_bfloat162*)(Cb + (size_t)row * N + col) =
                    __floats2bfloat162_rn(v0.x, v0.y);
                *(__nv_bfloat162*)(Cb + (size_t)(row + 8) * N + col) =
                    __floats2bfloat162_rn(v1.x, v1.y);
            }
        }
    }
}

// ---------------------------------------------------------------------------
// Plain GEMM (M64). Grid (N/128, M/64). amap per gemm_core64.
// ---------------------------------------------------------------------------
__global__ __launch_bounds__(128, 3) void gemm64(
    const __nv_bfloat16* __restrict__ A, const __nv_bfloat16* __restrict__ W,
    const float* __restrict__ bias, float* __restrict__ Cf,
    __nv_bfloat16* __restrict__ Cb, int N, int K, int ldA, int amap, int relu)
{
    extern __shared__ __align__(16) char dyn[];
    __nv_bfloat16* As = (__nv_bfloat16*)dyn;
    __nv_bfloat16* Bs = As + 3 * TILE_A64;

    const int m0 = blockIdx.y * 64, n0 = blockIdx.x * 128;
    const int t = threadIdx.x, warp = t >> 5, lane = t & 31;
    const int g = lane >> 2, tig = lane & 3;
    const int wm = (warp >> 1) * 32, wn = (warp & 1) * 64;

    float acc[2][8][4];
    gemm_core64(A, W + (size_t)n0 * K, ldA, K, m0, amap, As, Bs, acc);

#pragma unroll
    for (int mi = 0; mi < 2; ++mi) {
#pragma unroll
        for (int ni = 0; ni < 8; ++ni) {
            int col = n0 + wn + ni * 8 + 2 * tig;
            float b0v = bias[col], b1v = bias[col + 1];
            int row = m0 + wm + mi * 16 + g;
            float2 v0 = make_float2(acc[mi][ni][0] + b0v, acc[mi][ni][1] + b1v);
            float2 v1 = make_float2(acc[mi][ni][2] + b0v, acc[mi][ni][3] + b1v);
            if (relu) {
                v0.x = fmaxf(v0.x, 0.f); v0.y = fmaxf(v0.y, 0.f);
                v1.x = fmaxf(v1.x, 0.f); v1.y = fmaxf(v1.y, 0.f);
            }
            if (Cf) {
                *(float2*)(Cf + (size_t)row * N + col)       = v0;
                *(float2*)(Cf + (size_t)(row + 8) * N + col) = v1;
            }
            if (Cb) {
                *(__nv_bfloat162*)(Cb + (size_t)row * N + col) =
                    __floats2bfloat162_rn(v0.x, v0.y);
                *(__nv_bfloat162*)(Cb + (size_t)(row + 8) * N + col) =
                    __floats2bfloat162_rn(v1.x, v1.y);
            }
        }
    }
}

// ---------------------------------------------------------------------------
// Fused layer-1 qkv: flat grid of 648 blocks.
//   blocks [0,600): kv tiles (M128 core) -> g_kv1bf (N=KVS)
//   blocks [600,648): q tiles (M64 core, amap) -> g_q1bf (N=D)
// ---------------------------------------------------------------------------
__global__ __launch_bounds__(128, 2) void l1qkv_kernel(
    const __nv_bfloat16* __restrict__ A,
    const __nv_bfloat16* __restrict__ Wkv, const float* __restrict__ bkv,
    const __nv_bfloat16* __restrict__ Wq,  const float* __restrict__ bq)
{
    extern __shared__ __align__(16) char dyn[];
    const int t = threadIdx.x, warp = t >> 5, lane = t & 31;
    const int g = lane >> 2, tig = lane & 3;

    if (blockIdx.x < 600) {
        __nv_bfloat16* As = (__nv_bfloat16*)dyn;
        __nv_bfloat16* Bs = As + 3 * TILE;
        const int m0 = (blockIdx.x >> 1) * 128, n0 = (blockIdx.x & 1) * 128;
        const int wm = (warp >> 1) * 64, wn = (warp & 1) * 64;

        float acc[4][8][4];
        gemm_core(A, Wkv, D, m0, n0, As, Bs, acc);

#pragma unroll
        for (int mi = 0; mi < 4; ++mi) {
#pragma unroll
            for (int ni = 0; ni < 8; ++ni) {
                int col = n0 + wn + ni * 8 + 2 * tig;
                float b0v = bkv[col], b1v = bkv[col + 1];
                int row = m0 + wm + mi * 16 + g;
                *(__nv_bfloat162*)(g_kv1bf + (size_t)row * KVS + col) =
                    __floats2bfloat162_rn(acc[mi][ni][0] + b0v,
                                          acc[mi][ni][1] + b1v);
                *(__nv_bfloat162*)(g_kv1bf + (size_t)(row + 8) * KVS + col) =
                    __floats2bfloat162_rn(acc[mi][ni][2] + b0v,
                                          acc[mi][ni][3] + b1v);
            }
        }
    } else {
        __nv_bfloat16* As = (__nv_bfloat16*)dyn;
        __nv_bfloat16* Bs = As + 3 * TILE_A64;
        const int m0 = (blockIdx.x - 600) * 64;
        const int wm = (warp >> 1) * 32, wn = (warp & 1) * 64;

        float acc[2][8][4];
        gemm_core64(A, Wq, D, D, m0, 1, As, Bs, acc);

#pragma unroll
        for (int mi = 0; mi < 2; ++mi) {
#pragma unroll
            for (int ni = 0; ni < 8; ++ni) {
                int col = wn + ni * 8 + 2 * tig;
                float b0v = bq[col], b1v = bq[col + 1];
                int row = m0 + wm + mi * 16 + g;
                *(__nv_bfloat162*)(g_q1bf + (size_t)row * D + col) =
                    __floats2bfloat162_rn(acc[mi][ni][0] + b0v,
                                          acc[mi][ni][1] + b1v);
                *(__nv_bfloat162*)(g_q1bf + (size_t)(row + 8) * D + col) =
                    __floats2bfloat162_rn(acc[mi][ni][2] + b0v,
                                          acc[mi][ni][3] + b1v);
            }
        }
    }
}

// ---------------------------------------------------------------------------
// GEMM + residual + LayerNorm, M64. N == 128.
// gather=0: residual row n of Rres; 1: packed last-token map; 2: h0 map
// ---------------------------------------------------------------------------
__global__ __launch_bounds__(128, 3) void gemm_ln64(
    const __nv_bfloat16* __restrict__ A, const __nv_bfloat16* __restrict__ W,
    const float* __restrict__ bias, const float* __restrict__ lng,
    const float* __restrict__ lnb, const float* __restrict__ Rres,
    float* __restrict__ Yout, __nv_bfloat16* __restrict__ Ybf,
    int K, int gather)
{
    extern __shared__ __align__(16) char dyn[];
    __nv_bfloat16* As = (__nv_bfloat16*)dyn;
    __nv_bfloat16* Bs = As + 3 * TILE_A64;
    float* redS = (float*)(dyn + 3 * (TILE_A64 + TILE) * 2);  // [2][64]
    float* redQ = redS + 128;

    const int m0 = blockIdx.y * 64;
    const int t = threadIdx.x, warp = t >> 5, lane = t & 31;
    const int g = lane >> 2, tig = lane & 3;
    const int wm = (warp >> 1) * 32, wn = (warp & 1) * 64;
    const int cw = warp & 1;

    float acc[2][8][4];
    gemm_core64(A, W, K, K, m0, 0, As, Bs, acc);

    auto res_row = [&](int n) -> const float* {
        if (gather == 1) {
            int b = n / SEQT, s = n - b * SEQT;
            int src = 64 * s * (s + 1) + b * (s + 1) + s;
            return Rres + (size_t)src * D;
        }
        if (gather == 2) {
            int s = step_of(n);
            int r = n - 64 * s * (s + 1);
            int P = s + 1;
            int b = r / P;
            int tt = r - b * P;
            return g_h0 + (size_t)(b * SEQT + tt) * D;
        }
        return Rres + (size_t)n * D;
    };

#pragma unroll
    for (int mi = 0; mi < 2; ++mi) {
        int r0 = wm + mi * 16 + g, r1 = r0 + 8;
        const float* R0 = res_row(m0 + r0);
        const float* R1 = res_row(m0 + r1);
        float s0 = 0.f, q0 = 0.f, s1 = 0.f, q1 = 0.f;
#pragma unroll
        for (int ni = 0; ni < 8; ++ni) {
            int col = wn + ni * 8 + 2 * tig;
            float2 bv = *(const float2*)(bias + col);
            float2 y0 = *(const float2*)(R0 + col);
            float2 y1 = *(const float2*)(R1 + col);
            float a0 = acc[mi][ni][0] + bv.x + y0.x;
            float a1 = acc[mi][ni][1] + bv.y + y0.y;
            float a2 = acc[mi][ni][2] + bv.x + y1.x;
            float a3 = acc[mi][ni][3] + bv.y + y1.y;
            acc[mi][ni][0] = a0; acc[mi][ni][1] = a1;
            acc[mi][ni][2] = a2; acc[mi][ni][3] = a3;
            s0 += a0 + a1; q0 += a0 * a0 + a1 * a1;
            s1 += a2 + a3; q1 += a2 * a2 + a3 * a3;
        }
#pragma unroll
        for (int o = 1; o <= 2; o <<= 1) {
            s0 += __shfl_xor_sync(0xffffffffu, s0, o);
            q0 += __shfl_xor_sync(0xffffffffu, q0, o);
            s1 += __shfl_xor_sync(0xffffffffu, s1, o);
            q1 += __shfl_xor_sync(0xffffffffu, q1, o);
        }
        if (tig == 0) {
            redS[cw * 64 + r0] = s0; redQ[cw * 64 + r0] = q0;
            redS[cw * 64 + r1] = s1; redQ[cw * 64 + r1] = q1;
        }
    }
    __syncthreads();

#pragma unroll
    for (int mi = 0; mi < 2; ++mi) {
        int r0 = wm + mi * 16 + g, r1 = r0 + 8;
        float S0 = redS[r0] + redS[64 + r0], Q0 = redQ[r0] + redQ[64 + r0];
        float S1 = redS[r1] + redS[64 + r1], Q1 = redQ[r1] + redQ[64 + r1];
        float mu0 = S0 * (1.f / 128.f), mu1 = S1 * (1.f / 128.f);
        float iv0 = rsqrtf(Q0 * (1.f / 128.f) - mu0 * mu0 + 1e-5f);
        float iv1 = rsqrtf(Q1 * (1.f / 128.f) - mu1 * mu1 + 1e-5f);
#pragma unroll
        for (int ni = 0; ni < 8; ++ni) {
            int col = wn + ni * 8 + 2 * tig;
            float2 gv = *(const float2*)(lng + col);
            float2 bv = *(const float2*)(lnb + col);
            float o0 = (acc[mi][ni][0] - mu0) * iv0 * gv.x + bv.x;
            float o1 = (acc[mi][ni][1] - mu0) * iv0 * gv.y + bv.y;
            float o2 = (acc[mi][ni][2] - mu1) * iv1 * gv.x + bv.x;
            float o3 = (acc[mi][ni][3] - mu1) * iv1 * gv.y + bv.y;
            *(float2*)(Yout + (size_t)(m0 + r0) * D + col) = make_float2(o0, o1);
            *(float2*)(Yout + (size_t)(m0 + r1) * D + col) = make_float2(o2, o3);
            *(__nv_bfloat162*)(Ybf + (size_t)(m0 + r0) * D + col) =
                __floats2bfloat162_rn(o0, o1);
            *(__nv_bfloat162*)(Ybf + (size_t)(m0 + r1) * D + col) =
                __floats2bfloat162_rn(o2, o3);
        }
    }
}

// ---------------------------------------------------------------------------
// Split-K partial GEMM, M64, N=128, fp32 partials. blockIdx.z = part.
// ---------------------------------------------------------------------------
__global__ __launch_bounds__(128, 3) void gemm_part64(
    const __nv_bfloat16* __restrict__ A, const __nv_bfloat16* __restrict__ W,
    float* __restrict__ P, int ld, int Kpart, int Mtot)
{
    extern __shared__ __align__(16) char dyn[];
    __nv_bfloat16* As = (__nv_bfloat16*)dyn;
    __nv_bfloat16* Bs = As + 3 * TILE_A64;

    const int m0 = blockIdx.y * 64;
    const int part = blockIdx.z;
    A += (size_t)part * Kpart;
    W += (size_t)part * Kpart;
    P += (size_t)part * Mtot * D;

    const int t = threadIdx.x, warp = t >> 5, lane = t & 31;
    const int g = lane >> 2, tig = lane & 3;
    const int wm = (warp >> 1) * 32, wn = (warp & 1) * 64;

    float acc[2][8][4];
    gemm_core64(A, W, ld, Kpart, m0, 0, As, Bs, acc);

#pragma unroll
    for (int mi = 0; mi < 2; ++mi) {
        int r0 = wm + mi * 16 + g, r1 = r0 + 8;
#pragma unroll
        for (int ni = 0; ni < 8; ++ni) {
            int col = wn + ni * 8 + 2 * tig;
            *(float2*)(P + (size_t)(m0 + r0) * D + col) =
                make_float2(acc[mi][ni][0], acc[mi][ni][1]);
            *(float2*)(P + (size_t)(m0 + r1) * D + col) =
                make_float2(acc[mi][ni][2], acc[mi][ni][3]);
        }
    }
}

// ---------------------------------------------------------------------------
// fc combine: h0 = relu(P0..P3 + b_fc) + PE; writes fp32 + bf16
// ---------------------------------------------------------------------------
__global__ void fc_combine(const float* __restrict__ bias)
{
    int i = blockIdx.x * 256 + threadIdx.x;
    if (i >= NBT * D) return;
    int n = i >> 7, d = i & 127;
    int t = n % SEQT;
    float v = g_part[i] + g_part[NBT * D + i] + g_part[2 * NBT * D + i]
            + g_part[3 * NBT * D + i] + bias[d];
    v = fmaxf(v, 0.f);
    float freq = expf((float)(d & ~1) * (-9.210340371976184f / 128.f));
    float arg  = (float)t * freq;
    v += (d & 1) ? cosf(arg) : sinf(arg);
    g_h0[i]    = v;
    g_h0pbf[i] = __float2bfloat16(v);
}

// ---------------------------------------------------------------------------
// ff2-l0 combine (2 parts) + residual + LayerNorm -> packed Y / Ybf
// ---------------------------------------------------------------------------
__global__ __launch_bounds__(128) void ln_combine(
    const float* __restrict__ bias, const float* __restrict__ lng,
    const float* __restrict__ lnb)
{
    int n    = blockIdx.x * 4 + (threadIdx.x >> 5);
    int lane = threadIdx.x & 31;
    float v[4], s = 0.f, q = 0.f;
#pragma unroll
    for (int i = 0; i < 4; ++i) {
        int d = lane + 32 * i;
        size_t off = (size_t)n * D + d;
        v[i] = g_Y[off] + g_part[off] + g_part[(size_t)NT * D + off] + bias[d];
        s += v[i]; q += v[i] * v[i];
    }
    for (int o = 16; o; o >>= 1) {
        s += __shfl_xor_sync(0xffffffffu, s, o);
        q += __shfl_xor_sync(0xffffffffu, q, o);
    }
    float mu = s * (1.f / 128.f);
    float iv = rsqrtf(q * (1.f / 128.f) - mu * mu + 1e-5f);
#pragma unroll
    for (int i = 0; i < 4; ++i) {
        int d = lane + 32 * i;
        size_t off = (size_t)n * D + d;
        float o = (v[i] - mu) * iv * lng[d] + lnb[d];
        g_Y[off]   = o;
        g_Ybf[off] = __float2bfloat16(o);
    }
}

// ---------------------------------------------------------------------------
// ff2-l1 combine (4 parts) + residual + LayerNorm -> Ylast (fp32 only)
// ---------------------------------------------------------------------------
__global__ __launch_bounds__(128) void ln_combine_last(
    const float* __restrict__ bias, const float* __restrict__ lng,
    const float* __restrict__ lnb)
{
    int n    = blockIdx.x * 4 + (threadIdx.x >> 5);
    int lane = threadIdx.x & 31;
    float v[4], s = 0.f, q = 0.f;
#pragma unroll
    for (int i = 0; i < 4; ++i) {
        int d = lane + 32 * i;
        size_t off = (size_t)n * D + d;
        v[i] = g_Ylast[off] + g_part[off] + g_part[(size_t)NBT * D + off]
             + g_part[2ull * NBT * D + off] + g_part[3ull * NBT * D + off]
             + bias[d];
        s += v[i]; q += v[i] * v[i];
    }
    for (int o = 16; o; o >>= 1) {
        s += __shfl_xor_sync(0xffffffffu, s, o);
        q += __shfl_xor_sync(0xffffffffu, q, o);
    }
    float mu = s * (1.f / 128.f);
    float iv = rsqrtf(q * (1.f / 128.f) - mu * mu + 1e-5f);
#pragma unroll
    for (int i = 0; i < 4; ++i) {
        int d = lane + 32 * i;
        size_t off = (size_t)n * D + d;
        g_Ylast[off] = (v[i] - mu) * iv * lng[d] + lnb[d];
    }
}

// ---------------------------------------------------------------------------
// One-shot fp32 -> bf16 conversion
// ---------------------------------------------------------------------------
#define CVT_TOTAL 2818048
__global__ void cvt_all(const float* __restrict__ x, const float* __restrict__ wfc,
                        const float* __restrict__ qkvw, const float* __restrict__ outw,
                        const float* __restrict__ ff1w, const float* __restrict__ ff2w)
{
    int i = (blockIdx.x * 256 + threadIdx.x) * 4;
    if (i >= CVT_TOTAL) return;
    const float* s; __nv_bfloat16* d; int off;
    if      (i < 1572864) { s = x;    d = g_xbf;     off = i; }
    else if (i < 1638400) { s = wfc;  d = g_wfc_bf;  off = i - 1572864; }
    else if (i < 1736704) { s = qkvw; d = g_qkvw_bf; off = i - 1638400; }
    else if (i < 1769472) { s = outw; d = g_outw_bf; off = i - 1736704; }
    else if (i < 2293760) { s = ff1w; d = g_ff1w_bf; off = i - 1769472; }
    else                  { s = ff2w; d = g_ff2w_bf; off = i - 2293760; }
    float4 v = *(const float4*)(s + off);
    *(__nv_bfloat162*)(d + off)     = __floats2bfloat162_rn(v.x, v.y);
    *(__nv_bfloat162*)(d + off + 2) = __floats2bfloat162_rn(v.z, v.w);
}

// ---------------------------------------------------------------------------
// Layer-0 attention, prefix-dedup: one block per (b,h); 24x24 scores once,
// online-softmax prefix scan emits ctx for every step s >= t.
// ---------------------------------------------------------------------------
__global__ __launch_bounds__(64) void attn0_kernel()
{
    __shared__ float qs[SEQT][DH], ks[SEQT][DH], vs[SEQT][DH];
    __shared__ float sc[SEQT][SEQT];

    int blk = blockIdx.x;
    int b = blk >> 2;
    int h = blk & 3;
    int tid  = threadIdx.x;
    int w    = tid >> 5;
    int lane = tid & 31;

    for (int i = tid; i < SEQT * DH; i += 64) {
        int t = i >> 5, dd = i & 31;
        const __nv_bfloat16* row =
            g_qkv0bf + (size_t)(b * SEQT + t) * (3 * D) + h * DH + dd;
        qs[t][dd] = __bfloat162float(row[0]);
        ks[t][dd] = __bfloat162float(row[D]);
        vs[t][dd] = __bfloat162float(row[2 * D]);
    }
    __syncthreads();

    for (int p = tid; p < SEQT * SEQT; p += 64) {
        int t = p / SEQT, j = p - t * SEQT;
        float a = 0.f;
#pragma unroll
        for (int dd = 0; dd < DH; ++dd) a += qs[t][dd] * ks[j][dd];
        sc[t][j] = a * 0.17677669529663687f;
    }
    __syncthreads();

    for (int t = w; t < SEQT; t += 2) {
        float m = -1e30f, l = 0.f, acc = 0.f;
        for (int j = 0; j < SEQT; ++j) {
            float x = sc[t][j];
            float nm = fmaxf(m, x);
            float so = __expf(m - nm);
            float e  = __expf(x - nm);
            l   = l * so + e;
            acc = acc * so + e * vs[j][lane];
            m = nm;
            if (j >= t) {
                int dst = 64 * j * (j + 1) + b * (j + 1) + t;
                g_ctxbf[(size_t)dst * D + h * DH + lane] =
                    __float2bfloat16(acc / l);
            }
        }
    }
}

// ---------------------------------------------------------------------------
// Layer-1 attention, LAST query only
// ---------------------------------------------------------------------------
__global__ __launch_bounds__(128) void attn1_kernel()
{
    __shared__ float qs[NH][DH];
    __shared__ float ps[NH][32];

    int q = blockIdx.x;
    int s = q >> 7;
    int b = q & 127;
    int P = s + 1;
    int base = 64 * s * (s + 1) + b * P;
    int tid  = threadIdx.x;
    int h    = tid >> 5;
    int lane = tid & 31;

    qs[h][lane] = __bfloat162float(
        g_q1bf[(size_t)(b * SEQT + s) * D + h * DH + lane]);
    __syncthreads();

    float sc = -1e30f;
    if (lane < P) {
        const __nv_bfloat16* krow = g_kv1bf + (size_t)(base + lane) * KVS + h * DH;
        float a = 0.f;
#pragma unroll
        for (int dd = 0; dd < DH; ++dd) a += qs[h][dd] * __bfloat162float(krow[dd]);
        sc = a * 0.17677669529663687f;
    }
    float m = sc;
    for (int o = 16; o; o >>= 1) m = fmaxf(m, __shfl_xor_sync(0xffffffffu, m, o));
    float e = (lane < P) ? expf(sc - m) : 0.f;
    float sum = e;
    for (int o = 16; o; o >>= 1) sum += __shfl_xor_sync(0xffffffffu, sum, o);
    ps[h][lane] = e / sum;
    __syncwarp();

    float c = 0.f;
    for (int j = 0; j < P; ++j)
        c += ps[h][j] * __bfloat162float(
                 g_kv1bf[(size_t)(base + j) * KVS + D + h * DH + lane]);
    g_ctxlastbf[(size_t)(b * SEQT + s) * D + h * DH + lane] = __float2bfloat16(c);
}

// ---------------------------------------------------------------------------
// Classifier + log_softmax: 16 tokens per block, Wc1 staged in smem once.
// ---------------------------------------------------------------------------
#define CLS_TPB 16
__global__ __launch_bounds__(128) void cls_kernel(
    const float* __restrict__ Wc1, const float* __restrict__ bc1,
    const float* __restrict__ Wc2, const float* __restrict__ bc2,
    float* __restrict__ out)
{
    __shared__ float w1s[NC * D];
    __shared__ float rows[CLS_TPB][D];
    __shared__ float c1s[CLS_TPB][NC];

    int n0 = blockIdx.x * CLS_TPB;
    int t  = threadIdx.x;

    for (int i = t; i < NC * D / 4; i += 128)
        ((float4*)w1s)[i] = ((const float4*)Wc1)[i];
    for (int i = t; i < CLS_TPB * D / 4; i += 128) {
        int tok = i >> 5, c = i & 31;
        ((float4*)rows[tok])[c] =
            ((const float4*)(g_Ylast + (size_t)(n0 + tok) * D))[c];
    }
    __syncthreads();

#pragma unroll
    for (int p = 0; p < CLS_TPB * NC / 128; ++p) {
        int pair = t + p * 128;
        int tok = pair >> 6, o = pair & 63;
        float a = bc1[o];
        const float* wr = w1s + o * D;
        const float* rr = rows[tok];
#pragma unroll
        for (int d = 0; d < D; ++d) a += rr[d] * wr[d];
        c1s[tok][o] = fmaxf(a, 0.f);
    }
    __syncthreads();

    if (t < CLS_TPB) {
        float l0 = bc2[0], l1 = bc2[1];
#pragma unroll
        for (int j = 0; j < NC; ++j) {
            float c = c1s[t][j];
            l0 += c * Wc2[j];
            l1 += c * Wc2[NC + j];
        }
        float m   = fmaxf(l0, l1);
        float lse = m + logf(expf(l0 - m) + expf(l1 - m));
        out[(n0 + t) * 2 + 0] = l0 - lse;
        out[(n0 + t) * 2 + 1] = l1 - lse;
    }
}

// ---------------------------------------------------------------------------
extern "C" void kernel_launch(void* const* d_in, const int* in_sizes, int n_in,
                              void* d_out, int out_size)
{
    const float* x     = (const float*)d_in[0];
    const float* W_fc  = (const float*)d_in[1];
    const float* b_fc  = (const float*)d_in[2];
    const float* qkv_w = (const float*)d_in[3];
    const float* qkv_b = (const float*)d_in[4];
    const float* out_w = (const float*)d_in[5];
    const float* out_b = (const float*)d_in[6];
    const float* ln1_g = (const float*)d_in[7];
    const float* ln1_b = (const float*)d_in[8];
    const float* ln2_g = (const float*)d_in[9];
    const float* ln2_b = (const float*)d_in[10];
    const float* ff1_w = (const float*)d_in[11];
    const float* ff1_b = (const float*)d_in[12];
    const float* ff2_w = (const float*)d_in[13];
    const float* ff2_b = (const float*)d_in[14];
    const float* Wc1   = (const float*)d_in[15];
    const float* bc1   = (const float*)d_in[16];
    const float* Wc2   = (const float*)d_in[17];
    const float* bc2   = (const float*)d_in[18];

    cudaFuncSetAttribute(gemm_bf16, cudaFuncAttributeMaxDynamicSharedMemorySize,
                         GEMM_SMEM);
    cudaFuncSetAttribute(gemm64, cudaFuncAttributeMaxDynamicSharedMemorySize,
                         GEMM_SMEM_64);
    cudaFuncSetAttribute(gemm_ln64, cudaFuncAttributeMaxDynamicSharedMemorySize,
                         GEMM_SMEM_LN64);
    cudaFuncSetAttribute(gemm_part64, cudaFuncAttributeMaxDynamicSharedMemorySize,
                         GEMM_SMEM_64);
    cudaFuncSetAttribute(l1qkv_kernel, cudaFuncAttributeMaxDynamicSharedMemorySize,
                         GEMM_SMEM);

    void* p;
    cudaGetSymbolAddress(&p, g_Y);        float* Y     = (float*)p;
    cudaGetSymbolAddress(&p, g_Ylast);    float* Ylast = (float*)p;
    cudaGetSymbolAddress(&p, g_part);     float* part  = (float*)p;
    cudaGetSymbolAddress(&p, g_xbf);      __nv_bfloat16* xbf   = (__nv_bfloat16*)p;
    cudaGetSymbolAddress(&p, g_wfc_bf);   __nv_bfloat16* wfcb  = (__nv_bfloat16*)p;
    cudaGetSymbolAddress(&p, g_qkvw_bf);  __nv_bfloat16* qkvwb = (__nv_bfloat16*)p;
    cudaGetSymbolAddress(&p, g_outw_bf);  __nv_bfloat16* outwb = (__nv_bfloat16*)p;
    cudaGetSymbolAddress(&p, g_ff1w_bf);  __nv_bfloat16* ff1wb = (__nv_bfloat16*)p;
    cudaGetSymbolAddress(&p, g_ff2w_bf);  __nv_bfloat16* ff2wb = (__nv_bfloat16*)p;
    cudaGetSymbolAddress(&p, g_h0pbf);    __nv_bfloat16* h0pb  = (__nv_bfloat16*)p;
    cudaGetSymbolAddress(&p, g_qkv0bf);   __nv_bfloat16* qkv0b = (__nv_bfloat16*)p;
    cudaGetSymbolAddress(&p, g_Ybf);      __nv_bfloat16* ybf   = (__nv_bfloat16*)p;
    cudaGetSymbolAddress(&p, g_ctxbf);    __nv_bfloat16* ctxb  = (__nv_bfloat16*)p;
    cudaGetSymbolAddress(&p, g_ctxlastbf);__nv_bfloat16* ctxlb = (__nv_bfloat16*)p;
    cudaGetSymbolAddress(&p, g_Ylastbf);  __nv_bfloat16* ylbf  = (__nv_bfloat16*)p;
    cudaGetSymbolAddress(&p, g_Hbf);      __nv_bfloat16* hbf   = (__nv_bfloat16*)p;

    cvt_all<<<(CVT_TOTAL / 4 + 255) / 256, 256>>>(x, W_fc, qkv_w, out_w, ff1_w, ff2_w);

    // fc: split-K x4, combine applies bias+ReLU+PE
    gemm_part64<<<dim3(1, NBT / 64, 4), 128, GEMM_SMEM_64>>>(
        xbf, wfcb, part, DIN, DIN / 4, NBT);
    fc_combine<<<(NBT * D + 255) / 256, 256>>>(b_fc);

    // ---- layer 0 ----
    gemm64<<<dim3(3, NBT / 64), 128, GEMM_SMEM_64>>>(
        h0pb, qkvwb, qkv_b, nullptr, qkv0b, 3 * D, D, D, 0, 0);
    attn0_kernel<<<BATCH * NH, 64>>>();
    gemm_ln64<<<dim3(1, NT / 64), 128, GEMM_SMEM_LN64>>>(
        ctxb, outwb, out_b, ln1_g, ln1_b, nullptr, Y, ybf, D, 2);
    gemm_bf16<<<dim3(DFF / 128, NT / 128), 128, GEMM_SMEM>>>(
        ybf, ff1wb, ff1_b, nullptr, hbf, DFF, D, 1);
    gemm_part64<<<dim3(1, NT / 64, 2), 128, GEMM_SMEM_64>>>(
        hbf, ff2wb, part, DFF, DFF / 2, NT);
    ln_combine<<<NT / 4, 128>>>(ff2_b, ln2_g, ln2_b);

    // ---- layer 1 (K/V full; Q + tail last-token only) ----
    // fused kv + q launch: 600 kv tiles + 48 q tiles
    l1qkv_kernel<<<648, 128, GEMM_SMEM>>>(
        ybf,
        qkvwb + (size_t)3 * D * D + (size_t)D * D, qkv_b + 3 * D + D,
        qkvwb + (size_t)3 * D * D, qkv_b + 3 * D);
    attn1_kernel<<<S_STEPS * BATCH, 128>>>();
    gemm_ln64<<<dim3(1, NBT / 64), 128, GEMM_SMEM_LN64>>>(
        ctxlb, outwb + (size_t)D * D, out_b + D,
        ln1_g + D, ln1_b + D, Y, Ylast, ylbf, D, 1);
    gemm64<<<dim3(DFF / 128, NBT / 64), 128, GEMM_SMEM_64>>>(
        ylbf, ff1wb + (size_t)DFF * D, ff1_b + DFF, nullptr, hbf,
        DFF, D, D, 0, 1);
    gemm_part64<<<dim3(1, NBT / 64, 4), 128, GEMM_SMEM_64>>>(
        hbf, ff2wb + (size_t)D * DFF, part, DFF, DFF / 4, NBT);
    ln_combine_last<<<NBT / 4, 128>>>(ff2_b + D, ln2_g + D, ln2_b + D);

    cls_kernel<<<NBT / CLS_TPB, 128>>>(Wc1, bc1, Wc2, bc2, (float*)d_out);
}